// round 1
// baseline (speedup 1.0000x reference)
#include <cuda_runtime.h>
#include <math.h>

#define Bb 2
#define Ss 1024
#define HID 2048
#define NH 16
#define NS 8
#define Dd 128
#define Mm (Bb*Ss)      // 2048
#define BH (Bb*NH)      // 32

// ---------------- scratch (device globals; no allocation allowed) ----------
__device__ float g_Q[(size_t)Mm*HID];
__device__ float g_K[(size_t)Mm*HID];
__device__ float g_V[(size_t)Mm*HID];
__device__ float g_scores[(size_t)BH*Ss*Ss];     // 128 MB
__device__ float g_comb[(size_t)Mm*HID];
__device__ float g_qa[(size_t)BH*Ss*NS];
__device__ float g_ka[(size_t)BH*Ss*NS];
__device__ float g_kvmat[(size_t)BH*NS*Dd];
__device__ float g_ksum[BH*NS];
__device__ float g_pos[NH*NS*Dd];
__device__ float g_dir[NH*NS*Dd];
__device__ float g_possq[NH*NS];
__device__ float g_pdd[NH*NS];
__device__ float g_inv2s2[NH*NS];
__device__ float g_amp[NH*NS];
__device__ float g_ds;
__device__ float g_blend;

// ---------------- prep: normalize splats, softmax amps, scalars ------------
__global__ void prep_kernel(const float* __restrict__ pos_in,
                            const float* __restrict__ dir_in,
                            const float* __restrict__ ls_in,
                            const float* __restrict__ la_in,
                            const float* __restrict__ dstr,
                            const float* __restrict__ gstr)
{
    int i = threadIdx.x;                 // 128 threads, i = h*NS + n
    if (i < NH*NS) {
        const float* p = pos_in + (size_t)i*Dd;
        const float* dv = dir_in + (size_t)i*Dd;
        float np = 0.f, nd = 0.f;
        for (int d = 0; d < Dd; ++d) { np += p[d]*p[d]; nd += dv[d]*dv[d]; }
        float pscale = 3.39411254969543f / (sqrtf(np) + 1e-12f); // sqrt(128)*0.3
        float dscale = 1.0f / (sqrtf(nd) + 1e-12f);
        float psq = 0.f, pdd = 0.f;
        for (int d = 0; d < Dd; ++d) {
            float ps = p[d]*pscale, du = dv[d]*dscale;
            g_pos[(size_t)i*Dd + d] = ps;
            g_dir[(size_t)i*Dd + d] = du;
            psq += ps*ps;  pdd += ps*du;
        }
        g_possq[i] = psq;  g_pdd[i] = pdd;
        float sc = expf(ls_in[i]);
        sc = fminf(fmaxf(sc, 0.3f), 1.2f);
        g_inv2s2[i] = 0.5f / (sc*sc);
    }
    __syncthreads();
    if (i < NH) {
        float m = -1e30f;
        for (int n = 0; n < NS; ++n) m = fmaxf(m, la_in[i*NS+n]);
        float s = 0.f, e[NS];
        for (int n = 0; n < NS; ++n) { e[n] = expf(la_in[i*NS+n]-m); s += e[n]; }
        for (int n = 0; n < NS; ++n) g_amp[i*NS+n] = e[n]/s;
    }
    if (i == 0) {
        g_ds = 1.0f / (1.0f + expf(-dstr[0]));
        float gsa = 1.0f / (1.0f + expf(-gstr[0]));
        g_blend = fminf(0.05f, gsa*0.1f);
    }
}

// ---------------- 128x128x8 SGEMM core (256 threads, 8x8 microtile) --------
#define BMt 128
#define BNt 128
#define BKt 8

template<bool TRANSB>
__device__ __forceinline__ void sgemm_body(
    const float* __restrict__ A, int lda,
    const float* __restrict__ B, int ldb,
    float* __restrict__ C, int ldc,
    int K, float alpha, int row0, int col0)
{
    __shared__ float As[BKt][BMt];
    __shared__ float Bs[BKt][BNt];
    int tid  = threadIdx.x;
    int trow = (tid >> 4) * 8;
    int tcol = (tid & 15) * 8;
    int aRow = tid >> 1;           // 0..127
    int aCol = (tid & 1) * 4;      // 0 or 4
    int bRow = tid >> 5;           // 0..7
    int bCol = (tid & 31) * 4;     // 0..124
    float acc[8][8];
    #pragma unroll
    for (int i = 0; i < 8; ++i)
        #pragma unroll
        for (int j = 0; j < 8; ++j) acc[i][j] = 0.f;

    for (int k0 = 0; k0 < K; k0 += BKt) {
        float4 av = *(const float4*)(A + (size_t)(row0 + aRow)*lda + k0 + aCol);
        As[aCol+0][aRow] = av.x; As[aCol+1][aRow] = av.y;
        As[aCol+2][aRow] = av.z; As[aCol+3][aRow] = av.w;
        if (TRANSB) {
            float4 bv = *(const float4*)(B + (size_t)(col0 + aRow)*ldb + k0 + aCol);
            Bs[aCol+0][aRow] = bv.x; Bs[aCol+1][aRow] = bv.y;
            Bs[aCol+2][aRow] = bv.z; Bs[aCol+3][aRow] = bv.w;
        } else {
            float4 bv = *(const float4*)(B + (size_t)(k0 + bRow)*ldb + col0 + bCol);
            *(float4*)&Bs[bRow][bCol] = bv;
        }
        __syncthreads();
        #pragma unroll
        for (int k = 0; k < BKt; ++k) {
            float4 a0 = *(const float4*)&As[k][trow];
            float4 a1 = *(const float4*)&As[k][trow+4];
            float4 b0 = *(const float4*)&Bs[k][tcol];
            float4 b1 = *(const float4*)&Bs[k][tcol+4];
            float ra[8] = {a0.x,a0.y,a0.z,a0.w,a1.x,a1.y,a1.z,a1.w};
            float rb[8] = {b0.x,b0.y,b0.z,b0.w,b1.x,b1.y,b1.z,b1.w};
            #pragma unroll
            for (int i = 0; i < 8; ++i)
                #pragma unroll
                for (int j = 0; j < 8; ++j)
                    acc[i][j] += ra[i]*rb[j];
        }
        __syncthreads();
    }
    #pragma unroll
    for (int i = 0; i < 8; ++i) {
        float* cp = C + (size_t)(row0 + trow + i)*ldc + col0 + tcol;
        float4 v0 = {alpha*acc[i][0], alpha*acc[i][1], alpha*acc[i][2], alpha*acc[i][3]};
        float4 v1 = {alpha*acc[i][4], alpha*acc[i][5], alpha*acc[i][6], alpha*acc[i][7]};
        *(float4*)cp = v0;  *(float4*)(cp+4) = v1;
    }
}

// ---------------- GEMM wrapper kernels -------------------------------------
__global__ void qkv_kernel(const float* __restrict__ X,
                           const float* __restrict__ Wq,
                           const float* __restrict__ Wk,
                           const float* __restrict__ Wv)
{
    const float* W = (blockIdx.z == 0) ? Wq : (blockIdx.z == 1) ? Wk : Wv;
    float* Co = (blockIdx.z == 0) ? g_Q : (blockIdx.z == 1) ? g_K : g_V;
    sgemm_body<false>(X, HID, W, HID, Co, HID, HID, 1.0f,
                      blockIdx.y*BMt, blockIdx.x*BNt);
}

__global__ void scores_kernel()
{
    int bh = blockIdx.z;  int b = bh / NH, h = bh % NH;
    const float* Aq = g_Q + (size_t)b*Ss*HID + h*Dd;
    const float* Bk = g_K + (size_t)b*Ss*HID + h*Dd;
    float* Cs = g_scores + (size_t)bh*Ss*Ss;
    sgemm_body<true>(Aq, HID, Bk, HID, Cs, Ss, Dd, 0.08838834764831845f,
                     blockIdx.y*BMt, blockIdx.x*BNt);
}

__global__ void pv_kernel()
{
    int bh = blockIdx.z;  int b = bh / NH, h = bh % NH;
    const float* Aat = g_scores + (size_t)bh*Ss*Ss;
    const float* Bv = g_V + (size_t)b*Ss*HID + h*Dd;
    float* Cc = g_comb + (size_t)b*Ss*HID + h*Dd;
    float alpha = 1.0f - g_blend;
    sgemm_body<false>(Aat, Ss, Bv, HID, Cc, HID, Ss, alpha,
                      blockIdx.y*BMt, blockIdx.x*BNt);
}

__global__ void wo_kernel(const float* __restrict__ Wo, float* __restrict__ out)
{
    sgemm_body<false>(g_comb, HID, Wo, HID, out, HID, HID, 1.0f,
                      blockIdx.y*BMt, blockIdx.x*BNt);
}

// ---------------- softmax over rows of scores ------------------------------
__global__ void softmax_kernel()
{
    __shared__ float red[8];
    float* row = g_scores + ((size_t)blockIdx.y*Ss + blockIdx.x)*Ss;
    int tid = threadIdx.x;   // 256
    float v[4];
    float m = -1e30f;
    #pragma unroll
    for (int i = 0; i < 4; ++i) { v[i] = row[tid + i*256]; m = fmaxf(m, v[i]); }
    #pragma unroll
    for (int o = 16; o; o >>= 1) m = fmaxf(m, __shfl_xor_sync(0xffffffffu, m, o));
    if ((tid & 31) == 0) red[tid >> 5] = m;
    __syncthreads();
    m = red[0];
    #pragma unroll
    for (int w = 1; w < 8; ++w) m = fmaxf(m, red[w]);
    __syncthreads();
    float s = 0.f;
    #pragma unroll
    for (int i = 0; i < 4; ++i) { v[i] = expf(v[i]-m); s += v[i]; }
    #pragma unroll
    for (int o = 16; o; o >>= 1) s += __shfl_xor_sync(0xffffffffu, s, o);
    if ((tid & 31) == 0) red[tid >> 5] = s;
    __syncthreads();
    s = red[0]+red[1]+red[2]+red[3]+red[4]+red[5]+red[6]+red[7];
    float inv = 1.0f/s;
    #pragma unroll
    for (int i = 0; i < 4; ++i) row[tid + i*256] = v[i]*inv;
}

// ---------------- affinities qa / ka ---------------------------------------
__device__ __forceinline__ float bsum128(float v)
{
    __shared__ float red[4];
    #pragma unroll
    for (int o = 16; o; o >>= 1) v += __shfl_xor_sync(0xffffffffu, v, o);
    if ((threadIdx.x & 31) == 0) red[threadIdx.x >> 5] = v;
    __syncthreads();
    v = red[0]+red[1]+red[2]+red[3];
    __syncthreads();
    return v;
}

__global__ void affinity_kernel()
{
    int s  = blockIdx.x;
    int bh = blockIdx.y;  int b = bh / NH, h = bh % NH;
    int z  = blockIdx.z;                 // 0 -> qa(Q), 1 -> ka(K)
    int d  = threadIdx.x;                // 128
    const float* src = z ? g_K : g_Q;
    float* out = z ? g_ka : g_qa;
    float t = src[((size_t)b*Ss + s)*HID + h*Dd + d];
    float ds = g_ds;
    float tsq = bsum128(t*t);
    for (int n = 0; n < NS; ++n) {
        int hn = h*NS + n;
        float p  = g_pos[(size_t)hn*Dd + d];
        float dr = g_dir[(size_t)hn*Dd + d];
        float tp = bsum128(t*p);
        float td = bsum128(t*dr);
        if (d == 0) {
            float dist2 = fmaxf(tsq - 2.0f*tp + g_possq[hn], 0.0f);
            float proj  = td - g_pdd[hn];
            float perp2 = fmaxf(dist2 - proj*proj, 0.0f);
            float inv   = g_inv2s2[hn];
            float aff = (1.0f-ds)*expf(-dist2*inv) + ds*expf(-perp2*inv);
            out[((size_t)bh*Ss + s)*NS + n] = aff;
        }
        __syncthreads();
    }
}

// ---------------- GSA linear-attention precompute --------------------------
__global__ void gsa_kv_kernel()
{
    int bh = blockIdx.x;  int b = bh / NH, h = bh % NH;
    int d = threadIdx.x;  // 128
    const float* vb = g_V + (size_t)b*Ss*HID + h*Dd;
    const float* ka = g_ka + (size_t)bh*Ss*NS;
    float acc[NS];
    #pragma unroll
    for (int n = 0; n < NS; ++n) acc[n] = 0.f;
    for (int s = 0; s < Ss; ++s) {
        float vv = vb[(size_t)s*HID + d];
        #pragma unroll
        for (int n = 0; n < NS; ++n) acc[n] += ka[s*NS+n]*vv;
    }
    #pragma unroll
    for (int n = 0; n < NS; ++n) g_kvmat[((size_t)bh*NS + n)*Dd + d] = acc[n];
    if (d < NS) {
        float ks = 0.f;
        for (int s = 0; s < Ss; ++s) ks += ka[s*NS+d];
        g_ksum[bh*NS+d] = ks;
    }
}

__global__ void dgsa_kernel()
{
    int s  = blockIdx.x;
    int bh = blockIdx.y;  int b = bh / NH, h = bh % NH;
    int d  = threadIdx.x;  // 128
    float c[NS];
    float denom = 1e-8f;
    #pragma unroll
    for (int n = 0; n < NS; ++n) {
        c[n] = g_qa[((size_t)bh*Ss + s)*NS + n] * g_amp[h*NS+n];
        denom += c[n]*g_ksum[bh*NS+n];
    }
    float num = 0.f;
    #pragma unroll
    for (int n = 0; n < NS; ++n)
        num += c[n]*g_kvmat[((size_t)bh*NS + n)*Dd + d];
    size_t idx = ((size_t)b*Ss + s)*HID + h*Dd + d;
    g_comb[idx] += g_blend * (num/denom);
}

// ---------------- launch ----------------------------------------------------
extern "C" void kernel_launch(void* const* d_in, const int* in_sizes, int n_in,
                              void* d_out, int out_size)
{
    const float* X   = (const float*)d_in[0];
    const float* Wq  = (const float*)d_in[1];
    const float* Wk  = (const float*)d_in[2];
    const float* Wv  = (const float*)d_in[3];
    const float* Wo  = (const float*)d_in[4];
    const float* pos = (const float*)d_in[5];
    const float* dir = (const float*)d_in[6];
    const float* ls  = (const float*)d_in[7];
    const float* la  = (const float*)d_in[8];
    const float* dstr= (const float*)d_in[9];
    const float* gstr= (const float*)d_in[10];
    float* out = (float*)d_out;

    prep_kernel<<<1, 128>>>(pos, dir, ls, la, dstr, gstr);
    qkv_kernel<<<dim3(HID/BNt, Mm/BMt, 3), 256>>>(X, Wq, Wk, Wv);
    affinity_kernel<<<dim3(Ss, BH, 2), 128>>>();
    scores_kernel<<<dim3(Ss/BNt, Ss/BMt, BH), 256>>>();
    softmax_kernel<<<dim3(Ss, BH), 256>>>();
    gsa_kv_kernel<<<BH, 128>>>();
    pv_kernel<<<dim3(Dd/BNt, Ss/BMt, BH), 256>>>();
    dgsa_kernel<<<dim3(Ss, BH), 128>>>();
    wo_kernel<<<dim3(HID/BNt, Mm/BMt, 1), 256>>>(Wo, out);
}

// round 5
// speedup vs baseline: 2.0673x; 2.0673x over previous
#include <cuda_runtime.h>
#include <cuda.h>
#include <cuda_bf16.h>
#include <math.h>
#include <stdint.h>

#define Bb 2
#define Ss 1024
#define HID 2048
#define NH 16
#define NS 8
#define Dd 128
#define Mm (Bb*Ss)      // 2048
#define BH (Bb*NH)      // 32

typedef __nv_bfloat16 bf16;

// ---------------- scratch (device globals; no allocation allowed) ----------
__device__ float g_Q[(size_t)Mm*HID];
__device__ float g_K[(size_t)Mm*HID];
__device__ float g_V[(size_t)Mm*HID];
__device__ float g_scores[(size_t)BH*Ss*Ss];     // 128 MB
__device__ float g_comb[(size_t)Mm*HID];
__device__ float g_qa[(size_t)BH*Ss*NS];
__device__ float g_ka[(size_t)BH*Ss*NS];
__device__ float g_kvmat[(size_t)BH*NS*Dd];
__device__ float g_ksum[BH*NS];
__device__ float g_pos[NH*NS*Dd];
__device__ float g_dir[NH*NS*Dd];
__device__ float g_possq[NH*NS];
__device__ float g_pdd[NH*NS];
__device__ float g_inv2s2[NH*NS];
__device__ float g_amp[NH*NS];
__device__ float g_ds;
__device__ float g_blend;

// split-precision bf16 operand arrays
__device__ bf16 g_Xh[(size_t)Mm*HID],  g_Xl[(size_t)Mm*HID];
__device__ bf16 g_Wqt_h[(size_t)HID*HID], g_Wqt_l[(size_t)HID*HID];
__device__ bf16 g_Wkt_h[(size_t)HID*HID], g_Wkt_l[(size_t)HID*HID];
__device__ bf16 g_Wvt_h[(size_t)HID*HID], g_Wvt_l[(size_t)HID*HID];
__device__ bf16 g_Wot_h[(size_t)HID*HID], g_Wot_l[(size_t)HID*HID];
__device__ bf16 g_Qh[(size_t)Mm*HID], g_Ql[(size_t)Mm*HID];
__device__ bf16 g_Kh[(size_t)Mm*HID], g_Kl[(size_t)Mm*HID];
__device__ bf16 g_Vth[(size_t)BH*Dd*Ss], g_Vtl[(size_t)BH*Dd*Ss]; // [bh][d][s]
__device__ bf16 g_Ah[(size_t)BH*Ss*Ss], g_Al[(size_t)BH*Ss*Ss];   // attn hi/lo
__device__ bf16 g_Ch[(size_t)Mm*HID],  g_Cl[(size_t)Mm*HID];      // comb hi/lo

__device__ __forceinline__ void split2(float v, bf16& h, bf16& l){
    h = __float2bfloat16(v);
    l = __float2bfloat16(v - __bfloat162float(h));
}

// ================= low-level helpers =======================================
__device__ __forceinline__ uint32_t smem_u32(const void* p){
    uint32_t a;
    asm("{ .reg .u64 t; cvta.to.shared.u64 t, %1; cvt.u32.u64 %0, t; }" : "=r"(a) : "l"(p));
    return a;
}
__device__ __forceinline__ void mbar_init(uint32_t a, uint32_t cnt){
    asm volatile("mbarrier.init.shared.b64 [%0], %1;" :: "r"(a), "r"(cnt) : "memory");
}
__device__ __forceinline__ void mbar_inval(uint32_t a){
    asm volatile("mbarrier.inval.shared.b64 [%0];" :: "r"(a) : "memory");
}
__device__ __forceinline__ void wait_parity(uint32_t mbar, uint32_t ph){
    uint32_t done;
    asm volatile(
        "{\n\t.reg .pred p;\n\t"
        "mbarrier.try_wait.parity.acquire.cta.shared::cta.b64 p, [%1], %2;\n\t"
        "selp.b32 %0, 1, 0, p;\n\t}"
        : "=r"(done) : "r"(mbar), "r"(ph) : "memory");
    if (!done) {
        asm volatile(
            "{\n\t.reg .pred P1;\n\t"
            "WL%=:\n\t"
            "mbarrier.try_wait.parity.acquire.cta.shared::cta.b64 P1, [%0], %1, 0x989680;\n\t"
            "@P1 bra.uni WD%=;\n\t"
            "bra.uni WL%=;\n\t"
            "WD%=:\n\t}"
            :: "r"(mbar), "r"(ph) : "memory");
    }
}
__device__ __forceinline__ void tma2d(uint32_t dst, const CUtensorMap* m, int x, int y, uint32_t mbar){
    asm volatile(
        "cp.async.bulk.tensor.2d.shared::cta.global.tile.mbarrier::complete_tx::bytes "
        "[%0], [%1, {%2, %3}], [%4];"
        :: "r"(dst), "l"(m), "r"(x), "r"(y), "r"(mbar) : "memory");
}
__device__ __forceinline__ void ldm4(uint32_t* r, uint32_t a){
    asm volatile("ldmatrix.sync.aligned.m8n8.x4.shared.b16 {%0,%1,%2,%3}, [%4];"
        : "=r"(r[0]),"=r"(r[1]),"=r"(r[2]),"=r"(r[3]) : "r"(a));
}
__device__ __forceinline__ void mma16816(float* c, const uint32_t* a, uint32_t b0, uint32_t b1){
    asm volatile("mma.sync.aligned.m16n8k16.row.col.f32.bf16.bf16.f32 "
        "{%0,%1,%2,%3}, {%4,%5,%6,%7}, {%8,%9}, {%0,%1,%2,%3};"
        : "+f"(c[0]),"+f"(c[1]),"+f"(c[2]),"+f"(c[3])
        : "r"(a[0]),"r"(a[1]),"r"(a[2]),"r"(a[3]), "r"(b0),"r"(b1));
}
__device__ __forceinline__ uint32_t swz(uint32_t x){ return x ^ ((x>>3)&0x70); }

// SMEM layout: [0,16) two mbarriers; stages at 1024 and 1024+65536.
// Stage: Ah(16KB) Al(16KB) Bh(16KB) Bl(16KB); 128 rows x 64 bf16 (128B) SW128.
#define TILE_B   16384
#define STAGE_B  65536
#define SMEM_SZ  (1024 + 2*STAGE_B)

// ---------------- 128x128 CTA GEMM mainloop (256 threads, 8 warps) ---------
// C[128,128] += (Ah+Al)[128,K] * (Bh+Bl)[128,K]^T  (3-product split)
__device__ __forceinline__ void gemm_main(
    const CUtensorMap* mAh, const CUtensorMap* mAl,
    const CUtensorMap* mBh, const CUtensorMap* mBl,
    int ax0, int ay, int bx0, int by, int K, float* acc)
{
    extern __shared__ char smem[];
    uint32_t sb = smem_u32(smem);
    int tid = threadIdx.x, lane = tid & 31, wid = tid >> 5;
    int warp_m = (wid >> 2) * 64, warp_n = (wid & 3) * 32;

    if (tid == 0){ mbar_init(sb, 1); mbar_init(sb + 8, 1); }
    __syncthreads();

    #pragma unroll
    for (int i = 0; i < 64; ++i) acc[i] = 0.f;

    int NC = K / 64;

    auto issue = [&](int c){
        if (tid == 0){
            int st = c & 1;
            uint32_t mb = sb + 8*st;
            asm volatile("mbarrier.arrive.expect_tx.shared.b64 _, [%0], %1;"
                         :: "r"(mb), "r"((uint32_t)STAGE_B) : "memory");
            uint32_t dst = sb + 1024 + st*STAGE_B;
            tma2d(dst,            mAh, ax0 + c*64, ay, mb);
            tma2d(dst +   TILE_B, mAl, ax0 + c*64, ay, mb);
            tma2d(dst + 2*TILE_B, mBh, bx0 + c*64, by, mb);
            tma2d(dst + 3*TILE_B, mBl, bx0 + c*64, by, mb);
        }
    };
    issue(0);
    if (NC > 1) issue(1);

    uint32_t a_row  = warp_m + (lane & 15);
    uint32_t a_colb = (lane >> 4) * 16;
    uint32_t b_row  = warp_n + (lane & 7) + ((lane >> 4) << 3);
    uint32_t b_colb = ((lane >> 3) & 1) * 16;

    for (int c = 0; c < NC; ++c){
        wait_parity(sb + 8*(c & 1), (c >> 1) & 1);
        uint32_t st = sb + 1024 + (c & 1)*STAGE_B;
        #pragma unroll
        for (int ks = 0; ks < 4; ++ks){
            uint32_t ah[16], al[16], bh[8], bl[8];
            #pragma unroll
            for (int mt = 0; mt < 4; ++mt){
                uint32_t off = swz((a_row + mt*16)*128 + ks*32 + a_colb);
                ldm4(ah + mt*4, st + off);
                ldm4(al + mt*4, st + TILE_B + off);
            }
            #pragma unroll
            for (int nt = 0; nt < 2; ++nt){
                uint32_t off = swz((b_row + nt*16)*128 + ks*32 + b_colb);
                ldm4(bh + nt*4, st + 2*TILE_B + off);
                ldm4(bl + nt*4, st + 3*TILE_B + off);
            }
            #pragma unroll
            for (int mt = 0; mt < 4; ++mt)
                #pragma unroll
                for (int n8 = 0; n8 < 4; ++n8){
                    float* c4 = acc + (mt*4 + n8)*4;
                    int bi = (n8 >> 1)*4 + (n8 & 1)*2;
                    mma16816(c4, ah + mt*4, bh[bi], bh[bi+1]);
                    mma16816(c4, ah + mt*4, bl[bi], bl[bi+1]);
                    mma16816(c4, al + mt*4, bh[bi], bh[bi+1]);
                }
        }
        __syncthreads();
        if (c + 2 < NC) issue(c + 2);
    }
    if (tid == 0){ mbar_inval(sb); mbar_inval(sb + 8); }
}

// epilogue iteration helper: calls f(r, cc, v0, v1) per fp32 pair
template<class F>
__device__ __forceinline__ void epi_loop(const float* acc, F f){
    int lane = threadIdx.x & 31, wid = threadIdx.x >> 5;
    int warp_m = (wid >> 2) * 64, warp_n = (wid & 3) * 32;
    int g = lane >> 2, tg = (lane & 3) * 2;
    #pragma unroll
    for (int mt = 0; mt < 4; ++mt)
        #pragma unroll
        for (int n8 = 0; n8 < 4; ++n8){
            const float* c4 = acc + (mt*4 + n8)*4;
            #pragma unroll
            for (int hh = 0; hh < 2; ++hh){
                int r  = warp_m + mt*16 + g + hh*8;
                int cc = warp_n + n8*8 + tg;
                f(r, cc, c4[hh*2], c4[hh*2+1]);
            }
        }
}

// ================= GEMM kernels ============================================
__global__ void __launch_bounds__(256) qkv_tc(
    const __grid_constant__ CUtensorMap mXh, const __grid_constant__ CUtensorMap mXl,
    const __grid_constant__ CUtensorMap mWqh, const __grid_constant__ CUtensorMap mWql,
    const __grid_constant__ CUtensorMap mWkh, const __grid_constant__ CUtensorMap mWkl,
    const __grid_constant__ CUtensorMap mWvh, const __grid_constant__ CUtensorMap mWvl)
{
    int z = blockIdx.z;
    int row0 = blockIdx.y*128, col0 = blockIdx.x*128;
    const CUtensorMap *pbh, *pbl;
    if (z == 0){ pbh = &mWqh; pbl = &mWql; }
    else if (z == 1){ pbh = &mWkh; pbl = &mWkl; }
    else { pbh = &mWvh; pbl = &mWvl; }
    float acc[64];
    gemm_main(&mXh, &mXl, pbh, pbl, 0, row0, 0, col0, HID, acc);

    epi_loop(acc, [&](int r, int cc, float v0, float v1){
        int gr = row0 + r, gc = col0 + cc;
        size_t idx = (size_t)gr*HID + gc;
        bf16 h0,l0,h1,l1; split2(v0,h0,l0); split2(v1,h1,l1);
        float2 fv; fv.x = v0; fv.y = v1;
        __nv_bfloat162 hv; hv.x = h0; hv.y = h1;
        __nv_bfloat162 lv; lv.x = l0; lv.y = l1;
        if (z == 0){
            *(float2*)(g_Q + idx) = fv;
            *(__nv_bfloat162*)(g_Qh + idx) = hv;
            *(__nv_bfloat162*)(g_Ql + idx) = lv;
        } else if (z == 1){
            *(float2*)(g_K + idx) = fv;
            *(__nv_bfloat162*)(g_Kh + idx) = hv;
            *(__nv_bfloat162*)(g_Kl + idx) = lv;
        } else {
            *(float2*)(g_V + idx) = fv;
            int b = gr >> 10, s = gr & (Ss-1);
            int h = col0 >> 7, d = cc;
            size_t ti = (((size_t)(b*NH + h))*Dd + d)*Ss + s;
            g_Vth[ti] = h0; g_Vth[ti + Ss] = h1;
            g_Vtl[ti] = l0; g_Vtl[ti + Ss] = l1;
        }
    });
}

__global__ void __launch_bounds__(256) scores_tc(
    const __grid_constant__ CUtensorMap mQh, const __grid_constant__ CUtensorMap mQl,
    const __grid_constant__ CUtensorMap mKh, const __grid_constant__ CUtensorMap mKl)
{
    int bh = blockIdx.z, b = bh >> 4, h = bh & 15;
    int row0 = blockIdx.y*128, col0 = blockIdx.x*128;
    float acc[64];
    gemm_main(&mQh, &mQl, &mKh, &mKl, h*Dd, b*Ss + row0, h*Dd, b*Ss + col0, Dd, acc);
    float* out = g_scores + (size_t)bh*Ss*Ss;
    epi_loop(acc, [&](int r, int cc, float v0, float v1){
        float2 fv; fv.x = v0*0.08838834764831845f; fv.y = v1*0.08838834764831845f;
        *(float2*)(out + (size_t)(row0 + r)*Ss + col0 + cc) = fv;
    });
}

__global__ void __launch_bounds__(256) pv_tc(
    const __grid_constant__ CUtensorMap mAh, const __grid_constant__ CUtensorMap mAl,
    const __grid_constant__ CUtensorMap mVh, const __grid_constant__ CUtensorMap mVl)
{
    int bh = blockIdx.z, b = bh >> 4, h = bh & 15;
    int row0 = blockIdx.y*128;
    float acc[64];
    gemm_main(&mAh, &mAl, &mVh, &mVl, 0, bh*Ss + row0, 0, bh*Dd, Ss, acc);
    float alpha = 1.0f - g_blend;
    epi_loop(acc, [&](int r, int cc, float v0, float v1){
        float2 fv; fv.x = v0*alpha; fv.y = v1*alpha;
        *(float2*)(g_comb + ((size_t)b*Ss + row0 + r)*HID + h*Dd + cc) = fv;
    });
}

__global__ void __launch_bounds__(256) wo_tc(
    const __grid_constant__ CUtensorMap mCh, const __grid_constant__ CUtensorMap mCl,
    const __grid_constant__ CUtensorMap mWh, const __grid_constant__ CUtensorMap mWl,
    float* __restrict__ out)
{
    int row0 = blockIdx.y*128, col0 = blockIdx.x*128;
    float acc[64];
    gemm_main(&mCh, &mCl, &mWh, &mWl, 0, row0, 0, col0, HID, acc);
    epi_loop(acc, [&](int r, int cc, float v0, float v1){
        float2 fv; fv.x = v0; fv.y = v1;
        *(float2*)(out + (size_t)(row0 + r)*HID + col0 + cc) = fv;
    });
}

// ================= conversion kernels ======================================
__global__ void convert_x_kernel(const float* __restrict__ X){
    int i = (blockIdx.x*256 + threadIdx.x) * 4;
    float4 v = *(const float4*)(X + i);
    split2(v.x, g_Xh[i+0], g_Xl[i+0]);
    split2(v.y, g_Xh[i+1], g_Xl[i+1]);
    split2(v.z, g_Xh[i+2], g_Xl[i+2]);
    split2(v.w, g_Xh[i+3], g_Xl[i+3]);
}

__global__ void tsplit_kernel(const float* __restrict__ Wq, const float* __restrict__ Wk,
                              const float* __restrict__ Wv, const float* __restrict__ Wo){
    __shared__ float t[32][33];
    int z = blockIdx.z;
    const float* in = (z == 0) ? Wq : (z == 1) ? Wk : (z == 2) ? Wv : Wo;
    bf16* oh = (z == 0) ? g_Wqt_h : (z == 1) ? g_Wkt_h : (z == 2) ? g_Wvt_h : g_Wot_h;
    bf16* ol = (z == 0) ? g_Wqt_l : (z == 1) ? g_Wkt_l : (z == 2) ? g_Wvt_l : g_Wot_l;
    int n0 = blockIdx.x*32, k0 = blockIdx.y*32;
    int tx = threadIdx.x, ty = threadIdx.y;
    #pragma unroll
    for (int j = 0; j < 4; ++j)
        t[ty + 8*j][tx] = in[(size_t)(k0 + ty + 8*j)*HID + n0 + tx];
    __syncthreads();
    #pragma unroll
    for (int j = 0; j < 4; ++j){
        float v = t[tx][ty + 8*j];
        size_t o = (size_t)(n0 + ty + 8*j)*HID + k0 + tx;
        split2(v, oh[o], ol[o]);
    }
}

// ---------------- prep ------------------------------------------------------
__global__ void prep_kernel(const float* __restrict__ pos_in,
                            const float* __restrict__ dir_in,
                            const float* __restrict__ ls_in,
                            const float* __restrict__ la_in,
                            const float* __restrict__ dstr,
                            const float* __restrict__ gstr)
{
    int i = threadIdx.x;
    if (i < NH*NS) {
        const float* p = pos_in + (size_t)i*Dd;
        const float* dv = dir_in + (size_t)i*Dd;
        float np = 0.f, nd = 0.f;
        for (int d = 0; d < Dd; ++d) { np += p[d]*p[d]; nd += dv[d]*dv[d]; }
        float pscale = 3.39411254969543f / (sqrtf(np) + 1e-12f);
        float dscale = 1.0f / (sqrtf(nd) + 1e-12f);
        float psq = 0.f, pdd = 0.f;
        for (int d = 0; d < Dd; ++d) {
            float ps = p[d]*pscale, du = dv[d]*dscale;
            g_pos[(size_t)i*Dd + d] = ps;
            g_dir[(size_t)i*Dd + d] = du;
            psq += ps*ps;  pdd += ps*du;
        }
        g_possq[i] = psq;  g_pdd[i] = pdd;
        float sc = expf(ls_in[i]);
        sc = fminf(fmaxf(sc, 0.3f), 1.2f);
        g_inv2s2[i] = 0.5f / (sc*sc);
    }
    __syncthreads();
    if (i < NH) {
        float m = -1e30f;
        for (int n = 0; n < NS; ++n) m = fmaxf(m, la_in[i*NS+n]);
        float s = 0.f, e[NS];
        for (int n = 0; n < NS; ++n) { e[n] = expf(la_in[i*NS+n]-m); s += e[n]; }
        for (int n = 0; n < NS; ++n) g_amp[i*NS+n] = e[n]/s;
    }
    if (i == 0) {
        g_ds = 1.0f / (1.0f + expf(-dstr[0]));
        float gsa = 1.0f / (1.0f + expf(-gstr[0]));
        g_blend = fminf(0.05f, gsa*0.1f);
    }
}

// ---------------- softmax: fp32 scores -> attn hi/lo bf16 -------------------
__global__ void softmax_kernel()
{
    __shared__ float red[8];
    size_t base = ((size_t)blockIdx.y*Ss + blockIdx.x)*Ss;
    const float* row = g_scores + base;
    int tid = threadIdx.x;   // 256
    float v[4];
    float m = -1e30f;
    #pragma unroll
    for (int i = 0; i < 4; ++i) { v[i] = row[tid + i*256]; m = fmaxf(m, v[i]); }
    #pragma unroll
    for (int o = 16; o; o >>= 1) m = fmaxf(m, __shfl_xor_sync(0xffffffffu, m, o));
    if ((tid & 31) == 0) red[tid >> 5] = m;
    __syncthreads();
    m = red[0];
    #pragma unroll
    for (int w = 1; w < 8; ++w) m = fmaxf(m, red[w]);
    __syncthreads();
    float s = 0.f;
    #pragma unroll
    for (int i = 0; i < 4; ++i) { v[i] = expf(v[i]-m); s += v[i]; }
    #pragma unroll
    for (int o = 16; o; o >>= 1) s += __shfl_xor_sync(0xffffffffu, s, o);
    if ((tid & 31) == 0) red[tid >> 5] = s;
    __syncthreads();
    s = red[0]+red[1]+red[2]+red[3]+red[4]+red[5]+red[6]+red[7];
    float inv = 1.0f/s;
    #pragma unroll
    for (int i = 0; i < 4; ++i) {
        float a = v[i]*inv;
        split2(a, g_Ah[base + tid + i*256], g_Al[base + tid + i*256]);
    }
}

// ---------------- affinities qa / ka ---------------------------------------
__device__ __forceinline__ float bsum128(float v)
{
    __shared__ float red[4];
    #pragma unroll
    for (int o = 16; o; o >>= 1) v += __shfl_xor_sync(0xffffffffu, v, o);
    if ((threadIdx.x & 31) == 0) red[threadIdx.x >> 5] = v;
    __syncthreads();
    v = red[0]+red[1]+red[2]+red[3];
    __syncthreads();
    return v;
}

__global__ void affinity_kernel()
{
    int s  = blockIdx.x;
    int bh = blockIdx.y;  int b = bh / NH, h = bh % NH;
    int z  = blockIdx.z;
    int d  = threadIdx.x;
    const float* src = z ? g_K : g_Q;
    float* out = z ? g_ka : g_qa;
    float t = src[((size_t)b*Ss + s)*HID + h*Dd + d];
    float ds = g_ds;
    float tsq = bsum128(t*t);
    for (int n = 0; n < NS; ++n) {
        int hn = h*NS + n;
        float p  = g_pos[(size_t)hn*Dd + d];
        float dr = g_dir[(size_t)hn*Dd + d];
        float tp = bsum128(t*p);
        float td = bsum128(t*dr);
        if (d == 0) {
            float dist2 = fmaxf(tsq - 2.0f*tp + g_possq[hn], 0.0f);
            float proj  = td - g_pdd[hn];
            float perp2 = fmaxf(dist2 - proj*proj, 0.0f);
            float inv   = g_inv2s2[hn];
            float aff = (1.0f-ds)*expf(-dist2*inv) + ds*expf(-perp2*inv);
            out[((size_t)bh*Ss + s)*NS + n] = aff;
        }
        __syncthreads();
    }
}

// ---------------- GSA linear-attention precompute --------------------------
__global__ void gsa_kv_kernel()
{
    int bh = blockIdx.x;  int b = bh / NH, h = bh % NH;
    int d = threadIdx.x;
    const float* vb = g_V + (size_t)b*Ss*HID + h*Dd;
    const float* ka = g_ka + (size_t)bh*Ss*NS;
    float acc[NS];
    #pragma unroll
    for (int n = 0; n < NS; ++n) acc[n] = 0.f;
    for (int s = 0; s < Ss; ++s) {
        float vv = vb[(size_t)s*HID + d];
        #pragma unroll
        for (int n = 0; n < NS; ++n) acc[n] += ka[s*NS+n]*vv;
    }
    #pragma unroll
    for (int n = 0; n < NS; ++n) g_kvmat[((size_t)bh*NS + n)*Dd + d] = acc[n];
    if (d < NS) {
        float ks = 0.f;
        for (int s = 0; s < Ss; ++s) ks += ka[s*NS+d];
        g_ksum[bh*NS+d] = ks;
    }
}

__global__ void dgsa_kernel()
{
    int s  = blockIdx.x;
    int bh = blockIdx.y;  int b = bh / NH, h = bh % NH;
    int d  = threadIdx.x;
    float c[NS];
    float denom = 1e-8f;
    #pragma unroll
    for (int n = 0; n < NS; ++n) {
        c[n] = g_qa[((size_t)bh*Ss + s)*NS + n] * g_amp[h*NS+n];
        denom += c[n]*g_ksum[bh*NS+n];
    }
    float num = 0.f;
    #pragma unroll
    for (int n = 0; n < NS; ++n)
        num += c[n]*g_kvmat[((size_t)bh*NS + n)*Dd + d];
    size_t idx = ((size_t)b*Ss + s)*HID + h*Dd + d;
    float v = g_comb[idx] + g_blend * (num/denom);
    split2(v, g_Ch[idx], g_Cl[idx]);
}

// ---------------- host: tensormap construction -----------------------------
typedef CUresult (*TMapEncode)(CUtensorMap*, CUtensorMapDataType, cuuint32_t, void*,
    const cuuint64_t*, const cuuint64_t*, const cuuint32_t*, const cuuint32_t*,
    CUtensorMapInterleave, CUtensorMapSwizzle, CUtensorMapL2promotion, CUtensorMapFloatOOBfill);

static void make_map(TMapEncode enc, CUtensorMap* m, void* base, uint64_t d0, uint64_t d1){
    cuuint64_t dims[2]    = {d0, d1};
    cuuint64_t strides[1] = {d0 * 2};           // bytes
    cuuint32_t box[2]     = {64, 128};
    cuuint32_t es[2]      = {1, 1};
    enc(m, CU_TENSOR_MAP_DATA_TYPE_BFLOAT16, 2, base, dims, strides, box, es,
        CU_TENSOR_MAP_INTERLEAVE_NONE, CU_TENSOR_MAP_SWIZZLE_128B,
        CU_TENSOR_MAP_L2_PROMOTION_L2_128B, CU_TENSOR_MAP_FLOAT_OOB_FILL_NONE);
}

// ---------------- launch ----------------------------------------------------
extern "C" void kernel_launch(void* const* d_in, const int* in_sizes, int n_in,
                              void* d_out, int out_size)
{
    const float* X   = (const float*)d_in[0];
    const float* Wq  = (const float*)d_in[1];
    const float* Wk  = (const float*)d_in[2];
    const float* Wv  = (const float*)d_in[3];
    const float* Wo  = (const float*)d_in[4];
    const float* pos = (const float*)d_in[5];
    const float* dir = (const float*)d_in[6];
    const float* ls  = (const float*)d_in[7];
    const float* la  = (const float*)d_in[8];
    const float* dstr= (const float*)d_in[9];
    const float* gstr= (const float*)d_in[10];
    float* out = (float*)d_out;

    // resolve cuTensorMapEncodeTiled through the runtime (no -lcuda needed)
    void* fp = nullptr;
    cudaDriverEntryPointQueryResult qr;
#if CUDART_VERSION >= 12050
    cudaGetDriverEntryPointByVersion("cuTensorMapEncodeTiled", &fp, 12000, cudaEnableDefault, &qr);
#else
    cudaGetDriverEntryPoint("cuTensorMapEncodeTiled", &fp, cudaEnableDefault, &qr);
#endif
    TMapEncode enc = (TMapEncode)fp;

    void *pXh,*pXl,*pWqh,*pWql,*pWkh,*pWkl,*pWvh,*pWvl,*pWoh,*pWol;
    void *pQh,*pQl,*pKh,*pKl,*pAh,*pAl,*pVh,*pVl,*pCh,*pCl;
    cudaGetSymbolAddress(&pXh, g_Xh);   cudaGetSymbolAddress(&pXl, g_Xl);
    cudaGetSymbolAddress(&pWqh, g_Wqt_h); cudaGetSymbolAddress(&pWql, g_Wqt_l);
    cudaGetSymbolAddress(&pWkh, g_Wkt_h); cudaGetSymbolAddress(&pWkl, g_Wkt_l);
    cudaGetSymbolAddress(&pWvh, g_Wvt_h); cudaGetSymbolAddress(&pWvl, g_Wvt_l);
    cudaGetSymbolAddress(&pWoh, g_Wot_h); cudaGetSymbolAddress(&pWol, g_Wot_l);
    cudaGetSymbolAddress(&pQh, g_Qh);   cudaGetSymbolAddress(&pQl, g_Ql);
    cudaGetSymbolAddress(&pKh, g_Kh);   cudaGetSymbolAddress(&pKl, g_Kl);
    cudaGetSymbolAddress(&pAh, g_Ah);   cudaGetSymbolAddress(&pAl, g_Al);
    cudaGetSymbolAddress(&pVh, g_Vth);  cudaGetSymbolAddress(&pVl, g_Vtl);
    cudaGetSymbolAddress(&pCh, g_Ch);   cudaGetSymbolAddress(&pCl, g_Cl);

    CUtensorMap mXh,mXl,mWqh,mWql,mWkh,mWkl,mWvh,mWvl,mWoh,mWol;
    CUtensorMap mQh,mQl,mKh,mKl,mAh,mAl,mVh,mVl,mCh,mCl;
    make_map(enc,&mXh,pXh,HID,Mm);     make_map(enc,&mXl,pXl,HID,Mm);
    make_map(enc,&mWqh,pWqh,HID,HID);  make_map(enc,&mWql,pWql,HID,HID);
    make_map(enc,&mWkh,pWkh,HID,HID);  make_map(enc,&mWkl,pWkl,HID,HID);
    make_map(enc,&mWvh,pWvh,HID,HID);  make_map(enc,&mWvl,pWvl,HID,HID);
    make_map(enc,&mWoh,pWoh,HID,HID);  make_map(enc,&mWol,pWol,HID,HID);
    make_map(enc,&mQh,pQh,HID,Mm);     make_map(enc,&mQl,pQl,HID,Mm);
    make_map(enc,&mKh,pKh,HID,Mm);     make_map(enc,&mKl,pKl,HID,Mm);
    make_map(enc,&mAh,pAh,Ss,(uint64_t)BH*Ss);  make_map(enc,&mAl,pAl,Ss,(uint64_t)BH*Ss);
    make_map(enc,&mVh,pVh,Ss,(uint64_t)BH*Dd);  make_map(enc,&mVl,pVl,Ss,(uint64_t)BH*Dd);
    make_map(enc,&mCh,pCh,HID,Mm);     make_map(enc,&mCl,pCl,HID,Mm);

    cudaFuncSetAttribute(qkv_tc,    cudaFuncAttributeMaxDynamicSharedMemorySize, SMEM_SZ);
    cudaFuncSetAttribute(scores_tc, cudaFuncAttributeMaxDynamicSharedMemorySize, SMEM_SZ);
    cudaFuncSetAttribute(pv_tc,     cudaFuncAttributeMaxDynamicSharedMemorySize, SMEM_SZ);
    cudaFuncSetAttribute(wo_tc,     cudaFuncAttributeMaxDynamicSharedMemorySize, SMEM_SZ);

    prep_kernel<<<1, 128>>>(pos, dir, ls, la, dstr, gstr);
    convert_x_kernel<<<(Mm*HID)/1024, 256>>>(X);
    tsplit_kernel<<<dim3(HID/32, HID/32, 4), dim3(32, 8)>>>(Wq, Wk, Wv, Wo);
    qkv_tc<<<dim3(HID/128, Mm/128, 3), 256, SMEM_SZ>>>(mXh,mXl,mWqh,mWql,mWkh,mWkl,mWvh,mWvl);
    affinity_kernel<<<dim3(Ss, BH, 2), 128>>>();
    scores_tc<<<dim3(Ss/128, Ss/128, BH), 256, SMEM_SZ>>>(mQh,mQl,mKh,mKl);
    softmax_kernel<<<dim3(Ss, BH), 256>>>();
    gsa_kv_kernel<<<BH, 128>>>();
    pv_tc<<<dim3(1, Ss/128, BH), 256, SMEM_SZ>>>(mAh,mAl,mVh,mVl);
    dgsa_kernel<<<dim3(Ss, BH), 128>>>();
    wo_tc<<<dim3(HID/128, Mm/128, 1), 256, SMEM_SZ>>>(mCh,mCl,mWoh,mWol,out);
}

// round 6
// speedup vs baseline: 3.4001x; 1.6447x over previous
#include <cuda_runtime.h>
#include <cuda.h>
#include <cuda_bf16.h>
#include <math.h>
#include <stdint.h>

#define Bb 2
#define Ss 1024
#define HID 2048
#define NH 16
#define NS 8
#define Dd 128
#define Mm (Bb*Ss)      // 2048
#define BH (Bb*NH)      // 32

typedef __nv_bfloat16 bf16;

// ---------------- scratch (device globals; no allocation allowed) ----------
__device__ float g_V[(size_t)Mm*HID];
__device__ float g_qa[(size_t)BH*Ss*NS];
__device__ float g_ka[(size_t)BH*Ss*NS];
__device__ float g_kvmat[(size_t)BH*NS*Dd];
__device__ float g_ksum[BH*NS];
__device__ float g_kvp[(size_t)8*BH*NS*Dd];
__device__ float g_ksp[8*BH*NS];
__device__ float g_pos[NH*NS*Dd];
__device__ float g_dir[NH*NS*Dd];
__device__ float g_possq[NH*NS];
__device__ float g_pdd[NH*NS];
__device__ float g_inv2s2[NH*NS];
__device__ float g_amp[NH*NS];
__device__ float g_ds;
__device__ float g_blend;

// split-precision bf16 operand arrays
__device__ bf16 g_Xh[(size_t)Mm*HID],  g_Xl[(size_t)Mm*HID];
__device__ bf16 g_Wqt_h[(size_t)HID*HID], g_Wqt_l[(size_t)HID*HID];
__device__ bf16 g_Wkt_h[(size_t)HID*HID], g_Wkt_l[(size_t)HID*HID];
__device__ bf16 g_Wvt_h[(size_t)HID*HID], g_Wvt_l[(size_t)HID*HID];
__device__ bf16 g_Wot_h[(size_t)HID*HID], g_Wot_l[(size_t)HID*HID];
__device__ bf16 g_Qh[(size_t)Mm*HID], g_Ql[(size_t)Mm*HID];
__device__ bf16 g_Kh[(size_t)Mm*HID], g_Kl[(size_t)Mm*HID];
__device__ bf16 g_Vth[(size_t)BH*Dd*Ss], g_Vtl[(size_t)BH*Dd*Ss]; // [bh][d][s]
__device__ bf16 g_Ch[(size_t)Mm*HID],  g_Cl[(size_t)Mm*HID];      // comb hi/lo

__device__ __forceinline__ void split2(float v, bf16& h, bf16& l){
    h = __float2bfloat16(v);
    l = __float2bfloat16(v - __bfloat162float(h));
}
__device__ __forceinline__ void packsplit(float x, float y, uint32_t& hp, uint32_t& lp){
    __nv_bfloat162 hv, lv;
    hv.x = __float2bfloat16(x); hv.y = __float2bfloat16(y);
    lv.x = __float2bfloat16(x - __bfloat162float(hv.x));
    lv.y = __float2bfloat16(y - __bfloat162float(hv.y));
    hp = *(uint32_t*)&hv; lp = *(uint32_t*)&lv;
}

// ================= low-level helpers =======================================
__device__ __forceinline__ uint32_t smem_u32(const void* p){
    uint32_t a;
    asm("{ .reg .u64 t; cvta.to.shared.u64 t, %1; cvt.u32.u64 %0, t; }" : "=r"(a) : "l"(p));
    return a;
}
__device__ __forceinline__ void mbar_init(uint32_t a, uint32_t cnt){
    asm volatile("mbarrier.init.shared.b64 [%0], %1;" :: "r"(a), "r"(cnt) : "memory");
}
__device__ __forceinline__ void mbar_inval(uint32_t a){
    asm volatile("mbarrier.inval.shared.b64 [%0];" :: "r"(a) : "memory");
}
__device__ __forceinline__ void mbar_expect(uint32_t a, uint32_t bytes){
    asm volatile("mbarrier.arrive.expect_tx.shared.b64 _, [%0], %1;" :: "r"(a), "r"(bytes) : "memory");
}
__device__ __forceinline__ void wait_parity(uint32_t mbar, uint32_t ph){
    uint32_t done;
    asm volatile(
        "{\n\t.reg .pred p;\n\t"
        "mbarrier.try_wait.parity.acquire.cta.shared::cta.b64 p, [%1], %2;\n\t"
        "selp.b32 %0, 1, 0, p;\n\t}"
        : "=r"(done) : "r"(mbar), "r"(ph) : "memory");
    if (!done) {
        asm volatile(
            "{\n\t.reg .pred P1;\n\t"
            "WL%=:\n\t"
            "mbarrier.try_wait.parity.acquire.cta.shared::cta.b64 P1, [%0], %1, 0x989680;\n\t"
            "@P1 bra.uni WD%=;\n\t"
            "bra.uni WL%=;\n\t"
            "WD%=:\n\t}"
            :: "r"(mbar), "r"(ph) : "memory");
    }
}
__device__ __forceinline__ void tma2d(uint32_t dst, const CUtensorMap* m, int x, int y, uint32_t mbar){
    asm volatile(
        "cp.async.bulk.tensor.2d.shared::cta.global.tile.mbarrier::complete_tx::bytes "
        "[%0], [%1, {%2, %3}], [%4];"
        :: "r"(dst), "l"(m), "r"(x), "r"(y), "r"(mbar) : "memory");
}
__device__ __forceinline__ void ldm4(uint32_t* r, uint32_t a){
    asm volatile("ldmatrix.sync.aligned.m8n8.x4.shared.b16 {%0,%1,%2,%3}, [%4];"
        : "=r"(r[0]),"=r"(r[1]),"=r"(r[2]),"=r"(r[3]) : "r"(a));
}
__device__ __forceinline__ void mma16816(float* c, const uint32_t* a, uint32_t b0, uint32_t b1){
    asm volatile("mma.sync.aligned.m16n8k16.row.col.f32.bf16.bf16.f32 "
        "{%0,%1,%2,%3}, {%4,%5,%6,%7}, {%8,%9}, {%0,%1,%2,%3};"
        : "+f"(c[0]),"+f"(c[1]),"+f"(c[2]),"+f"(c[3])
        : "r"(a[0]),"r"(a[1]),"r"(a[2]),"r"(a[3]), "r"(b0),"r"(b1));
}
__device__ __forceinline__ uint32_t swz(uint32_t x){ return x ^ ((x>>3)&0x70); }
__device__ __forceinline__ float wsum(float v){
    #pragma unroll
    for (int o = 16; o; o >>= 1) v += __shfl_xor_sync(0xffffffffu, v, o);
    return v;
}

#define TILE_B   16384
#define STAGE_B  65536
#define SMEM_SZ  (1024 + 3*STAGE_B)    // 3-stage gemm
#define SMEM_FL  (1024 + STAGE_B + 2*STAGE_B)  // flash: Q(64K) + 2 stages

// ---------------- 128x128 CTA GEMM mainloop (256 threads, 8 warps) ---------
__device__ __forceinline__ void gemm_main(
    const CUtensorMap* mAh, const CUtensorMap* mAl,
    const CUtensorMap* mBh, const CUtensorMap* mBl,
    int ax0, int ay, int bx0, int by, int K, float* acc)
{
    extern __shared__ char smem[];
    uint32_t sb = smem_u32(smem);
    int tid = threadIdx.x, lane = tid & 31, wid = tid >> 5;
    int warp_m = (wid >> 2) * 64, warp_n = (wid & 3) * 32;

    if (tid == 0){ mbar_init(sb, 1); mbar_init(sb + 8, 1); mbar_init(sb + 16, 1); }
    __syncthreads();

    #pragma unroll
    for (int i = 0; i < 64; ++i) acc[i] = 0.f;

    int NC = K / 64;

    auto issue = [&](int c){
        if (tid == 0){
            int st = c % 3;
            uint32_t mb = sb + 8*st;
            mbar_expect(mb, (uint32_t)STAGE_B);
            uint32_t dst = sb + 1024 + st*STAGE_B;
            tma2d(dst,            mAh, ax0 + c*64, ay, mb);
            tma2d(dst +   TILE_B, mAl, ax0 + c*64, ay, mb);
            tma2d(dst + 2*TILE_B, mBh, bx0 + c*64, by, mb);
            tma2d(dst + 3*TILE_B, mBl, bx0 + c*64, by, mb);
        }
    };
    issue(0);
    if (NC > 1) issue(1);
    if (NC > 2) issue(2);

    uint32_t a_row  = warp_m + (lane & 15);
    uint32_t a_colb = (lane >> 4) * 16;
    uint32_t b_row  = warp_n + (lane & 7) + ((lane >> 4) << 3);
    uint32_t b_colb = ((lane >> 3) & 1) * 16;

    for (int c = 0; c < NC; ++c){
        wait_parity(sb + 8*(c % 3), (c / 3) & 1);
        uint32_t st = sb + 1024 + (c % 3)*STAGE_B;
        #pragma unroll
        for (int ks = 0; ks < 4; ++ks){
            uint32_t ah[16], al[16], bh[8], bl[8];
            #pragma unroll
            for (int mt = 0; mt < 4; ++mt){
                uint32_t off = swz((a_row + mt*16)*128 + ks*32 + a_colb);
                ldm4(ah + mt*4, st + off);
                ldm4(al + mt*4, st + TILE_B + off);
            }
            #pragma unroll
            for (int nt = 0; nt < 2; ++nt){
                uint32_t off = swz((b_row + nt*16)*128 + ks*32 + b_colb);
                ldm4(bh + nt*4, st + 2*TILE_B + off);
                ldm4(bl + nt*4, st + 3*TILE_B + off);
            }
            #pragma unroll
            for (int mt = 0; mt < 4; ++mt)
                #pragma unroll
                for (int n8 = 0; n8 < 4; ++n8){
                    float* c4 = acc + (mt*4 + n8)*4;
                    int bi = (n8 >> 1)*4 + (n8 & 1)*2;
                    mma16816(c4, ah + mt*4, bh[bi], bh[bi+1]);
                    mma16816(c4, ah + mt*4, bl[bi], bl[bi+1]);
                    mma16816(c4, al + mt*4, bh[bi], bh[bi+1]);
                }
        }
        __syncthreads();
        if (c + 3 < NC) issue(c + 3);
    }
    if (tid == 0){ mbar_inval(sb); mbar_inval(sb + 8); mbar_inval(sb + 16); }
}

template<class F>
__device__ __forceinline__ void epi_loop(const float* acc, F f){
    int lane = threadIdx.x & 31, wid = threadIdx.x >> 5;
    int warp_m = (wid >> 2) * 64, warp_n = (wid & 3) * 32;
    int g = lane >> 2, tg = (lane & 3) * 2;
    #pragma unroll
    for (int mt = 0; mt < 4; ++mt)
        #pragma unroll
        for (int n8 = 0; n8 < 4; ++n8){
            const float* c4 = acc + (mt*4 + n8)*4;
            #pragma unroll
            for (int hh = 0; hh < 2; ++hh){
                int r  = warp_m + mt*16 + g + hh*8;
                int cc = warp_n + n8*8 + tg;
                f(r, cc, c4[hh*2], c4[hh*2+1]);
            }
        }
}

// ================= GEMM kernels ============================================
__global__ void __launch_bounds__(256) qkv_tc(
    const __grid_constant__ CUtensorMap mXh, const __grid_constant__ CUtensorMap mXl,
    const __grid_constant__ CUtensorMap mWqh, const __grid_constant__ CUtensorMap mWql,
    const __grid_constant__ CUtensorMap mWkh, const __grid_constant__ CUtensorMap mWkl,
    const __grid_constant__ CUtensorMap mWvh, const __grid_constant__ CUtensorMap mWvl)
{
    int z = blockIdx.z;
    int row0 = blockIdx.y*128, col0 = blockIdx.x*128;
    const CUtensorMap *pbh, *pbl;
    if (z == 0){ pbh = &mWqh; pbl = &mWql; }
    else if (z == 1){ pbh = &mWkh; pbl = &mWkl; }
    else { pbh = &mWvh; pbl = &mWvl; }
    float acc[64];
    gemm_main(&mXh, &mXl, pbh, pbl, 0, row0, 0, col0, HID, acc);

    epi_loop(acc, [&](int r, int cc, float v0, float v1){
        int gr = row0 + r, gc = col0 + cc;
        size_t idx = (size_t)gr*HID + gc;
        bf16 h0,l0,h1,l1; split2(v0,h0,l0); split2(v1,h1,l1);
        __nv_bfloat162 hv; hv.x = h0; hv.y = h1;
        __nv_bfloat162 lv; lv.x = l0; lv.y = l1;
        if (z == 0){
            *(__nv_bfloat162*)(g_Qh + idx) = hv;
            *(__nv_bfloat162*)(g_Ql + idx) = lv;
        } else if (z == 1){
            *(__nv_bfloat162*)(g_Kh + idx) = hv;
            *(__nv_bfloat162*)(g_Kl + idx) = lv;
        } else {
            float2 fv; fv.x = v0; fv.y = v1;
            *(float2*)(g_V + idx) = fv;
            int b = gr >> 10, s = gr & (Ss-1);
            int h = col0 >> 7, d = cc;
            size_t ti = (((size_t)(b*NH + h))*Dd + d)*Ss + s;
            g_Vth[ti] = h0; g_Vth[ti + Ss] = h1;
            g_Vtl[ti] = l0; g_Vtl[ti + Ss] = l1;
        }
    });
}

__global__ void __launch_bounds__(256) wo_tc(
    const __grid_constant__ CUtensorMap mCh, const __grid_constant__ CUtensorMap mCl,
    const __grid_constant__ CUtensorMap mWh, const __grid_constant__ CUtensorMap mWl,
    float* __restrict__ out)
{
    int row0 = blockIdx.y*128, col0 = blockIdx.x*128;
    float acc[64];
    gemm_main(&mCh, &mCl, &mWh, &mWl, 0, row0, 0, col0, HID, acc);
    epi_loop(acc, [&](int r, int cc, float v0, float v1){
        float2 fv; fv.x = v0; fv.y = v1;
        *(float2*)(out + (size_t)(row0 + r)*HID + col0 + cc) = fv;
    });
}

// ================= flash attention kernel ==================================
// grid (Ss/128, BH), 256 threads. Computes std attention + fused GSA blend,
// writes Ch/Cl (split bf16) for the Wo GEMM.
__global__ void __launch_bounds__(256) flash_tc(
    const __grid_constant__ CUtensorMap mQh, const __grid_constant__ CUtensorMap mQl,
    const __grid_constant__ CUtensorMap mK64h, const __grid_constant__ CUtensorMap mK64l,
    const __grid_constant__ CUtensorMap mVh, const __grid_constant__ CUtensorMap mVl)
{
    extern __shared__ char smem[];
    uint32_t sb = smem_u32(smem);
    int tid = threadIdx.x, lane = tid & 31, wid = tid >> 5;
    int bh = blockIdx.y, b = bh >> 4, h = bh & 15;
    int row0 = blockIdx.x * 128;

    const uint32_t QH  = sb + 1024;          // two 16KB halves
    const uint32_t QL  = QH + 32768;
    const uint32_t ST0 = QL + 32768;
    // stage: KH0(8K) KH1(8K) KL0(8K) KL1(8K) VH(16K) VL(16K) = 64KB

    if (tid == 0){ mbar_init(sb,1); mbar_init(sb+8,1); mbar_init(sb+16,1); }
    __syncthreads();

    if (tid == 0){
        mbar_expect(sb+16, 65536u);
        tma2d(QH,        &mQh, h*128,    b*Ss+row0, sb+16);
        tma2d(QH+16384,  &mQh, h*128+64, b*Ss+row0, sb+16);
        tma2d(QL,        &mQl, h*128,    b*Ss+row0, sb+16);
        tma2d(QL+16384,  &mQl, h*128+64, b*Ss+row0, sb+16);
    }
    auto issue = [&](int j){
        if (tid == 0){
            uint32_t mb = sb + 8*(j&1);
            mbar_expect(mb, 65536u);
            uint32_t st = ST0 + (j&1)*STAGE_B;
            tma2d(st,         &mK64h, h*128,    b*Ss+j*64, mb);
            tma2d(st+8192,    &mK64h, h*128+64, b*Ss+j*64, mb);
            tma2d(st+16384,   &mK64l, h*128,    b*Ss+j*64, mb);
            tma2d(st+24576,   &mK64l, h*128+64, b*Ss+j*64, mb);
            tma2d(st+32768,   &mVh,   j*64, bh*128, mb);
            tma2d(st+49152,   &mVl,   j*64, bh*128, mb);
        }
    };
    issue(0); issue(1);

    float O[64];
    #pragma unroll
    for (int i = 0; i < 64; ++i) O[i] = 0.f;
    float m0 = -1e30f, m1 = -1e30f, l0 = 0.f, l1 = 0.f;
    const float qk = 0.08838834764831845f;

    uint32_t a_row = wid*16 + (lane & 15), a_colb = (lane >> 4)*16;
    uint32_t b_rw  = (lane & 7) + ((lane >> 4) << 3);
    uint32_t b_cb  = ((lane >> 3) & 1)*16;

    wait_parity(sb+16, 0);

    for (int j = 0; j < 16; ++j){
        wait_parity(sb + 8*(j&1), (j>>1)&1);
        uint32_t st = ST0 + (j&1)*STAGE_B;

        // ---- S = Q K^T (128x64 per CTA; 16x64 per warp), split 3-product
        float s[32];
        #pragma unroll
        for (int i = 0; i < 32; ++i) s[i] = 0.f;
        #pragma unroll
        for (int ks = 0; ks < 8; ++ks){
            uint32_t qh_[4], ql_[4], kh_[16], kl_[16];
            uint32_t offa = (ks>>2)*16384 + swz(a_row*128 + (ks&3)*32 + a_colb);
            ldm4(qh_, QH + offa);
            ldm4(ql_, QL + offa);
            #pragma unroll
            for (int nt = 0; nt < 4; ++nt){
                uint32_t offb = (ks>>2)*8192 + swz((b_rw + nt*16)*128 + (ks&3)*32 + b_cb);
                ldm4(kh_ + nt*4, st + offb);
                ldm4(kl_ + nt*4, st + 16384 + offb);
            }
            #pragma unroll
            for (int n8 = 0; n8 < 8; ++n8){
                int bi = (n8 >> 1)*4 + (n8 & 1)*2;
                mma16816(s + n8*4, qh_, kh_[bi], kh_[bi+1]);
                mma16816(s + n8*4, qh_, kl_[bi], kl_[bi+1]);
                mma16816(s + n8*4, ql_, kh_[bi], kh_[bi+1]);
            }
        }

        // ---- online softmax (rows g and g+8, each owned by a 4-lane quad)
        float tm0 = -1e30f, tm1 = -1e30f;
        #pragma unroll
        for (int t = 0; t < 8; ++t){
            s[t*4+0] *= qk; s[t*4+1] *= qk; s[t*4+2] *= qk; s[t*4+3] *= qk;
            tm0 = fmaxf(tm0, fmaxf(s[t*4+0], s[t*4+1]));
            tm1 = fmaxf(tm1, fmaxf(s[t*4+2], s[t*4+3]));
        }
        tm0 = fmaxf(tm0, __shfl_xor_sync(0xffffffffu, tm0, 1));
        tm0 = fmaxf(tm0, __shfl_xor_sync(0xffffffffu, tm0, 2));
        tm1 = fmaxf(tm1, __shfl_xor_sync(0xffffffffu, tm1, 1));
        tm1 = fmaxf(tm1, __shfl_xor_sync(0xffffffffu, tm1, 2));
        float nm0 = fmaxf(m0, tm0), nm1 = fmaxf(m1, tm1);
        float al0 = expf(m0 - nm0), al1 = expf(m1 - nm1);
        float ts0 = 0.f, ts1 = 0.f;
        #pragma unroll
        for (int t = 0; t < 8; ++t){
            s[t*4+0] = expf(s[t*4+0] - nm0); s[t*4+1] = expf(s[t*4+1] - nm0);
            s[t*4+2] = expf(s[t*4+2] - nm1); s[t*4+3] = expf(s[t*4+3] - nm1);
            ts0 += s[t*4+0] + s[t*4+1];
            ts1 += s[t*4+2] + s[t*4+3];
        }
        ts0 += __shfl_xor_sync(0xffffffffu, ts0, 1);
        ts0 += __shfl_xor_sync(0xffffffffu, ts0, 2);
        ts1 += __shfl_xor_sync(0xffffffffu, ts1, 1);
        ts1 += __shfl_xor_sync(0xffffffffu, ts1, 2);
        l0 = l0*al0 + ts0;  l1 = l1*al1 + ts1;
        m0 = nm0;  m1 = nm1;
        #pragma unroll
        for (int t = 0; t < 16; ++t){
            O[t*4+0] *= al0; O[t*4+1] *= al0; O[t*4+2] *= al1; O[t*4+3] *= al1;
        }

        // ---- pack P into A fragments (hi/lo) — S C-layout == A layout
        uint32_t ph_[16], pl_[16];
        #pragma unroll
        for (int t = 0; t < 4; ++t){
            packsplit(s[(2*t)*4+0],   s[(2*t)*4+1],   ph_[t*4+0], pl_[t*4+0]);
            packsplit(s[(2*t)*4+2],   s[(2*t)*4+3],   ph_[t*4+1], pl_[t*4+1]);
            packsplit(s[(2*t+1)*4+0], s[(2*t+1)*4+1], ph_[t*4+2], pl_[t*4+2]);
            packsplit(s[(2*t+1)*4+2], s[(2*t+1)*4+3], ph_[t*4+3], pl_[t*4+3]);
        }

        // ---- O += P V  (n = d = 128, k = s = 64)
        #pragma unroll
        for (int ks = 0; ks < 4; ++ks){
            uint32_t vh_[32], vl_[32];
            #pragma unroll
            for (int nt = 0; nt < 8; ++nt){
                uint32_t offv = swz((b_rw + nt*16)*128 + ks*32 + b_cb);
                ldm4(vh_ + nt*4, st + 32768 + offv);
                ldm4(vl_ + nt*4, st + 49152 + offv);
            }
            #pragma unroll
            for (int n8 = 0; n8 < 16; ++n8){
                int bi = (n8 >> 1)*4 + (n8 & 1)*2;
                mma16816(O + n8*4, ph_ + ks*4, vh_[bi], vh_[bi+1]);
                mma16816(O + n8*4, ph_ + ks*4, vl_[bi], vl_[bi+1]);
                mma16816(O + n8*4, pl_ + ks*4, vh_[bi], vh_[bi+1]);
            }
        }
        __syncthreads();
        if (j + 2 < 16) issue(j + 2);
    }

    // ---- epilogue: normalize, fuse GSA blend, write Ch/Cl splits
    float inv0 = 1.f / l0, inv1 = 1.f / l1;
    float blend = g_blend, ob = 1.f - blend;
    int g = lane >> 2, tg2 = (lane & 3)*2;
    int s0g = row0 + wid*16 + g, s1g = s0g + 8;

    float c0[8], c1[8];
    float den0 = 1e-8f, den1 = 1e-8f;
    #pragma unroll
    for (int n = 0; n < 8; ++n){
        float a = g_amp[h*8 + n], kss = g_ksum[bh*8 + n];
        c0[n] = g_qa[((size_t)bh*Ss + s0g)*8 + n] * a;  den0 += c0[n]*kss;
        c1[n] = g_qa[((size_t)bh*Ss + s1g)*8 + n] * a;  den1 += c1[n]*kss;
    }
    float id0 = blend/den0, id1 = blend/den1;

    size_t base0 = ((size_t)(b*Ss + s0g))*HID + h*128;
    size_t base1 = ((size_t)(b*Ss + s1g))*HID + h*128;
    #pragma unroll
    for (int n8 = 0; n8 < 16; ++n8){
        int d = n8*8 + tg2;
        float num00=0.f, num01=0.f, num10=0.f, num11=0.f;
        #pragma unroll
        for (int n = 0; n < 8; ++n){
            float2 kv = *(const float2*)(g_kvmat + ((size_t)bh*8 + n)*128 + d);
            num00 += c0[n]*kv.x;  num01 += c0[n]*kv.y;
            num10 += c1[n]*kv.x;  num11 += c1[n]*kv.y;
        }
        float v00 = ob*O[n8*4+0]*inv0 + id0*num00;
        float v01 = ob*O[n8*4+1]*inv0 + id0*num01;
        float v10 = ob*O[n8*4+2]*inv1 + id1*num10;
        float v11 = ob*O[n8*4+3]*inv1 + id1*num11;
        bf16 h00,l00,h01,l01,h10,l10,h11,l11;
        split2(v00,h00,l00); split2(v01,h01,l01);
        split2(v10,h10,l10); split2(v11,h11,l11);
        __nv_bfloat162 t2;
        t2.x=h00; t2.y=h01; *(__nv_bfloat162*)(g_Ch + base0 + d) = t2;
        t2.x=l00; t2.y=l01; *(__nv_bfloat162*)(g_Cl + base0 + d) = t2;
        t2.x=h10; t2.y=h11; *(__nv_bfloat162*)(g_Ch + base1 + d) = t2;
        t2.x=l10; t2.y=l11; *(__nv_bfloat162*)(g_Cl + base1 + d) = t2;
    }
    __syncthreads();
    if (tid == 0){ mbar_inval(sb); mbar_inval(sb+8); mbar_inval(sb+16); }
}

// ================= conversion kernels ======================================
__global__ void convert_x_kernel(const float* __restrict__ X){
    int i = (blockIdx.x*256 + threadIdx.x) * 4;
    float4 v = *(const float4*)(X + i);
    split2(v.x, g_Xh[i+0], g_Xl[i+0]);
    split2(v.y, g_Xh[i+1], g_Xl[i+1]);
    split2(v.z, g_Xh[i+2], g_Xl[i+2]);
    split2(v.w, g_Xh[i+3], g_Xl[i+3]);
}

__global__ void tsplit_kernel(const float* __restrict__ Wq, const float* __restrict__ Wk,
                              const float* __restrict__ Wv, const float* __restrict__ Wo){
    __shared__ float t[32][33];
    int z = blockIdx.z;
    const float* in = (z == 0) ? Wq : (z == 1) ? Wk : (z == 2) ? Wv : Wo;
    bf16* oh = (z == 0) ? g_Wqt_h : (z == 1) ? g_Wkt_h : (z == 2) ? g_Wvt_h : g_Wot_h;
    bf16* ol = (z == 0) ? g_Wqt_l : (z == 1) ? g_Wkt_l : (z == 2) ? g_Wvt_l : g_Wot_l;
    int n0 = blockIdx.x*32, k0 = blockIdx.y*32;
    int tx = threadIdx.x, ty = threadIdx.y;
    #pragma unroll
    for (int j = 0; j < 4; ++j)
        t[ty + 8*j][tx] = in[(size_t)(k0 + ty + 8*j)*HID + n0 + tx];
    __syncthreads();
    #pragma unroll
    for (int j = 0; j < 4; ++j){
        float v = t[tx][ty + 8*j];
        size_t o = (size_t)(n0 + ty + 8*j)*HID + k0 + tx;
        split2(v, oh[o], ol[o]);
    }
}

// ---------------- prep ------------------------------------------------------
__global__ void prep_kernel(const float* __restrict__ pos_in,
                            const float* __restrict__ dir_in,
                            const float* __restrict__ ls_in,
                            const float* __restrict__ la_in,
                            const float* __restrict__ dstr,
                            const float* __restrict__ gstr)
{
    int i = threadIdx.x;
    if (i < NH*NS) {
        const float* p = pos_in + (size_t)i*Dd;
        const float* dv = dir_in + (size_t)i*Dd;
        float np = 0.f, nd = 0.f;
        for (int d = 0; d < Dd; ++d) { np += p[d]*p[d]; nd += dv[d]*dv[d]; }
        float pscale = 3.39411254969543f / (sqrtf(np) + 1e-12f);
        float dscale = 1.0f / (sqrtf(nd) + 1e-12f);
        float psq = 0.f, pdd = 0.f;
        for (int d = 0; d < Dd; ++d) {
            float ps = p[d]*pscale, du = dv[d]*dscale;
            g_pos[(size_t)i*Dd + d] = ps;
            g_dir[(size_t)i*Dd + d] = du;
            psq += ps*ps;  pdd += ps*du;
        }
        g_possq[i] = psq;  g_pdd[i] = pdd;
        float sc = expf(ls_in[i]);
        sc = fminf(fmaxf(sc, 0.3f), 1.2f);
        g_inv2s2[i] = 0.5f / (sc*sc);
    }
    __syncthreads();
    if (i < NH) {
        float m = -1e30f;
        for (int n = 0; n < NS; ++n) m = fmaxf(m, la_in[i*NS+n]);
        float s = 0.f, e[NS];
        for (int n = 0; n < NS; ++n) { e[n] = expf(la_in[i*NS+n]-m); s += e[n]; }
        for (int n = 0; n < NS; ++n) g_amp[i*NS+n] = e[n]/s;
    }
    if (i == 0) {
        g_ds = 1.0f / (1.0f + expf(-dstr[0]));
        float gsa = 1.0f / (1.0f + expf(-gstr[0]));
        g_blend = fminf(0.05f, gsa*0.1f);
    }
}

// ---------------- affinities (warp per token) -------------------------------
__global__ void __launch_bounds__(256) affinity2()
{
    int gidx = blockIdx.x*8 + (threadIdx.x >> 5);   // 0..65535
    int lane = threadIdx.x & 31;
    int z = gidx >> 15;
    int rem = gidx & 32767;
    int bh = rem >> 10, s = rem & 1023;
    int b = bh >> 4, h = bh & 15;
    const bf16* sh = z ? g_Kh : g_Qh;
    const bf16* sl = z ? g_Kl : g_Ql;
    size_t base = ((size_t)(b*Ss + s))*HID + h*128;
    float t[4];
    #pragma unroll
    for (int k = 0; k < 4; ++k){
        int d = k*32 + lane;
        t[k] = __bfloat162float(sh[base+d]) + __bfloat162float(sl[base+d]);
    }
    float tsq = wsum(t[0]*t[0] + t[1]*t[1] + t[2]*t[2] + t[3]*t[3]);
    float ds = g_ds;
    float* out = (z ? g_ka : g_qa) + ((size_t)bh*Ss + s)*NS;
    #pragma unroll
    for (int n = 0; n < NS; ++n){
        int hn = h*NS + n;
        float tp = 0.f, td = 0.f;
        #pragma unroll
        for (int k = 0; k < 4; ++k){
            int d = k*32 + lane;
            tp += t[k]*g_pos[hn*Dd + d];
            td += t[k]*g_dir[hn*Dd + d];
        }
        tp = wsum(tp);  td = wsum(td);
        if (lane == n){
            float dist2 = fmaxf(tsq - 2.0f*tp + g_possq[hn], 0.0f);
            float proj  = td - g_pdd[hn];
            float perp2 = fmaxf(dist2 - proj*proj, 0.0f);
            float inv   = g_inv2s2[hn];
            out[n] = (1.0f-ds)*expf(-dist2*inv) + ds*expf(-perp2*inv);
        }
    }
}

// ---------------- GSA linear-attention precompute (2-phase) ----------------
__global__ void gsa_kv_part()
{
    int ch = blockIdx.x, bh = blockIdx.y;
    int b = bh >> 4, h = bh & 15;
    int d = threadIdx.x;
    const float* vb = g_V + (size_t)b*Ss*HID + h*Dd;
    const float* ka = g_ka + (size_t)bh*Ss*NS;
    float acc[NS];
    #pragma unroll
    for (int n = 0; n < NS; ++n) acc[n] = 0.f;
    int s0 = ch*128;
    for (int s = s0; s < s0+128; ++s){
        float vv = vb[(size_t)s*HID + d];
        #pragma unroll
        for (int n = 0; n < NS; ++n) acc[n] += ka[s*NS+n]*vv;
    }
    #pragma unroll
    for (int n = 0; n < NS; ++n)
        g_kvp[(((size_t)ch*BH + bh)*NS + n)*Dd + d] = acc[n];
    if (d < NS){
        float kssum = 0.f;
        for (int s = s0; s < s0+128; ++s) kssum += ka[s*NS+d];
        g_ksp[(ch*BH + bh)*NS + d] = kssum;
    }
}

__global__ void gsa_red()
{
    int bh = blockIdx.x, d = threadIdx.x;
    #pragma unroll
    for (int n = 0; n < NS; ++n){
        float t = 0.f;
        #pragma unroll
        for (int ch = 0; ch < 8; ++ch)
            t += g_kvp[(((size_t)ch*BH + bh)*NS + n)*Dd + d];
        g_kvmat[((size_t)bh*NS + n)*Dd + d] = t;
    }
    if (d < NS){
        float t = 0.f;
        #pragma unroll
        for (int ch = 0; ch < 8; ++ch) t += g_ksp[(ch*BH + bh)*NS + d];
        g_ksum[bh*NS + d] = t;
    }
}

// ---------------- host: tensormap construction -----------------------------
typedef CUresult (*TMapEncode)(CUtensorMap*, CUtensorMapDataType, cuuint32_t, void*,
    const cuuint64_t*, const cuuint64_t*, const cuuint32_t*, const cuuint32_t*,
    CUtensorMapInterleave, CUtensorMapSwizzle, CUtensorMapL2promotion, CUtensorMapFloatOOBfill);

static void make_map(TMapEncode enc, CUtensorMap* m, void* base, uint64_t d0, uint64_t d1,
                     uint32_t b0, uint32_t b1){
    cuuint64_t dims[2]    = {d0, d1};
    cuuint64_t strides[1] = {d0 * 2};
    cuuint32_t box[2]     = {b0, b1};
    cuuint32_t es[2]      = {1, 1};
    enc(m, CU_TENSOR_MAP_DATA_TYPE_BFLOAT16, 2, base, dims, strides, box, es,
        CU_TENSOR_MAP_INTERLEAVE_NONE, CU_TENSOR_MAP_SWIZZLE_128B,
        CU_TENSOR_MAP_L2_PROMOTION_L2_128B, CU_TENSOR_MAP_FLOAT_OOB_FILL_NONE);
}

// ---------------- launch ----------------------------------------------------
extern "C" void kernel_launch(void* const* d_in, const int* in_sizes, int n_in,
                              void* d_out, int out_size)
{
    const float* X   = (const float*)d_in[0];
    const float* Wq  = (const float*)d_in[1];
    const float* Wk  = (const float*)d_in[2];
    const float* Wv  = (const float*)d_in[3];
    const float* Wo  = (const float*)d_in[4];
    const float* pos = (const float*)d_in[5];
    const float* dir = (const float*)d_in[6];
    const float* ls  = (const float*)d_in[7];
    const float* la  = (const float*)d_in[8];
    const float* dstr= (const float*)d_in[9];
    const float* gstr= (const float*)d_in[10];
    float* out = (float*)d_out;

    void* fp = nullptr;
    cudaDriverEntryPointQueryResult qr;
#if CUDART_VERSION >= 12050
    cudaGetDriverEntryPointByVersion("cuTensorMapEncodeTiled", &fp, 12000, cudaEnableDefault, &qr);
#else
    cudaGetDriverEntryPoint("cuTensorMapEncodeTiled", &fp, cudaEnableDefault, &qr);
#endif
    TMapEncode enc = (TMapEncode)fp;

    void *pXh,*pXl,*pWqh,*pWql,*pWkh,*pWkl,*pWvh,*pWvl,*pWoh,*pWol;
    void *pQh,*pQl,*pKh,*pKl,*pVh,*pVl,*pCh,*pCl;
    cudaGetSymbolAddress(&pXh, g_Xh);   cudaGetSymbolAddress(&pXl, g_Xl);
    cudaGetSymbolAddress(&pWqh, g_Wqt_h); cudaGetSymbolAddress(&pWql, g_Wqt_l);
    cudaGetSymbolAddress(&pWkh, g_Wkt_h); cudaGetSymbolAddress(&pWkl, g_Wkt_l);
    cudaGetSymbolAddress(&pWvh, g_Wvt_h); cudaGetSymbolAddress(&pWvl, g_Wvt_l);
    cudaGetSymbolAddress(&pWoh, g_Wot_h); cudaGetSymbolAddress(&pWol, g_Wot_l);
    cudaGetSymbolAddress(&pQh, g_Qh);   cudaGetSymbolAddress(&pQl, g_Ql);
    cudaGetSymbolAddress(&pKh, g_Kh);   cudaGetSymbolAddress(&pKl, g_Kl);
    cudaGetSymbolAddress(&pVh, g_Vth);  cudaGetSymbolAddress(&pVl, g_Vtl);
    cudaGetSymbolAddress(&pCh, g_Ch);   cudaGetSymbolAddress(&pCl, g_Cl);

    CUtensorMap mXh,mXl,mWqh,mWql,mWkh,mWkl,mWvh,mWvl,mWoh,mWol;
    CUtensorMap mQh,mQl,mK64h,mK64l,mVh,mVl,mCh,mCl;
    make_map(enc,&mXh,pXh,HID,Mm,64,128);     make_map(enc,&mXl,pXl,HID,Mm,64,128);
    make_map(enc,&mWqh,pWqh,HID,HID,64,128);  make_map(enc,&mWql,pWql,HID,HID,64,128);
    make_map(enc,&mWkh,pWkh,HID,HID,64,128);  make_map(enc,&mWkl,pWkl,HID,HID,64,128);
    make_map(enc,&mWvh,pWvh,HID,HID,64,128);  make_map(enc,&mWvl,pWvl,HID,HID,64,128);
    make_map(enc,&mWoh,pWoh,HID,HID,64,128);  make_map(enc,&mWol,pWol,HID,HID,64,128);
    make_map(enc,&mQh,pQh,HID,Mm,64,128);     make_map(enc,&mQl,pQl,HID,Mm,64,128);
    make_map(enc,&mK64h,pKh,HID,Mm,64,64);    make_map(enc,&mK64l,pKl,HID,Mm,64,64);
    make_map(enc,&mVh,pVh,Ss,(uint64_t)BH*Dd,64,128);
    make_map(enc,&mVl,pVl,Ss,(uint64_t)BH*Dd,64,128);
    make_map(enc,&mCh,pCh,HID,Mm,64,128);     make_map(enc,&mCl,pCl,HID,Mm,64,128);

    cudaFuncSetAttribute(qkv_tc,   cudaFuncAttributeMaxDynamicSharedMemorySize, SMEM_SZ);
    cudaFuncSetAttribute(wo_tc,    cudaFuncAttributeMaxDynamicSharedMemorySize, SMEM_SZ);
    cudaFuncSetAttribute(flash_tc, cudaFuncAttributeMaxDynamicSharedMemorySize, SMEM_FL);

    prep_kernel<<<1, 128>>>(pos, dir, ls, la, dstr, gstr);
    convert_x_kernel<<<(Mm*HID)/1024, 256>>>(X);
    tsplit_kernel<<<dim3(HID/32, HID/32, 4), dim3(32, 8)>>>(Wq, Wk, Wv, Wo);
    qkv_tc<<<dim3(HID/128, Mm/128, 3), 256, SMEM_SZ>>>(mXh,mXl,mWqh,mWql,mWkh,mWkl,mWvh,mWvl);
    affinity2<<<(Ss*BH*2)/8, 256>>>();
    gsa_kv_part<<<dim3(8, BH), 128>>>();
    gsa_red<<<BH, 128>>>();
    flash_tc<<<dim3(Ss/128, BH), 256, SMEM_FL>>>(mQh,mQl,mK64h,mK64l,mVh,mVl);
    wo_tc<<<dim3(HID/128, Mm/128, 1), 256, SMEM_SZ>>>(mCh,mCl,mWoh,mWol,out);
}

// round 7
// speedup vs baseline: 4.4654x; 1.3133x over previous
#include <cuda_runtime.h>
#include <cuda.h>
#include <cuda_fp16.h>
#include <math.h>
#include <stdint.h>

#define Bb 2
#define Ss 1024
#define HID 2048
#define NH 16
#define NS 8
#define Dd 128
#define Mm (Bb*Ss)      // 2048
#define BH (Bb*NH)      // 32

typedef __half f16;

// ---------------- scratch (device globals; no allocation allowed) ----------
__device__ float g_V[(size_t)Mm*HID];
__device__ float g_qa[(size_t)BH*Ss*NS];
__device__ float g_ka[(size_t)BH*Ss*NS];
__device__ float g_kvmat[(size_t)BH*NS*Dd];
__device__ float g_ksum[BH*NS];
__device__ float g_kvp[(size_t)8*BH*NS*Dd];
__device__ float g_ksp[8*BH*NS];
__device__ float g_pos[NH*NS*Dd];
__device__ float g_dir[NH*NS*Dd];
__device__ float g_possq[NH*NS];
__device__ float g_pdd[NH*NS];
__device__ float g_inv2s2[NH*NS];
__device__ float g_amp[NH*NS];
__device__ float g_ds;
__device__ float g_blend;

// fp16 operand arrays: A-side plain, B-side split hi/lo
__device__ f16 g_Xf[(size_t)Mm*HID];
__device__ f16 g_Wqt_h[(size_t)HID*HID], g_Wqt_l[(size_t)HID*HID];
__device__ f16 g_Wkt_h[(size_t)HID*HID], g_Wkt_l[(size_t)HID*HID];
__device__ f16 g_Wvt_h[(size_t)HID*HID], g_Wvt_l[(size_t)HID*HID];
__device__ f16 g_Wot_h[(size_t)HID*HID], g_Wot_l[(size_t)HID*HID];
__device__ f16 g_Qf[(size_t)Mm*HID];
__device__ f16 g_Kh[(size_t)Mm*HID], g_Kl[(size_t)Mm*HID];
__device__ f16 g_Vth[(size_t)BH*Dd*Ss], g_Vtl[(size_t)BH*Dd*Ss]; // [bh][d][s]
__device__ f16 g_Cf[(size_t)Mm*HID];

__device__ __forceinline__ void split2(float v, f16& h, f16& l){
    h = __float2half(v);
    l = __float2half(v - __half2float(h));
}
__device__ __forceinline__ uint32_t packh2(float x, float y){
    __half2 t = __floats2half2_rn(x, y);
    return *(uint32_t*)&t;
}

// ================= low-level helpers =======================================
__device__ __forceinline__ uint32_t smem_u32(const void* p){
    uint32_t a;
    asm("{ .reg .u64 t; cvta.to.shared.u64 t, %1; cvt.u32.u64 %0, t; }" : "=r"(a) : "l"(p));
    return a;
}
__device__ __forceinline__ void mbar_init(uint32_t a, uint32_t cnt){
    asm volatile("mbarrier.init.shared.b64 [%0], %1;" :: "r"(a), "r"(cnt) : "memory");
}
__device__ __forceinline__ void mbar_inval(uint32_t a){
    asm volatile("mbarrier.inval.shared.b64 [%0];" :: "r"(a) : "memory");
}
__device__ __forceinline__ void mbar_expect(uint32_t a, uint32_t bytes){
    asm volatile("mbarrier.arrive.expect_tx.shared.b64 _, [%0], %1;" :: "r"(a), "r"(bytes) : "memory");
}
__device__ __forceinline__ void wait_parity(uint32_t mbar, uint32_t ph){
    uint32_t done;
    asm volatile(
        "{\n\t.reg .pred p;\n\t"
        "mbarrier.try_wait.parity.acquire.cta.shared::cta.b64 p, [%1], %2;\n\t"
        "selp.b32 %0, 1, 0, p;\n\t}"
        : "=r"(done) : "r"(mbar), "r"(ph) : "memory");
    if (!done) {
        asm volatile(
            "{\n\t.reg .pred P1;\n\t"
            "WL%=:\n\t"
            "mbarrier.try_wait.parity.acquire.cta.shared::cta.b64 P1, [%0], %1, 0x989680;\n\t"
            "@P1 bra.uni WD%=;\n\t"
            "bra.uni WL%=;\n\t"
            "WD%=:\n\t}"
            :: "r"(mbar), "r"(ph) : "memory");
    }
}
__device__ __forceinline__ void tma2d(uint32_t dst, const CUtensorMap* m, int x, int y, uint32_t mbar){
    asm volatile(
        "cp.async.bulk.tensor.2d.shared::cta.global.tile.mbarrier::complete_tx::bytes "
        "[%0], [%1, {%2, %3}], [%4];"
        :: "r"(dst), "l"(m), "r"(x), "r"(y), "r"(mbar) : "memory");
}
__device__ __forceinline__ void ldm4(uint32_t* r, uint32_t a){
    asm volatile("ldmatrix.sync.aligned.m8n8.x4.shared.b16 {%0,%1,%2,%3}, [%4];"
        : "=r"(r[0]),"=r"(r[1]),"=r"(r[2]),"=r"(r[3]) : "r"(a));
}
__device__ __forceinline__ void mma16816(float* c, const uint32_t* a, uint32_t b0, uint32_t b1){
    asm volatile("mma.sync.aligned.m16n8k16.row.col.f32.f16.f16.f32 "
        "{%0,%1,%2,%3}, {%4,%5,%6,%7}, {%8,%9}, {%0,%1,%2,%3};"
        : "+f"(c[0]),"+f"(c[1]),"+f"(c[2]),"+f"(c[3])
        : "r"(a[0]),"r"(a[1]),"r"(a[2]),"r"(a[3]), "r"(b0),"r"(b1));
}
__device__ __forceinline__ uint32_t swz(uint32_t x){ return x ^ ((x>>3)&0x70); }
__device__ __forceinline__ float wsum(float v){
    #pragma unroll
    for (int o = 16; o; o >>= 1) v += __shfl_xor_sync(0xffffffffu, v, o);
    return v;
}

#define TILE_B    16384
#define QSTAGE_B  49152                         // A(16K) Bh(16K) Bl(16K)
#define SMEM_SZ   (1024 + 4*QSTAGE_B)           // 4-stage gemm
#define FSTAGE_B  65536                         // Kh Kl Vh Vl
#define SMEM_FL   (1024 + 32768 + 2*FSTAGE_B)   // Q(32K) + 2 stages

// ---------------- 128x128 CTA GEMM mainloop (256 threads, 8 warps) ---------
// C[128,128] += A[128,K] * (Bh+Bl)[128,K]^T  (asymmetric 2-product)
__device__ __forceinline__ void gemm_main(
    const CUtensorMap* mA,
    const CUtensorMap* mBh, const CUtensorMap* mBl,
    int ax0, int ay, int bx0, int by, int K, float* acc)
{
    extern __shared__ char smem[];
    uint32_t sb = smem_u32(smem);
    int tid = threadIdx.x, lane = tid & 31, wid = tid >> 5;
    int warp_m = (wid >> 2) * 64, warp_n = (wid & 3) * 32;

    if (tid == 0){ mbar_init(sb,1); mbar_init(sb+8,1); mbar_init(sb+16,1); mbar_init(sb+24,1); }
    __syncthreads();

    #pragma unroll
    for (int i = 0; i < 64; ++i) acc[i] = 0.f;

    int NC = K / 64;

    auto issue = [&](int c){
        if (tid == 0){
            int st = c & 3;
            uint32_t mb = sb + 8*st;
            mbar_expect(mb, (uint32_t)QSTAGE_B);
            uint32_t dst = sb + 1024 + st*QSTAGE_B;
            tma2d(dst,            mA,  ax0 + c*64, ay, mb);
            tma2d(dst +   TILE_B, mBh, bx0 + c*64, by, mb);
            tma2d(dst + 2*TILE_B, mBl, bx0 + c*64, by, mb);
        }
    };
    issue(0);
    if (NC > 1) issue(1);
    if (NC > 2) issue(2);
    if (NC > 3) issue(3);

    uint32_t a_row  = warp_m + (lane & 15);
    uint32_t a_colb = (lane >> 4) * 16;
    uint32_t b_row  = warp_n + (lane & 7) + ((lane >> 4) << 3);
    uint32_t b_colb = ((lane >> 3) & 1) * 16;

    for (int c = 0; c < NC; ++c){
        wait_parity(sb + 8*(c & 3), (c >> 2) & 1);
        uint32_t st = sb + 1024 + (c & 3)*QSTAGE_B;
        #pragma unroll
        for (int ks = 0; ks < 4; ++ks){
            uint32_t a_[16], bh[8], bl[8];
            #pragma unroll
            for (int mt = 0; mt < 4; ++mt){
                uint32_t off = swz((a_row + mt*16)*128 + ks*32 + a_colb);
                ldm4(a_ + mt*4, st + off);
            }
            #pragma unroll
            for (int nt = 0; nt < 2; ++nt){
                uint32_t off = swz((b_row + nt*16)*128 + ks*32 + b_colb);
                ldm4(bh + nt*4, st + TILE_B + off);
                ldm4(bl + nt*4, st + 2*TILE_B + off);
            }
            #pragma unroll
            for (int mt = 0; mt < 4; ++mt)
                #pragma unroll
                for (int n8 = 0; n8 < 4; ++n8){
                    float* c4 = acc + (mt*4 + n8)*4;
                    int bi = (n8 >> 1)*4 + (n8 & 1)*2;
                    mma16816(c4, a_ + mt*4, bh[bi], bh[bi+1]);
                    mma16816(c4, a_ + mt*4, bl[bi], bl[bi+1]);
                }
        }
        __syncthreads();
        if (c + 4 < NC) issue(c + 4);
    }
    if (tid == 0){ mbar_inval(sb); mbar_inval(sb+8); mbar_inval(sb+16); mbar_inval(sb+24); }
}

template<class F>
__device__ __forceinline__ void epi_loop(const float* acc, F f){
    int lane = threadIdx.x & 31, wid = threadIdx.x >> 5;
    int warp_m = (wid >> 2) * 64, warp_n = (wid & 3) * 32;
    int g = lane >> 2, tg = (lane & 3) * 2;
    #pragma unroll
    for (int mt = 0; mt < 4; ++mt)
        #pragma unroll
        for (int n8 = 0; n8 < 4; ++n8){
            const float* c4 = acc + (mt*4 + n8)*4;
            #pragma unroll
            for (int hh = 0; hh < 2; ++hh){
                int r  = warp_m + mt*16 + g + hh*8;
                int cc = warp_n + n8*8 + tg;
                f(r, cc, c4[hh*2], c4[hh*2+1]);
            }
        }
}

// ================= GEMM kernels ============================================
__global__ void __launch_bounds__(256) qkv_tc(
    const __grid_constant__ CUtensorMap mXf,
    const __grid_constant__ CUtensorMap mWqh, const __grid_constant__ CUtensorMap mWql,
    const __grid_constant__ CUtensorMap mWkh, const __grid_constant__ CUtensorMap mWkl,
    const __grid_constant__ CUtensorMap mWvh, const __grid_constant__ CUtensorMap mWvl)
{
    int z = blockIdx.z;
    int row0 = blockIdx.y*128, col0 = blockIdx.x*128;
    const CUtensorMap *pbh, *pbl;
    if (z == 0){ pbh = &mWqh; pbl = &mWql; }
    else if (z == 1){ pbh = &mWkh; pbl = &mWkl; }
    else { pbh = &mWvh; pbl = &mWvl; }
    float acc[64];
    gemm_main(&mXf, pbh, pbl, 0, row0, 0, col0, HID, acc);

    epi_loop(acc, [&](int r, int cc, float v0, float v1){
        int gr = row0 + r;
        size_t idx = (size_t)gr*HID + col0 + cc;
        if (z == 0){
            *(uint32_t*)(g_Qf + idx) = packh2(v0, v1);
        } else if (z == 1){
            f16 h0,l0,h1,l1; split2(v0,h0,l0); split2(v1,h1,l1);
            __half2 hv; hv.x=h0; hv.y=h1;
            __half2 lv; lv.x=l0; lv.y=l1;
            *(__half2*)(g_Kh + idx) = hv;
            *(__half2*)(g_Kl + idx) = lv;
        } else {
            float2 fv; fv.x = v0; fv.y = v1;
            *(float2*)(g_V + idx) = fv;
            int b = gr >> 10, s = gr & (Ss-1);
            int h = col0 >> 7, d = cc;
            f16 h0,l0,h1,l1; split2(v0,h0,l0); split2(v1,h1,l1);
            size_t ti = (((size_t)(b*NH + h))*Dd + d)*Ss + s;
            g_Vth[ti] = h0; g_Vth[ti + Ss] = h1;
            g_Vtl[ti] = l0; g_Vtl[ti + Ss] = l1;
        }
    });
}

__global__ void __launch_bounds__(256) wo_tc(
    const __grid_constant__ CUtensorMap mCf,
    const __grid_constant__ CUtensorMap mWh, const __grid_constant__ CUtensorMap mWl,
    float* __restrict__ out)
{
    int row0 = blockIdx.y*128, col0 = blockIdx.x*128;
    float acc[64];
    gemm_main(&mCf, &mWh, &mWl, 0, row0, 0, col0, HID, acc);
    epi_loop(acc, [&](int r, int cc, float v0, float v1){
        float2 fv; fv.x = v0; fv.y = v1;
        *(float2*)(out + (size_t)(row0 + r)*HID + col0 + cc) = fv;
    });
}

// ================= flash attention kernel ==================================
__global__ void __launch_bounds__(256) flash_tc(
    const __grid_constant__ CUtensorMap mQf,
    const __grid_constant__ CUtensorMap mK64h, const __grid_constant__ CUtensorMap mK64l,
    const __grid_constant__ CUtensorMap mVh, const __grid_constant__ CUtensorMap mVl)
{
    extern __shared__ char smem[];
    uint32_t sb = smem_u32(smem);
    int tid = threadIdx.x, lane = tid & 31, wid = tid >> 5;
    int bh = blockIdx.y, b = bh >> 4, h = bh & 15;
    int row0 = blockIdx.x * 128;

    const uint32_t QF  = sb + 1024;          // two 16KB halves
    const uint32_t ST0 = QF + 32768;
    // stage: KH0(8K) KH1(8K) KL0(8K) KL1(8K) VH(16K) VL(16K) = 64KB

    if (tid == 0){ mbar_init(sb,1); mbar_init(sb+8,1); mbar_init(sb+16,1); }
    __syncthreads();

    if (tid == 0){
        mbar_expect(sb+16, 32768u);
        tma2d(QF,        &mQf, h*128,    b*Ss+row0, sb+16);
        tma2d(QF+16384,  &mQf, h*128+64, b*Ss+row0, sb+16);
    }
    auto issue = [&](int j){
        if (tid == 0){
            uint32_t mb = sb + 8*(j&1);
            mbar_expect(mb, 65536u);
            uint32_t st = ST0 + (j&1)*FSTAGE_B;
            tma2d(st,         &mK64h, h*128,    b*Ss+j*64, mb);
            tma2d(st+8192,    &mK64h, h*128+64, b*Ss+j*64, mb);
            tma2d(st+16384,   &mK64l, h*128,    b*Ss+j*64, mb);
            tma2d(st+24576,   &mK64l, h*128+64, b*Ss+j*64, mb);
            tma2d(st+32768,   &mVh,   j*64, bh*128, mb);
            tma2d(st+49152,   &mVl,   j*64, bh*128, mb);
        }
    };
    issue(0); issue(1);

    float O[64];
    #pragma unroll
    for (int i = 0; i < 64; ++i) O[i] = 0.f;
    float m0 = -1e30f, m1 = -1e30f, l0 = 0.f, l1 = 0.f;
    const float qk = 0.08838834764831845f;

    uint32_t a_row = wid*16 + (lane & 15), a_colb = (lane >> 4)*16;
    uint32_t b_rw  = (lane & 7) + ((lane >> 4) << 3);
    uint32_t b_cb  = ((lane >> 3) & 1)*16;

    wait_parity(sb+16, 0);

    for (int j = 0; j < 16; ++j){
        wait_parity(sb + 8*(j&1), (j>>1)&1);
        uint32_t st = ST0 + (j&1)*FSTAGE_B;

        // ---- S = Q K^T (Q plain, K split)
        float s[32];
        #pragma unroll
        for (int i = 0; i < 32; ++i) s[i] = 0.f;
        #pragma unroll
        for (int ks = 0; ks < 8; ++ks){
            uint32_t qf_[4], kh_[16], kl_[16];
            uint32_t offa = (ks>>2)*16384 + swz(a_row*128 + (ks&3)*32 + a_colb);
            ldm4(qf_, QF + offa);
            #pragma unroll
            for (int nt = 0; nt < 4; ++nt){
                uint32_t offb = (ks>>2)*8192 + swz((b_rw + nt*16)*128 + (ks&3)*32 + b_cb);
                ldm4(kh_ + nt*4, st + offb);
                ldm4(kl_ + nt*4, st + 16384 + offb);
            }
            #pragma unroll
            for (int n8 = 0; n8 < 8; ++n8){
                int bi = (n8 >> 1)*4 + (n8 & 1)*2;
                mma16816(s + n8*4, qf_, kh_[bi], kh_[bi+1]);
                mma16816(s + n8*4, qf_, kl_[bi], kl_[bi+1]);
            }
        }

        // ---- online softmax
        float tm0 = -1e30f, tm1 = -1e30f;
        #pragma unroll
        for (int t = 0; t < 8; ++t){
            s[t*4+0] *= qk; s[t*4+1] *= qk; s[t*4+2] *= qk; s[t*4+3] *= qk;
            tm0 = fmaxf(tm0, fmaxf(s[t*4+0], s[t*4+1]));
            tm1 = fmaxf(tm1, fmaxf(s[t*4+2], s[t*4+3]));
        }
        tm0 = fmaxf(tm0, __shfl_xor_sync(0xffffffffu, tm0, 1));
        tm0 = fmaxf(tm0, __shfl_xor_sync(0xffffffffu, tm0, 2));
        tm1 = fmaxf(tm1, __shfl_xor_sync(0xffffffffu, tm1, 1));
        tm1 = fmaxf(tm1, __shfl_xor_sync(0xffffffffu, tm1, 2));
        float nm0 = fmaxf(m0, tm0), nm1 = fmaxf(m1, tm1);
        float al0 = expf(m0 - nm0), al1 = expf(m1 - nm1);
        float ts0 = 0.f, ts1 = 0.f;
        #pragma unroll
        for (int t = 0; t < 8; ++t){
            s[t*4+0] = expf(s[t*4+0] - nm0); s[t*4+1] = expf(s[t*4+1] - nm0);
            s[t*4+2] = expf(s[t*4+2] - nm1); s[t*4+3] = expf(s[t*4+3] - nm1);
            ts0 += s[t*4+0] + s[t*4+1];
            ts1 += s[t*4+2] + s[t*4+3];
        }
        ts0 += __shfl_xor_sync(0xffffffffu, ts0, 1);
        ts0 += __shfl_xor_sync(0xffffffffu, ts0, 2);
        ts1 += __shfl_xor_sync(0xffffffffu, ts1, 1);
        ts1 += __shfl_xor_sync(0xffffffffu, ts1, 2);
        l0 = l0*al0 + ts0;  l1 = l1*al1 + ts1;
        m0 = nm0;  m1 = nm1;
        #pragma unroll
        for (int t = 0; t < 16; ++t){
            O[t*4+0] *= al0; O[t*4+1] *= al0; O[t*4+2] *= al1; O[t*4+3] *= al1;
        }

        // ---- pack P (plain fp16) into A fragments
        uint32_t ph_[16];
        #pragma unroll
        for (int t = 0; t < 4; ++t){
            ph_[t*4+0] = packh2(s[(2*t)*4+0],   s[(2*t)*4+1]);
            ph_[t*4+1] = packh2(s[(2*t)*4+2],   s[(2*t)*4+3]);
            ph_[t*4+2] = packh2(s[(2*t+1)*4+0], s[(2*t+1)*4+1]);
            ph_[t*4+3] = packh2(s[(2*t+1)*4+2], s[(2*t+1)*4+3]);
        }

        // ---- O += P V (P plain, V split)
        #pragma unroll
        for (int ks = 0; ks < 4; ++ks){
            uint32_t vh_[32], vl_[32];
            #pragma unroll
            for (int nt = 0; nt < 8; ++nt){
                uint32_t offv = swz((b_rw + nt*16)*128 + ks*32 + b_cb);
                ldm4(vh_ + nt*4, st + 32768 + offv);
                ldm4(vl_ + nt*4, st + 49152 + offv);
            }
            #pragma unroll
            for (int n8 = 0; n8 < 16; ++n8){
                int bi = (n8 >> 1)*4 + (n8 & 1)*2;
                mma16816(O + n8*4, ph_ + ks*4, vh_[bi], vh_[bi+1]);
                mma16816(O + n8*4, ph_ + ks*4, vl_[bi], vl_[bi+1]);
            }
        }
        __syncthreads();
        if (j + 2 < 16) issue(j + 2);
    }

    // ---- epilogue: normalize, fuse GSA blend, write Cf (plain fp16)
    float inv0 = 1.f / l0, inv1 = 1.f / l1;
    float blend = g_blend, ob = 1.f - blend;
    int g = lane >> 2, tg2 = (lane & 3)*2;
    int s0g = row0 + wid*16 + g, s1g = s0g + 8;

    float c0[8], c1[8];
    float den0 = 1e-8f, den1 = 1e-8f;
    #pragma unroll
    for (int n = 0; n < 8; ++n){
        float a = g_amp[h*8 + n], kss = g_ksum[bh*8 + n];
        c0[n] = g_qa[((size_t)bh*Ss + s0g)*8 + n] * a;  den0 += c0[n]*kss;
        c1[n] = g_qa[((size_t)bh*Ss + s1g)*8 + n] * a;  den1 += c1[n]*kss;
    }
    float id0 = blend/den0, id1 = blend/den1;

    size_t base0 = ((size_t)(b*Ss + s0g))*HID + h*128;
    size_t base1 = ((size_t)(b*Ss + s1g))*HID + h*128;
    #pragma unroll
    for (int n8 = 0; n8 < 16; ++n8){
        int d = n8*8 + tg2;
        float num00=0.f, num01=0.f, num10=0.f, num11=0.f;
        #pragma unroll
        for (int n = 0; n < 8; ++n){
            float2 kv = *(const float2*)(g_kvmat + ((size_t)bh*8 + n)*128 + d);
            num00 += c0[n]*kv.x;  num01 += c0[n]*kv.y;
            num10 += c1[n]*kv.x;  num11 += c1[n]*kv.y;
        }
        float v00 = ob*O[n8*4+0]*inv0 + id0*num00;
        float v01 = ob*O[n8*4+1]*inv0 + id0*num01;
        float v10 = ob*O[n8*4+2]*inv1 + id1*num10;
        float v11 = ob*O[n8*4+3]*inv1 + id1*num11;
        *(uint32_t*)(g_Cf + base0 + d) = packh2(v00, v01);
        *(uint32_t*)(g_Cf + base1 + d) = packh2(v10, v11);
    }
    __syncthreads();
    if (tid == 0){ mbar_inval(sb); mbar_inval(sb+8); mbar_inval(sb+16); }
}

// ================= conversion kernels ======================================
__global__ void convert_x_kernel(const float* __restrict__ X){
    int i = (blockIdx.x*256 + threadIdx.x) * 4;
    float4 v = *(const float4*)(X + i);
    *(uint32_t*)(g_Xf + i)     = packh2(v.x, v.y);
    *(uint32_t*)(g_Xf + i + 2) = packh2(v.z, v.w);
}

__global__ void tsplit_kernel(const float* __restrict__ Wq, const float* __restrict__ Wk,
                              const float* __restrict__ Wv, const float* __restrict__ Wo){
    __shared__ float t[32][33];
    int z = blockIdx.z;
    const float* in = (z == 0) ? Wq : (z == 1) ? Wk : (z == 2) ? Wv : Wo;
    f16* oh = (z == 0) ? g_Wqt_h : (z == 1) ? g_Wkt_h : (z == 2) ? g_Wvt_h : g_Wot_h;
    f16* ol = (z == 0) ? g_Wqt_l : (z == 1) ? g_Wkt_l : (z == 2) ? g_Wvt_l : g_Wot_l;
    int n0 = blockIdx.x*32, k0 = blockIdx.y*32;
    int tx = threadIdx.x, ty = threadIdx.y;
    #pragma unroll
    for (int j = 0; j < 4; ++j)
        t[ty + 8*j][tx] = in[(size_t)(k0 + ty + 8*j)*HID + n0 + tx];
    __syncthreads();
    #pragma unroll
    for (int j = 0; j < 4; ++j){
        float v = t[tx][ty + 8*j];
        size_t o = (size_t)(n0 + ty + 8*j)*HID + k0 + tx;
        split2(v, oh[o], ol[o]);
    }
}

// ---------------- prep ------------------------------------------------------
__global__ void prep_kernel(const float* __restrict__ pos_in,
                            const float* __restrict__ dir_in,
                            const float* __restrict__ ls_in,
                            const float* __restrict__ la_in,
                            const float* __restrict__ dstr,
                            const float* __restrict__ gstr)
{
    int i = threadIdx.x;
    if (i < NH*NS) {
        const float* p = pos_in + (size_t)i*Dd;
        const float* dv = dir_in + (size_t)i*Dd;
        float np = 0.f, nd = 0.f;
        for (int d = 0; d < Dd; ++d) { np += p[d]*p[d]; nd += dv[d]*dv[d]; }
        float pscale = 3.39411254969543f / (sqrtf(np) + 1e-12f);
        float dscale = 1.0f / (sqrtf(nd) + 1e-12f);
        float psq = 0.f, pdd = 0.f;
        for (int d = 0; d < Dd; ++d) {
            float ps = p[d]*pscale, du = dv[d]*dscale;
            g_pos[(size_t)i*Dd + d] = ps;
            g_dir[(size_t)i*Dd + d] = du;
            psq += ps*ps;  pdd += ps*du;
        }
        g_possq[i] = psq;  g_pdd[i] = pdd;
        float sc = expf(ls_in[i]);
        sc = fminf(fmaxf(sc, 0.3f), 1.2f);
        g_inv2s2[i] = 0.5f / (sc*sc);
    }
    __syncthreads();
    if (i < NH) {
        float m = -1e30f;
        for (int n = 0; n < NS; ++n) m = fmaxf(m, la_in[i*NS+n]);
        float s = 0.f, e[NS];
        for (int n = 0; n < NS; ++n) { e[n] = expf(la_in[i*NS+n]-m); s += e[n]; }
        for (int n = 0; n < NS; ++n) g_amp[i*NS+n] = e[n]/s;
    }
    if (i == 0) {
        g_ds = 1.0f / (1.0f + expf(-dstr[0]));
        float gsa = 1.0f / (1.0f + expf(-gstr[0]));
        g_blend = fminf(0.05f, gsa*0.1f);
    }
}

// ---------------- affinities (warp per token) -------------------------------
__global__ void __launch_bounds__(256) affinity2()
{
    int gidx = blockIdx.x*8 + (threadIdx.x >> 5);   // 0..65535
    int lane = threadIdx.x & 31;
    int z = gidx >> 15;
    int rem = gidx & 32767;
    int bh = rem >> 10, s = rem & 1023;
    int b = bh >> 4, h = bh & 15;
    size_t base = ((size_t)(b*Ss + s))*HID + h*128;
    float t[4];
    #pragma unroll
    for (int k = 0; k < 4; ++k){
        int d = k*32 + lane;
        t[k] = z ? (__half2float(g_Kh[base+d]) + __half2float(g_Kl[base+d]))
                 : __half2float(g_Qf[base+d]);
    }
    float tsq = wsum(t[0]*t[0] + t[1]*t[1] + t[2]*t[2] + t[3]*t[3]);
    float ds = g_ds;
    float* out = (z ? g_ka : g_qa) + ((size_t)bh*Ss + s)*NS;
    #pragma unroll
    for (int n = 0; n < NS; ++n){
        int hn = h*NS + n;
        float tp = 0.f, td = 0.f;
        #pragma unroll
        for (int k = 0; k < 4; ++k){
            int d = k*32 + lane;
            tp += t[k]*g_pos[hn*Dd + d];
            td += t[k]*g_dir[hn*Dd + d];
        }
        tp = wsum(tp);  td = wsum(td);
        if (lane == n){
            float dist2 = fmaxf(tsq - 2.0f*tp + g_possq[hn], 0.0f);
            float proj  = td - g_pdd[hn];
            float perp2 = fmaxf(dist2 - proj*proj, 0.0f);
            float inv   = g_inv2s2[hn];
            out[n] = (1.0f-ds)*expf(-dist2*inv) + ds*expf(-perp2*inv);
        }
    }
}

// ---------------- GSA linear-attention precompute (2-phase) ----------------
__global__ void gsa_kv_part()
{
    int ch = blockIdx.x, bh = blockIdx.y;
    int b = bh >> 4, h = bh & 15;
    int d = threadIdx.x;
    const float* vb = g_V + (size_t)b*Ss*HID + h*Dd;
    const float* ka = g_ka + (size_t)bh*Ss*NS;
    float acc[NS];
    #pragma unroll
    for (int n = 0; n < NS; ++n) acc[n] = 0.f;
    int s0 = ch*128;
    for (int s = s0; s < s0+128; ++s){
        float vv = vb[(size_t)s*HID + d];
        #pragma unroll
        for (int n = 0; n < NS; ++n) acc[n] += ka[s*NS+n]*vv;
    }
    #pragma unroll
    for (int n = 0; n < NS; ++n)
        g_kvp[(((size_t)ch*BH + bh)*NS + n)*Dd + d] = acc[n];
    if (d < NS){
        float kssum = 0.f;
        for (int s = s0; s < s0+128; ++s) kssum += ka[s*NS+d];
        g_ksp[(ch*BH + bh)*NS + d] = kssum;
    }
}

__global__ void gsa_red()
{
    int bh = blockIdx.x, d = threadIdx.x;
    #pragma unroll
    for (int n = 0; n < NS; ++n){
        float t = 0.f;
        #pragma unroll
        for (int ch = 0; ch < 8; ++ch)
            t += g_kvp[(((size_t)ch*BH + bh)*NS + n)*Dd + d];
        g_kvmat[((size_t)bh*NS + n)*Dd + d] = t;
    }
    if (d < NS){
        float t = 0.f;
        #pragma unroll
        for (int ch = 0; ch < 8; ++ch) t += g_ksp[(ch*BH + bh)*NS + d];
        g_ksum[bh*NS + d] = t;
    }
}

// ---------------- host: tensormap construction -----------------------------
typedef CUresult (*TMapEncode)(CUtensorMap*, CUtensorMapDataType, cuuint32_t, void*,
    const cuuint64_t*, const cuuint64_t*, const cuuint32_t*, const cuuint32_t*,
    CUtensorMapInterleave, CUtensorMapSwizzle, CUtensorMapL2promotion, CUtensorMapFloatOOBfill);

static void make_map(TMapEncode enc, CUtensorMap* m, void* base, uint64_t d0, uint64_t d1,
                     uint32_t b0, uint32_t b1){
    cuuint64_t dims[2]    = {d0, d1};
    cuuint64_t strides[1] = {d0 * 2};
    cuuint32_t box[2]     = {b0, b1};
    cuuint32_t es[2]      = {1, 1};
    enc(m, CU_TENSOR_MAP_DATA_TYPE_FLOAT16, 2, base, dims, strides, box, es,
        CU_TENSOR_MAP_INTERLEAVE_NONE, CU_TENSOR_MAP_SWIZZLE_128B,
        CU_TENSOR_MAP_L2_PROMOTION_L2_128B, CU_TENSOR_MAP_FLOAT_OOB_FILL_NONE);
}

// ---------------- launch ----------------------------------------------------
extern "C" void kernel_launch(void* const* d_in, const int* in_sizes, int n_in,
                              void* d_out, int out_size)
{
    const float* X   = (const float*)d_in[0];
    const float* Wq  = (const float*)d_in[1];
    const float* Wk  = (const float*)d_in[2];
    const float* Wv  = (const float*)d_in[3];
    const float* Wo  = (const float*)d_in[4];
    const float* pos = (const float*)d_in[5];
    const float* dir = (const float*)d_in[6];
    const float* ls  = (const float*)d_in[7];
    const float* la  = (const float*)d_in[8];
    const float* dstr= (const float*)d_in[9];
    const float* gstr= (const float*)d_in[10];
    float* out = (float*)d_out;

    void* fp = nullptr;
    cudaDriverEntryPointQueryResult qr;
#if CUDART_VERSION >= 12050
    cudaGetDriverEntryPointByVersion("cuTensorMapEncodeTiled", &fp, 12000, cudaEnableDefault, &qr);
#else
    cudaGetDriverEntryPoint("cuTensorMapEncodeTiled", &fp, cudaEnableDefault, &qr);
#endif
    TMapEncode enc = (TMapEncode)fp;

    void *pXf,*pWqh,*pWql,*pWkh,*pWkl,*pWvh,*pWvl,*pWoh,*pWol;
    void *pQf,*pKh,*pKl,*pVh,*pVl,*pCf;
    cudaGetSymbolAddress(&pXf, g_Xf);
    cudaGetSymbolAddress(&pWqh, g_Wqt_h); cudaGetSymbolAddress(&pWql, g_Wqt_l);
    cudaGetSymbolAddress(&pWkh, g_Wkt_h); cudaGetSymbolAddress(&pWkl, g_Wkt_l);
    cudaGetSymbolAddress(&pWvh, g_Wvt_h); cudaGetSymbolAddress(&pWvl, g_Wvt_l);
    cudaGetSymbolAddress(&pWoh, g_Wot_h); cudaGetSymbolAddress(&pWol, g_Wot_l);
    cudaGetSymbolAddress(&pQf, g_Qf);
    cudaGetSymbolAddress(&pKh, g_Kh);   cudaGetSymbolAddress(&pKl, g_Kl);
    cudaGetSymbolAddress(&pVh, g_Vth);  cudaGetSymbolAddress(&pVl, g_Vtl);
    cudaGetSymbolAddress(&pCf, g_Cf);

    CUtensorMap mXf,mWqh,mWql,mWkh,mWkl,mWvh,mWvl,mWoh,mWol;
    CUtensorMap mQf,mK64h,mK64l,mVh,mVl,mCf;
    make_map(enc,&mXf,pXf,HID,Mm,64,128);
    make_map(enc,&mWqh,pWqh,HID,HID,64,128);  make_map(enc,&mWql,pWql,HID,HID,64,128);
    make_map(enc,&mWkh,pWkh,HID,HID,64,128);  make_map(enc,&mWkl,pWkl,HID,HID,64,128);
    make_map(enc,&mWvh,pWvh,HID,HID,64,128);  make_map(enc,&mWvl,pWvl,HID,HID,64,128);
    make_map(enc,&mWoh,pWoh,HID,HID,64,128);  make_map(enc,&mWol,pWol,HID,HID,64,128);
    make_map(enc,&mQf,pQf,HID,Mm,64,128);
    make_map(enc,&mK64h,pKh,HID,Mm,64,64);    make_map(enc,&mK64l,pKl,HID,Mm,64,64);
    make_map(enc,&mVh,pVh,Ss,(uint64_t)BH*Dd,64,128);
    make_map(enc,&mVl,pVl,Ss,(uint64_t)BH*Dd,64,128);
    make_map(enc,&mCf,pCf,HID,Mm,64,128);

    cudaFuncSetAttribute(qkv_tc,   cudaFuncAttributeMaxDynamicSharedMemorySize, SMEM_SZ);
    cudaFuncSetAttribute(wo_tc,    cudaFuncAttributeMaxDynamicSharedMemorySize, SMEM_SZ);
    cudaFuncSetAttribute(flash_tc, cudaFuncAttributeMaxDynamicSharedMemorySize, SMEM_FL);

    prep_kernel<<<1, 128>>>(pos, dir, ls, la, dstr, gstr);
    convert_x_kernel<<<(Mm*HID)/1024, 256>>>(X);
    tsplit_kernel<<<dim3(HID/32, HID/32, 4), dim3(32, 8)>>>(Wq, Wk, Wv, Wo);
    qkv_tc<<<dim3(HID/128, Mm/128, 3), 256, SMEM_SZ>>>(mXf,mWqh,mWql,mWkh,mWkl,mWvh,mWvl);
    affinity2<<<(Ss*BH*2)/8, 256>>>();
    gsa_kv_part<<<dim3(8, BH), 128>>>();
    gsa_red<<<BH, 128>>>();
    flash_tc<<<dim3(Ss/128, BH), 256, SMEM_FL>>>(mQf,mK64h,mK64l,mVh,mVl);
    wo_tc<<<dim3(HID/128, Mm/128, 1), 256, SMEM_SZ>>>(mCf,mWoh,mWol,out);
}

// round 9
// speedup vs baseline: 4.7089x; 1.0545x over previous
#include <cuda_runtime.h>
#include <cuda.h>
#include <cuda_fp16.h>
#include <math.h>
#include <stdint.h>

#define Bb 2
#define Ss 1024
#define HID 2048
#define NH 16
#define NS 8
#define Dd 128
#define Mm (Bb*Ss)      // 2048
#define BH (Bb*NH)      // 32

typedef __half f16;

// ---------------- scratch (device globals; no allocation allowed) ----------
__device__ float g_V[(size_t)Mm*HID];
__device__ float g_qa[(size_t)BH*Ss*NS];
__device__ float g_ka[(size_t)BH*Ss*NS];
__device__ float g_kvmat[(size_t)BH*NS*Dd];
__device__ float g_ksum[BH*NS];
__device__ float g_kvp[(size_t)8*BH*NS*Dd];
__device__ float g_ksp[8*BH*NS];
__device__ float g_pos[NH*NS*Dd];
__device__ float g_dir[NH*NS*Dd];
__device__ float g_possq[NH*NS];
__device__ float g_pdd[NH*NS];
__device__ float g_inv2s2[NH*NS];
__device__ float g_amp[NH*NS];
__device__ float g_ds;
__device__ float g_blend;

// fp16 operand arrays: A-side plain, B-side split hi/lo (V plain)
__device__ f16 g_Xf[(size_t)Mm*HID];
__device__ f16 g_Wqt_h[(size_t)HID*HID], g_Wqt_l[(size_t)HID*HID];
__device__ f16 g_Wkt_h[(size_t)HID*HID], g_Wkt_l[(size_t)HID*HID];
__device__ f16 g_Wvt_h[(size_t)HID*HID], g_Wvt_l[(size_t)HID*HID];
__device__ f16 g_Wot_h[(size_t)HID*HID], g_Wot_l[(size_t)HID*HID];
__device__ f16 g_Qf[(size_t)Mm*HID];
__device__ f16 g_Kh[(size_t)Mm*HID], g_Kl[(size_t)Mm*HID];
__device__ f16 g_Vth[(size_t)BH*Dd*Ss];            // [bh][d][s], plain
__device__ f16 g_Cf[(size_t)Mm*HID];

__device__ __forceinline__ void split2(float v, f16& h, f16& l){
    h = __float2half(v);
    l = __float2half(v - __half2float(h));
}
__device__ __forceinline__ uint32_t packh2(float x, float y){
    __half2 t = __floats2half2_rn(x, y);
    return *(uint32_t*)&t;
}

// ================= low-level helpers =======================================
__device__ __forceinline__ uint32_t smem_u32(const void* p){
    uint32_t a;
    asm("{ .reg .u64 t; cvta.to.shared.u64 t, %1; cvt.u32.u64 %0, t; }" : "=r"(a) : "l"(p));
    return a;
}
__device__ __forceinline__ void mbar_init(uint32_t a, uint32_t cnt){
    asm volatile("mbarrier.init.shared.b64 [%0], %1;" :: "r"(a), "r"(cnt) : "memory");
}
__device__ __forceinline__ void mbar_inval(uint32_t a){
    asm volatile("mbarrier.inval.shared.b64 [%0];" :: "r"(a) : "memory");
}
__device__ __forceinline__ void mbar_expect(uint32_t a, uint32_t bytes){
    asm volatile("mbarrier.arrive.expect_tx.shared.b64 _, [%0], %1;" :: "r"(a), "r"(bytes) : "memory");
}
__device__ __forceinline__ void wait_parity(uint32_t mbar, uint32_t ph){
    uint32_t done;
    asm volatile(
        "{\n\t.reg .pred p;\n\t"
        "mbarrier.try_wait.parity.acquire.cta.shared::cta.b64 p, [%1], %2;\n\t"
        "selp.b32 %0, 1, 0, p;\n\t}"
        : "=r"(done) : "r"(mbar), "r"(ph) : "memory");
    if (!done) {
        asm volatile(
            "{\n\t.reg .pred P1;\n\t"
            "WL%=:\n\t"
            "mbarrier.try_wait.parity.acquire.cta.shared::cta.b64 P1, [%0], %1, 0x989680;\n\t"
            "@P1 bra.uni WD%=;\n\t"
            "bra.uni WL%=;\n\t"
            "WD%=:\n\t}"
            :: "r"(mbar), "r"(ph) : "memory");
    }
}
__device__ __forceinline__ void tma2d(uint32_t dst, const CUtensorMap* m, int x, int y, uint32_t mbar){
    asm volatile(
        "cp.async.bulk.tensor.2d.shared::cta.global.tile.mbarrier::complete_tx::bytes "
        "[%0], [%1, {%2, %3}], [%4];"
        :: "r"(dst), "l"(m), "r"(x), "r"(y), "r"(mbar) : "memory");
}
__device__ __forceinline__ void ldm4(uint32_t* r, uint32_t a){
    asm volatile("ldmatrix.sync.aligned.m8n8.x4.shared.b16 {%0,%1,%2,%3}, [%4];"
        : "=r"(r[0]),"=r"(r[1]),"=r"(r[2]),"=r"(r[3]) : "r"(a));
}
__device__ __forceinline__ void mma16816(float* c, const uint32_t* a, uint32_t b0, uint32_t b1){
    asm volatile("mma.sync.aligned.m16n8k16.row.col.f32.f16.f16.f32 "
        "{%0,%1,%2,%3}, {%4,%5,%6,%7}, {%8,%9}, {%0,%1,%2,%3};"
        : "+f"(c[0]),"+f"(c[1]),"+f"(c[2]),"+f"(c[3])
        : "r"(a[0]),"r"(a[1]),"r"(a[2]),"r"(a[3]), "r"(b0),"r"(b1));
}
__device__ __forceinline__ uint32_t swz(uint32_t x){ return x ^ ((x>>3)&0x70); }
__device__ __forceinline__ float wsum(float v){
    #pragma unroll
    for (int o = 16; o; o >>= 1) v += __shfl_xor_sync(0xffffffffu, v, o);
    return v;
}

#define TILE_B    16384
#define GSTAGE_B  98304                          // A(32K) Bh(32K) Bl(32K)
#define SMEM_SZ   (1024 + 2*GSTAGE_B)            // 2-stage, 128-K per stage
#define FSTAGE_B  49152                          // Kh(16K) Kl(16K) Vh(16K)
#define SMEM_FL   (1024 + 32768 + 3*FSTAGE_B)    // Q(32K) + 3 stages

// ---------------- 128x128 CTA GEMM mainloop (256 threads, 8 warps) ---------
// C[128,128] += A[128,K] * (Bh+Bl)[128,K]^T, 128-K columns per stage
__device__ __forceinline__ void gemm_main(
    const CUtensorMap* mA,
    const CUtensorMap* mBh, const CUtensorMap* mBl,
    int ax0, int ay, int bx0, int by, int K, float* acc)
{
    extern __shared__ char smem[];
    uint32_t sb = smem_u32(smem);
    int tid = threadIdx.x, lane = tid & 31, wid = tid >> 5;
    int warp_m = (wid >> 2) * 64, warp_n = (wid & 3) * 32;

    if (tid == 0){ mbar_init(sb,1); mbar_init(sb+8,1); }
    __syncthreads();

    #pragma unroll
    for (int i = 0; i < 64; ++i) acc[i] = 0.f;

    int NC = K / 128;

    auto issue = [&](int c){
        if (tid == 0){
            int st = c & 1;
            uint32_t mb = sb + 8*st;
            mbar_expect(mb, (uint32_t)GSTAGE_B);
            uint32_t dst = sb + 1024 + st*GSTAGE_B;
            int ax = ax0 + c*128, bx = bx0 + c*128;
            tma2d(dst,            mA,  ax,      ay, mb);
            tma2d(dst +   TILE_B, mA,  ax + 64, ay, mb);
            tma2d(dst + 2*TILE_B, mBh, bx,      by, mb);
            tma2d(dst + 3*TILE_B, mBh, bx + 64, by, mb);
            tma2d(dst + 4*TILE_B, mBl, bx,      by, mb);
            tma2d(dst + 5*TILE_B, mBl, bx + 64, by, mb);
        }
    };
    issue(0);
    if (NC > 1) issue(1);

    uint32_t a_row  = warp_m + (lane & 15);
    uint32_t a_colb = (lane >> 4) * 16;
    uint32_t b_row  = warp_n + (lane & 7) + ((lane >> 4) << 3);
    uint32_t b_colb = ((lane >> 3) & 1) * 16;

    for (int c = 0; c < NC; ++c){
        wait_parity(sb + 8*(c & 1), (c >> 1) & 1);
        uint32_t st = sb + 1024 + (c & 1)*GSTAGE_B;
        #pragma unroll
        for (int ks = 0; ks < 8; ++ks){
            uint32_t base = (ks >> 2)*TILE_B;
            uint32_t a_[16], bh[8], bl[8];
            #pragma unroll
            for (int mt = 0; mt < 4; ++mt){
                uint32_t off = base + swz((a_row + mt*16)*128 + (ks&3)*32 + a_colb);
                ldm4(a_ + mt*4, st + off);
            }
            #pragma unroll
            for (int nt = 0; nt < 2; ++nt){
                uint32_t off = base + swz((b_row + nt*16)*128 + (ks&3)*32 + b_colb);
                ldm4(bh + nt*4, st + 2*TILE_B + off);
                ldm4(bl + nt*4, st + 4*TILE_B + off);
            }
            #pragma unroll
            for (int mt = 0; mt < 4; ++mt)
                #pragma unroll
                for (int n8 = 0; n8 < 4; ++n8){
                    float* c4 = acc + (mt*4 + n8)*4;
                    int bi = (n8 >> 1)*4 + (n8 & 1)*2;
                    mma16816(c4, a_ + mt*4, bh[bi], bh[bi+1]);
                    mma16816(c4, a_ + mt*4, bl[bi], bl[bi+1]);
                }
        }
        __syncthreads();
        if (c + 2 < NC) issue(c + 2);
    }
    if (tid == 0){ mbar_inval(sb); mbar_inval(sb+8); }
}

template<class F>
__device__ __forceinline__ void epi_loop(const float* acc, F f){
    int lane = threadIdx.x & 31, wid = threadIdx.x >> 5;
    int warp_m = (wid >> 2) * 64, warp_n = (wid & 3) * 32;
    int g = lane >> 2, tg = (lane & 3) * 2;
    #pragma unroll
    for (int mt = 0; mt < 4; ++mt)
        #pragma unroll
        for (int n8 = 0; n8 < 4; ++n8){
            const float* c4 = acc + (mt*4 + n8)*4;
            #pragma unroll
            for (int hh = 0; hh < 2; ++hh){
                int r  = warp_m + mt*16 + g + hh*8;
                int cc = warp_n + n8*8 + tg;
                f(r, cc, c4[hh*2], c4[hh*2+1]);
            }
        }
}

// ================= GEMM kernels ============================================
__global__ void __launch_bounds__(256) qkv_tc(
    const __grid_constant__ CUtensorMap mXf,
    const __grid_constant__ CUtensorMap mWqh, const __grid_constant__ CUtensorMap mWql,
    const __grid_constant__ CUtensorMap mWkh, const __grid_constant__ CUtensorMap mWkl,
    const __grid_constant__ CUtensorMap mWvh, const __grid_constant__ CUtensorMap mWvl)
{
    int z = blockIdx.z;
    int row0 = blockIdx.y*128, col0 = blockIdx.x*128;
    const CUtensorMap *pbh, *pbl;
    if (z == 0){ pbh = &mWqh; pbl = &mWql; }
    else if (z == 1){ pbh = &mWkh; pbl = &mWkl; }
    else { pbh = &mWvh; pbl = &mWvl; }
    float acc[64];
    gemm_main(&mXf, pbh, pbl, 0, row0, 0, col0, HID, acc);

    epi_loop(acc, [&](int r, int cc, float v0, float v1){
        int gr = row0 + r;
        size_t idx = (size_t)gr*HID + col0 + cc;
        if (z == 0){
            *(uint32_t*)(g_Qf + idx) = packh2(v0, v1);
        } else if (z == 1){
            f16 h0,l0,h1,l1; split2(v0,h0,l0); split2(v1,h1,l1);
            __half2 hv; hv.x=h0; hv.y=h1;
            __half2 lv; lv.x=l0; lv.y=l1;
            *(__half2*)(g_Kh + idx) = hv;
            *(__half2*)(g_Kl + idx) = lv;
        } else {
            float2 fv; fv.x = v0; fv.y = v1;
            *(float2*)(g_V + idx) = fv;
            int b = gr >> 10, s = gr & (Ss-1);
            int h = col0 >> 7, d = cc;
            size_t ti = (((size_t)(b*NH + h))*Dd + d)*Ss + s;
            g_Vth[ti]      = __float2half(v0);
            g_Vth[ti + Ss] = __float2half(v1);
        }
    });
}

__global__ void __launch_bounds__(256) wo_tc(
    const __grid_constant__ CUtensorMap mCf,
    const __grid_constant__ CUtensorMap mWh, const __grid_constant__ CUtensorMap mWl,
    float* __restrict__ out)
{
    int row0 = blockIdx.y*128, col0 = blockIdx.x*128;
    float acc[64];
    gemm_main(&mCf, &mWh, &mWl, 0, row0, 0, col0, HID, acc);
    epi_loop(acc, [&](int r, int cc, float v0, float v1){
        float2 fv; fv.x = v0; fv.y = v1;
        *(float2*)(out + (size_t)(row0 + r)*HID + col0 + cc) = fv;
    });
}

// ================= flash attention kernel ==================================
__global__ void __launch_bounds__(256) flash_tc(
    const __grid_constant__ CUtensorMap mQf,
    const __grid_constant__ CUtensorMap mK64h, const __grid_constant__ CUtensorMap mK64l,
    const __grid_constant__ CUtensorMap mVh)
{
    extern __shared__ char smem[];
    uint32_t sb = smem_u32(smem);
    int tid = threadIdx.x, lane = tid & 31, wid = tid >> 5;
    int bh = blockIdx.y, b = bh >> 4, h = bh & 15;
    int row0 = blockIdx.x * 128;

    const uint32_t QF  = sb + 1024;          // two 16KB halves
    const uint32_t ST0 = QF + 32768;
    // stage: KH0(8K) KH1(8K) KL0(8K) KL1(8K) VH(16K) = 48KB

    if (tid == 0){ mbar_init(sb,1); mbar_init(sb+8,1); mbar_init(sb+16,1); mbar_init(sb+24,1); }
    __syncthreads();

    if (tid == 0){
        mbar_expect(sb+24, 32768u);
        tma2d(QF,        &mQf, h*128,    b*Ss+row0, sb+24);
        tma2d(QF+16384,  &mQf, h*128+64, b*Ss+row0, sb+24);
    }
    auto issue = [&](int j){
        if (tid == 0){
            int st3 = j % 3;
            uint32_t mb = sb + 8*st3;
            mbar_expect(mb, (uint32_t)FSTAGE_B);
            uint32_t st = ST0 + st3*FSTAGE_B;
            tma2d(st,         &mK64h, h*128,    b*Ss+j*64, mb);
            tma2d(st+8192,    &mK64h, h*128+64, b*Ss+j*64, mb);
            tma2d(st+16384,   &mK64l, h*128,    b*Ss+j*64, mb);
            tma2d(st+24576,   &mK64l, h*128+64, b*Ss+j*64, mb);
            tma2d(st+32768,   &mVh,   j*64, bh*128, mb);
        }
    };
    issue(0); issue(1); issue(2);

    float O[64];
    #pragma unroll
    for (int i = 0; i < 64; ++i) O[i] = 0.f;
    float m0 = -1e30f, m1 = -1e30f, l0 = 0.f, l1 = 0.f;
    const float qk = 0.08838834764831845f;

    uint32_t a_row = wid*16 + (lane & 15), a_colb = (lane >> 4)*16;
    uint32_t b_rw  = (lane & 7) + ((lane >> 4) << 3);
    uint32_t b_cb  = ((lane >> 3) & 1)*16;

    wait_parity(sb+24, 0);

    for (int j = 0; j < 16; ++j){
        wait_parity(sb + 8*(j % 3), (j / 3) & 1);
        uint32_t st = ST0 + (j % 3)*FSTAGE_B;

        // ---- S = Q K^T (Q plain, K split)
        float s[32];
        #pragma unroll
        for (int i = 0; i < 32; ++i) s[i] = 0.f;
        #pragma unroll
        for (int ks = 0; ks < 8; ++ks){
            uint32_t qf_[4], kh_[16], kl_[16];
            uint32_t offa = (ks>>2)*16384 + swz(a_row*128 + (ks&3)*32 + a_colb);
            ldm4(qf_, QF + offa);
            #pragma unroll
            for (int nt = 0; nt < 4; ++nt){
                uint32_t offb = (ks>>2)*8192 + swz((b_rw + nt*16)*128 + (ks&3)*32 + b_cb);
                ldm4(kh_ + nt*4, st + offb);
                ldm4(kl_ + nt*4, st + 16384 + offb);
            }
            #pragma unroll
            for (int n8 = 0; n8 < 8; ++n8){
                int bi = (n8 >> 1)*4 + (n8 & 1)*2;
                mma16816(s + n8*4, qf_, kh_[bi], kh_[bi+1]);
                mma16816(s + n8*4, qf_, kl_[bi], kl_[bi+1]);
            }
        }

        // ---- online softmax
        float tm0 = -1e30f, tm1 = -1e30f;
        #pragma unroll
        for (int t = 0; t < 8; ++t){
            s[t*4+0] *= qk; s[t*4+1] *= qk; s[t*4+2] *= qk; s[t*4+3] *= qk;
            tm0 = fmaxf(tm0, fmaxf(s[t*4+0], s[t*4+1]));
            tm1 = fmaxf(tm1, fmaxf(s[t*4+2], s[t*4+3]));
        }
        tm0 = fmaxf(tm0, __shfl_xor_sync(0xffffffffu, tm0, 1));
        tm0 = fmaxf(tm0, __shfl_xor_sync(0xffffffffu, tm0, 2));
        tm1 = fmaxf(tm1, __shfl_xor_sync(0xffffffffu, tm1, 1));
        tm1 = fmaxf(tm1, __shfl_xor_sync(0xffffffffu, tm1, 2));
        float nm0 = fmaxf(m0, tm0), nm1 = fmaxf(m1, tm1);
        float al0 = expf(m0 - nm0), al1 = expf(m1 - nm1);
        float ts0 = 0.f, ts1 = 0.f;
        #pragma unroll
        for (int t = 0; t < 8; ++t){
            s[t*4+0] = expf(s[t*4+0] - nm0); s[t*4+1] = expf(s[t*4+1] - nm0);
            s[t*4+2] = expf(s[t*4+2] - nm1); s[t*4+3] = expf(s[t*4+3] - nm1);
            ts0 += s[t*4+0] + s[t*4+1];
            ts1 += s[t*4+2] + s[t*4+3];
        }
        ts0 += __shfl_xor_sync(0xffffffffu, ts0, 1);
        ts0 += __shfl_xor_sync(0xffffffffu, ts0, 2);
        ts1 += __shfl_xor_sync(0xffffffffu, ts1, 1);
        ts1 += __shfl_xor_sync(0xffffffffu, ts1, 2);
        l0 = l0*al0 + ts0;  l1 = l1*al1 + ts1;
        m0 = nm0;  m1 = nm1;
        #pragma unroll
        for (int t = 0; t < 16; ++t){
            O[t*4+0] *= al0; O[t*4+1] *= al0; O[t*4+2] *= al1; O[t*4+3] *= al1;
        }

        // ---- pack P (plain fp16) into A fragments
        uint32_t ph_[16];
        #pragma unroll
        for (int t = 0; t < 4; ++t){
            ph_[t*4+0] = packh2(s[(2*t)*4+0],   s[(2*t)*4+1]);
            ph_[t*4+1] = packh2(s[(2*t)*4+2],   s[(2*t)*4+3]);
            ph_[t*4+2] = packh2(s[(2*t+1)*4+0], s[(2*t+1)*4+1]);
            ph_[t*4+3] = packh2(s[(2*t+1)*4+2], s[(2*t+1)*4+3]);
        }

        // ---- O += P V (both plain)
        #pragma unroll
        for (int ks = 0; ks < 4; ++ks){
            uint32_t vh_[32];
            #pragma unroll
            for (int nt = 0; nt < 8; ++nt){
                uint32_t offv = swz((b_rw + nt*16)*128 + ks*32 + b_cb);
                ldm4(vh_ + nt*4, st + 32768 + offv);
            }
            #pragma unroll
            for (int n8 = 0; n8 < 16; ++n8){
                int bi = (n8 >> 1)*4 + (n8 & 1)*2;
                mma16816(O + n8*4, ph_ + ks*4, vh_[bi], vh_[bi+1]);
            }
        }
        __syncthreads();
        if (j + 3 < 16) issue(j + 3);
    }

    // ---- epilogue: normalize, fuse GSA blend, write Cf (plain fp16)
    float inv0 = 1.f / l0, inv1 = 1.f / l1;
    float blend = g_blend, ob = 1.f - blend;
    int g = lane >> 2, tg2 = (lane & 3)*2;
    int s0g = row0 + wid*16 + g, s1g = s0g + 8;

    float c0[8], c1[8];
    float den0 = 1e-8f, den1 = 1e-8f;
    #pragma unroll
    for (int n = 0; n < 8; ++n){
        float a = g_amp[h*8 + n], kss = g_ksum[bh*8 + n];
        c0[n] = g_qa[((size_t)bh*Ss + s0g)*8 + n] * a;  den0 += c0[n]*kss;
        c1[n] = g_qa[((size_t)bh*Ss + s1g)*8 + n] * a;  den1 += c1[n]*kss;
    }
    float id0 = blend/den0, id1 = blend/den1;

    size_t base0 = ((size_t)(b*Ss + s0g))*HID + h*128;
    size_t base1 = ((size_t)(b*Ss + s1g))*HID + h*128;
    #pragma unroll
    for (int n8 = 0; n8 < 16; ++n8){
        int d = n8*8 + tg2;
        float num00=0.f, num01=0.f, num10=0.f, num11=0.f;
        #pragma unroll
        for (int n = 0; n < 8; ++n){
            float2 kv = *(const float2*)(g_kvmat + ((size_t)bh*8 + n)*128 + d);
            num00 += c0[n]*kv.x;  num01 += c0[n]*kv.y;
            num10 += c1[n]*kv.x;  num11 += c1[n]*kv.y;
        }
        float v00 = ob*O[n8*4+0]*inv0 + id0*num00;
        float v01 = ob*O[n8*4+1]*inv0 + id0*num01;
        float v10 = ob*O[n8*4+2]*inv1 + id1*num10;
        float v11 = ob*O[n8*4+3]*inv1 + id1*num11;
        *(uint32_t*)(g_Cf + base0 + d) = packh2(v00, v01);
        *(uint32_t*)(g_Cf + base1 + d) = packh2(v10, v11);
    }
    __syncthreads();
    if (tid == 0){ mbar_inval(sb); mbar_inval(sb+8); mbar_inval(sb+16); mbar_inval(sb+24); }
}

// ================= conversion kernels ======================================
__global__ void convert_x_kernel(const float* __restrict__ X){
    int i = (blockIdx.x*256 + threadIdx.x) * 4;
    float4 v = *(const float4*)(X + i);
    *(uint32_t*)(g_Xf + i)     = packh2(v.x, v.y);
    *(uint32_t*)(g_Xf + i + 2) = packh2(v.z, v.w);
}

__global__ void tsplit_kernel(const float* __restrict__ Wq, const float* __restrict__ Wk,
                              const float* __restrict__ Wv, const float* __restrict__ Wo){
    __shared__ float t[32][33];
    int z = blockIdx.z;
    const float* in = (z == 0) ? Wq : (z == 1) ? Wk : (z == 2) ? Wv : Wo;
    f16* oh = (z == 0) ? g_Wqt_h : (z == 1) ? g_Wkt_h : (z == 2) ? g_Wvt_h : g_Wot_h;
    f16* ol = (z == 0) ? g_Wqt_l : (z == 1) ? g_Wkt_l : (z == 2) ? g_Wvt_l : g_Wot_l;
    int n0 = blockIdx.x*32, k0 = blockIdx.y*32;
    int tx = threadIdx.x, ty = threadIdx.y;
    #pragma unroll
    for (int j = 0; j < 4; ++j)
        t[ty + 8*j][tx] = in[(size_t)(k0 + ty + 8*j)*HID + n0 + tx];
    __syncthreads();
    #pragma unroll
    for (int j = 0; j < 4; ++j){
        float v = t[tx][ty + 8*j];
        size_t o = (size_t)(n0 + ty + 8*j)*HID + k0 + tx;
        split2(v, oh[o], ol[o]);
    }
}

// ---------------- prep ------------------------------------------------------
__global__ void prep_kernel(const float* __restrict__ pos_in,
                            const float* __restrict__ dir_in,
                            const float* __restrict__ ls_in,
                            const float* __restrict__ la_in,
                            const float* __restrict__ dstr,
                            const float* __restrict__ gstr)
{
    int i = threadIdx.x;
    if (i < NH*NS) {
        const float* p = pos_in + (size_t)i*Dd;
        const float* dv = dir_in + (size_t)i*Dd;
        float np = 0.f, nd = 0.f;
        for (int d = 0; d < Dd; ++d) { np += p[d]*p[d]; nd += dv[d]*dv[d]; }
        float pscale = 3.39411254969543f / (sqrtf(np) + 1e-12f);
        float dscale = 1.0f / (sqrtf(nd) + 1e-12f);
        float psq = 0.f, pdd = 0.f;
        for (int d = 0; d < Dd; ++d) {
            float ps = p[d]*pscale, du = dv[d]*dscale;
            g_pos[(size_t)i*Dd + d] = ps;
            g_dir[(size_t)i*Dd + d] = du;
            psq += ps*ps;  pdd += ps*du;
        }
        g_possq[i] = psq;  g_pdd[i] = pdd;
        float sc = expf(ls_in[i]);
        sc = fminf(fmaxf(sc, 0.3f), 1.2f);
        g_inv2s2[i] = 0.5f / (sc*sc);
    }
    __syncthreads();
    if (i < NH) {
        float m = -1e30f;
        for (int n = 0; n < NS; ++n) m = fmaxf(m, la_in[i*NS+n]);
        float s = 0.f, e[NS];
        for (int n = 0; n < NS; ++n) { e[n] = expf(la_in[i*NS+n]-m); s += e[n]; }
        for (int n = 0; n < NS; ++n) g_amp[i*NS+n] = e[n]/s;
    }
    if (i == 0) {
        g_ds = 1.0f / (1.0f + expf(-dstr[0]));
        float gsa = 1.0f / (1.0f + expf(-gstr[0]));
        g_blend = fminf(0.05f, gsa*0.1f);
    }
}

// ---------------- affinities (warp per token) -------------------------------
__global__ void __launch_bounds__(256) affinity2()
{
    int gidx = blockIdx.x*8 + (threadIdx.x >> 5);   // 0..65535
    int lane = threadIdx.x & 31;
    int z = gidx >> 15;
    int rem = gidx & 32767;
    int bh = rem >> 10, s = rem & 1023;
    int b = bh >> 4, h = bh & 15;
    size_t base = ((size_t)(b*Ss + s))*HID + h*128;
    float t[4];
    #pragma unroll
    for (int k = 0; k < 4; ++k){
        int d = k*32 + lane;
        t[k] = z ? (__half2float(g_Kh[base+d]) + __half2float(g_Kl[base+d]))
                 : __half2float(g_Qf[base+d]);
    }
    float tsq = wsum(t[0]*t[0] + t[1]*t[1] + t[2]*t[2] + t[3]*t[3]);
    float ds = g_ds;
    float* out = (z ? g_ka : g_qa) + ((size_t)bh*Ss + s)*NS;
    #pragma unroll
    for (int n = 0; n < NS; ++n){
        int hn = h*NS + n;
        float tp = 0.f, td = 0.f;
        #pragma unroll
        for (int k = 0; k < 4; ++k){
            int d = k*32 + lane;
            tp += t[k]*g_pos[hn*Dd + d];
            td += t[k]*g_dir[hn*Dd + d];
        }
        tp = wsum(tp);  td = wsum(td);
        if (lane == n){
            float dist2 = fmaxf(tsq - 2.0f*tp + g_possq[hn], 0.0f);
            float proj  = td - g_pdd[hn];
            float perp2 = fmaxf(dist2 - proj*proj, 0.0f);
            float inv   = g_inv2s2[hn];
            out[n] = (1.0f-ds)*expf(-dist2*inv) + ds*expf(-perp2*inv);
        }
    }
}

// ---------------- GSA linear-attention precompute (2-phase) ----------------
__global__ void gsa_kv_part()
{
    int ch = blockIdx.x, bh = blockIdx.y;
    int b = bh >> 4, h = bh & 15;
    int d = threadIdx.x;
    const float* vb = g_V + (size_t)b*Ss*HID + h*Dd;
    const float* ka = g_ka + (size_t)bh*Ss*NS;
    float acc[NS];
    #pragma unroll
    for (int n = 0; n < NS; ++n) acc[n] = 0.f;
    int s0 = ch*128;
    for (int s = s0; s < s0+128; ++s){
        float vv = vb[(size_t)s*HID + d];
        #pragma unroll
        for (int n = 0; n < NS; ++n) acc[n] += ka[s*NS+n]*vv;
    }
    #pragma unroll
    for (int n = 0; n < NS; ++n)
        g_kvp[(((size_t)ch*BH + bh)*NS + n)*Dd + d] = acc[n];
    if (d < NS){
        float kssum = 0.f;
        for (int s = s0; s < s0+128; ++s) kssum += ka[s*NS+d];
        g_ksp[(ch*BH + bh)*NS + d] = kssum;
    }
}

__global__ void gsa_red()
{
    int bh = blockIdx.x, d = threadIdx.x;
    #pragma unroll
    for (int n = 0; n < NS; ++n){
        float t = 0.f;
        #pragma unroll
        for (int ch = 0; ch < 8; ++ch)
            t += g_kvp[(((size_t)ch*BH + bh)*NS + n)*Dd + d];
        g_kvmat[((size_t)bh*NS + n)*Dd + d] = t;
    }
    if (d < NS){
        float t = 0.f;
        #pragma unroll
        for (int ch = 0; ch < 8; ++ch) t += g_ksp[(ch*BH + bh)*NS + d];
        g_ksum[bh*NS + d] = t;
    }
}

// ---------------- host: tensormap construction -----------------------------
typedef CUresult (*TMapEncode)(CUtensorMap*, CUtensorMapDataType, cuuint32_t, void*,
    const cuuint64_t*, const cuuint64_t*, const cuuint32_t*, const cuuint32_t*,
    CUtensorMapInterleave, CUtensorMapSwizzle, CUtensorMapL2promotion, CUtensorMapFloatOOBfill);

static void make_map(TMapEncode enc, CUtensorMap* m, void* base, uint64_t d0, uint64_t d1,
                     uint32_t b0, uint32_t b1){
    cuuint64_t dims[2]    = {d0, d1};
    cuuint64_t strides[1] = {d0 * 2};
    cuuint32_t box[2]     = {b0, b1};
    cuuint32_t es[2]      = {1, 1};
    enc(m, CU_TENSOR_MAP_DATA_TYPE_FLOAT16, 2, base, dims, strides, box, es,
        CU_TENSOR_MAP_INTERLEAVE_NONE, CU_TENSOR_MAP_SWIZZLE_128B,
        CU_TENSOR_MAP_L2_PROMOTION_L2_128B, CU_TENSOR_MAP_FLOAT_OOB_FILL_NONE);
}

// ---------------- launch ----------------------------------------------------
extern "C" void kernel_launch(void* const* d_in, const int* in_sizes, int n_in,
                              void* d_out, int out_size)
{
    const float* X   = (const float*)d_in[0];
    const float* Wq  = (const float*)d_in[1];
    const float* Wk  = (const float*)d_in[2];
    const float* Wv  = (const float*)d_in[3];
    const float* Wo  = (const float*)d_in[4];
    const float* pos = (const float*)d_in[5];
    const float* dir = (const float*)d_in[6];
    const float* ls  = (const float*)d_in[7];
    const float* la  = (const float*)d_in[8];
    const float* dstr= (const float*)d_in[9];
    const float* gstr= (const float*)d_in[10];
    float* out = (float*)d_out;

    void* fp = nullptr;
    cudaDriverEntryPointQueryResult qr;
#if CUDART_VERSION >= 12050
    cudaGetDriverEntryPointByVersion("cuTensorMapEncodeTiled", &fp, 12000, cudaEnableDefault, &qr);
#else
    cudaGetDriverEntryPoint("cuTensorMapEncodeTiled", &fp, cudaEnableDefault, &qr);
#endif
    TMapEncode enc = (TMapEncode)fp;

    void *pXf,*pWqh,*pWql,*pWkh,*pWkl,*pWvh,*pWvl,*pWoh,*pWol;
    void *pQf,*pKh,*pKl,*pVh,*pCf;
    cudaGetSymbolAddress(&pXf, g_Xf);
    cudaGetSymbolAddress(&pWqh, g_Wqt_h); cudaGetSymbolAddress(&pWql, g_Wqt_l);
    cudaGetSymbolAddress(&pWkh, g_Wkt_h); cudaGetSymbolAddress(&pWkl, g_Wkt_l);
    cudaGetSymbolAddress(&pWvh, g_Wvt_h); cudaGetSymbolAddress(&pWvl, g_Wvt_l);
    cudaGetSymbolAddress(&pWoh, g_Wot_h); cudaGetSymbolAddress(&pWol, g_Wot_l);
    cudaGetSymbolAddress(&pQf, g_Qf);
    cudaGetSymbolAddress(&pKh, g_Kh);   cudaGetSymbolAddress(&pKl, g_Kl);
    cudaGetSymbolAddress(&pVh, g_Vth);
    cudaGetSymbolAddress(&pCf, g_Cf);

    CUtensorMap mXf,mWqh,mWql,mWkh,mWkl,mWvh,mWvl,mWoh,mWol;
    CUtensorMap mQf,mK64h,mK64l,mVh,mCf;
    make_map(enc,&mXf,pXf,HID,Mm,64,128);
    make_map(enc,&mWqh,pWqh,HID,HID,64,128);  make_map(enc,&mWql,pWql,HID,HID,64,128);
    make_map(enc,&mWkh,pWkh,HID,HID,64,128);  make_map(enc,&mWkl,pWkl,HID,HID,64,128);
    make_map(enc,&mWvh,pWvh,HID,HID,64,128);  make_map(enc,&mWvl,pWvl,HID,HID,64,128);
    make_map(enc,&mWoh,pWoh,HID,HID,64,128);  make_map(enc,&mWol,pWol,HID,HID,64,128);
    make_map(enc,&mQf,pQf,HID,Mm,64,128);
    make_map(enc,&mK64h,pKh,HID,Mm,64,64);    make_map(enc,&mK64l,pKl,HID,Mm,64,64);
    make_map(enc,&mVh,pVh,Ss,(uint64_t)BH*Dd,64,128);
    make_map(enc,&mCf,pCf,HID,Mm,64,128);

    cudaFuncSetAttribute(qkv_tc,   cudaFuncAttributeMaxDynamicSharedMemorySize, SMEM_SZ);
    cudaFuncSetAttribute(wo_tc,    cudaFuncAttributeMaxDynamicSharedMemorySize, SMEM_SZ);
    cudaFuncSetAttribute(flash_tc, cudaFuncAttributeMaxDynamicSharedMemorySize, SMEM_FL);

    prep_kernel<<<1, 128>>>(pos, dir, ls, la, dstr, gstr);
    convert_x_kernel<<<(Mm*HID)/1024, 256>>>(X);
    tsplit_kernel<<<dim3(HID/32, HID/32, 4), dim3(32, 8)>>>(Wq, Wk, Wv, Wo);
    qkv_tc<<<dim3(HID/128, Mm/128, 3), 256, SMEM_SZ>>>(mXf,mWqh,mWql,mWkh,mWkl,mWvh,mWvl);
    affinity2<<<(Ss*BH*2)/8, 256>>>();
    gsa_kv_part<<<dim3(8, BH), 128>>>();
    gsa_red<<<BH, 128>>>();
    flash_tc<<<dim3(Ss/128, BH), 256, SMEM_FL>>>(mQf,mK64h,mK64l,mVh);
    wo_tc<<<dim3(HID/128, Mm/128, 1), 256, SMEM_SZ>>>(mCf,mWoh,mWol,out);
}

// round 10
// speedup vs baseline: 4.8416x; 1.0282x over previous
#include <cuda_runtime.h>
#include <cuda.h>
#include <cuda_fp16.h>
#include <math.h>
#include <stdint.h>

#define Bb 2
#define Ss 1024
#define HID 2048
#define NH 16
#define NS 8
#define Dd 128
#define Mm (Bb*Ss)      // 2048
#define BH (Bb*NH)      // 32

typedef __half f16;

// ---------------- scratch (device globals; no allocation allowed) ----------
__device__ float g_V[(size_t)Mm*HID];
__device__ float g_qa[(size_t)BH*Ss*NS];
__device__ float g_ka[(size_t)BH*Ss*NS];
__device__ float g_kvmat[(size_t)BH*NS*Dd];
__device__ float g_ksum[BH*NS];
__device__ float g_kvp[(size_t)8*BH*NS*Dd];
__device__ float g_ksp[8*BH*NS];
__device__ float g_pos[NH*NS*Dd];
__device__ float g_dir[NH*NS*Dd];
__device__ float g_possq[NH*NS];
__device__ float g_pdd[NH*NS];
__device__ float g_inv2s2[NH*NS];
__device__ float g_amp[NH*NS];
__device__ float g_ds;
__device__ float g_blend;

// fp16 operand arrays: A-side plain, B-side split hi/lo (V plain)
__device__ f16 g_Xf[(size_t)Mm*HID];
__device__ f16 g_Wqt_h[(size_t)HID*HID], g_Wqt_l[(size_t)HID*HID];
__device__ f16 g_Wkt_h[(size_t)HID*HID], g_Wkt_l[(size_t)HID*HID];
__device__ f16 g_Wvt_h[(size_t)HID*HID], g_Wvt_l[(size_t)HID*HID];
__device__ f16 g_Wot_h[(size_t)HID*HID], g_Wot_l[(size_t)HID*HID];
__device__ f16 g_Qf[(size_t)Mm*HID];
__device__ f16 g_Kh[(size_t)Mm*HID], g_Kl[(size_t)Mm*HID];
__device__ f16 g_Vth[(size_t)BH*Dd*Ss];            // [bh][d][s], plain
__device__ f16 g_Cf[(size_t)Mm*HID];

__device__ __forceinline__ void split2(float v, f16& h, f16& l){
    h = __float2half(v);
    l = __float2half(v - __half2float(h));
}
__device__ __forceinline__ uint32_t packh2(float x, float y){
    __half2 t = __floats2half2_rn(x, y);
    return *(uint32_t*)&t;
}

// ================= low-level helpers =======================================
__device__ __forceinline__ uint32_t smem_u32(const void* p){
    uint32_t a;
    asm("{ .reg .u64 t; cvta.to.shared.u64 t, %1; cvt.u32.u64 %0, t; }" : "=r"(a) : "l"(p));
    return a;
}
__device__ __forceinline__ void mbar_init(uint32_t a, uint32_t cnt){
    asm volatile("mbarrier.init.shared.b64 [%0], %1;" :: "r"(a), "r"(cnt) : "memory");
}
__device__ __forceinline__ void mbar_inval(uint32_t a){
    asm volatile("mbarrier.inval.shared.b64 [%0];" :: "r"(a) : "memory");
}
__device__ __forceinline__ void mbar_expect(uint32_t a, uint32_t bytes){
    asm volatile("mbarrier.arrive.expect_tx.shared.b64 _, [%0], %1;" :: "r"(a), "r"(bytes) : "memory");
}
__device__ __forceinline__ void wait_parity(uint32_t mbar, uint32_t ph){
    uint32_t done;
    asm volatile(
        "{\n\t.reg .pred p;\n\t"
        "mbarrier.try_wait.parity.acquire.cta.shared::cta.b64 p, [%1], %2;\n\t"
        "selp.b32 %0, 1, 0, p;\n\t}"
        : "=r"(done) : "r"(mbar), "r"(ph) : "memory");
    if (!done) {
        asm volatile(
            "{\n\t.reg .pred P1;\n\t"
            "WL%=:\n\t"
            "mbarrier.try_wait.parity.acquire.cta.shared::cta.b64 P1, [%0], %1, 0x989680;\n\t"
            "@P1 bra.uni WD%=;\n\t"
            "bra.uni WL%=;\n\t"
            "WD%=:\n\t}"
            :: "r"(mbar), "r"(ph) : "memory");
    }
}
__device__ __forceinline__ void tma2d(uint32_t dst, const CUtensorMap* m, int x, int y, uint32_t mbar){
    asm volatile(
        "cp.async.bulk.tensor.2d.shared::cta.global.tile.mbarrier::complete_tx::bytes "
        "[%0], [%1, {%2, %3}], [%4];"
        :: "r"(dst), "l"(m), "r"(x), "r"(y), "r"(mbar) : "memory");
}
__device__ __forceinline__ void ldm4(uint32_t* r, uint32_t a){
    asm volatile("ldmatrix.sync.aligned.m8n8.x4.shared.b16 {%0,%1,%2,%3}, [%4];"
        : "=r"(r[0]),"=r"(r[1]),"=r"(r[2]),"=r"(r[3]) : "r"(a));
}
__device__ __forceinline__ void mma16816(float* c, const uint32_t* a, uint32_t b0, uint32_t b1){
    asm volatile("mma.sync.aligned.m16n8k16.row.col.f32.f16.f16.f32 "
        "{%0,%1,%2,%3}, {%4,%5,%6,%7}, {%8,%9}, {%0,%1,%2,%3};"
        : "+f"(c[0]),"+f"(c[1]),"+f"(c[2]),"+f"(c[3])
        : "r"(a[0]),"r"(a[1]),"r"(a[2]),"r"(a[3]), "r"(b0),"r"(b1));
}
__device__ __forceinline__ uint32_t swz(uint32_t x){ return x ^ ((x>>3)&0x70); }
__device__ __forceinline__ float wsum(float v){
    #pragma unroll
    for (int o = 16; o; o >>= 1) v += __shfl_xor_sync(0xffffffffu, v, o);
    return v;
}

#define TILE_B    16384
#define GSTAGE_B  49152                          // A(16K) Bh(16K) Bl(16K)
#define SMEM_SZ   (1024 + 2*GSTAGE_B)            // 2-stage, 64-K per stage -> 2 CTAs/SM
#define FSTAGE_B  49152                          // Kh(16K) Kl(16K) Vh(16K)
#define SMEM_FL   (1024 + 32768 + 3*FSTAGE_B)    // Q(32K) + 3 stages

// ---------------- 128x128 CTA GEMM mainloop (256 threads, 8 warps) ---------
// C[128,128] += A[128,K] * (Bh+Bl)[128,K]^T, 64-K columns per stage
__device__ __forceinline__ void gemm_main(
    const CUtensorMap* mA,
    const CUtensorMap* mBh, const CUtensorMap* mBl,
    int ax0, int ay, int bx0, int by, int K, float* acc)
{
    extern __shared__ char smem[];
    uint32_t sb = smem_u32(smem);
    int tid = threadIdx.x, lane = tid & 31, wid = tid >> 5;
    int warp_m = (wid >> 2) * 64, warp_n = (wid & 3) * 32;

    if (tid == 0){ mbar_init(sb,1); mbar_init(sb+8,1); }
    __syncthreads();

    #pragma unroll
    for (int i = 0; i < 64; ++i) acc[i] = 0.f;

    int NC = K / 64;

    auto issue = [&](int c){
        if (tid == 0){
            int st = c & 1;
            uint32_t mb = sb + 8*st;
            mbar_expect(mb, (uint32_t)GSTAGE_B);
            uint32_t dst = sb + 1024 + st*GSTAGE_B;
            tma2d(dst,            mA,  ax0 + c*64, ay, mb);
            tma2d(dst +   TILE_B, mBh, bx0 + c*64, by, mb);
            tma2d(dst + 2*TILE_B, mBl, bx0 + c*64, by, mb);
        }
    };
    issue(0);
    if (NC > 1) issue(1);

    uint32_t a_row  = warp_m + (lane & 15);
    uint32_t a_colb = (lane >> 4) * 16;
    uint32_t b_row  = warp_n + (lane & 7) + ((lane >> 4) << 3);
    uint32_t b_colb = ((lane >> 3) & 1) * 16;

    for (int c = 0; c < NC; ++c){
        wait_parity(sb + 8*(c & 1), (c >> 1) & 1);
        uint32_t st = sb + 1024 + (c & 1)*GSTAGE_B;
        #pragma unroll
        for (int ks = 0; ks < 4; ++ks){
            uint32_t a_[16], bh[8], bl[8];
            #pragma unroll
            for (int mt = 0; mt < 4; ++mt){
                uint32_t off = swz((a_row + mt*16)*128 + ks*32 + a_colb);
                ldm4(a_ + mt*4, st + off);
            }
            #pragma unroll
            for (int nt = 0; nt < 2; ++nt){
                uint32_t off = swz((b_row + nt*16)*128 + ks*32 + b_colb);
                ldm4(bh + nt*4, st + TILE_B + off);
                ldm4(bl + nt*4, st + 2*TILE_B + off);
            }
            #pragma unroll
            for (int mt = 0; mt < 4; ++mt)
                #pragma unroll
                for (int n8 = 0; n8 < 4; ++n8){
                    float* c4 = acc + (mt*4 + n8)*4;
                    int bi = (n8 >> 1)*4 + (n8 & 1)*2;
                    mma16816(c4, a_ + mt*4, bh[bi], bh[bi+1]);
                    mma16816(c4, a_ + mt*4, bl[bi], bl[bi+1]);
                }
        }
        __syncthreads();
        if (c + 2 < NC) issue(c + 2);
    }
    if (tid == 0){ mbar_inval(sb); mbar_inval(sb+8); }
}

template<class F>
__device__ __forceinline__ void epi_loop(const float* acc, F f){
    int lane = threadIdx.x & 31, wid = threadIdx.x >> 5;
    int warp_m = (wid >> 2) * 64, warp_n = (wid & 3) * 32;
    int g = lane >> 2, tg = (lane & 3) * 2;
    #pragma unroll
    for (int mt = 0; mt < 4; ++mt)
        #pragma unroll
        for (int n8 = 0; n8 < 4; ++n8){
            const float* c4 = acc + (mt*4 + n8)*4;
            #pragma unroll
            for (int hh = 0; hh < 2; ++hh){
                int r  = warp_m + mt*16 + g + hh*8;
                int cc = warp_n + n8*8 + tg;
                f(r, cc, c4[hh*2], c4[hh*2+1]);
            }
        }
}

// ================= GEMM kernels ============================================
__global__ void __launch_bounds__(256, 2) qkv_tc(
    const __grid_constant__ CUtensorMap mXf,
    const __grid_constant__ CUtensorMap mWqh, const __grid_constant__ CUtensorMap mWql,
    const __grid_constant__ CUtensorMap mWkh, const __grid_constant__ CUtensorMap mWkl,
    const __grid_constant__ CUtensorMap mWvh, const __grid_constant__ CUtensorMap mWvl)
{
    int z = blockIdx.z;
    int row0 = blockIdx.y*128, col0 = blockIdx.x*128;
    const CUtensorMap *pbh, *pbl;
    if (z == 0){ pbh = &mWqh; pbl = &mWql; }
    else if (z == 1){ pbh = &mWkh; pbl = &mWkl; }
    else { pbh = &mWvh; pbl = &mWvl; }
    float acc[64];
    gemm_main(&mXf, pbh, pbl, 0, row0, 0, col0, HID, acc);

    epi_loop(acc, [&](int r, int cc, float v0, float v1){
        int gr = row0 + r;
        size_t idx = (size_t)gr*HID + col0 + cc;
        if (z == 0){
            *(uint32_t*)(g_Qf + idx) = packh2(v0, v1);
        } else if (z == 1){
            f16 h0,l0,h1,l1; split2(v0,h0,l0); split2(v1,h1,l1);
            __half2 hv; hv.x=h0; hv.y=h1;
            __half2 lv; lv.x=l0; lv.y=l1;
            *(__half2*)(g_Kh + idx) = hv;
            *(__half2*)(g_Kl + idx) = lv;
        } else {
            float2 fv; fv.x = v0; fv.y = v1;
            *(float2*)(g_V + idx) = fv;
            int b = gr >> 10, s = gr & (Ss-1);
            int h = col0 >> 7, d = cc;
            size_t ti = (((size_t)(b*NH + h))*Dd + d)*Ss + s;
            g_Vth[ti]      = __float2half(v0);
            g_Vth[ti + Ss] = __float2half(v1);
        }
    });
}

__global__ void __launch_bounds__(256, 2) wo_tc(
    const __grid_constant__ CUtensorMap mCf,
    const __grid_constant__ CUtensorMap mWh, const __grid_constant__ CUtensorMap mWl,
    float* __restrict__ out)
{
    int row0 = blockIdx.y*128, col0 = blockIdx.x*128;
    float acc[64];
    gemm_main(&mCf, &mWh, &mWl, 0, row0, 0, col0, HID, acc);
    epi_loop(acc, [&](int r, int cc, float v0, float v1){
        float2 fv; fv.x = v0; fv.y = v1;
        *(float2*)(out + (size_t)(row0 + r)*HID + col0 + cc) = fv;
    });
}

// ================= flash attention kernel ==================================
__global__ void __launch_bounds__(256) flash_tc(
    const __grid_constant__ CUtensorMap mQf,
    const __grid_constant__ CUtensorMap mK64h, const __grid_constant__ CUtensorMap mK64l,
    const __grid_constant__ CUtensorMap mVh)
{
    extern __shared__ char smem[];
    uint32_t sb = smem_u32(smem);
    int tid = threadIdx.x, lane = tid & 31, wid = tid >> 5;
    int bh = blockIdx.y, b = bh >> 4, h = bh & 15;
    int row0 = blockIdx.x * 128;

    const uint32_t QF  = sb + 1024;          // two 16KB halves
    const uint32_t ST0 = QF + 32768;
    // stage: KH0(8K) KH1(8K) KL0(8K) KL1(8K) VH(16K) = 48KB

    if (tid == 0){ mbar_init(sb,1); mbar_init(sb+8,1); mbar_init(sb+16,1); mbar_init(sb+24,1); }
    __syncthreads();

    if (tid == 0){
        mbar_expect(sb+24, 32768u);
        tma2d(QF,        &mQf, h*128,    b*Ss+row0, sb+24);
        tma2d(QF+16384,  &mQf, h*128+64, b*Ss+row0, sb+24);
    }
    auto issue = [&](int j){
        if (tid == 0){
            int st3 = j % 3;
            uint32_t mb = sb + 8*st3;
            mbar_expect(mb, (uint32_t)FSTAGE_B);
            uint32_t st = ST0 + st3*FSTAGE_B;
            tma2d(st,         &mK64h, h*128,    b*Ss+j*64, mb);
            tma2d(st+8192,    &mK64h, h*128+64, b*Ss+j*64, mb);
            tma2d(st+16384,   &mK64l, h*128,    b*Ss+j*64, mb);
            tma2d(st+24576,   &mK64l, h*128+64, b*Ss+j*64, mb);
            tma2d(st+32768,   &mVh,   j*64, bh*128, mb);
        }
    };
    issue(0); issue(1); issue(2);

    float O[64];
    #pragma unroll
    for (int i = 0; i < 64; ++i) O[i] = 0.f;
    float m0 = -1e30f, m1 = -1e30f, l0 = 0.f, l1 = 0.f;
    const float qk = 0.08838834764831845f;

    uint32_t a_row = wid*16 + (lane & 15), a_colb = (lane >> 4)*16;
    uint32_t b_rw  = (lane & 7) + ((lane >> 4) << 3);
    uint32_t b_cb  = ((lane >> 3) & 1)*16;

    wait_parity(sb+24, 0);

    for (int j = 0; j < 16; ++j){
        wait_parity(sb + 8*(j % 3), (j / 3) & 1);
        uint32_t st = ST0 + (j % 3)*FSTAGE_B;

        // ---- S = Q K^T (Q plain, K split)
        float s[32];
        #pragma unroll
        for (int i = 0; i < 32; ++i) s[i] = 0.f;
        #pragma unroll
        for (int ks = 0; ks < 8; ++ks){
            uint32_t qf_[4], kh_[16], kl_[16];
            uint32_t offa = (ks>>2)*16384 + swz(a_row*128 + (ks&3)*32 + a_colb);
            ldm4(qf_, QF + offa);
            #pragma unroll
            for (int nt = 0; nt < 4; ++nt){
                uint32_t offb = (ks>>2)*8192 + swz((b_rw + nt*16)*128 + (ks&3)*32 + b_cb);
                ldm4(kh_ + nt*4, st + offb);
                ldm4(kl_ + nt*4, st + 16384 + offb);
            }
            #pragma unroll
            for (int n8 = 0; n8 < 8; ++n8){
                int bi = (n8 >> 1)*4 + (n8 & 1)*2;
                mma16816(s + n8*4, qf_, kh_[bi], kh_[bi+1]);
                mma16816(s + n8*4, qf_, kl_[bi], kl_[bi+1]);
            }
        }

        // ---- online softmax
        float tm0 = -1e30f, tm1 = -1e30f;
        #pragma unroll
        for (int t = 0; t < 8; ++t){
            s[t*4+0] *= qk; s[t*4+1] *= qk; s[t*4+2] *= qk; s[t*4+3] *= qk;
            tm0 = fmaxf(tm0, fmaxf(s[t*4+0], s[t*4+1]));
            tm1 = fmaxf(tm1, fmaxf(s[t*4+2], s[t*4+3]));
        }
        tm0 = fmaxf(tm0, __shfl_xor_sync(0xffffffffu, tm0, 1));
        tm0 = fmaxf(tm0, __shfl_xor_sync(0xffffffffu, tm0, 2));
        tm1 = fmaxf(tm1, __shfl_xor_sync(0xffffffffu, tm1, 1));
        tm1 = fmaxf(tm1, __shfl_xor_sync(0xffffffffu, tm1, 2));
        float nm0 = fmaxf(m0, tm0), nm1 = fmaxf(m1, tm1);
        float al0 = expf(m0 - nm0), al1 = expf(m1 - nm1);
        float ts0 = 0.f, ts1 = 0.f;
        #pragma unroll
        for (int t = 0; t < 8; ++t){
            s[t*4+0] = expf(s[t*4+0] - nm0); s[t*4+1] = expf(s[t*4+1] - nm0);
            s[t*4+2] = expf(s[t*4+2] - nm1); s[t*4+3] = expf(s[t*4+3] - nm1);
            ts0 += s[t*4+0] + s[t*4+1];
            ts1 += s[t*4+2] + s[t*4+3];
        }
        ts0 += __shfl_xor_sync(0xffffffffu, ts0, 1);
        ts0 += __shfl_xor_sync(0xffffffffu, ts0, 2);
        ts1 += __shfl_xor_sync(0xffffffffu, ts1, 1);
        ts1 += __shfl_xor_sync(0xffffffffu, ts1, 2);
        l0 = l0*al0 + ts0;  l1 = l1*al1 + ts1;
        m0 = nm0;  m1 = nm1;
        #pragma unroll
        for (int t = 0; t < 16; ++t){
            O[t*4+0] *= al0; O[t*4+1] *= al0; O[t*4+2] *= al1; O[t*4+3] *= al1;
        }

        // ---- pack P (plain fp16) into A fragments
        uint32_t ph_[16];
        #pragma unroll
        for (int t = 0; t < 4; ++t){
            ph_[t*4+0] = packh2(s[(2*t)*4+0],   s[(2*t)*4+1]);
            ph_[t*4+1] = packh2(s[(2*t)*4+2],   s[(2*t)*4+3]);
            ph_[t*4+2] = packh2(s[(2*t+1)*4+0], s[(2*t+1)*4+1]);
            ph_[t*4+3] = packh2(s[(2*t+1)*4+2], s[(2*t+1)*4+3]);
        }

        // ---- O += P V (both plain)
        #pragma unroll
        for (int ks = 0; ks < 4; ++ks){
            uint32_t vh_[32];
            #pragma unroll
            for (int nt = 0; nt < 8; ++nt){
                uint32_t offv = swz((b_rw + nt*16)*128 + ks*32 + b_cb);
                ldm4(vh_ + nt*4, st + 32768 + offv);
            }
            #pragma unroll
            for (int n8 = 0; n8 < 16; ++n8){
                int bi = (n8 >> 1)*4 + (n8 & 1)*2;
                mma16816(O + n8*4, ph_ + ks*4, vh_[bi], vh_[bi+1]);
            }
        }
        __syncthreads();
        if (j + 3 < 16) issue(j + 3);
    }

    // ---- epilogue: normalize, fuse GSA blend, write Cf (plain fp16)
    float inv0 = 1.f / l0, inv1 = 1.f / l1;
    float blend = g_blend, ob = 1.f - blend;
    int g = lane >> 2, tg2 = (lane & 3)*2;
    int s0g = row0 + wid*16 + g, s1g = s0g + 8;

    float c0[8], c1[8];
    float den0 = 1e-8f, den1 = 1e-8f;
    #pragma unroll
    for (int n = 0; n < 8; ++n){
        float a = g_amp[h*8 + n], kss = g_ksum[bh*8 + n];
        c0[n] = g_qa[((size_t)bh*Ss + s0g)*8 + n] * a;  den0 += c0[n]*kss;
        c1[n] = g_qa[((size_t)bh*Ss + s1g)*8 + n] * a;  den1 += c1[n]*kss;
    }
    float id0 = blend/den0, id1 = blend/den1;

    size_t base0 = ((size_t)(b*Ss + s0g))*HID + h*128;
    size_t base1 = ((size_t)(b*Ss + s1g))*HID + h*128;
    #pragma unroll
    for (int n8 = 0; n8 < 16; ++n8){
        int d = n8*8 + tg2;
        float num00=0.f, num01=0.f, num10=0.f, num11=0.f;
        #pragma unroll
        for (int n = 0; n < 8; ++n){
            float2 kv = *(const float2*)(g_kvmat + ((size_t)bh*8 + n)*128 + d);
            num00 += c0[n]*kv.x;  num01 += c0[n]*kv.y;
            num10 += c1[n]*kv.x;  num11 += c1[n]*kv.y;
        }
        float v00 = ob*O[n8*4+0]*inv0 + id0*num00;
        float v01 = ob*O[n8*4+1]*inv0 + id0*num01;
        float v10 = ob*O[n8*4+2]*inv1 + id1*num10;
        float v11 = ob*O[n8*4+3]*inv1 + id1*num11;
        *(uint32_t*)(g_Cf + base0 + d) = packh2(v00, v01);
        *(uint32_t*)(g_Cf + base1 + d) = packh2(v10, v11);
    }
    __syncthreads();
    if (tid == 0){ mbar_inval(sb); mbar_inval(sb+8); mbar_inval(sb+16); mbar_inval(sb+24); }
}

// ================= conversion kernels ======================================
__global__ void convert_x_kernel(const float* __restrict__ X){
    int i = (blockIdx.x*256 + threadIdx.x) * 4;
    float4 v = *(const float4*)(X + i);
    *(uint32_t*)(g_Xf + i)     = packh2(v.x, v.y);
    *(uint32_t*)(g_Xf + i + 2) = packh2(v.z, v.w);
}

__global__ void tsplit_kernel(const float* __restrict__ Wq, const float* __restrict__ Wk,
                              const float* __restrict__ Wv, const float* __restrict__ Wo){
    __shared__ float t[32][33];
    int z = blockIdx.z;
    const float* in = (z == 0) ? Wq : (z == 1) ? Wk : (z == 2) ? Wv : Wo;
    f16* oh = (z == 0) ? g_Wqt_h : (z == 1) ? g_Wkt_h : (z == 2) ? g_Wvt_h : g_Wot_h;
    f16* ol = (z == 0) ? g_Wqt_l : (z == 1) ? g_Wkt_l : (z == 2) ? g_Wvt_l : g_Wot_l;
    int n0 = blockIdx.x*32, k0 = blockIdx.y*32;
    int tx = threadIdx.x, ty = threadIdx.y;
    #pragma unroll
    for (int j = 0; j < 4; ++j)
        t[ty + 8*j][tx] = in[(size_t)(k0 + ty + 8*j)*HID + n0 + tx];
    __syncthreads();
    #pragma unroll
    for (int j = 0; j < 4; ++j){
        float v = t[tx][ty + 8*j];
        size_t o = (size_t)(n0 + ty + 8*j)*HID + k0 + tx;
        split2(v, oh[o], ol[o]);
    }
}

// ---------------- prep ------------------------------------------------------
__global__ void prep_kernel(const float* __restrict__ pos_in,
                            const float* __restrict__ dir_in,
                            const float* __restrict__ ls_in,
                            const float* __restrict__ la_in,
                            const float* __restrict__ dstr,
                            const float* __restrict__ gstr)
{
    int i = threadIdx.x;
    if (i < NH*NS) {
        const float* p = pos_in + (size_t)i*Dd;
        const float* dv = dir_in + (size_t)i*Dd;
        float np = 0.f, nd = 0.f;
        for (int d = 0; d < Dd; ++d) { np += p[d]*p[d]; nd += dv[d]*dv[d]; }
        float pscale = 3.39411254969543f / (sqrtf(np) + 1e-12f);
        float dscale = 1.0f / (sqrtf(nd) + 1e-12f);
        float psq = 0.f, pdd = 0.f;
        for (int d = 0; d < Dd; ++d) {
            float ps = p[d]*pscale, du = dv[d]*dscale;
            g_pos[(size_t)i*Dd + d] = ps;
            g_dir[(size_t)i*Dd + d] = du;
            psq += ps*ps;  pdd += ps*du;
        }
        g_possq[i] = psq;  g_pdd[i] = pdd;
        float sc = expf(ls_in[i]);
        sc = fminf(fmaxf(sc, 0.3f), 1.2f);
        g_inv2s2[i] = 0.5f / (sc*sc);
    }
    __syncthreads();
    if (i < NH) {
        float m = -1e30f;
        for (int n = 0; n < NS; ++n) m = fmaxf(m, la_in[i*NS+n]);
        float s = 0.f, e[NS];
        for (int n = 0; n < NS; ++n) { e[n] = expf(la_in[i*NS+n]-m); s += e[n]; }
        for (int n = 0; n < NS; ++n) g_amp[i*NS+n] = e[n]/s;
    }
    if (i == 0) {
        g_ds = 1.0f / (1.0f + expf(-dstr[0]));
        float gsa = 1.0f / (1.0f + expf(-gstr[0]));
        g_blend = fminf(0.05f, gsa*0.1f);
    }
}

// ---------------- affinities (warp per token) -------------------------------
__global__ void __launch_bounds__(256) affinity2()
{
    int gidx = blockIdx.x*8 + (threadIdx.x >> 5);   // 0..65535
    int lane = threadIdx.x & 31;
    int z = gidx >> 15;
    int rem = gidx & 32767;
    int bh = rem >> 10, s = rem & 1023;
    int b = bh >> 4, h = bh & 15;
    size_t base = ((size_t)(b*Ss + s))*HID + h*128;
    float t[4];
    #pragma unroll
    for (int k = 0; k < 4; ++k){
        int d = k*32 + lane;
        t[k] = z ? (__half2float(g_Kh[base+d]) + __half2float(g_Kl[base+d]))
                 : __half2float(g_Qf[base+d]);
    }
    float tsq = wsum(t[0]*t[0] + t[1]*t[1] + t[2]*t[2] + t[3]*t[3]);
    float ds = g_ds;
    float* out = (z ? g_ka : g_qa) + ((size_t)bh*Ss + s)*NS;
    #pragma unroll
    for (int n = 0; n < NS; ++n){
        int hn = h*NS + n;
        float tp = 0.f, td = 0.f;
        #pragma unroll
        for (int k = 0; k < 4; ++k){
            int d = k*32 + lane;
            tp += t[k]*g_pos[hn*Dd + d];
            td += t[k]*g_dir[hn*Dd + d];
        }
        tp = wsum(tp);  td = wsum(td);
        if (lane == n){
            float dist2 = fmaxf(tsq - 2.0f*tp + g_possq[hn], 0.0f);
            float proj  = td - g_pdd[hn];
            float perp2 = fmaxf(dist2 - proj*proj, 0.0f);
            float inv   = g_inv2s2[hn];
            out[n] = (1.0f-ds)*expf(-dist2*inv) + ds*expf(-perp2*inv);
        }
    }
}

// ---------------- GSA linear-attention precompute (2-phase) ----------------
__global__ void gsa_kv_part()
{
    int ch = blockIdx.x, bh = blockIdx.y;
    int b = bh >> 4, h = bh & 15;
    int d = threadIdx.x;
    const float* vb = g_V + (size_t)b*Ss*HID + h*Dd;
    const float* ka = g_ka + (size_t)bh*Ss*NS;
    float acc[NS];
    #pragma unroll
    for (int n = 0; n < NS; ++n) acc[n] = 0.f;
    int s0 = ch*128;
    for (int s = s0; s < s0+128; ++s){
        float vv = vb[(size_t)s*HID + d];
        #pragma unroll
        for (int n = 0; n < NS; ++n) acc[n] += ka[s*NS+n]*vv;
    }
    #pragma unroll
    for (int n = 0; n < NS; ++n)
        g_kvp[(((size_t)ch*BH + bh)*NS + n)*Dd + d] = acc[n];
    if (d < NS){
        float kssum = 0.f;
        for (int s = s0; s < s0+128; ++s) kssum += ka[s*NS+d];
        g_ksp[(ch*BH + bh)*NS + d] = kssum;
    }
}

__global__ void gsa_red()
{
    int bh = blockIdx.x, d = threadIdx.x;
    #pragma unroll
    for (int n = 0; n < NS; ++n){
        float t = 0.f;
        #pragma unroll
        for (int ch = 0; ch < 8; ++ch)
            t += g_kvp[(((size_t)ch*BH + bh)*NS + n)*Dd + d];
        g_kvmat[((size_t)bh*NS + n)*Dd + d] = t;
    }
    if (d < NS){
        float t = 0.f;
        #pragma unroll
        for (int ch = 0; ch < 8; ++ch) t += g_ksp[(ch*BH + bh)*NS + d];
        g_ksum[bh*NS + d] = t;
    }
}

// ---------------- host: tensormap construction -----------------------------
typedef CUresult (*TMapEncode)(CUtensorMap*, CUtensorMapDataType, cuuint32_t, void*,
    const cuuint64_t*, const cuuint64_t*, const cuuint32_t*, const cuuint32_t*,
    CUtensorMapInterleave, CUtensorMapSwizzle, CUtensorMapL2promotion, CUtensorMapFloatOOBfill);

static void make_map(TMapEncode enc, CUtensorMap* m, void* base, uint64_t d0, uint64_t d1,
                     uint32_t b0, uint32_t b1){
    cuuint64_t dims[2]    = {d0, d1};
    cuuint64_t strides[1] = {d0 * 2};
    cuuint32_t box[2]     = {b0, b1};
    cuuint32_t es[2]      = {1, 1};
    enc(m, CU_TENSOR_MAP_DATA_TYPE_FLOAT16, 2, base, dims, strides, box, es,
        CU_TENSOR_MAP_INTERLEAVE_NONE, CU_TENSOR_MAP_SWIZZLE_128B,
        CU_TENSOR_MAP_L2_PROMOTION_L2_128B, CU_TENSOR_MAP_FLOAT_OOB_FILL_NONE);
}

// ---------------- launch ----------------------------------------------------
extern "C" void kernel_launch(void* const* d_in, const int* in_sizes, int n_in,
                              void* d_out, int out_size)
{
    const float* X   = (const float*)d_in[0];
    const float* Wq  = (const float*)d_in[1];
    const float* Wk  = (const float*)d_in[2];
    const float* Wv  = (const float*)d_in[3];
    const float* Wo  = (const float*)d_in[4];
    const float* pos = (const float*)d_in[5];
    const float* dir = (const float*)d_in[6];
    const float* ls  = (const float*)d_in[7];
    const float* la  = (const float*)d_in[8];
    const float* dstr= (const float*)d_in[9];
    const float* gstr= (const float*)d_in[10];
    float* out = (float*)d_out;

    void* fp = nullptr;
    cudaDriverEntryPointQueryResult qr;
#if CUDART_VERSION >= 12050
    cudaGetDriverEntryPointByVersion("cuTensorMapEncodeTiled", &fp, 12000, cudaEnableDefault, &qr);
#else
    cudaGetDriverEntryPoint("cuTensorMapEncodeTiled", &fp, cudaEnableDefault, &qr);
#endif
    TMapEncode enc = (TMapEncode)fp;

    void *pXf,*pWqh,*pWql,*pWkh,*pWkl,*pWvh,*pWvl,*pWoh,*pWol;
    void *pQf,*pKh,*pKl,*pVh,*pCf;
    cudaGetSymbolAddress(&pXf, g_Xf);
    cudaGetSymbolAddress(&pWqh, g_Wqt_h); cudaGetSymbolAddress(&pWql, g_Wqt_l);
    cudaGetSymbolAddress(&pWkh, g_Wkt_h); cudaGetSymbolAddress(&pWkl, g_Wkt_l);
    cudaGetSymbolAddress(&pWvh, g_Wvt_h); cudaGetSymbolAddress(&pWvl, g_Wvt_l);
    cudaGetSymbolAddress(&pWoh, g_Wot_h); cudaGetSymbolAddress(&pWol, g_Wot_l);
    cudaGetSymbolAddress(&pQf, g_Qf);
    cudaGetSymbolAddress(&pKh, g_Kh);   cudaGetSymbolAddress(&pKl, g_Kl);
    cudaGetSymbolAddress(&pVh, g_Vth);
    cudaGetSymbolAddress(&pCf, g_Cf);

    CUtensorMap mXf,mWqh,mWql,mWkh,mWkl,mWvh,mWvl,mWoh,mWol;
    CUtensorMap mQf,mK64h,mK64l,mVh,mCf;
    make_map(enc,&mXf,pXf,HID,Mm,64,128);
    make_map(enc,&mWqh,pWqh,HID,HID,64,128);  make_map(enc,&mWql,pWql,HID,HID,64,128);
    make_map(enc,&mWkh,pWkh,HID,HID,64,128);  make_map(enc,&mWkl,pWkl,HID,HID,64,128);
    make_map(enc,&mWvh,pWvh,HID,HID,64,128);  make_map(enc,&mWvl,pWvl,HID,HID,64,128);
    make_map(enc,&mWoh,pWoh,HID,HID,64,128);  make_map(enc,&mWol,pWol,HID,HID,64,128);
    make_map(enc,&mQf,pQf,HID,Mm,64,128);
    make_map(enc,&mK64h,pKh,HID,Mm,64,64);    make_map(enc,&mK64l,pKl,HID,Mm,64,64);
    make_map(enc,&mVh,pVh,Ss,(uint64_t)BH*Dd,64,128);
    make_map(enc,&mCf,pCf,HID,Mm,64,128);

    cudaFuncSetAttribute(qkv_tc,   cudaFuncAttributeMaxDynamicSharedMemorySize, SMEM_SZ);
    cudaFuncSetAttribute(wo_tc,    cudaFuncAttributeMaxDynamicSharedMemorySize, SMEM_SZ);
    cudaFuncSetAttribute(flash_tc, cudaFuncAttributeMaxDynamicSharedMemorySize, SMEM_FL);

    prep_kernel<<<1, 128>>>(pos, dir, ls, la, dstr, gstr);
    convert_x_kernel<<<(Mm*HID)/1024, 256>>>(X);
    tsplit_kernel<<<dim3(HID/32, HID/32, 4), dim3(32, 8)>>>(Wq, Wk, Wv, Wo);
    qkv_tc<<<dim3(HID/128, Mm/128, 3), 256, SMEM_SZ>>>(mXf,mWqh,mWql,mWkh,mWkl,mWvh,mWvl);
    affinity2<<<(Ss*BH*2)/8, 256>>>();
    gsa_kv_part<<<dim3(8, BH), 128>>>();
    gsa_red<<<BH, 128>>>();
    flash_tc<<<dim3(Ss/128, BH), 256, SMEM_FL>>>(mQf,mK64h,mK64l,mVh);
    wo_tc<<<dim3(HID/128, Mm/128, 1), 256, SMEM_SZ>>>(mCf,mWoh,mWol,out);
}

// round 11
// speedup vs baseline: 4.8896x; 1.0099x over previous
#include <cuda_runtime.h>
#include <cuda.h>
#include <cuda_fp16.h>
#include <math.h>
#include <stdint.h>

#define Bb 2
#define Ss 1024
#define HID 2048
#define NH 16
#define NS 8
#define Dd 128
#define Mm (Bb*Ss)      // 2048
#define BH (Bb*NH)      // 32

typedef __half f16;

// ---------------- scratch (device globals; no allocation allowed) ----------
__device__ float g_qa[(size_t)BH*Ss*NS];
__device__ float g_ka[(size_t)BH*Ss*NS];
__device__ float g_kvmat[(size_t)BH*NS*Dd];
__device__ float g_ksum[BH*NS];
__device__ float g_kvp[(size_t)8*BH*NS*Dd];
__device__ float g_ksp[8*BH*NS];
__device__ float g_pos[NH*NS*Dd];
__device__ float g_dir[NH*NS*Dd];
__device__ float g_possq[NH*NS];
__device__ float g_pdd[NH*NS];
__device__ float g_inv2s2[NH*NS];
__device__ float g_amp[NH*NS];
__device__ float g_ds;
__device__ float g_blend;

// fp16 operand arrays: A-side plain, B-side split hi/lo (V plain)
__device__ f16 g_Xf[(size_t)Mm*HID];
__device__ f16 g_Wqt_h[(size_t)HID*HID], g_Wqt_l[(size_t)HID*HID];
__device__ f16 g_Wkt_h[(size_t)HID*HID], g_Wkt_l[(size_t)HID*HID];
__device__ f16 g_Wvt_h[(size_t)HID*HID], g_Wvt_l[(size_t)HID*HID];
__device__ f16 g_Wot_h[(size_t)HID*HID], g_Wot_l[(size_t)HID*HID];
__device__ f16 g_Qf[(size_t)Mm*HID];
__device__ f16 g_Kh[(size_t)Mm*HID], g_Kl[(size_t)Mm*HID];
__device__ f16 g_Vth[(size_t)BH*Dd*Ss];            // [bh][d][s], plain
__device__ f16 g_Cf[(size_t)Mm*HID];

__device__ __forceinline__ void split2(float v, f16& h, f16& l){
    h = __float2half(v);
    l = __float2half(v - __half2float(h));
}
__device__ __forceinline__ uint32_t packh2(float x, float y){
    __half2 t = __floats2half2_rn(x, y);
    return *(uint32_t*)&t;
}

// ================= low-level helpers =======================================
__device__ __forceinline__ uint32_t smem_u32(const void* p){
    uint32_t a;
    asm("{ .reg .u64 t; cvta.to.shared.u64 t, %1; cvt.u32.u64 %0, t; }" : "=r"(a) : "l"(p));
    return a;
}
__device__ __forceinline__ void mbar_init(uint32_t a, uint32_t cnt){
    asm volatile("mbarrier.init.shared.b64 [%0], %1;" :: "r"(a), "r"(cnt) : "memory");
}
__device__ __forceinline__ void mbar_inval(uint32_t a){
    asm volatile("mbarrier.inval.shared.b64 [%0];" :: "r"(a) : "memory");
}
__device__ __forceinline__ void mbar_expect(uint32_t a, uint32_t bytes){
    asm volatile("mbarrier.arrive.expect_tx.shared.b64 _, [%0], %1;" :: "r"(a), "r"(bytes) : "memory");
}
__device__ __forceinline__ void wait_parity(uint32_t mbar, uint32_t ph){
    uint32_t done;
    asm volatile(
        "{\n\t.reg .pred p;\n\t"
        "mbarrier.try_wait.parity.acquire.cta.shared::cta.b64 p, [%1], %2;\n\t"
        "selp.b32 %0, 1, 0, p;\n\t}"
        : "=r"(done) : "r"(mbar), "r"(ph) : "memory");
    if (!done) {
        asm volatile(
            "{\n\t.reg .pred P1;\n\t"
            "WL%=:\n\t"
            "mbarrier.try_wait.parity.acquire.cta.shared::cta.b64 P1, [%0], %1, 0x989680;\n\t"
            "@P1 bra.uni WD%=;\n\t"
            "bra.uni WL%=;\n\t"
            "WD%=:\n\t}"
            :: "r"(mbar), "r"(ph) : "memory");
    }
}
__device__ __forceinline__ void tma2d(uint32_t dst, const CUtensorMap* m, int x, int y, uint32_t mbar){
    asm volatile(
        "cp.async.bulk.tensor.2d.shared::cta.global.tile.mbarrier::complete_tx::bytes "
        "[%0], [%1, {%2, %3}], [%4];"
        :: "r"(dst), "l"(m), "r"(x), "r"(y), "r"(mbar) : "memory");
}
__device__ __forceinline__ void ldm4(uint32_t* r, uint32_t a){
    asm volatile("ldmatrix.sync.aligned.m8n8.x4.shared.b16 {%0,%1,%2,%3}, [%4];"
        : "=r"(r[0]),"=r"(r[1]),"=r"(r[2]),"=r"(r[3]) : "r"(a));
}
__device__ __forceinline__ void mma16816(float* c, const uint32_t* a, uint32_t b0, uint32_t b1){
    asm volatile("mma.sync.aligned.m16n8k16.row.col.f32.f16.f16.f32 "
        "{%0,%1,%2,%3}, {%4,%5,%6,%7}, {%8,%9}, {%0,%1,%2,%3};"
        : "+f"(c[0]),"+f"(c[1]),"+f"(c[2]),"+f"(c[3])
        : "r"(a[0]),"r"(a[1]),"r"(a[2]),"r"(a[3]), "r"(b0),"r"(b1));
}
__device__ __forceinline__ uint32_t swz(uint32_t x){ return x ^ ((x>>3)&0x70); }
__device__ __forceinline__ float wsum(float v){
    #pragma unroll
    for (int o = 16; o; o >>= 1) v += __shfl_xor_sync(0xffffffffu, v, o);
    return v;
}

#define TILE_B    16384
#define GSTAGE_B  49152                          // A(16K) Bh(16K) Bl(16K)
#define SMEM_SZ   (1024 + 2*GSTAGE_B)            // 2-stage, 64-K per stage -> 2 CTAs/SM
#define FSTAGE_B  49152                          // Kh(16K) Kl(16K) Vh(16K)
#define SMEM_FL   (1024 + 32768 + 3*FSTAGE_B)    // Q(32K) + 3 stages

// ---------------- 128x128 CTA GEMM mainloop (256 threads, 8 warps) ---------
// C[128,128] += A[128,K] * (Bh+Bl)[128,K]^T, 64-K columns per stage
__device__ __forceinline__ void gemm_main(
    const CUtensorMap* mA,
    const CUtensorMap* mBh, const CUtensorMap* mBl,
    int ax0, int ay, int bx0, int by, int K, float* acc)
{
    extern __shared__ char smem[];
    uint32_t sb = smem_u32(smem);
    int tid = threadIdx.x, lane = tid & 31, wid = tid >> 5;
    int warp_m = (wid >> 2) * 64, warp_n = (wid & 3) * 32;

    if (tid == 0){ mbar_init(sb,1); mbar_init(sb+8,1); }
    __syncthreads();

    #pragma unroll
    for (int i = 0; i < 64; ++i) acc[i] = 0.f;

    int NC = K / 64;

    auto issue = [&](int c){
        if (tid == 0){
            int st = c & 1;
            uint32_t mb = sb + 8*st;
            mbar_expect(mb, (uint32_t)GSTAGE_B);
            uint32_t dst = sb + 1024 + st*GSTAGE_B;
            tma2d(dst,            mA,  ax0 + c*64, ay, mb);
            tma2d(dst +   TILE_B, mBh, bx0 + c*64, by, mb);
            tma2d(dst + 2*TILE_B, mBl, bx0 + c*64, by, mb);
        }
    };
    issue(0);
    if (NC > 1) issue(1);

    uint32_t a_row  = warp_m + (lane & 15);
    uint32_t a_colb = (lane >> 4) * 16;
    uint32_t b_row  = warp_n + (lane & 7) + ((lane >> 4) << 3);
    uint32_t b_colb = ((lane >> 3) & 1) * 16;

    for (int c = 0; c < NC; ++c){
        wait_parity(sb + 8*(c & 1), (c >> 1) & 1);
        uint32_t st = sb + 1024 + (c & 1)*GSTAGE_B;
        #pragma unroll
        for (int ks = 0; ks < 4; ++ks){
            uint32_t a_[16], bh[8], bl[8];
            #pragma unroll
            for (int mt = 0; mt < 4; ++mt){
                uint32_t off = swz((a_row + mt*16)*128 + ks*32 + a_colb);
                ldm4(a_ + mt*4, st + off);
            }
            #pragma unroll
            for (int nt = 0; nt < 2; ++nt){
                uint32_t off = swz((b_row + nt*16)*128 + ks*32 + b_colb);
                ldm4(bh + nt*4, st + TILE_B + off);
                ldm4(bl + nt*4, st + 2*TILE_B + off);
            }
            #pragma unroll
            for (int mt = 0; mt < 4; ++mt)
                #pragma unroll
                for (int n8 = 0; n8 < 4; ++n8){
                    float* c4 = acc + (mt*4 + n8)*4;
                    int bi = (n8 >> 1)*4 + (n8 & 1)*2;
                    mma16816(c4, a_ + mt*4, bh[bi], bh[bi+1]);
                    mma16816(c4, a_ + mt*4, bl[bi], bl[bi+1]);
                }
        }
        __syncthreads();
        if (c + 2 < NC) issue(c + 2);
    }
    if (tid == 0){ mbar_inval(sb); mbar_inval(sb+8); }
}

template<class F>
__device__ __forceinline__ void epi_loop(const float* acc, F f){
    int lane = threadIdx.x & 31, wid = threadIdx.x >> 5;
    int warp_m = (wid >> 2) * 64, warp_n = (wid & 3) * 32;
    int g = lane >> 2, tg = (lane & 3) * 2;
    #pragma unroll
    for (int mt = 0; mt < 4; ++mt)
        #pragma unroll
        for (int n8 = 0; n8 < 4; ++n8){
            const float* c4 = acc + (mt*4 + n8)*4;
            #pragma unroll
            for (int hh = 0; hh < 2; ++hh){
                int r  = warp_m + mt*16 + g + hh*8;
                int cc = warp_n + n8*8 + tg;
                f(r, cc, c4[hh*2], c4[hh*2+1]);
            }
        }
}

// ================= GEMM kernels ============================================
__global__ void __launch_bounds__(256, 2) qkv_tc(
    const __grid_constant__ CUtensorMap mXf,
    const __grid_constant__ CUtensorMap mWqh, const __grid_constant__ CUtensorMap mWql,
    const __grid_constant__ CUtensorMap mWkh, const __grid_constant__ CUtensorMap mWkl,
    const __grid_constant__ CUtensorMap mWvh, const __grid_constant__ CUtensorMap mWvl)
{
    extern __shared__ char smem[];
    int z = blockIdx.z;
    int row0 = blockIdx.y*128, col0 = blockIdx.x*128;
    const CUtensorMap *pbh, *pbl;
    if (z == 0){ pbh = &mWqh; pbl = &mWql; }
    else if (z == 1){ pbh = &mWkh; pbl = &mWkl; }
    else { pbh = &mWvh; pbl = &mWvl; }
    float acc[64];
    gemm_main(&mXf, pbh, pbl, 0, row0, 0, col0, HID, acc);

    if (z == 0){
        epi_loop(acc, [&](int r, int cc, float v0, float v1){
            size_t idx = (size_t)(row0 + r)*HID + col0 + cc;
            *(uint32_t*)(g_Qf + idx) = packh2(v0, v1);
        });
    } else if (z == 1){
        epi_loop(acc, [&](int r, int cc, float v0, float v1){
            size_t idx = (size_t)(row0 + r)*HID + col0 + cc;
            f16 h0,l0,h1,l1; split2(v0,h0,l0); split2(v1,h1,l1);
            __half2 hv; hv.x=h0; hv.y=h1;
            __half2 lv; lv.x=l0; lv.y=l1;
            *(__half2*)(g_Kh + idx) = hv;
            *(__half2*)(g_Kl + idx) = lv;
        });
    } else {
        // stage transposed V tile in SMEM, then coalesced write to g_Vth
        f16* Ts = (f16*)(smem + 1024);      // [128 d][136 s-stride]
        epi_loop(acc, [&](int r, int cc, float v0, float v1){
            Ts[cc*136 + r]       = __float2half(v0);
            Ts[(cc+1)*136 + r]   = __float2half(v1);
        });
        __syncthreads();
        int b = row0 >> 10, s0 = row0 & (Ss-1);
        int h = col0 >> 7;
        size_t dbase = ((size_t)(b*NH + h))*Dd;
        for (int it = threadIdx.x; it < 128*16; it += 256){
            int d = it >> 4, seg = it & 15;
            uint4 val = *(const uint4*)(Ts + d*136 + seg*8);   // 272B stride, 16B aligned
            *(uint4*)(g_Vth + (dbase + d)*Ss + s0 + seg*8) = val;
        }
    }
}

__global__ void __launch_bounds__(256, 2) wo_tc(
    const __grid_constant__ CUtensorMap mCf,
    const __grid_constant__ CUtensorMap mWh, const __grid_constant__ CUtensorMap mWl,
    float* __restrict__ out)
{
    int row0 = blockIdx.y*128, col0 = blockIdx.x*128;
    float acc[64];
    gemm_main(&mCf, &mWh, &mWl, 0, row0, 0, col0, HID, acc);
    epi_loop(acc, [&](int r, int cc, float v0, float v1){
        float2 fv; fv.x = v0; fv.y = v1;
        *(float2*)(out + (size_t)(row0 + r)*HID + col0 + cc) = fv;
    });
}

// ================= flash attention kernel ==================================
__global__ void __launch_bounds__(256) flash_tc(
    const __grid_constant__ CUtensorMap mQf,
    const __grid_constant__ CUtensorMap mK64h, const __grid_constant__ CUtensorMap mK64l,
    const __grid_constant__ CUtensorMap mVh)
{
    extern __shared__ char smem[];
    uint32_t sb = smem_u32(smem);
    int tid = threadIdx.x, lane = tid & 31, wid = tid >> 5;
    int bh = blockIdx.y, b = bh >> 4, h = bh & 15;
    int row0 = blockIdx.x * 128;

    const uint32_t QF  = sb + 1024;          // two 16KB halves
    const uint32_t ST0 = QF + 32768;
    // stage: KH0(8K) KH1(8K) KL0(8K) KL1(8K) VH(16K) = 48KB

    if (tid == 0){ mbar_init(sb,1); mbar_init(sb+8,1); mbar_init(sb+16,1); mbar_init(sb+24,1); }
    __syncthreads();

    if (tid == 0){
        mbar_expect(sb+24, 32768u);
        tma2d(QF,        &mQf, h*128,    b*Ss+row0, sb+24);
        tma2d(QF+16384,  &mQf, h*128+64, b*Ss+row0, sb+24);
    }
    auto issue = [&](int j){
        if (tid == 0){
            int st3 = j % 3;
            uint32_t mb = sb + 8*st3;
            mbar_expect(mb, (uint32_t)FSTAGE_B);
            uint32_t st = ST0 + st3*FSTAGE_B;
            tma2d(st,         &mK64h, h*128,    b*Ss+j*64, mb);
            tma2d(st+8192,    &mK64h, h*128+64, b*Ss+j*64, mb);
            tma2d(st+16384,   &mK64l, h*128,    b*Ss+j*64, mb);
            tma2d(st+24576,   &mK64l, h*128+64, b*Ss+j*64, mb);
            tma2d(st+32768,   &mVh,   j*64, bh*128, mb);
        }
    };
    issue(0); issue(1); issue(2);

    float O[64];
    #pragma unroll
    for (int i = 0; i < 64; ++i) O[i] = 0.f;
    float m0 = -1e30f, m1 = -1e30f, l0 = 0.f, l1 = 0.f;
    const float qk = 0.08838834764831845f;

    uint32_t a_row = wid*16 + (lane & 15), a_colb = (lane >> 4)*16;
    uint32_t b_rw  = (lane & 7) + ((lane >> 4) << 3);
    uint32_t b_cb  = ((lane >> 3) & 1)*16;

    wait_parity(sb+24, 0);

    for (int j = 0; j < 16; ++j){
        wait_parity(sb + 8*(j % 3), (j / 3) & 1);
        uint32_t st = ST0 + (j % 3)*FSTAGE_B;

        // ---- S = Q K^T (Q plain, K split)
        float s[32];
        #pragma unroll
        for (int i = 0; i < 32; ++i) s[i] = 0.f;
        #pragma unroll
        for (int ks = 0; ks < 8; ++ks){
            uint32_t qf_[4], kh_[16], kl_[16];
            uint32_t offa = (ks>>2)*16384 + swz(a_row*128 + (ks&3)*32 + a_colb);
            ldm4(qf_, QF + offa);
            #pragma unroll
            for (int nt = 0; nt < 4; ++nt){
                uint32_t offb = (ks>>2)*8192 + swz((b_rw + nt*16)*128 + (ks&3)*32 + b_cb);
                ldm4(kh_ + nt*4, st + offb);
                ldm4(kl_ + nt*4, st + 16384 + offb);
            }
            #pragma unroll
            for (int n8 = 0; n8 < 8; ++n8){
                int bi = (n8 >> 1)*4 + (n8 & 1)*2;
                mma16816(s + n8*4, qf_, kh_[bi], kh_[bi+1]);
                mma16816(s + n8*4, qf_, kl_[bi], kl_[bi+1]);
            }
        }

        // ---- online softmax
        float tm0 = -1e30f, tm1 = -1e30f;
        #pragma unroll
        for (int t = 0; t < 8; ++t){
            s[t*4+0] *= qk; s[t*4+1] *= qk; s[t*4+2] *= qk; s[t*4+3] *= qk;
            tm0 = fmaxf(tm0, fmaxf(s[t*4+0], s[t*4+1]));
            tm1 = fmaxf(tm1, fmaxf(s[t*4+2], s[t*4+3]));
        }
        tm0 = fmaxf(tm0, __shfl_xor_sync(0xffffffffu, tm0, 1));
        tm0 = fmaxf(tm0, __shfl_xor_sync(0xffffffffu, tm0, 2));
        tm1 = fmaxf(tm1, __shfl_xor_sync(0xffffffffu, tm1, 1));
        tm1 = fmaxf(tm1, __shfl_xor_sync(0xffffffffu, tm1, 2));
        float nm0 = fmaxf(m0, tm0), nm1 = fmaxf(m1, tm1);
        float al0 = expf(m0 - nm0), al1 = expf(m1 - nm1);
        float ts0 = 0.f, ts1 = 0.f;
        #pragma unroll
        for (int t = 0; t < 8; ++t){
            s[t*4+0] = expf(s[t*4+0] - nm0); s[t*4+1] = expf(s[t*4+1] - nm0);
            s[t*4+2] = expf(s[t*4+2] - nm1); s[t*4+3] = expf(s[t*4+3] - nm1);
            ts0 += s[t*4+0] + s[t*4+1];
            ts1 += s[t*4+2] + s[t*4+3];
        }
        ts0 += __shfl_xor_sync(0xffffffffu, ts0, 1);
        ts0 += __shfl_xor_sync(0xffffffffu, ts0, 2);
        ts1 += __shfl_xor_sync(0xffffffffu, ts1, 1);
        ts1 += __shfl_xor_sync(0xffffffffu, ts1, 2);
        l0 = l0*al0 + ts0;  l1 = l1*al1 + ts1;
        m0 = nm0;  m1 = nm1;
        #pragma unroll
        for (int t = 0; t < 16; ++t){
            O[t*4+0] *= al0; O[t*4+1] *= al0; O[t*4+2] *= al1; O[t*4+3] *= al1;
        }

        // ---- pack P (plain fp16) into A fragments
        uint32_t ph_[16];
        #pragma unroll
        for (int t = 0; t < 4; ++t){
            ph_[t*4+0] = packh2(s[(2*t)*4+0],   s[(2*t)*4+1]);
            ph_[t*4+1] = packh2(s[(2*t)*4+2],   s[(2*t)*4+3]);
            ph_[t*4+2] = packh2(s[(2*t+1)*4+0], s[(2*t+1)*4+1]);
            ph_[t*4+3] = packh2(s[(2*t+1)*4+2], s[(2*t+1)*4+3]);
        }

        // ---- O += P V (both plain)
        #pragma unroll
        for (int ks = 0; ks < 4; ++ks){
            uint32_t vh_[32];
            #pragma unroll
            for (int nt = 0; nt < 8; ++nt){
                uint32_t offv = swz((b_rw + nt*16)*128 + ks*32 + b_cb);
                ldm4(vh_ + nt*4, st + 32768 + offv);
            }
            #pragma unroll
            for (int n8 = 0; n8 < 16; ++n8){
                int bi = (n8 >> 1)*4 + (n8 & 1)*2;
                mma16816(O + n8*4, ph_ + ks*4, vh_[bi], vh_[bi+1]);
            }
        }
        __syncthreads();
        if (j + 3 < 16) issue(j + 3);
    }

    // ---- epilogue: normalize, fuse GSA blend, write Cf (plain fp16)
    float inv0 = 1.f / l0, inv1 = 1.f / l1;
    float blend = g_blend, ob = 1.f - blend;
    int g = lane >> 2, tg2 = (lane & 3)*2;
    int s0g = row0 + wid*16 + g, s1g = s0g + 8;

    float c0[8], c1[8];
    float den0 = 1e-8f, den1 = 1e-8f;
    #pragma unroll
    for (int n = 0; n < 8; ++n){
        float a = g_amp[h*8 + n], kss = g_ksum[bh*8 + n];
        c0[n] = g_qa[((size_t)bh*Ss + s0g)*8 + n] * a;  den0 += c0[n]*kss;
        c1[n] = g_qa[((size_t)bh*Ss + s1g)*8 + n] * a;  den1 += c1[n]*kss;
    }
    float id0 = blend/den0, id1 = blend/den1;

    size_t base0 = ((size_t)(b*Ss + s0g))*HID + h*128;
    size_t base1 = ((size_t)(b*Ss + s1g))*HID + h*128;
    #pragma unroll
    for (int n8 = 0; n8 < 16; ++n8){
        int d = n8*8 + tg2;
        float num00=0.f, num01=0.f, num10=0.f, num11=0.f;
        #pragma unroll
        for (int n = 0; n < 8; ++n){
            float2 kv = *(const float2*)(g_kvmat + ((size_t)bh*8 + n)*128 + d);
            num00 += c0[n]*kv.x;  num01 += c0[n]*kv.y;
            num10 += c1[n]*kv.x;  num11 += c1[n]*kv.y;
        }
        float v00 = ob*O[n8*4+0]*inv0 + id0*num00;
        float v01 = ob*O[n8*4+1]*inv0 + id0*num01;
        float v10 = ob*O[n8*4+2]*inv1 + id1*num10;
        float v11 = ob*O[n8*4+3]*inv1 + id1*num11;
        *(uint32_t*)(g_Cf + base0 + d) = packh2(v00, v01);
        *(uint32_t*)(g_Cf + base1 + d) = packh2(v10, v11);
    }
    __syncthreads();
    if (tid == 0){ mbar_inval(sb); mbar_inval(sb+8); mbar_inval(sb+16); mbar_inval(sb+24); }
}

// ================= conversion kernels ======================================
__global__ void convert_x_kernel(const float* __restrict__ X){
    int i = (blockIdx.x*256 + threadIdx.x) * 4;
    float4 v = *(const float4*)(X + i);
    *(uint32_t*)(g_Xf + i)     = packh2(v.x, v.y);
    *(uint32_t*)(g_Xf + i + 2) = packh2(v.z, v.w);
}

__global__ void tsplit_kernel(const float* __restrict__ Wq, const float* __restrict__ Wk,
                              const float* __restrict__ Wv, const float* __restrict__ Wo){
    __shared__ float t[32][33];
    int z = blockIdx.z;
    const float* in = (z == 0) ? Wq : (z == 1) ? Wk : (z == 2) ? Wv : Wo;
    f16* oh = (z == 0) ? g_Wqt_h : (z == 1) ? g_Wkt_h : (z == 2) ? g_Wvt_h : g_Wot_h;
    f16* ol = (z == 0) ? g_Wqt_l : (z == 1) ? g_Wkt_l : (z == 2) ? g_Wvt_l : g_Wot_l;
    int n0 = blockIdx.x*32, k0 = blockIdx.y*32;
    int tx = threadIdx.x, ty = threadIdx.y;
    #pragma unroll
    for (int j = 0; j < 4; ++j)
        t[ty + 8*j][tx] = in[(size_t)(k0 + ty + 8*j)*HID + n0 + tx];
    __syncthreads();
    #pragma unroll
    for (int j = 0; j < 4; ++j){
        float v = t[tx][ty + 8*j];
        size_t o = (size_t)(n0 + ty + 8*j)*HID + k0 + tx;
        split2(v, oh[o], ol[o]);
    }
}

// ---------------- prep ------------------------------------------------------
__global__ void prep_kernel(const float* __restrict__ pos_in,
                            const float* __restrict__ dir_in,
                            const float* __restrict__ ls_in,
                            const float* __restrict__ la_in,
                            const float* __restrict__ dstr,
                            const float* __restrict__ gstr)
{
    int i = threadIdx.x;
    if (i < NH*NS) {
        const float* p = pos_in + (size_t)i*Dd;
        const float* dv = dir_in + (size_t)i*Dd;
        float np = 0.f, nd = 0.f;
        for (int d = 0; d < Dd; ++d) { np += p[d]*p[d]; nd += dv[d]*dv[d]; }
        float pscale = 3.39411254969543f / (sqrtf(np) + 1e-12f);
        float dscale = 1.0f / (sqrtf(nd) + 1e-12f);
        float psq = 0.f, pdd = 0.f;
        for (int d = 0; d < Dd; ++d) {
            float ps = p[d]*pscale, du = dv[d]*dscale;
            g_pos[(size_t)i*Dd + d] = ps;
            g_dir[(size_t)i*Dd + d] = du;
            psq += ps*ps;  pdd += ps*du;
        }
        g_possq[i] = psq;  g_pdd[i] = pdd;
        float sc = expf(ls_in[i]);
        sc = fminf(fmaxf(sc, 0.3f), 1.2f);
        g_inv2s2[i] = 0.5f / (sc*sc);
    }
    __syncthreads();
    if (i < NH) {
        float m = -1e30f;
        for (int n = 0; n < NS; ++n) m = fmaxf(m, la_in[i*NS+n]);
        float s = 0.f, e[NS];
        for (int n = 0; n < NS; ++n) { e[n] = expf(la_in[i*NS+n]-m); s += e[n]; }
        for (int n = 0; n < NS; ++n) g_amp[i*NS+n] = e[n]/s;
    }
    if (i == 0) {
        g_ds = 1.0f / (1.0f + expf(-dstr[0]));
        float gsa = 1.0f / (1.0f + expf(-gstr[0]));
        g_blend = fminf(0.05f, gsa*0.1f);
    }
}

// ---------------- affinities (warp per token) -------------------------------
__global__ void __launch_bounds__(256) affinity2()
{
    int gidx = blockIdx.x*8 + (threadIdx.x >> 5);   // 0..65535
    int lane = threadIdx.x & 31;
    int z = gidx >> 15;
    int rem = gidx & 32767;
    int bh = rem >> 10, s = rem & 1023;
    int b = bh >> 4, h = bh & 15;
    size_t base = ((size_t)(b*Ss + s))*HID + h*128;
    float t[4];
    #pragma unroll
    for (int k = 0; k < 4; ++k){
        int d = k*32 + lane;
        t[k] = z ? (__half2float(g_Kh[base+d]) + __half2float(g_Kl[base+d]))
                 : __half2float(g_Qf[base+d]);
    }
    float tsq = wsum(t[0]*t[0] + t[1]*t[1] + t[2]*t[2] + t[3]*t[3]);
    float ds = g_ds;
    float* out = (z ? g_ka : g_qa) + ((size_t)bh*Ss + s)*NS;
    #pragma unroll
    for (int n = 0; n < NS; ++n){
        int hn = h*NS + n;
        float tp = 0.f, td = 0.f;
        #pragma unroll
        for (int k = 0; k < 4; ++k){
            int d = k*32 + lane;
            tp += t[k]*g_pos[hn*Dd + d];
            td += t[k]*g_dir[hn*Dd + d];
        }
        tp = wsum(tp);  td = wsum(td);
        if (lane == n){
            float dist2 = fmaxf(tsq - 2.0f*tp + g_possq[hn], 0.0f);
            float proj  = td - g_pdd[hn];
            float perp2 = fmaxf(dist2 - proj*proj, 0.0f);
            float inv   = g_inv2s2[hn];
            out[n] = (1.0f-ds)*expf(-dist2*inv) + ds*expf(-perp2*inv);
        }
    }
}

// ---------------- GSA linear-attention precompute (2-phase) ----------------
__global__ void gsa_kv_part()
{
    int ch = blockIdx.x, bh = blockIdx.y;
    int d = threadIdx.x;
    const f16* vb = g_Vth + (size_t)bh*Dd*Ss + (size_t)d*Ss;
    const float* ka = g_ka + (size_t)bh*Ss*NS;
    float acc[NS];
    #pragma unroll
    for (int n = 0; n < NS; ++n) acc[n] = 0.f;
    int s0 = ch*128;
    for (int s = s0; s < s0+128; ++s){
        float vv = __half2float(vb[s]);
        #pragma unroll
        for (int n = 0; n < NS; ++n) acc[n] += ka[s*NS+n]*vv;
    }
    #pragma unroll
    for (int n = 0; n < NS; ++n)
        g_kvp[(((size_t)ch*BH + bh)*NS + n)*Dd + d] = acc[n];
    if (d < NS){
        float kssum = 0.f;
        for (int s = s0; s < s0+128; ++s) kssum += ka[s*NS+d];
        g_ksp[(ch*BH + bh)*NS + d] = kssum;
    }
}

__global__ void gsa_red()
{
    int bh = blockIdx.x, d = threadIdx.x;
    #pragma unroll
    for (int n = 0; n < NS; ++n){
        float t = 0.f;
        #pragma unroll
        for (int ch = 0; ch < 8; ++ch)
            t += g_kvp[(((size_t)ch*BH + bh)*NS + n)*Dd + d];
        g_kvmat[((size_t)bh*NS + n)*Dd + d] = t;
    }
    if (d < NS){
        float t = 0.f;
        #pragma unroll
        for (int ch = 0; ch < 8; ++ch) t += g_ksp[(ch*BH + bh)*NS + d];
        g_ksum[bh*NS + d] = t;
    }
}

// ---------------- host: tensormap construction -----------------------------
typedef CUresult (*TMapEncode)(CUtensorMap*, CUtensorMapDataType, cuuint32_t, void*,
    const cuuint64_t*, const cuuint64_t*, const cuuint32_t*, const cuuint32_t*,
    CUtensorMapInterleave, CUtensorMapSwizzle, CUtensorMapL2promotion, CUtensorMapFloatOOBfill);

static void make_map(TMapEncode enc, CUtensorMap* m, void* base, uint64_t d0, uint64_t d1,
                     uint32_t b0, uint32_t b1){
    cuuint64_t dims[2]    = {d0, d1};
    cuuint64_t strides[1] = {d0 * 2};
    cuuint32_t box[2]     = {b0, b1};
    cuuint32_t es[2]      = {1, 1};
    enc(m, CU_TENSOR_MAP_DATA_TYPE_FLOAT16, 2, base, dims, strides, box, es,
        CU_TENSOR_MAP_INTERLEAVE_NONE, CU_TENSOR_MAP_SWIZZLE_128B,
        CU_TENSOR_MAP_L2_PROMOTION_L2_128B, CU_TENSOR_MAP_FLOAT_OOB_FILL_NONE);
}

// ---------------- launch ----------------------------------------------------
extern "C" void kernel_launch(void* const* d_in, const int* in_sizes, int n_in,
                              void* d_out, int out_size)
{
    const float* X   = (const float*)d_in[0];
    const float* Wq  = (const float*)d_in[1];
    const float* Wk  = (const float*)d_in[2];
    const float* Wv  = (const float*)d_in[3];
    const float* Wo  = (const float*)d_in[4];
    const float* pos = (const float*)d_in[5];
    const float* dir = (const float*)d_in[6];
    const float* ls  = (const float*)d_in[7];
    const float* la  = (const float*)d_in[8];
    const float* dstr= (const float*)d_in[9];
    const float* gstr= (const float*)d_in[10];
    float* out = (float*)d_out;

    void* fp = nullptr;
    cudaDriverEntryPointQueryResult qr;
#if CUDART_VERSION >= 12050
    cudaGetDriverEntryPointByVersion("cuTensorMapEncodeTiled", &fp, 12000, cudaEnableDefault, &qr);
#else
    cudaGetDriverEntryPoint("cuTensorMapEncodeTiled", &fp, cudaEnableDefault, &qr);
#endif
    TMapEncode enc = (TMapEncode)fp;

    void *pXf,*pWqh,*pWql,*pWkh,*pWkl,*pWvh,*pWvl,*pWoh,*pWol;
    void *pQf,*pKh,*pKl,*pVh,*pCf;
    cudaGetSymbolAddress(&pXf, g_Xf);
    cudaGetSymbolAddress(&pWqh, g_Wqt_h); cudaGetSymbolAddress(&pWql, g_Wqt_l);
    cudaGetSymbolAddress(&pWkh, g_Wkt_h); cudaGetSymbolAddress(&pWkl, g_Wkt_l);
    cudaGetSymbolAddress(&pWvh, g_Wvt_h); cudaGetSymbolAddress(&pWvl, g_Wvt_l);
    cudaGetSymbolAddress(&pWoh, g_Wot_h); cudaGetSymbolAddress(&pWol, g_Wot_l);
    cudaGetSymbolAddress(&pQf, g_Qf);
    cudaGetSymbolAddress(&pKh, g_Kh);   cudaGetSymbolAddress(&pKl, g_Kl);
    cudaGetSymbolAddress(&pVh, g_Vth);
    cudaGetSymbolAddress(&pCf, g_Cf);

    CUtensorMap mXf,mWqh,mWql,mWkh,mWkl,mWvh,mWvl,mWoh,mWol;
    CUtensorMap mQf,mK64h,mK64l,mVh,mCf;
    make_map(enc,&mXf,pXf,HID,Mm,64,128);
    make_map(enc,&mWqh,pWqh,HID,HID,64,128);  make_map(enc,&mWql,pWql,HID,HID,64,128);
    make_map(enc,&mWkh,pWkh,HID,HID,64,128);  make_map(enc,&mWkl,pWkl,HID,HID,64,128);
    make_map(enc,&mWvh,pWvh,HID,HID,64,128);  make_map(enc,&mWvl,pWvl,HID,HID,64,128);
    make_map(enc,&mWoh,pWoh,HID,HID,64,128);  make_map(enc,&mWol,pWol,HID,HID,64,128);
    make_map(enc,&mQf,pQf,HID,Mm,64,128);
    make_map(enc,&mK64h,pKh,HID,Mm,64,64);    make_map(enc,&mK64l,pKl,HID,Mm,64,64);
    make_map(enc,&mVh,pVh,Ss,(uint64_t)BH*Dd,64,128);
    make_map(enc,&mCf,pCf,HID,Mm,64,128);

    cudaFuncSetAttribute(qkv_tc,   cudaFuncAttributeMaxDynamicSharedMemorySize, SMEM_SZ);
    cudaFuncSetAttribute(wo_tc,    cudaFuncAttributeMaxDynamicSharedMemorySize, SMEM_SZ);
    cudaFuncSetAttribute(flash_tc, cudaFuncAttributeMaxDynamicSharedMemorySize, SMEM_FL);

    prep_kernel<<<1, 128>>>(pos, dir, ls, la, dstr, gstr);
    convert_x_kernel<<<(Mm*HID)/1024, 256>>>(X);
    tsplit_kernel<<<dim3(HID/32, HID/32, 4), dim3(32, 8)>>>(Wq, Wk, Wv, Wo);
    qkv_tc<<<dim3(HID/128, Mm/128, 3), 256, SMEM_SZ>>>(mXf,mWqh,mWql,mWkh,mWkl,mWvh,mWvl);
    affinity2<<<(Ss*BH*2)/8, 256>>>();
    gsa_kv_part<<<dim3(8, BH), 128>>>();
    gsa_red<<<BH, 128>>>();
    flash_tc<<<dim3(Ss/128, BH), 256, SMEM_FL>>>(mQf,mK64h,mK64l,mVh);
    wo_tc<<<dim3(HID/128, Mm/128, 1), 256, SMEM_SZ>>>(mCf,mWoh,mWol,out);
}

// round 12
// speedup vs baseline: 5.8944x; 1.2055x over previous
#include <cuda_runtime.h>
#include <cuda.h>
#include <cuda_fp16.h>
#include <math.h>
#include <stdint.h>

#define Bb 2
#define Ss 1024
#define HID 2048
#define NH 16
#define NS 8
#define Dd 128
#define Mm (Bb*Ss)      // 2048
#define BH (Bb*NH)      // 32

typedef __half f16;

// ---------------- scratch (device globals; no allocation allowed) ----------
__device__ float g_qa[(size_t)BH*Ss*NS];
__device__ float g_ka[(size_t)BH*Ss*NS];
__device__ float g_kvmat[(size_t)BH*NS*Dd];
__device__ float g_ksum[BH*NS];
__device__ float g_kvp[(size_t)8*BH*NS*Dd];
__device__ float g_ksp[8*BH*NS];
__device__ float g_pos[NH*NS*Dd];
__device__ float g_dir[NH*NS*Dd];
__device__ float g_possq[NH*NS];
__device__ float g_pdd[NH*NS];
__device__ float g_inv2s2[NH*NS];
__device__ float g_amp[NH*NS];
__device__ float g_ds;
__device__ float g_blend;

// fp16 operand arrays: QKV weights plain; Wo split; K split for flash
__device__ f16 g_Xf[(size_t)Mm*HID];
__device__ f16 g_Wqt[(size_t)HID*HID];
__device__ f16 g_Wkt[(size_t)HID*HID];
__device__ f16 g_Wvt[(size_t)HID*HID];
__device__ f16 g_Wot_h[(size_t)HID*HID], g_Wot_l[(size_t)HID*HID];
__device__ f16 g_Qf[(size_t)Mm*HID];
__device__ f16 g_Kh[(size_t)Mm*HID], g_Kl[(size_t)Mm*HID];
__device__ f16 g_Vth[(size_t)BH*Dd*Ss];            // [bh][d][s], plain
__device__ f16 g_Cf[(size_t)Mm*HID];

__device__ __forceinline__ void split2(float v, f16& h, f16& l){
    h = __float2half(v);
    l = __float2half(v - __half2float(h));
}
__device__ __forceinline__ uint32_t packh2(float x, float y){
    __half2 t = __floats2half2_rn(x, y);
    return *(uint32_t*)&t;
}

// ================= low-level helpers =======================================
__device__ __forceinline__ uint32_t smem_u32(const void* p){
    uint32_t a;
    asm("{ .reg .u64 t; cvta.to.shared.u64 t, %1; cvt.u32.u64 %0, t; }" : "=r"(a) : "l"(p));
    return a;
}
__device__ __forceinline__ void mbar_init(uint32_t a, uint32_t cnt){
    asm volatile("mbarrier.init.shared.b64 [%0], %1;" :: "r"(a), "r"(cnt) : "memory");
}
__device__ __forceinline__ void mbar_inval(uint32_t a){
    asm volatile("mbarrier.inval.shared.b64 [%0];" :: "r"(a) : "memory");
}
__device__ __forceinline__ void mbar_expect(uint32_t a, uint32_t bytes){
    asm volatile("mbarrier.arrive.expect_tx.shared.b64 _, [%0], %1;" :: "r"(a), "r"(bytes) : "memory");
}
__device__ __forceinline__ void wait_parity(uint32_t mbar, uint32_t ph){
    uint32_t done;
    asm volatile(
        "{\n\t.reg .pred p;\n\t"
        "mbarrier.try_wait.parity.acquire.cta.shared::cta.b64 p, [%1], %2;\n\t"
        "selp.b32 %0, 1, 0, p;\n\t}"
        : "=r"(done) : "r"(mbar), "r"(ph) : "memory");
    if (!done) {
        asm volatile(
            "{\n\t.reg .pred P1;\n\t"
            "WL%=:\n\t"
            "mbarrier.try_wait.parity.acquire.cta.shared::cta.b64 P1, [%0], %1, 0x989680;\n\t"
            "@P1 bra.uni WD%=;\n\t"
            "bra.uni WL%=;\n\t"
            "WD%=:\n\t}"
            :: "r"(mbar), "r"(ph) : "memory");
    }
}
__device__ __forceinline__ void tma2d(uint32_t dst, const CUtensorMap* m, int x, int y, uint32_t mbar){
    asm volatile(
        "cp.async.bulk.tensor.2d.shared::cta.global.tile.mbarrier::complete_tx::bytes "
        "[%0], [%1, {%2, %3}], [%4];"
        :: "r"(dst), "l"(m), "r"(x), "r"(y), "r"(mbar) : "memory");
}
__device__ __forceinline__ void ldm4(uint32_t* r, uint32_t a){
    asm volatile("ldmatrix.sync.aligned.m8n8.x4.shared.b16 {%0,%1,%2,%3}, [%4];"
        : "=r"(r[0]),"=r"(r[1]),"=r"(r[2]),"=r"(r[3]) : "r"(a));
}
__device__ __forceinline__ void mma16816(float* c, const uint32_t* a, uint32_t b0, uint32_t b1){
    asm volatile("mma.sync.aligned.m16n8k16.row.col.f32.f16.f16.f32 "
        "{%0,%1,%2,%3}, {%4,%5,%6,%7}, {%8,%9}, {%0,%1,%2,%3};"
        : "+f"(c[0]),"+f"(c[1]),"+f"(c[2]),"+f"(c[3])
        : "r"(a[0]),"r"(a[1]),"r"(a[2]),"r"(a[3]), "r"(b0),"r"(b1));
}
__device__ __forceinline__ uint32_t swz(uint32_t x){ return x ^ ((x>>3)&0x70); }
__device__ __forceinline__ float wsum(float v){
    #pragma unroll
    for (int o = 16; o; o >>= 1) v += __shfl_xor_sync(0xffffffffu, v, o);
    return v;
}

#define TILE_B    16384
#define SMEM_SZ   99328                          // qkv: 3x32K stages; wo: 2x48K stages (+1K)
#define FSTAGE_B  49152                          // Kh(16K) Kl(16K) Vh(16K)
#define SMEM_FL   (1024 + 32768 + 3*FSTAGE_B)    // Q(32K) + 3 stages

// ---------------- 128x128 CTA GEMM mainloop (256 threads, 8 warps) ---------
// C[128,128] += A[128,K] * B[128,K]^T  (B optionally split hi+lo)
template<int NST, bool SPLITB>
__device__ __forceinline__ void gemm_main(
    const CUtensorMap* mA,
    const CUtensorMap* mBh, const CUtensorMap* mBl,
    int ax0, int ay, int bx0, int by, int K, float* acc)
{
    extern __shared__ char smem[];
    uint32_t sb = smem_u32(smem);
    int tid = threadIdx.x, lane = tid & 31, wid = tid >> 5;
    int warp_m = (wid >> 2) * 64, warp_n = (wid & 3) * 32;
    const uint32_t STB = SPLITB ? 3*TILE_B : 2*TILE_B;

    if (tid == 0){
        #pragma unroll
        for (int s = 0; s < NST; ++s) mbar_init(sb + 8*s, 1);
    }
    __syncthreads();

    #pragma unroll
    for (int i = 0; i < 64; ++i) acc[i] = 0.f;

    int NC = K / 64;

    auto issue = [&](int c){
        if (tid == 0){
            int st = c % NST;
            uint32_t mb = sb + 8*st;
            mbar_expect(mb, STB);
            uint32_t dst = sb + 1024 + st*STB;
            tma2d(dst,            mA,  ax0 + c*64, ay, mb);
            tma2d(dst +   TILE_B, mBh, bx0 + c*64, by, mb);
            if (SPLITB) tma2d(dst + 2*TILE_B, mBl, bx0 + c*64, by, mb);
        }
    };
    issue(0);
    if (NC > 1) issue(1);
    if (NST > 2 && NC > 2) issue(2);

    uint32_t a_row  = warp_m + (lane & 15);
    uint32_t a_colb = (lane >> 4) * 16;
    uint32_t b_row  = warp_n + (lane & 7) + ((lane >> 4) << 3);
    uint32_t b_colb = ((lane >> 3) & 1) * 16;

    for (int c = 0; c < NC; ++c){
        wait_parity(sb + 8*(c % NST), (c / NST) & 1);
        uint32_t st = sb + 1024 + (c % NST)*STB;
        #pragma unroll
        for (int ks = 0; ks < 4; ++ks){
            uint32_t a_[16], bh[8], bl[8];
            #pragma unroll
            for (int mt = 0; mt < 4; ++mt){
                uint32_t off = swz((a_row + mt*16)*128 + ks*32 + a_colb);
                ldm4(a_ + mt*4, st + off);
            }
            #pragma unroll
            for (int nt = 0; nt < 2; ++nt){
                uint32_t off = swz((b_row + nt*16)*128 + ks*32 + b_colb);
                ldm4(bh + nt*4, st + TILE_B + off);
                if (SPLITB) ldm4(bl + nt*4, st + 2*TILE_B + off);
            }
            #pragma unroll
            for (int mt = 0; mt < 4; ++mt)
                #pragma unroll
                for (int n8 = 0; n8 < 4; ++n8){
                    float* c4 = acc + (mt*4 + n8)*4;
                    int bi = (n8 >> 1)*4 + (n8 & 1)*2;
                    mma16816(c4, a_ + mt*4, bh[bi], bh[bi+1]);
                    if (SPLITB) mma16816(c4, a_ + mt*4, bl[bi], bl[bi+1]);
                }
        }
        __syncthreads();
        if (c + NST < NC) issue(c + NST);
    }
    if (tid == 0){
        #pragma unroll
        for (int s = 0; s < NST; ++s) mbar_inval(sb + 8*s);
    }
}

template<class F>
__device__ __forceinline__ void epi_loop(const float* acc, F f){
    int lane = threadIdx.x & 31, wid = threadIdx.x >> 5;
    int warp_m = (wid >> 2) * 64, warp_n = (wid & 3) * 32;
    int g = lane >> 2, tg = (lane & 3) * 2;
    #pragma unroll
    for (int mt = 0; mt < 4; ++mt)
        #pragma unroll
        for (int n8 = 0; n8 < 4; ++n8){
            const float* c4 = acc + (mt*4 + n8)*4;
            #pragma unroll
            for (int hh = 0; hh < 2; ++hh){
                int r  = warp_m + mt*16 + g + hh*8;
                int cc = warp_n + n8*8 + tg;
                f(r, cc, c4[hh*2], c4[hh*2+1]);
            }
        }
}

// ================= GEMM kernels ============================================
__global__ void __launch_bounds__(256, 2) qkv_tc(
    const __grid_constant__ CUtensorMap mXf,
    const __grid_constant__ CUtensorMap mWq,
    const __grid_constant__ CUtensorMap mWk,
    const __grid_constant__ CUtensorMap mWv)
{
    extern __shared__ char smem[];
    int z = blockIdx.z;
    int row0 = blockIdx.y*128, col0 = blockIdx.x*128;
    const CUtensorMap* pb = (z == 0) ? &mWq : (z == 1) ? &mWk : &mWv;
    float acc[64];
    gemm_main<3,false>(&mXf, pb, pb, 0, row0, 0, col0, HID, acc);

    if (z == 0){
        epi_loop(acc, [&](int r, int cc, float v0, float v1){
            size_t idx = (size_t)(row0 + r)*HID + col0 + cc;
            *(uint32_t*)(g_Qf + idx) = packh2(v0, v1);
        });
    } else if (z == 1){
        epi_loop(acc, [&](int r, int cc, float v0, float v1){
            size_t idx = (size_t)(row0 + r)*HID + col0 + cc;
            f16 h0,l0,h1,l1; split2(v0,h0,l0); split2(v1,h1,l1);
            __half2 hv; hv.x=h0; hv.y=h1;
            __half2 lv; lv.x=l0; lv.y=l1;
            *(__half2*)(g_Kh + idx) = hv;
            *(__half2*)(g_Kl + idx) = lv;
        });
    } else {
        // stage transposed V tile in SMEM, then coalesced write to g_Vth
        f16* Ts = (f16*)(smem + 1024);      // [128 d][136 s-stride]
        epi_loop(acc, [&](int r, int cc, float v0, float v1){
            Ts[cc*136 + r]       = __float2half(v0);
            Ts[(cc+1)*136 + r]   = __float2half(v1);
        });
        __syncthreads();
        int b = row0 >> 10, s0 = row0 & (Ss-1);
        int h = col0 >> 7;
        size_t dbase = ((size_t)(b*NH + h))*Dd;
        for (int it = threadIdx.x; it < 128*16; it += 256){
            int d = it >> 4, seg = it & 15;
            uint4 val = *(const uint4*)(Ts + d*136 + seg*8);
            *(uint4*)(g_Vth + (dbase + d)*Ss + s0 + seg*8) = val;
        }
    }
}

__global__ void __launch_bounds__(256, 2) wo_tc(
    const __grid_constant__ CUtensorMap mCf,
    const __grid_constant__ CUtensorMap mWh, const __grid_constant__ CUtensorMap mWl,
    float* __restrict__ out)
{
    int row0 = blockIdx.y*128, col0 = blockIdx.x*128;
    float acc[64];
    gemm_main<2,true>(&mCf, &mWh, &mWl, 0, row0, 0, col0, HID, acc);
    epi_loop(acc, [&](int r, int cc, float v0, float v1){
        float2 fv; fv.x = v0; fv.y = v1;
        *(float2*)(out + (size_t)(row0 + r)*HID + col0 + cc) = fv;
    });
}

// ================= flash attention kernel ==================================
__global__ void __launch_bounds__(256) flash_tc(
    const __grid_constant__ CUtensorMap mQf,
    const __grid_constant__ CUtensorMap mK64h, const __grid_constant__ CUtensorMap mK64l,
    const __grid_constant__ CUtensorMap mVh)
{
    extern __shared__ char smem[];
    uint32_t sb = smem_u32(smem);
    int tid = threadIdx.x, lane = tid & 31, wid = tid >> 5;
    int bh = blockIdx.y, b = bh >> 4, h = bh & 15;
    int row0 = blockIdx.x * 128;

    const uint32_t QF  = sb + 1024;          // two 16KB halves
    const uint32_t ST0 = QF + 32768;
    // stage: KH0(8K) KH1(8K) KL0(8K) KL1(8K) VH(16K) = 48KB

    if (tid == 0){ mbar_init(sb,1); mbar_init(sb+8,1); mbar_init(sb+16,1); mbar_init(sb+24,1); }
    __syncthreads();

    if (tid == 0){
        mbar_expect(sb+24, 32768u);
        tma2d(QF,        &mQf, h*128,    b*Ss+row0, sb+24);
        tma2d(QF+16384,  &mQf, h*128+64, b*Ss+row0, sb+24);
    }
    auto issue = [&](int j){
        if (tid == 0){
            int st3 = j % 3;
            uint32_t mb = sb + 8*st3;
            mbar_expect(mb, (uint32_t)FSTAGE_B);
            uint32_t st = ST0 + st3*FSTAGE_B;
            tma2d(st,         &mK64h, h*128,    b*Ss+j*64, mb);
            tma2d(st+8192,    &mK64h, h*128+64, b*Ss+j*64, mb);
            tma2d(st+16384,   &mK64l, h*128,    b*Ss+j*64, mb);
            tma2d(st+24576,   &mK64l, h*128+64, b*Ss+j*64, mb);
            tma2d(st+32768,   &mVh,   j*64, bh*128, mb);
        }
    };
    issue(0); issue(1); issue(2);

    float O[64];
    #pragma unroll
    for (int i = 0; i < 64; ++i) O[i] = 0.f;
    float m0 = -1e30f, m1 = -1e30f, l0 = 0.f, l1 = 0.f;
    const float qk = 0.08838834764831845f;

    uint32_t a_row = wid*16 + (lane & 15), a_colb = (lane >> 4)*16;
    uint32_t b_rw  = (lane & 7) + ((lane >> 4) << 3);
    uint32_t b_cb  = ((lane >> 3) & 1)*16;

    wait_parity(sb+24, 0);

    for (int j = 0; j < 16; ++j){
        wait_parity(sb + 8*(j % 3), (j / 3) & 1);
        uint32_t st = ST0 + (j % 3)*FSTAGE_B;

        // ---- S = Q K^T (Q plain, K split)
        float s[32];
        #pragma unroll
        for (int i = 0; i < 32; ++i) s[i] = 0.f;
        #pragma unroll
        for (int ks = 0; ks < 8; ++ks){
            uint32_t qf_[4], kh_[16], kl_[16];
            uint32_t offa = (ks>>2)*16384 + swz(a_row*128 + (ks&3)*32 + a_colb);
            ldm4(qf_, QF + offa);
            #pragma unroll
            for (int nt = 0; nt < 4; ++nt){
                uint32_t offb = (ks>>2)*8192 + swz((b_rw + nt*16)*128 + (ks&3)*32 + b_cb);
                ldm4(kh_ + nt*4, st + offb);
                ldm4(kl_ + nt*4, st + 16384 + offb);
            }
            #pragma unroll
            for (int n8 = 0; n8 < 8; ++n8){
                int bi = (n8 >> 1)*4 + (n8 & 1)*2;
                mma16816(s + n8*4, qf_, kh_[bi], kh_[bi+1]);
                mma16816(s + n8*4, qf_, kl_[bi], kl_[bi+1]);
            }
        }

        // ---- online softmax
        float tm0 = -1e30f, tm1 = -1e30f;
        #pragma unroll
        for (int t = 0; t < 8; ++t){
            s[t*4+0] *= qk; s[t*4+1] *= qk; s[t*4+2] *= qk; s[t*4+3] *= qk;
            tm0 = fmaxf(tm0, fmaxf(s[t*4+0], s[t*4+1]));
            tm1 = fmaxf(tm1, fmaxf(s[t*4+2], s[t*4+3]));
        }
        tm0 = fmaxf(tm0, __shfl_xor_sync(0xffffffffu, tm0, 1));
        tm0 = fmaxf(tm0, __shfl_xor_sync(0xffffffffu, tm0, 2));
        tm1 = fmaxf(tm1, __shfl_xor_sync(0xffffffffu, tm1, 1));
        tm1 = fmaxf(tm1, __shfl_xor_sync(0xffffffffu, tm1, 2));
        float nm0 = fmaxf(m0, tm0), nm1 = fmaxf(m1, tm1);
        float al0 = expf(m0 - nm0), al1 = expf(m1 - nm1);
        float ts0 = 0.f, ts1 = 0.f;
        #pragma unroll
        for (int t = 0; t < 8; ++t){
            s[t*4+0] = expf(s[t*4+0] - nm0); s[t*4+1] = expf(s[t*4+1] - nm0);
            s[t*4+2] = expf(s[t*4+2] - nm1); s[t*4+3] = expf(s[t*4+3] - nm1);
            ts0 += s[t*4+0] + s[t*4+1];
            ts1 += s[t*4+2] + s[t*4+3];
        }
        ts0 += __shfl_xor_sync(0xffffffffu, ts0, 1);
        ts0 += __shfl_xor_sync(0xffffffffu, ts0, 2);
        ts1 += __shfl_xor_sync(0xffffffffu, ts1, 1);
        ts1 += __shfl_xor_sync(0xffffffffu, ts1, 2);
        l0 = l0*al0 + ts0;  l1 = l1*al1 + ts1;
        m0 = nm0;  m1 = nm1;
        #pragma unroll
        for (int t = 0; t < 16; ++t){
            O[t*4+0] *= al0; O[t*4+1] *= al0; O[t*4+2] *= al1; O[t*4+3] *= al1;
        }

        // ---- pack P (plain fp16) into A fragments
        uint32_t ph_[16];
        #pragma unroll
        for (int t = 0; t < 4; ++t){
            ph_[t*4+0] = packh2(s[(2*t)*4+0],   s[(2*t)*4+1]);
            ph_[t*4+1] = packh2(s[(2*t)*4+2],   s[(2*t)*4+3]);
            ph_[t*4+2] = packh2(s[(2*t+1)*4+0], s[(2*t+1)*4+1]);
            ph_[t*4+3] = packh2(s[(2*t+1)*4+2], s[(2*t+1)*4+3]);
        }

        // ---- O += P V (both plain)
        #pragma unroll
        for (int ks = 0; ks < 4; ++ks){
            uint32_t vh_[32];
            #pragma unroll
            for (int nt = 0; nt < 8; ++nt){
                uint32_t offv = swz((b_rw + nt*16)*128 + ks*32 + b_cb);
                ldm4(vh_ + nt*4, st + 32768 + offv);
            }
            #pragma unroll
            for (int n8 = 0; n8 < 16; ++n8){
                int bi = (n8 >> 1)*4 + (n8 & 1)*2;
                mma16816(O + n8*4, ph_ + ks*4, vh_[bi], vh_[bi+1]);
            }
        }
        __syncthreads();
        if (j + 3 < 16) issue(j + 3);
    }

    // ---- epilogue: normalize, fuse GSA blend, write Cf (plain fp16)
    float inv0 = 1.f / l0, inv1 = 1.f / l1;
    float blend = g_blend, ob = 1.f - blend;
    int g = lane >> 2, tg2 = (lane & 3)*2;
    int s0g = row0 + wid*16 + g, s1g = s0g + 8;

    float c0[8], c1[8];
    float den0 = 1e-8f, den1 = 1e-8f;
    #pragma unroll
    for (int n = 0; n < 8; ++n){
        float a = g_amp[h*8 + n], kss = g_ksum[bh*8 + n];
        c0[n] = g_qa[((size_t)bh*Ss + s0g)*8 + n] * a;  den0 += c0[n]*kss;
        c1[n] = g_qa[((size_t)bh*Ss + s1g)*8 + n] * a;  den1 += c1[n]*kss;
    }
    float id0 = blend/den0, id1 = blend/den1;

    size_t base0 = ((size_t)(b*Ss + s0g))*HID + h*128;
    size_t base1 = ((size_t)(b*Ss + s1g))*HID + h*128;
    #pragma unroll
    for (int n8 = 0; n8 < 16; ++n8){
        int d = n8*8 + tg2;
        float num00=0.f, num01=0.f, num10=0.f, num11=0.f;
        #pragma unroll
        for (int n = 0; n < 8; ++n){
            float2 kv = *(const float2*)(g_kvmat + ((size_t)bh*8 + n)*128 + d);
            num00 += c0[n]*kv.x;  num01 += c0[n]*kv.y;
            num10 += c1[n]*kv.x;  num11 += c1[n]*kv.y;
        }
        float v00 = ob*O[n8*4+0]*inv0 + id0*num00;
        float v01 = ob*O[n8*4+1]*inv0 + id0*num01;
        float v10 = ob*O[n8*4+2]*inv1 + id1*num10;
        float v11 = ob*O[n8*4+3]*inv1 + id1*num11;
        *(uint32_t*)(g_Cf + base0 + d) = packh2(v00, v01);
        *(uint32_t*)(g_Cf + base1 + d) = packh2(v10, v11);
    }
    __syncthreads();
    if (tid == 0){ mbar_inval(sb); mbar_inval(sb+8); mbar_inval(sb+16); mbar_inval(sb+24); }
}

// ================= conversion kernels ======================================
__global__ void convert_x_kernel(const float* __restrict__ X){
    int i = (blockIdx.x*256 + threadIdx.x) * 4;
    float4 v = *(const float4*)(X + i);
    *(uint32_t*)(g_Xf + i)     = packh2(v.x, v.y);
    *(uint32_t*)(g_Xf + i + 2) = packh2(v.z, v.w);
}

__global__ void tsplit_kernel(const float* __restrict__ Wq, const float* __restrict__ Wk,
                              const float* __restrict__ Wv, const float* __restrict__ Wo){
    __shared__ float t[32][33];
    int z = blockIdx.z;
    const float* in = (z == 0) ? Wq : (z == 1) ? Wk : (z == 2) ? Wv : Wo;
    int n0 = blockIdx.x*32, k0 = blockIdx.y*32;
    int tx = threadIdx.x, ty = threadIdx.y;
    #pragma unroll
    for (int j = 0; j < 4; ++j)
        t[ty + 8*j][tx] = in[(size_t)(k0 + ty + 8*j)*HID + n0 + tx];
    __syncthreads();
    if (z < 3){
        f16* oh = (z == 0) ? g_Wqt : (z == 1) ? g_Wkt : g_Wvt;
        #pragma unroll
        for (int j = 0; j < 4; ++j){
            float v = t[tx][ty + 8*j];
            oh[(size_t)(n0 + ty + 8*j)*HID + k0 + tx] = __float2half(v);
        }
    } else {
        #pragma unroll
        for (int j = 0; j < 4; ++j){
            float v = t[tx][ty + 8*j];
            size_t o = (size_t)(n0 + ty + 8*j)*HID + k0 + tx;
            split2(v, g_Wot_h[o], g_Wot_l[o]);
        }
    }
}

// ---------------- prep ------------------------------------------------------
__global__ void prep_kernel(const float* __restrict__ pos_in,
                            const float* __restrict__ dir_in,
                            const float* __restrict__ ls_in,
                            const float* __restrict__ la_in,
                            const float* __restrict__ dstr,
                            const float* __restrict__ gstr)
{
    int i = threadIdx.x;
    if (i < NH*NS) {
        const float* p = pos_in + (size_t)i*Dd;
        const float* dv = dir_in + (size_t)i*Dd;
        float np = 0.f, nd = 0.f;
        for (int d = 0; d < Dd; ++d) { np += p[d]*p[d]; nd += dv[d]*dv[d]; }
        float pscale = 3.39411254969543f / (sqrtf(np) + 1e-12f);
        float dscale = 1.0f / (sqrtf(nd) + 1e-12f);
        float psq = 0.f, pdd = 0.f;
        for (int d = 0; d < Dd; ++d) {
            float ps = p[d]*pscale, du = dv[d]*dscale;
            g_pos[(size_t)i*Dd + d] = ps;
            g_dir[(size_t)i*Dd + d] = du;
            psq += ps*ps;  pdd += ps*du;
        }
        g_possq[i] = psq;  g_pdd[i] = pdd;
        float sc = expf(ls_in[i]);
        sc = fminf(fmaxf(sc, 0.3f), 1.2f);
        g_inv2s2[i] = 0.5f / (sc*sc);
    }
    __syncthreads();
    if (i < NH) {
        float m = -1e30f;
        for (int n = 0; n < NS; ++n) m = fmaxf(m, la_in[i*NS+n]);
        float s = 0.f, e[NS];
        for (int n = 0; n < NS; ++n) { e[n] = expf(la_in[i*NS+n]-m); s += e[n]; }
        for (int n = 0; n < NS; ++n) g_amp[i*NS+n] = e[n]/s;
    }
    if (i == 0) {
        g_ds = 1.0f / (1.0f + expf(-dstr[0]));
        float gsa = 1.0f / (1.0f + expf(-gstr[0]));
        g_blend = fminf(0.05f, gsa*0.1f);
    }
}

// ---------------- affinities (warp per token) -------------------------------
__global__ void __launch_bounds__(256) affinity2()
{
    int gidx = blockIdx.x*8 + (threadIdx.x >> 5);   // 0..65535
    int lane = threadIdx.x & 31;
    int z = gidx >> 15;
    int rem = gidx & 32767;
    int bh = rem >> 10, s = rem & 1023;
    int b = bh >> 4, h = bh & 15;
    size_t base = ((size_t)(b*Ss + s))*HID + h*128;
    float t[4];
    #pragma unroll
    for (int k = 0; k < 4; ++k){
        int d = k*32 + lane;
        t[k] = z ? (__half2float(g_Kh[base+d]) + __half2float(g_Kl[base+d]))
                 : __half2float(g_Qf[base+d]);
    }
    float tsq = wsum(t[0]*t[0] + t[1]*t[1] + t[2]*t[2] + t[3]*t[3]);
    float ds = g_ds;
    float* out = (z ? g_ka : g_qa) + ((size_t)bh*Ss + s)*NS;
    #pragma unroll
    for (int n = 0; n < NS; ++n){
        int hn = h*NS + n;
        float tp = 0.f, td = 0.f;
        #pragma unroll
        for (int k = 0; k < 4; ++k){
            int d = k*32 + lane;
            tp += t[k]*g_pos[hn*Dd + d];
            td += t[k]*g_dir[hn*Dd + d];
        }
        tp = wsum(tp);  td = wsum(td);
        if (lane == n){
            float dist2 = fmaxf(tsq - 2.0f*tp + g_possq[hn], 0.0f);
            float proj  = td - g_pdd[hn];
            float perp2 = fmaxf(dist2 - proj*proj, 0.0f);
            float inv   = g_inv2s2[hn];
            out[n] = (1.0f-ds)*expf(-dist2*inv) + ds*expf(-perp2*inv);
        }
    }
}

// ---------------- GSA linear-attention precompute (2-phase) ----------------
__global__ void gsa_kv_part()
{
    int ch = blockIdx.x, bh = blockIdx.y;
    int d = threadIdx.x;
    const f16* vb = g_Vth + (size_t)bh*Dd*Ss + (size_t)d*Ss;
    const float* ka = g_ka + (size_t)bh*Ss*NS;
    float acc[NS];
    #pragma unroll
    for (int n = 0; n < NS; ++n) acc[n] = 0.f;
    int s0 = ch*128;
    for (int s = s0; s < s0+128; ++s){
        float vv = __half2float(vb[s]);
        #pragma unroll
        for (int n = 0; n < NS; ++n) acc[n] += ka[s*NS+n]*vv;
    }
    #pragma unroll
    for (int n = 0; n < NS; ++n)
        g_kvp[(((size_t)ch*BH + bh)*NS + n)*Dd + d] = acc[n];
    if (d < NS){
        float kssum = 0.f;
        for (int s = s0; s < s0+128; ++s) kssum += ka[s*NS+d];
        g_ksp[(ch*BH + bh)*NS + d] = kssum;
    }
}

__global__ void gsa_red()
{
    int bh = blockIdx.x, d = threadIdx.x;
    #pragma unroll
    for (int n = 0; n < NS; ++n){
        float t = 0.f;
        #pragma unroll
        for (int ch = 0; ch < 8; ++ch)
            t += g_kvp[(((size_t)ch*BH + bh)*NS + n)*Dd + d];
        g_kvmat[((size_t)bh*NS + n)*Dd + d] = t;
    }
    if (d < NS){
        float t = 0.f;
        #pragma unroll
        for (int ch = 0; ch < 8; ++ch) t += g_ksp[(ch*BH + bh)*NS + d];
        g_ksum[bh*NS + d] = t;
    }
}

// ---------------- host: tensormap construction -----------------------------
typedef CUresult (*TMapEncode)(CUtensorMap*, CUtensorMapDataType, cuuint32_t, void*,
    const cuuint64_t*, const cuuint64_t*, const cuuint32_t*, const cuuint32_t*,
    CUtensorMapInterleave, CUtensorMapSwizzle, CUtensorMapL2promotion, CUtensorMapFloatOOBfill);

static void make_map(TMapEncode enc, CUtensorMap* m, void* base, uint64_t d0, uint64_t d1,
                     uint32_t b0, uint32_t b1){
    cuuint64_t dims[2]    = {d0, d1};
    cuuint64_t strides[1] = {d0 * 2};
    cuuint32_t box[2]     = {b0, b1};
    cuuint32_t es[2]      = {1, 1};
    enc(m, CU_TENSOR_MAP_DATA_TYPE_FLOAT16, 2, base, dims, strides, box, es,
        CU_TENSOR_MAP_INTERLEAVE_NONE, CU_TENSOR_MAP_SWIZZLE_128B,
        CU_TENSOR_MAP_L2_PROMOTION_L2_128B, CU_TENSOR_MAP_FLOAT_OOB_FILL_NONE);
}

// ---------------- launch ----------------------------------------------------
extern "C" void kernel_launch(void* const* d_in, const int* in_sizes, int n_in,
                              void* d_out, int out_size)
{
    const float* X   = (const float*)d_in[0];
    const float* Wq  = (const float*)d_in[1];
    const float* Wk  = (const float*)d_in[2];
    const float* Wv  = (const float*)d_in[3];
    const float* Wo  = (const float*)d_in[4];
    const float* pos = (const float*)d_in[5];
    const float* dir = (const float*)d_in[6];
    const float* ls  = (const float*)d_in[7];
    const float* la  = (const float*)d_in[8];
    const float* dstr= (const float*)d_in[9];
    const float* gstr= (const float*)d_in[10];
    float* out = (float*)d_out;

    void* fp = nullptr;
    cudaDriverEntryPointQueryResult qr;
#if CUDART_VERSION >= 12050
    cudaGetDriverEntryPointByVersion("cuTensorMapEncodeTiled", &fp, 12000, cudaEnableDefault, &qr);
#else
    cudaGetDriverEntryPoint("cuTensorMapEncodeTiled", &fp, cudaEnableDefault, &qr);
#endif
    TMapEncode enc = (TMapEncode)fp;

    void *pXf,*pWq,*pWk,*pWv,*pWoh,*pWol;
    void *pQf,*pKh,*pKl,*pVh,*pCf;
    cudaGetSymbolAddress(&pXf, g_Xf);
    cudaGetSymbolAddress(&pWq, g_Wqt);
    cudaGetSymbolAddress(&pWk, g_Wkt);
    cudaGetSymbolAddress(&pWv, g_Wvt);
    cudaGetSymbolAddress(&pWoh, g_Wot_h); cudaGetSymbolAddress(&pWol, g_Wot_l);
    cudaGetSymbolAddress(&pQf, g_Qf);
    cudaGetSymbolAddress(&pKh, g_Kh);   cudaGetSymbolAddress(&pKl, g_Kl);
    cudaGetSymbolAddress(&pVh, g_Vth);
    cudaGetSymbolAddress(&pCf, g_Cf);

    CUtensorMap mXf,mWq,mWk,mWv,mWoh,mWol;
    CUtensorMap mQf,mK64h,mK64l,mVh,mCf;
    make_map(enc,&mXf,pXf,HID,Mm,64,128);
    make_map(enc,&mWq,pWq,HID,HID,64,128);
    make_map(enc,&mWk,pWk,HID,HID,64,128);
    make_map(enc,&mWv,pWv,HID,HID,64,128);
    make_map(enc,&mWoh,pWoh,HID,HID,64,128);  make_map(enc,&mWol,pWol,HID,HID,64,128);
    make_map(enc,&mQf,pQf,HID,Mm,64,128);
    make_map(enc,&mK64h,pKh,HID,Mm,64,64);    make_map(enc,&mK64l,pKl,HID,Mm,64,64);
    make_map(enc,&mVh,pVh,Ss,(uint64_t)BH*Dd,64,128);
    make_map(enc,&mCf,pCf,HID,Mm,64,128);

    cudaFuncSetAttribute(qkv_tc,   cudaFuncAttributeMaxDynamicSharedMemorySize, SMEM_SZ);
    cudaFuncSetAttribute(wo_tc,    cudaFuncAttributeMaxDynamicSharedMemorySize, SMEM_SZ);
    cudaFuncSetAttribute(flash_tc, cudaFuncAttributeMaxDynamicSharedMemorySize, SMEM_FL);

    prep_kernel<<<1, 128>>>(pos, dir, ls, la, dstr, gstr);
    convert_x_kernel<<<(Mm*HID)/1024, 256>>>(X);
    tsplit_kernel<<<dim3(HID/32, HID/32, 4), dim3(32, 8)>>>(Wq, Wk, Wv, Wo);
    qkv_tc<<<dim3(HID/128, Mm/128, 3), 256, SMEM_SZ>>>(mXf,mWq,mWk,mWv);
    affinity2<<<(Ss*BH*2)/8, 256>>>();
    gsa_kv_part<<<dim3(8, BH), 128>>>();
    gsa_red<<<BH, 128>>>();
    flash_tc<<<dim3(Ss/128, BH), 256, SMEM_FL>>>(mQf,mK64h,mK64l,mVh);
    wo_tc<<<dim3(HID/128, Mm/128, 1), 256, SMEM_SZ>>>(mCf,mWoh,mWol,out);
}

// round 13
// speedup vs baseline: 6.8159x; 1.1564x over previous
#include <cuda_runtime.h>
#include <cuda.h>
#include <cuda_fp16.h>
#include <math.h>
#include <stdint.h>

#define Bb 2
#define Ss 1024
#define HID 2048
#define NH 16
#define NS 8
#define Dd 128
#define Mm (Bb*Ss)      // 2048
#define BH (Bb*NH)      // 32

typedef __half f16;

// ---------------- scratch (device globals; no allocation allowed) ----------
__device__ float g_qa[(size_t)BH*Ss*NS];
__device__ float g_ka[(size_t)BH*Ss*NS];
__device__ float g_kvmat[(size_t)BH*NS*Dd];
__device__ float g_ksum[BH*NS];
__device__ float g_kvp[(size_t)8*BH*NS*Dd];
__device__ float g_ksp[8*BH*NS];
__device__ float g_pos[NH*NS*Dd];
__device__ float g_dir[NH*NS*Dd];
__device__ float g_possq[NH*NS];
__device__ float g_pdd[NH*NS];
__device__ float g_inv2s2[NH*NS];
__device__ float g_amp[NH*NS];
__device__ float g_ds;
__device__ float g_blend;

// fp16 operand arrays: everything plain now
__device__ f16 g_Xf[(size_t)Mm*HID];
__device__ f16 g_Wqt[(size_t)HID*HID];
__device__ f16 g_Wkt[(size_t)HID*HID];
__device__ f16 g_Wvt[(size_t)HID*HID];
__device__ f16 g_Wot[(size_t)HID*HID];
__device__ f16 g_Qf[(size_t)Mm*HID];
__device__ f16 g_Kf[(size_t)Mm*HID];
__device__ f16 g_Vth[(size_t)BH*Dd*Ss];            // [bh][d][s]
__device__ f16 g_Cf[(size_t)Mm*HID];

__device__ __forceinline__ uint32_t packh2(float x, float y){
    __half2 t = __floats2half2_rn(x, y);
    return *(uint32_t*)&t;
}

// ================= low-level helpers =======================================
__device__ __forceinline__ uint32_t smem_u32(const void* p){
    uint32_t a;
    asm("{ .reg .u64 t; cvta.to.shared.u64 t, %1; cvt.u32.u64 %0, t; }" : "=r"(a) : "l"(p));
    return a;
}
__device__ __forceinline__ void mbar_init(uint32_t a, uint32_t cnt){
    asm volatile("mbarrier.init.shared.b64 [%0], %1;" :: "r"(a), "r"(cnt) : "memory");
}
__device__ __forceinline__ void mbar_inval(uint32_t a){
    asm volatile("mbarrier.inval.shared.b64 [%0];" :: "r"(a) : "memory");
}
__device__ __forceinline__ void mbar_expect(uint32_t a, uint32_t bytes){
    asm volatile("mbarrier.arrive.expect_tx.shared.b64 _, [%0], %1;" :: "r"(a), "r"(bytes) : "memory");
}
__device__ __forceinline__ void wait_parity(uint32_t mbar, uint32_t ph){
    uint32_t done;
    asm volatile(
        "{\n\t.reg .pred p;\n\t"
        "mbarrier.try_wait.parity.acquire.cta.shared::cta.b64 p, [%1], %2;\n\t"
        "selp.b32 %0, 1, 0, p;\n\t}"
        : "=r"(done) : "r"(mbar), "r"(ph) : "memory");
    if (!done) {
        asm volatile(
            "{\n\t.reg .pred P1;\n\t"
            "WL%=:\n\t"
            "mbarrier.try_wait.parity.acquire.cta.shared::cta.b64 P1, [%0], %1, 0x989680;\n\t"
            "@P1 bra.uni WD%=;\n\t"
            "bra.uni WL%=;\n\t"
            "WD%=:\n\t}"
            :: "r"(mbar), "r"(ph) : "memory");
    }
}
__device__ __forceinline__ void tma2d(uint32_t dst, const CUtensorMap* m, int x, int y, uint32_t mbar){
    asm volatile(
        "cp.async.bulk.tensor.2d.shared::cta.global.tile.mbarrier::complete_tx::bytes "
        "[%0], [%1, {%2, %3}], [%4];"
        :: "r"(dst), "l"(m), "r"(x), "r"(y), "r"(mbar) : "memory");
}
__device__ __forceinline__ void ldm4(uint32_t* r, uint32_t a){
    asm volatile("ldmatrix.sync.aligned.m8n8.x4.shared.b16 {%0,%1,%2,%3}, [%4];"
        : "=r"(r[0]),"=r"(r[1]),"=r"(r[2]),"=r"(r[3]) : "r"(a));
}
__device__ __forceinline__ void mma16816(float* c, const uint32_t* a, uint32_t b0, uint32_t b1){
    asm volatile("mma.sync.aligned.m16n8k16.row.col.f32.f16.f16.f32 "
        "{%0,%1,%2,%3}, {%4,%5,%6,%7}, {%8,%9}, {%0,%1,%2,%3};"
        : "+f"(c[0]),"+f"(c[1]),"+f"(c[2]),"+f"(c[3])
        : "r"(a[0]),"r"(a[1]),"r"(a[2]),"r"(a[3]), "r"(b0),"r"(b1));
}
__device__ __forceinline__ uint32_t swz(uint32_t x){ return x ^ ((x>>3)&0x70); }
__device__ __forceinline__ float wsum(float v){
    #pragma unroll
    for (int o = 16; o; o >>= 1) v += __shfl_xor_sync(0xffffffffu, v, o);
    return v;
}

#define TILE_B    16384
#define SMEM_SZ   99328                          // 3 x 32K stages (+1K)
#define FSTAGE_B  32768                          // Kf(16K) Vh(16K)
#define SMEM_FL   (1024 + 32768 + 2*FSTAGE_B)    // Q(32K) + 2 stages = 97K -> 2 CTAs/SM

// ---------------- 128x128 CTA GEMM mainloop (256 threads, 8 warps) ---------
// C[128,128] += A[128,K] * B[128,K]^T   (plain fp16 both sides)
__device__ __forceinline__ void gemm_main(
    const CUtensorMap* mA, const CUtensorMap* mB,
    int ax0, int ay, int bx0, int by, int K, float* acc)
{
    extern __shared__ char smem[];
    uint32_t sb = smem_u32(smem);
    int tid = threadIdx.x, lane = tid & 31, wid = tid >> 5;
    int warp_m = (wid >> 2) * 64, warp_n = (wid & 3) * 32;

    if (tid == 0){ mbar_init(sb,1); mbar_init(sb+8,1); mbar_init(sb+16,1); }
    __syncthreads();

    #pragma unroll
    for (int i = 0; i < 64; ++i) acc[i] = 0.f;

    int NC = K / 64;

    auto issue = [&](int c){
        if (tid == 0){
            int st = c % 3;
            uint32_t mb = sb + 8*st;
            mbar_expect(mb, 2*TILE_B);
            uint32_t dst = sb + 1024 + st*2*TILE_B;
            tma2d(dst,          mA, ax0 + c*64, ay, mb);
            tma2d(dst + TILE_B, mB, bx0 + c*64, by, mb);
        }
    };
    issue(0);
    if (NC > 1) issue(1);
    if (NC > 2) issue(2);

    uint32_t a_row  = warp_m + (lane & 15);
    uint32_t a_colb = (lane >> 4) * 16;
    uint32_t b_row  = warp_n + (lane & 7) + ((lane >> 4) << 3);
    uint32_t b_colb = ((lane >> 3) & 1) * 16;

    for (int c = 0; c < NC; ++c){
        wait_parity(sb + 8*(c % 3), (c / 3) & 1);
        uint32_t st = sb + 1024 + (c % 3)*2*TILE_B;
        #pragma unroll
        for (int ks = 0; ks < 4; ++ks){
            uint32_t a_[16], bh[8];
            #pragma unroll
            for (int mt = 0; mt < 4; ++mt){
                uint32_t off = swz((a_row + mt*16)*128 + ks*32 + a_colb);
                ldm4(a_ + mt*4, st + off);
            }
            #pragma unroll
            for (int nt = 0; nt < 2; ++nt){
                uint32_t off = swz((b_row + nt*16)*128 + ks*32 + b_colb);
                ldm4(bh + nt*4, st + TILE_B + off);
            }
            #pragma unroll
            for (int mt = 0; mt < 4; ++mt)
                #pragma unroll
                for (int n8 = 0; n8 < 4; ++n8){
                    float* c4 = acc + (mt*4 + n8)*4;
                    int bi = (n8 >> 1)*4 + (n8 & 1)*2;
                    mma16816(c4, a_ + mt*4, bh[bi], bh[bi+1]);
                }
        }
        __syncthreads();
        if (c + 3 < NC) issue(c + 3);
    }
    if (tid == 0){ mbar_inval(sb); mbar_inval(sb+8); mbar_inval(sb+16); }
}

template<class F>
__device__ __forceinline__ void epi_loop(const float* acc, F f){
    int lane = threadIdx.x & 31, wid = threadIdx.x >> 5;
    int warp_m = (wid >> 2) * 64, warp_n = (wid & 3) * 32;
    int g = lane >> 2, tg = (lane & 3) * 2;
    #pragma unroll
    for (int mt = 0; mt < 4; ++mt)
        #pragma unroll
        for (int n8 = 0; n8 < 4; ++n8){
            const float* c4 = acc + (mt*4 + n8)*4;
            #pragma unroll
            for (int hh = 0; hh < 2; ++hh){
                int r  = warp_m + mt*16 + g + hh*8;
                int cc = warp_n + n8*8 + tg;
                f(r, cc, c4[hh*2], c4[hh*2+1]);
            }
        }
}

// ================= GEMM kernels ============================================
__global__ void __launch_bounds__(256, 2) qkv_tc(
    const __grid_constant__ CUtensorMap mXf,
    const __grid_constant__ CUtensorMap mWq,
    const __grid_constant__ CUtensorMap mWk,
    const __grid_constant__ CUtensorMap mWv)
{
    extern __shared__ char smem[];
    int z = blockIdx.z;
    int row0 = blockIdx.y*128, col0 = blockIdx.x*128;
    const CUtensorMap* pb = (z == 0) ? &mWq : (z == 1) ? &mWk : &mWv;
    float acc[64];
    gemm_main(&mXf, pb, 0, row0, 0, col0, HID, acc);

    if (z == 0){
        epi_loop(acc, [&](int r, int cc, float v0, float v1){
            size_t idx = (size_t)(row0 + r)*HID + col0 + cc;
            *(uint32_t*)(g_Qf + idx) = packh2(v0, v1);
        });
    } else if (z == 1){
        epi_loop(acc, [&](int r, int cc, float v0, float v1){
            size_t idx = (size_t)(row0 + r)*HID + col0 + cc;
            *(uint32_t*)(g_Kf + idx) = packh2(v0, v1);
        });
    } else {
        // stage transposed V tile in SMEM, then coalesced write to g_Vth
        f16* Ts = (f16*)(smem + 1024);      // [128 d][136 s-stride]
        epi_loop(acc, [&](int r, int cc, float v0, float v1){
            Ts[cc*136 + r]       = __float2half(v0);
            Ts[(cc+1)*136 + r]   = __float2half(v1);
        });
        __syncthreads();
        int b = row0 >> 10, s0 = row0 & (Ss-1);
        int h = col0 >> 7;
        size_t dbase = ((size_t)(b*NH + h))*Dd;
        for (int it = threadIdx.x; it < 128*16; it += 256){
            int d = it >> 4, seg = it & 15;
            uint4 val = *(const uint4*)(Ts + d*136 + seg*8);
            *(uint4*)(g_Vth + (dbase + d)*Ss + s0 + seg*8) = val;
        }
    }
}

__global__ void __launch_bounds__(256, 2) wo_tc(
    const __grid_constant__ CUtensorMap mCf,
    const __grid_constant__ CUtensorMap mWo,
    float* __restrict__ out)
{
    int row0 = blockIdx.y*128, col0 = blockIdx.x*128;
    float acc[64];
    gemm_main(&mCf, &mWo, 0, row0, 0, col0, HID, acc);
    epi_loop(acc, [&](int r, int cc, float v0, float v1){
        float2 fv; fv.x = v0; fv.y = v1;
        *(float2*)(out + (size_t)(row0 + r)*HID + col0 + cc) = fv;
    });
}

// ================= flash attention kernel ==================================
// 2 CTAs/SM, 2-stage; K and V plain fp16
__global__ void __launch_bounds__(256, 2) flash_tc(
    const __grid_constant__ CUtensorMap mQf,
    const __grid_constant__ CUtensorMap mK64,
    const __grid_constant__ CUtensorMap mVh)
{
    extern __shared__ char smem[];
    uint32_t sb = smem_u32(smem);
    int tid = threadIdx.x, lane = tid & 31, wid = tid >> 5;
    int bh = blockIdx.y, b = bh >> 4, h = bh & 15;
    int row0 = blockIdx.x * 128;

    const uint32_t QF  = sb + 1024;          // two 16KB halves
    const uint32_t ST0 = QF + 32768;
    // stage: KF0(8K) KF1(8K) VH(16K) = 32KB

    if (tid == 0){ mbar_init(sb,1); mbar_init(sb+8,1); mbar_init(sb+16,1); }
    __syncthreads();

    if (tid == 0){
        mbar_expect(sb+16, 32768u);
        tma2d(QF,        &mQf, h*128,    b*Ss+row0, sb+16);
        tma2d(QF+16384,  &mQf, h*128+64, b*Ss+row0, sb+16);
    }
    auto issue = [&](int j){
        if (tid == 0){
            uint32_t mb = sb + 8*(j&1);
            mbar_expect(mb, (uint32_t)FSTAGE_B);
            uint32_t st = ST0 + (j&1)*FSTAGE_B;
            tma2d(st,         &mK64, h*128,    b*Ss+j*64, mb);
            tma2d(st+8192,    &mK64, h*128+64, b*Ss+j*64, mb);
            tma2d(st+16384,   &mVh,  j*64, bh*128, mb);
        }
    };
    issue(0); issue(1);

    float O[64];
    #pragma unroll
    for (int i = 0; i < 64; ++i) O[i] = 0.f;
    float m0 = -1e30f, m1 = -1e30f, l0 = 0.f, l1 = 0.f;
    const float qk = 0.08838834764831845f;

    uint32_t a_row = wid*16 + (lane & 15), a_colb = (lane >> 4)*16;
    uint32_t b_rw  = (lane & 7) + ((lane >> 4) << 3);
    uint32_t b_cb  = ((lane >> 3) & 1)*16;

    wait_parity(sb+16, 0);

    for (int j = 0; j < 16; ++j){
        wait_parity(sb + 8*(j&1), (j>>1)&1);
        uint32_t st = ST0 + (j&1)*FSTAGE_B;

        // ---- S = Q K^T (both plain)
        float s[32];
        #pragma unroll
        for (int i = 0; i < 32; ++i) s[i] = 0.f;
        #pragma unroll
        for (int ks = 0; ks < 8; ++ks){
            uint32_t qf_[4], kh_[16];
            uint32_t offa = (ks>>2)*16384 + swz(a_row*128 + (ks&3)*32 + a_colb);
            ldm4(qf_, QF + offa);
            #pragma unroll
            for (int nt = 0; nt < 4; ++nt){
                uint32_t offb = (ks>>2)*8192 + swz((b_rw + nt*16)*128 + (ks&3)*32 + b_cb);
                ldm4(kh_ + nt*4, st + offb);
            }
            #pragma unroll
            for (int n8 = 0; n8 < 8; ++n8){
                int bi = (n8 >> 1)*4 + (n8 & 1)*2;
                mma16816(s + n8*4, qf_, kh_[bi], kh_[bi+1]);
            }
        }

        // ---- online softmax
        float tm0 = -1e30f, tm1 = -1e30f;
        #pragma unroll
        for (int t = 0; t < 8; ++t){
            s[t*4+0] *= qk; s[t*4+1] *= qk; s[t*4+2] *= qk; s[t*4+3] *= qk;
            tm0 = fmaxf(tm0, fmaxf(s[t*4+0], s[t*4+1]));
            tm1 = fmaxf(tm1, fmaxf(s[t*4+2], s[t*4+3]));
        }
        tm0 = fmaxf(tm0, __shfl_xor_sync(0xffffffffu, tm0, 1));
        tm0 = fmaxf(tm0, __shfl_xor_sync(0xffffffffu, tm0, 2));
        tm1 = fmaxf(tm1, __shfl_xor_sync(0xffffffffu, tm1, 1));
        tm1 = fmaxf(tm1, __shfl_xor_sync(0xffffffffu, tm1, 2));
        float nm0 = fmaxf(m0, tm0), nm1 = fmaxf(m1, tm1);
        float al0 = expf(m0 - nm0), al1 = expf(m1 - nm1);
        float ts0 = 0.f, ts1 = 0.f;
        #pragma unroll
        for (int t = 0; t < 8; ++t){
            s[t*4+0] = expf(s[t*4+0] - nm0); s[t*4+1] = expf(s[t*4+1] - nm0);
            s[t*4+2] = expf(s[t*4+2] - nm1); s[t*4+3] = expf(s[t*4+3] - nm1);
            ts0 += s[t*4+0] + s[t*4+1];
            ts1 += s[t*4+2] + s[t*4+3];
        }
        ts0 += __shfl_xor_sync(0xffffffffu, ts0, 1);
        ts0 += __shfl_xor_sync(0xffffffffu, ts0, 2);
        ts1 += __shfl_xor_sync(0xffffffffu, ts1, 1);
        ts1 += __shfl_xor_sync(0xffffffffu, ts1, 2);
        l0 = l0*al0 + ts0;  l1 = l1*al1 + ts1;
        m0 = nm0;  m1 = nm1;
        #pragma unroll
        for (int t = 0; t < 16; ++t){
            O[t*4+0] *= al0; O[t*4+1] *= al0; O[t*4+2] *= al1; O[t*4+3] *= al1;
        }

        // ---- pack P (plain fp16) into A fragments
        uint32_t ph_[16];
        #pragma unroll
        for (int t = 0; t < 4; ++t){
            ph_[t*4+0] = packh2(s[(2*t)*4+0],   s[(2*t)*4+1]);
            ph_[t*4+1] = packh2(s[(2*t)*4+2],   s[(2*t)*4+3]);
            ph_[t*4+2] = packh2(s[(2*t+1)*4+0], s[(2*t+1)*4+1]);
            ph_[t*4+3] = packh2(s[(2*t+1)*4+2], s[(2*t+1)*4+3]);
        }

        // ---- O += P V (both plain)
        #pragma unroll
        for (int ks = 0; ks < 4; ++ks){
            uint32_t vh_[32];
            #pragma unroll
            for (int nt = 0; nt < 8; ++nt){
                uint32_t offv = swz((b_rw + nt*16)*128 + ks*32 + b_cb);
                ldm4(vh_ + nt*4, st + 16384 + offv);
            }
            #pragma unroll
            for (int n8 = 0; n8 < 16; ++n8){
                int bi = (n8 >> 1)*4 + (n8 & 1)*2;
                mma16816(O + n8*4, ph_ + ks*4, vh_[bi], vh_[bi+1]);
            }
        }
        __syncthreads();
        if (j + 2 < 16) issue(j + 2);
    }

    // ---- epilogue: normalize, fuse GSA blend, write Cf (plain fp16)
    float inv0 = 1.f / l0, inv1 = 1.f / l1;
    float blend = g_blend, ob = 1.f - blend;
    int g = lane >> 2, tg2 = (lane & 3)*2;
    int s0g = row0 + wid*16 + g, s1g = s0g + 8;

    float c0[8], c1[8];
    float den0 = 1e-8f, den1 = 1e-8f;
    #pragma unroll
    for (int n = 0; n < 8; ++n){
        float a = g_amp[h*8 + n], kss = g_ksum[bh*8 + n];
        c0[n] = g_qa[((size_t)bh*Ss + s0g)*8 + n] * a;  den0 += c0[n]*kss;
        c1[n] = g_qa[((size_t)bh*Ss + s1g)*8 + n] * a;  den1 += c1[n]*kss;
    }
    float id0 = blend/den0, id1 = blend/den1;

    size_t base0 = ((size_t)(b*Ss + s0g))*HID + h*128;
    size_t base1 = ((size_t)(b*Ss + s1g))*HID + h*128;
    #pragma unroll
    for (int n8 = 0; n8 < 16; ++n8){
        int d = n8*8 + tg2;
        float num00=0.f, num01=0.f, num10=0.f, num11=0.f;
        #pragma unroll
        for (int n = 0; n < 8; ++n){
            float2 kv = *(const float2*)(g_kvmat + ((size_t)bh*8 + n)*128 + d);
            num00 += c0[n]*kv.x;  num01 += c0[n]*kv.y;
            num10 += c1[n]*kv.x;  num11 += c1[n]*kv.y;
        }
        float v00 = ob*O[n8*4+0]*inv0 + id0*num00;
        float v01 = ob*O[n8*4+1]*inv0 + id0*num01;
        float v10 = ob*O[n8*4+2]*inv1 + id1*num10;
        float v11 = ob*O[n8*4+3]*inv1 + id1*num11;
        *(uint32_t*)(g_Cf + base0 + d) = packh2(v00, v01);
        *(uint32_t*)(g_Cf + base1 + d) = packh2(v10, v11);
    }
    __syncthreads();
    if (tid == 0){ mbar_inval(sb); mbar_inval(sb+8); mbar_inval(sb+16); }
}

// ================= conversion kernels ======================================
__global__ void convert_x_kernel(const float* __restrict__ X){
    int i = (blockIdx.x*256 + threadIdx.x) * 4;
    float4 v = *(const float4*)(X + i);
    *(uint32_t*)(g_Xf + i)     = packh2(v.x, v.y);
    *(uint32_t*)(g_Xf + i + 2) = packh2(v.z, v.w);
}

__global__ void tsplit_kernel(const float* __restrict__ Wq, const float* __restrict__ Wk,
                              const float* __restrict__ Wv, const float* __restrict__ Wo){
    __shared__ float t[32][33];
    int z = blockIdx.z;
    const float* in = (z == 0) ? Wq : (z == 1) ? Wk : (z == 2) ? Wv : Wo;
    f16* oh = (z == 0) ? g_Wqt : (z == 1) ? g_Wkt : (z == 2) ? g_Wvt : g_Wot;
    int n0 = blockIdx.x*32, k0 = blockIdx.y*32;
    int tx = threadIdx.x, ty = threadIdx.y;
    #pragma unroll
    for (int j = 0; j < 4; ++j)
        t[ty + 8*j][tx] = in[(size_t)(k0 + ty + 8*j)*HID + n0 + tx];
    __syncthreads();
    #pragma unroll
    for (int j = 0; j < 4; ++j){
        float v = t[tx][ty + 8*j];
        oh[(size_t)(n0 + ty + 8*j)*HID + k0 + tx] = __float2half(v);
    }
}

// ---------------- prep ------------------------------------------------------
__global__ void prep_kernel(const float* __restrict__ pos_in,
                            const float* __restrict__ dir_in,
                            const float* __restrict__ ls_in,
                            const float* __restrict__ la_in,
                            const float* __restrict__ dstr,
                            const float* __restrict__ gstr)
{
    int i = threadIdx.x;
    if (i < NH*NS) {
        const float* p = pos_in + (size_t)i*Dd;
        const float* dv = dir_in + (size_t)i*Dd;
        float np = 0.f, nd = 0.f;
        for (int d = 0; d < Dd; ++d) { np += p[d]*p[d]; nd += dv[d]*dv[d]; }
        float pscale = 3.39411254969543f / (sqrtf(np) + 1e-12f);
        float dscale = 1.0f / (sqrtf(nd) + 1e-12f);
        float psq = 0.f, pdd = 0.f;
        for (int d = 0; d < Dd; ++d) {
            float ps = p[d]*pscale, du = dv[d]*dscale;
            g_pos[(size_t)i*Dd + d] = ps;
            g_dir[(size_t)i*Dd + d] = du;
            psq += ps*ps;  pdd += ps*du;
        }
        g_possq[i] = psq;  g_pdd[i] = pdd;
        float sc = expf(ls_in[i]);
        sc = fminf(fmaxf(sc, 0.3f), 1.2f);
        g_inv2s2[i] = 0.5f / (sc*sc);
    }
    __syncthreads();
    if (i < NH) {
        float m = -1e30f;
        for (int n = 0; n < NS; ++n) m = fmaxf(m, la_in[i*NS+n]);
        float s = 0.f, e[NS];
        for (int n = 0; n < NS; ++n) { e[n] = expf(la_in[i*NS+n]-m); s += e[n]; }
        for (int n = 0; n < NS; ++n) g_amp[i*NS+n] = e[n]/s;
    }
    if (i == 0) {
        g_ds = 1.0f / (1.0f + expf(-dstr[0]));
        float gsa = 1.0f / (1.0f + expf(-gstr[0]));
        g_blend = fminf(0.05f, gsa*0.1f);
    }
}

// ---------------- affinities (warp per token) -------------------------------
__global__ void __launch_bounds__(256) affinity2()
{
    int gidx = blockIdx.x*8 + (threadIdx.x >> 5);   // 0..65535
    int lane = threadIdx.x & 31;
    int z = gidx >> 15;
    int rem = gidx & 32767;
    int bh = rem >> 10, s = rem & 1023;
    int b = bh >> 4, h = bh & 15;
    const f16* src = z ? g_Kf : g_Qf;
    size_t base = ((size_t)(b*Ss + s))*HID + h*128;
    float t[4];
    #pragma unroll
    for (int k = 0; k < 4; ++k){
        int d = k*32 + lane;
        t[k] = __half2float(src[base+d]);
    }
    float tsq = wsum(t[0]*t[0] + t[1]*t[1] + t[2]*t[2] + t[3]*t[3]);
    float ds = g_ds;
    float* out = (z ? g_ka : g_qa) + ((size_t)bh*Ss + s)*NS;
    #pragma unroll
    for (int n = 0; n < NS; ++n){
        int hn = h*NS + n;
        float tp = 0.f, td = 0.f;
        #pragma unroll
        for (int k = 0; k < 4; ++k){
            int d = k*32 + lane;
            tp += t[k]*g_pos[hn*Dd + d];
            td += t[k]*g_dir[hn*Dd + d];
        }
        tp = wsum(tp);  td = wsum(td);
        if (lane == n){
            float dist2 = fmaxf(tsq - 2.0f*tp + g_possq[hn], 0.0f);
            float proj  = td - g_pdd[hn];
            float perp2 = fmaxf(dist2 - proj*proj, 0.0f);
            float inv   = g_inv2s2[hn];
            out[n] = (1.0f-ds)*expf(-dist2*inv) + ds*expf(-perp2*inv);
        }
    }
}

// ---------------- GSA linear-attention precompute (2-phase) ----------------
__global__ void gsa_kv_part()
{
    int ch = blockIdx.x, bh = blockIdx.y;
    int d = threadIdx.x;
    const f16* vb = g_Vth + (size_t)bh*Dd*Ss + (size_t)d*Ss;
    const float* ka = g_ka + (size_t)bh*Ss*NS;
    float acc[NS];
    #pragma unroll
    for (int n = 0; n < NS; ++n) acc[n] = 0.f;
    int s0 = ch*128;
    for (int s = s0; s < s0+128; ++s){
        float vv = __half2float(vb[s]);
        #pragma unroll
        for (int n = 0; n < NS; ++n) acc[n] += ka[s*NS+n]*vv;
    }
    #pragma unroll
    for (int n = 0; n < NS; ++n)
        g_kvp[(((size_t)ch*BH + bh)*NS + n)*Dd + d] = acc[n];
    if (d < NS){
        float kssum = 0.f;
        for (int s = s0; s < s0+128; ++s) kssum += ka[s*NS+d];
        g_ksp[(ch*BH + bh)*NS + d] = kssum;
    }
}

__global__ void gsa_red()
{
    int bh = blockIdx.x, d = threadIdx.x;
    #pragma unroll
    for (int n = 0; n < NS; ++n){
        float t = 0.f;
        #pragma unroll
        for (int ch = 0; ch < 8; ++ch)
            t += g_kvp[(((size_t)ch*BH + bh)*NS + n)*Dd + d];
        g_kvmat[((size_t)bh*NS + n)*Dd + d] = t;
    }
    if (d < NS){
        float t = 0.f;
        #pragma unroll
        for (int ch = 0; ch < 8; ++ch) t += g_ksp[(ch*BH + bh)*NS + d];
        g_ksum[bh*NS + d] = t;
    }
}

// ---------------- host: tensormap construction -----------------------------
typedef CUresult (*TMapEncode)(CUtensorMap*, CUtensorMapDataType, cuuint32_t, void*,
    const cuuint64_t*, const cuuint64_t*, const cuuint32_t*, const cuuint32_t*,
    CUtensorMapInterleave, CUtensorMapSwizzle, CUtensorMapL2promotion, CUtensorMapFloatOOBfill);

static void make_map(TMapEncode enc, CUtensorMap* m, void* base, uint64_t d0, uint64_t d1,
                     uint32_t b0, uint32_t b1){
    cuuint64_t dims[2]    = {d0, d1};
    cuuint64_t strides[1] = {d0 * 2};
    cuuint32_t box[2]     = {b0, b1};
    cuuint32_t es[2]      = {1, 1};
    enc(m, CU_TENSOR_MAP_DATA_TYPE_FLOAT16, 2, base, dims, strides, box, es,
        CU_TENSOR_MAP_INTERLEAVE_NONE, CU_TENSOR_MAP_SWIZZLE_128B,
        CU_TENSOR_MAP_L2_PROMOTION_L2_128B, CU_TENSOR_MAP_FLOAT_OOB_FILL_NONE);
}

// ---------------- launch ----------------------------------------------------
extern "C" void kernel_launch(void* const* d_in, const int* in_sizes, int n_in,
                              void* d_out, int out_size)
{
    const float* X   = (const float*)d_in[0];
    const float* Wq  = (const float*)d_in[1];
    const float* Wk  = (const float*)d_in[2];
    const float* Wv  = (const float*)d_in[3];
    const float* Wo  = (const float*)d_in[4];
    const float* pos = (const float*)d_in[5];
    const float* dir = (const float*)d_in[6];
    const float* ls  = (const float*)d_in[7];
    const float* la  = (const float*)d_in[8];
    const float* dstr= (const float*)d_in[9];
    const float* gstr= (const float*)d_in[10];
    float* out = (float*)d_out;

    void* fp = nullptr;
    cudaDriverEntryPointQueryResult qr;
#if CUDART_VERSION >= 12050
    cudaGetDriverEntryPointByVersion("cuTensorMapEncodeTiled", &fp, 12000, cudaEnableDefault, &qr);
#else
    cudaGetDriverEntryPoint("cuTensorMapEncodeTiled", &fp, cudaEnableDefault, &qr);
#endif
    TMapEncode enc = (TMapEncode)fp;

    void *pXf,*pWq,*pWk,*pWv,*pWo;
    void *pQf,*pKf,*pVh,*pCf;
    cudaGetSymbolAddress(&pXf, g_Xf);
    cudaGetSymbolAddress(&pWq, g_Wqt);
    cudaGetSymbolAddress(&pWk, g_Wkt);
    cudaGetSymbolAddress(&pWv, g_Wvt);
    cudaGetSymbolAddress(&pWo, g_Wot);
    cudaGetSymbolAddress(&pQf, g_Qf);
    cudaGetSymbolAddress(&pKf, g_Kf);
    cudaGetSymbolAddress(&pVh, g_Vth);
    cudaGetSymbolAddress(&pCf, g_Cf);

    CUtensorMap mXf,mWq,mWk,mWv,mWo;
    CUtensorMap mQf,mK64,mVh,mCf;
    make_map(enc,&mXf,pXf,HID,Mm,64,128);
    make_map(enc,&mWq,pWq,HID,HID,64,128);
    make_map(enc,&mWk,pWk,HID,HID,64,128);
    make_map(enc,&mWv,pWv,HID,HID,64,128);
    make_map(enc,&mWo,pWo,HID,HID,64,128);
    make_map(enc,&mQf,pQf,HID,Mm,64,128);
    make_map(enc,&mK64,pKf,HID,Mm,64,64);
    make_map(enc,&mVh,pVh,Ss,(uint64_t)BH*Dd,64,128);
    make_map(enc,&mCf,pCf,HID,Mm,64,128);

    cudaFuncSetAttribute(qkv_tc,   cudaFuncAttributeMaxDynamicSharedMemorySize, SMEM_SZ);
    cudaFuncSetAttribute(wo_tc,    cudaFuncAttributeMaxDynamicSharedMemorySize, SMEM_SZ);
    cudaFuncSetAttribute(flash_tc, cudaFuncAttributeMaxDynamicSharedMemorySize, SMEM_FL);

    prep_kernel<<<1, 128>>>(pos, dir, ls, la, dstr, gstr);
    convert_x_kernel<<<(Mm*HID)/1024, 256>>>(X);
    tsplit_kernel<<<dim3(HID/32, HID/32, 4), dim3(32, 8)>>>(Wq, Wk, Wv, Wo);
    qkv_tc<<<dim3(HID/128, Mm/128, 3), 256, SMEM_SZ>>>(mXf,mWq,mWk,mWv);
    affinity2<<<(Ss*BH*2)/8, 256>>>();
    gsa_kv_part<<<dim3(8, BH), 128>>>();
    gsa_red<<<BH, 128>>>();
    flash_tc<<<dim3(Ss/128, BH), 256, SMEM_FL>>>(mQf,mK64,mVh);
    wo_tc<<<dim3(HID/128, Mm/128, 1), 256, SMEM_SZ>>>(mCf,mWo,out);
}

// round 14
// speedup vs baseline: 6.8260x; 1.0015x over previous
#include <cuda_runtime.h>
#include <cuda.h>
#include <cuda_fp16.h>
#include <math.h>
#include <stdint.h>

#define Bb 2
#define Ss 1024
#define HID 2048
#define NH 16
#define NS 8
#define Dd 128
#define Mm (Bb*Ss)      // 2048
#define BH (Bb*NH)      // 32

typedef __half f16;

// ---------------- scratch (device globals; no allocation allowed) ----------
__device__ float g_qa[(size_t)BH*Ss*NS];
__device__ float g_ka[(size_t)BH*Ss*NS];
__device__ float g_kvmat[(size_t)BH*NS*Dd];
__device__ float g_ksum[BH*NS];
__device__ float g_kvp[(size_t)8*BH*NS*Dd];
__device__ float g_ksp[8*BH*NS];
__device__ float g_pos[NH*NS*Dd];
__device__ float g_dir[NH*NS*Dd];
__device__ float g_possq[NH*NS];
__device__ float g_pdd[NH*NS];
__device__ float g_inv2s2[NH*NS];
__device__ float g_amp[NH*NS];
__device__ float g_ds;
__device__ float g_blend;

// fp16 operand arrays (all plain)
__device__ f16 g_Xf[(size_t)Mm*HID];
__device__ f16 g_Wqt[(size_t)HID*HID];
__device__ f16 g_Wkt[(size_t)HID*HID];
__device__ f16 g_Wvt[(size_t)HID*HID];
__device__ f16 g_Wot[(size_t)HID*HID];
__device__ f16 g_Qf[(size_t)Mm*HID];
__device__ f16 g_Kf[(size_t)Mm*HID];
__device__ f16 g_Vth[(size_t)BH*Dd*Ss];            // [bh][d][s]
__device__ f16 g_Cf[(size_t)Mm*HID];

__device__ __forceinline__ uint32_t packh2(float x, float y){
    __half2 t = __floats2half2_rn(x, y);
    return *(uint32_t*)&t;
}

// ================= low-level helpers =======================================
__device__ __forceinline__ uint32_t smem_u32(const void* p){
    uint32_t a;
    asm("{ .reg .u64 t; cvta.to.shared.u64 t, %1; cvt.u32.u64 %0, t; }" : "=r"(a) : "l"(p));
    return a;
}
__device__ __forceinline__ void mbar_init(uint32_t a, uint32_t cnt){
    asm volatile("mbarrier.init.shared.b64 [%0], %1;" :: "r"(a), "r"(cnt) : "memory");
}
__device__ __forceinline__ void mbar_inval(uint32_t a){
    asm volatile("mbarrier.inval.shared.b64 [%0];" :: "r"(a) : "memory");
}
__device__ __forceinline__ void mbar_expect(uint32_t a, uint32_t bytes){
    asm volatile("mbarrier.arrive.expect_tx.shared.b64 _, [%0], %1;" :: "r"(a), "r"(bytes) : "memory");
}
__device__ __forceinline__ void wait_parity(uint32_t mbar, uint32_t ph){
    uint32_t done;
    asm volatile(
        "{\n\t.reg .pred p;\n\t"
        "mbarrier.try_wait.parity.acquire.cta.shared::cta.b64 p, [%1], %2;\n\t"
        "selp.b32 %0, 1, 0, p;\n\t}"
        : "=r"(done) : "r"(mbar), "r"(ph) : "memory");
    if (!done) {
        asm volatile(
            "{\n\t.reg .pred P1;\n\t"
            "WL%=:\n\t"
            "mbarrier.try_wait.parity.acquire.cta.shared::cta.b64 P1, [%0], %1, 0x989680;\n\t"
            "@P1 bra.uni WD%=;\n\t"
            "bra.uni WL%=;\n\t"
            "WD%=:\n\t}"
            :: "r"(mbar), "r"(ph) : "memory");
    }
}
__device__ __forceinline__ void tma2d(uint32_t dst, const CUtensorMap* m, int x, int y, uint32_t mbar){
    asm volatile(
        "cp.async.bulk.tensor.2d.shared::cta.global.tile.mbarrier::complete_tx::bytes "
        "[%0], [%1, {%2, %3}], [%4];"
        :: "r"(dst), "l"(m), "r"(x), "r"(y), "r"(mbar) : "memory");
}
__device__ __forceinline__ void ldm4(uint32_t* r, uint32_t a){
    asm volatile("ldmatrix.sync.aligned.m8n8.x4.shared.b16 {%0,%1,%2,%3}, [%4];"
        : "=r"(r[0]),"=r"(r[1]),"=r"(r[2]),"=r"(r[3]) : "r"(a));
}
__device__ __forceinline__ void mma16816(float* c, const uint32_t* a, uint32_t b0, uint32_t b1){
    asm volatile("mma.sync.aligned.m16n8k16.row.col.f32.f16.f16.f32 "
        "{%0,%1,%2,%3}, {%4,%5,%6,%7}, {%8,%9}, {%0,%1,%2,%3};"
        : "+f"(c[0]),"+f"(c[1]),"+f"(c[2]),"+f"(c[3])
        : "r"(a[0]),"r"(a[1]),"r"(a[2]),"r"(a[3]), "r"(b0),"r"(b1));
}
__device__ __forceinline__ uint32_t swz(uint32_t x){ return x ^ ((x>>3)&0x70); }
__device__ __forceinline__ float wsum(float v){
    #pragma unroll
    for (int o = 16; o; o >>= 1) v += __shfl_xor_sync(0xffffffffu, v, o);
    return v;
}

#define TILE_B    16384
#define SMEM_SZ   99328                          // 3 x 32K stages (+1K); epilogue reuses as 68K stage
#define FSTAGE_B  32768                          // Kf(16K) Vh(16K)
#define SMEM_FL   (1024 + 32768 + 2*FSTAGE_B)    // Q(32K) + 2 stages = 97K -> 2 CTAs/SM

// ---------------- 128x128 CTA GEMM mainloop (256 threads, 8 warps) ---------
__device__ __forceinline__ void gemm_main(
    const CUtensorMap* mA, const CUtensorMap* mB,
    int ax0, int ay, int bx0, int by, int K, float* acc)
{
    extern __shared__ char smem[];
    uint32_t sb = smem_u32(smem);
    int tid = threadIdx.x, lane = tid & 31, wid = tid >> 5;
    int warp_m = (wid >> 2) * 64, warp_n = (wid & 3) * 32;

    if (tid == 0){ mbar_init(sb,1); mbar_init(sb+8,1); mbar_init(sb+16,1); }
    __syncthreads();

    #pragma unroll
    for (int i = 0; i < 64; ++i) acc[i] = 0.f;

    int NC = K / 64;

    auto issue = [&](int c){
        if (tid == 0){
            int st = c % 3;
            uint32_t mb = sb + 8*st;
            mbar_expect(mb, 2*TILE_B);
            uint32_t dst = sb + 1024 + st*2*TILE_B;
            tma2d(dst,          mA, ax0 + c*64, ay, mb);
            tma2d(dst + TILE_B, mB, bx0 + c*64, by, mb);
        }
    };
    issue(0);
    if (NC > 1) issue(1);
    if (NC > 2) issue(2);

    uint32_t a_row  = warp_m + (lane & 15);
    uint32_t a_colb = (lane >> 4) * 16;
    uint32_t b_row  = warp_n + (lane & 7) + ((lane >> 4) << 3);
    uint32_t b_colb = ((lane >> 3) & 1) * 16;

    for (int c = 0; c < NC; ++c){
        wait_parity(sb + 8*(c % 3), (c / 3) & 1);
        uint32_t st = sb + 1024 + (c % 3)*2*TILE_B;
        #pragma unroll
        for (int ks = 0; ks < 4; ++ks){
            uint32_t a_[16], bh[8];
            #pragma unroll
            for (int mt = 0; mt < 4; ++mt){
                uint32_t off = swz((a_row + mt*16)*128 + ks*32 + a_colb);
                ldm4(a_ + mt*4, st + off);
            }
            #pragma unroll
            for (int nt = 0; nt < 2; ++nt){
                uint32_t off = swz((b_row + nt*16)*128 + ks*32 + b_colb);
                ldm4(bh + nt*4, st + TILE_B + off);
            }
            #pragma unroll
            for (int mt = 0; mt < 4; ++mt)
                #pragma unroll
                for (int n8 = 0; n8 < 4; ++n8){
                    float* c4 = acc + (mt*4 + n8)*4;
                    int bi = (n8 >> 1)*4 + (n8 & 1)*2;
                    mma16816(c4, a_ + mt*4, bh[bi], bh[bi+1]);
                }
        }
        __syncthreads();
        if (c + 3 < NC) issue(c + 3);
    }
    if (tid == 0){ mbar_inval(sb); mbar_inval(sb+8); mbar_inval(sb+16); }
}

template<class F>
__device__ __forceinline__ void epi_loop(const float* acc, F f){
    int lane = threadIdx.x & 31, wid = threadIdx.x >> 5;
    int warp_m = (wid >> 2) * 64, warp_n = (wid & 3) * 32;
    int g = lane >> 2, tg = (lane & 3) * 2;
    #pragma unroll
    for (int mt = 0; mt < 4; ++mt)
        #pragma unroll
        for (int n8 = 0; n8 < 4; ++n8){
            const float* c4 = acc + (mt*4 + n8)*4;
            #pragma unroll
            for (int hh = 0; hh < 2; ++hh){
                int r  = warp_m + mt*16 + g + hh*8;
                int cc = warp_n + n8*8 + tg;
                f(r, cc, c4[hh*2], c4[hh*2+1]);
            }
        }
}

// ================= GEMM kernels ============================================
__global__ void __launch_bounds__(256, 2) qkv_tc(
    const __grid_constant__ CUtensorMap mXf,
    const __grid_constant__ CUtensorMap mWq,
    const __grid_constant__ CUtensorMap mWk,
    const __grid_constant__ CUtensorMap mWv)
{
    extern __shared__ char smem[];
    int z = blockIdx.z;
    int row0 = blockIdx.y*128, col0 = blockIdx.x*128;
    const CUtensorMap* pb = (z == 0) ? &mWq : (z == 1) ? &mWk : &mWv;
    float acc[64];
    gemm_main(&mXf, pb, 0, row0, 0, col0, HID, acc);

    int lane = threadIdx.x & 31, wid = threadIdx.x >> 5;

    if (z < 2){
        // write fp16 Q/K + stage fp32 tile for fused affinity
        float* Ts = (float*)(smem + 1024);   // [128][132]
        f16* dst16 = z ? g_Kf : g_Qf;
        epi_loop(acc, [&](int r, int cc, float v0, float v1){
            size_t idx = (size_t)(row0 + r)*HID + col0 + cc;
            *(uint32_t*)(dst16 + idx) = packh2(v0, v1);
            Ts[r*132 + cc]     = v0;
            Ts[r*132 + cc + 1] = v1;
        });
        __syncthreads();

        // fused affinity: 8 warps x 16 tokens, head h = col0/128
        int h = col0 >> 7;
        int bh = ((row0 >> 10) << 4) | h;
        float ds = g_ds;
        float* outp = (z ? g_ka : g_qa)
                    + (size_t)bh*Ss*NS + (size_t)(row0 & (Ss-1))*NS;
        for (int tt = 0; tt < 16; ++tt){
            int r = wid*16 + tt;
            const float* row = Ts + r*132;
            float tv0 = row[lane], tv1 = row[lane+32], tv2 = row[lane+64], tv3 = row[lane+96];
            float tsq = wsum(tv0*tv0 + tv1*tv1 + tv2*tv2 + tv3*tv3);
            #pragma unroll
            for (int n = 0; n < NS; ++n){
                int hn = h*NS + n;
                const float* pp = g_pos + hn*Dd;
                const float* dd = g_dir + hn*Dd;
                float tp = tv0*pp[lane] + tv1*pp[lane+32] + tv2*pp[lane+64] + tv3*pp[lane+96];
                float td = tv0*dd[lane] + tv1*dd[lane+32] + tv2*dd[lane+64] + tv3*dd[lane+96];
                tp = wsum(tp);  td = wsum(td);
                if (lane == n){
                    float dist2 = fmaxf(tsq - 2.0f*tp + g_possq[hn], 0.0f);
                    float proj  = td - g_pdd[hn];
                    float perp2 = fmaxf(dist2 - proj*proj, 0.0f);
                    float inv   = g_inv2s2[hn];
                    outp[(size_t)r*NS + n] = (1.0f-ds)*expf(-dist2*inv) + ds*expf(-perp2*inv);
                }
            }
        }
    } else {
        // stage transposed V tile in SMEM, then coalesced write to g_Vth
        f16* Ts = (f16*)(smem + 1024);      // [128 d][136 s-stride]
        epi_loop(acc, [&](int r, int cc, float v0, float v1){
            Ts[cc*136 + r]       = __float2half(v0);
            Ts[(cc+1)*136 + r]   = __float2half(v1);
        });
        __syncthreads();
        int b = row0 >> 10, s0 = row0 & (Ss-1);
        int h = col0 >> 7;
        size_t dbase = ((size_t)(b*NH + h))*Dd;
        for (int it = threadIdx.x; it < 128*16; it += 256){
            int d = it >> 4, seg = it & 15;
            uint4 val = *(const uint4*)(Ts + d*136 + seg*8);
            *(uint4*)(g_Vth + (dbase + d)*Ss + s0 + seg*8) = val;
        }
    }
}

__global__ void __launch_bounds__(256, 2) wo_tc(
    const __grid_constant__ CUtensorMap mCf,
    const __grid_constant__ CUtensorMap mWo,
    float* __restrict__ out)
{
    int row0 = blockIdx.y*128, col0 = blockIdx.x*128;
    float acc[64];
    gemm_main(&mCf, &mWo, 0, row0, 0, col0, HID, acc);
    epi_loop(acc, [&](int r, int cc, float v0, float v1){
        float2 fv; fv.x = v0; fv.y = v1;
        *(float2*)(out + (size_t)(row0 + r)*HID + col0 + cc) = fv;
    });
}

// ================= flash attention kernel ==================================
__global__ void __launch_bounds__(256, 2) flash_tc(
    const __grid_constant__ CUtensorMap mQf,
    const __grid_constant__ CUtensorMap mK64,
    const __grid_constant__ CUtensorMap mVh)
{
    extern __shared__ char smem[];
    uint32_t sb = smem_u32(smem);
    int tid = threadIdx.x, lane = tid & 31, wid = tid >> 5;
    int bh = blockIdx.y, b = bh >> 4, h = bh & 15;
    int row0 = blockIdx.x * 128;

    const uint32_t QF  = sb + 1024;          // two 16KB halves
    const uint32_t ST0 = QF + 32768;
    // stage: KF0(8K) KF1(8K) VH(16K) = 32KB

    if (tid == 0){ mbar_init(sb,1); mbar_init(sb+8,1); mbar_init(sb+16,1); }
    __syncthreads();

    if (tid == 0){
        mbar_expect(sb+16, 32768u);
        tma2d(QF,        &mQf, h*128,    b*Ss+row0, sb+16);
        tma2d(QF+16384,  &mQf, h*128+64, b*Ss+row0, sb+16);
    }
    auto issue = [&](int j){
        if (tid == 0){
            uint32_t mb = sb + 8*(j&1);
            mbar_expect(mb, (uint32_t)FSTAGE_B);
            uint32_t st = ST0 + (j&1)*FSTAGE_B;
            tma2d(st,         &mK64, h*128,    b*Ss+j*64, mb);
            tma2d(st+8192,    &mK64, h*128+64, b*Ss+j*64, mb);
            tma2d(st+16384,   &mVh,  j*64, bh*128, mb);
        }
    };
    issue(0); issue(1);

    float O[64];
    #pragma unroll
    for (int i = 0; i < 64; ++i) O[i] = 0.f;
    float m0 = -1e30f, m1 = -1e30f, l0 = 0.f, l1 = 0.f;
    const float qk = 0.08838834764831845f;

    uint32_t a_row = wid*16 + (lane & 15), a_colb = (lane >> 4)*16;
    uint32_t b_rw  = (lane & 7) + ((lane >> 4) << 3);
    uint32_t b_cb  = ((lane >> 3) & 1)*16;

    wait_parity(sb+16, 0);

    for (int j = 0; j < 16; ++j){
        wait_parity(sb + 8*(j&1), (j>>1)&1);
        uint32_t st = ST0 + (j&1)*FSTAGE_B;

        // ---- S = Q K^T
        float s[32];
        #pragma unroll
        for (int i = 0; i < 32; ++i) s[i] = 0.f;
        #pragma unroll
        for (int ks = 0; ks < 8; ++ks){
            uint32_t qf_[4], kh_[16];
            uint32_t offa = (ks>>2)*16384 + swz(a_row*128 + (ks&3)*32 + a_colb);
            ldm4(qf_, QF + offa);
            #pragma unroll
            for (int nt = 0; nt < 4; ++nt){
                uint32_t offb = (ks>>2)*8192 + swz((b_rw + nt*16)*128 + (ks&3)*32 + b_cb);
                ldm4(kh_ + nt*4, st + offb);
            }
            #pragma unroll
            for (int n8 = 0; n8 < 8; ++n8){
                int bi = (n8 >> 1)*4 + (n8 & 1)*2;
                mma16816(s + n8*4, qf_, kh_[bi], kh_[bi+1]);
            }
        }

        // ---- online softmax
        float tm0 = -1e30f, tm1 = -1e30f;
        #pragma unroll
        for (int t = 0; t < 8; ++t){
            s[t*4+0] *= qk; s[t*4+1] *= qk; s[t*4+2] *= qk; s[t*4+3] *= qk;
            tm0 = fmaxf(tm0, fmaxf(s[t*4+0], s[t*4+1]));
            tm1 = fmaxf(tm1, fmaxf(s[t*4+2], s[t*4+3]));
        }
        tm0 = fmaxf(tm0, __shfl_xor_sync(0xffffffffu, tm0, 1));
        tm0 = fmaxf(tm0, __shfl_xor_sync(0xffffffffu, tm0, 2));
        tm1 = fmaxf(tm1, __shfl_xor_sync(0xffffffffu, tm1, 1));
        tm1 = fmaxf(tm1, __shfl_xor_sync(0xffffffffu, tm1, 2));
        float nm0 = fmaxf(m0, tm0), nm1 = fmaxf(m1, tm1);
        float al0 = expf(m0 - nm0), al1 = expf(m1 - nm1);
        float ts0 = 0.f, ts1 = 0.f;
        #pragma unroll
        for (int t = 0; t < 8; ++t){
            s[t*4+0] = expf(s[t*4+0] - nm0); s[t*4+1] = expf(s[t*4+1] - nm0);
            s[t*4+2] = expf(s[t*4+2] - nm1); s[t*4+3] = expf(s[t*4+3] - nm1);
            ts0 += s[t*4+0] + s[t*4+1];
            ts1 += s[t*4+2] + s[t*4+3];
        }
        ts0 += __shfl_xor_sync(0xffffffffu, ts0, 1);
        ts0 += __shfl_xor_sync(0xffffffffu, ts0, 2);
        ts1 += __shfl_xor_sync(0xffffffffu, ts1, 1);
        ts1 += __shfl_xor_sync(0xffffffffu, ts1, 2);
        l0 = l0*al0 + ts0;  l1 = l1*al1 + ts1;
        m0 = nm0;  m1 = nm1;
        #pragma unroll
        for (int t = 0; t < 16; ++t){
            O[t*4+0] *= al0; O[t*4+1] *= al0; O[t*4+2] *= al1; O[t*4+3] *= al1;
        }

        // ---- pack P into A fragments
        uint32_t ph_[16];
        #pragma unroll
        for (int t = 0; t < 4; ++t){
            ph_[t*4+0] = packh2(s[(2*t)*4+0],   s[(2*t)*4+1]);
            ph_[t*4+1] = packh2(s[(2*t)*4+2],   s[(2*t)*4+3]);
            ph_[t*4+2] = packh2(s[(2*t+1)*4+0], s[(2*t+1)*4+1]);
            ph_[t*4+3] = packh2(s[(2*t+1)*4+2], s[(2*t+1)*4+3]);
        }

        // ---- O += P V
        #pragma unroll
        for (int ks = 0; ks < 4; ++ks){
            uint32_t vh_[32];
            #pragma unroll
            for (int nt = 0; nt < 8; ++nt){
                uint32_t offv = swz((b_rw + nt*16)*128 + ks*32 + b_cb);
                ldm4(vh_ + nt*4, st + 16384 + offv);
            }
            #pragma unroll
            for (int n8 = 0; n8 < 16; ++n8){
                int bi = (n8 >> 1)*4 + (n8 & 1)*2;
                mma16816(O + n8*4, ph_ + ks*4, vh_[bi], vh_[bi+1]);
            }
        }
        __syncthreads();
        if (j + 2 < 16) issue(j + 2);
    }

    // ---- epilogue: normalize, fuse GSA blend, write Cf
    float inv0 = 1.f / l0, inv1 = 1.f / l1;
    float blend = g_blend, ob = 1.f - blend;
    int g = lane >> 2, tg2 = (lane & 3)*2;
    int s0g = row0 + wid*16 + g, s1g = s0g + 8;

    float c0[8], c1[8];
    float den0 = 1e-8f, den1 = 1e-8f;
    #pragma unroll
    for (int n = 0; n < 8; ++n){
        float a = g_amp[h*8 + n], kss = g_ksum[bh*8 + n];
        c0[n] = g_qa[((size_t)bh*Ss + s0g)*8 + n] * a;  den0 += c0[n]*kss;
        c1[n] = g_qa[((size_t)bh*Ss + s1g)*8 + n] * a;  den1 += c1[n]*kss;
    }
    float id0 = blend/den0, id1 = blend/den1;

    size_t base0 = ((size_t)(b*Ss + s0g))*HID + h*128;
    size_t base1 = ((size_t)(b*Ss + s1g))*HID + h*128;
    #pragma unroll
    for (int n8 = 0; n8 < 16; ++n8){
        int d = n8*8 + tg2;
        float num00=0.f, num01=0.f, num10=0.f, num11=0.f;
        #pragma unroll
        for (int n = 0; n < 8; ++n){
            float2 kv = *(const float2*)(g_kvmat + ((size_t)bh*8 + n)*128 + d);
            num00 += c0[n]*kv.x;  num01 += c0[n]*kv.y;
            num10 += c1[n]*kv.x;  num11 += c1[n]*kv.y;
        }
        float v00 = ob*O[n8*4+0]*inv0 + id0*num00;
        float v01 = ob*O[n8*4+1]*inv0 + id0*num01;
        float v10 = ob*O[n8*4+2]*inv1 + id1*num10;
        float v11 = ob*O[n8*4+3]*inv1 + id1*num11;
        *(uint32_t*)(g_Cf + base0 + d) = packh2(v00, v01);
        *(uint32_t*)(g_Cf + base1 + d) = packh2(v10, v11);
    }
    __syncthreads();
    if (tid == 0){ mbar_inval(sb); mbar_inval(sb+8); mbar_inval(sb+16); }
}

// ================= conversion kernel (weights transpose + X round) =========
__global__ void tsplit_kernel(const float* __restrict__ Wq, const float* __restrict__ Wk,
                              const float* __restrict__ Wv, const float* __restrict__ Wo,
                              const float* __restrict__ X){
    __shared__ float t[32][33];
    int z = blockIdx.z;
    int n0 = blockIdx.x*32, k0 = blockIdx.y*32;
    int tx = threadIdx.x, ty = threadIdx.y;
    if (z == 4){
        // direct round of X (no transpose)
        #pragma unroll
        for (int j = 0; j < 4; ++j){
            size_t idx = (size_t)(k0 + ty + 8*j)*HID + n0 + tx;
            g_Xf[idx] = __float2half(X[idx]);
        }
        return;
    }
    const float* in = (z == 0) ? Wq : (z == 1) ? Wk : (z == 2) ? Wv : Wo;
    f16* oh = (z == 0) ? g_Wqt : (z == 1) ? g_Wkt : (z == 2) ? g_Wvt : g_Wot;
    #pragma unroll
    for (int j = 0; j < 4; ++j)
        t[ty + 8*j][tx] = in[(size_t)(k0 + ty + 8*j)*HID + n0 + tx];
    __syncthreads();
    #pragma unroll
    for (int j = 0; j < 4; ++j){
        float v = t[tx][ty + 8*j];
        oh[(size_t)(n0 + ty + 8*j)*HID + k0 + tx] = __float2half(v);
    }
}

// ---------------- prep ------------------------------------------------------
__global__ void prep_kernel(const float* __restrict__ pos_in,
                            const float* __restrict__ dir_in,
                            const float* __restrict__ ls_in,
                            const float* __restrict__ la_in,
                            const float* __restrict__ dstr,
                            const float* __restrict__ gstr)
{
    int i = threadIdx.x;
    if (i < NH*NS) {
        const float* p = pos_in + (size_t)i*Dd;
        const float* dv = dir_in + (size_t)i*Dd;
        float np = 0.f, nd = 0.f;
        for (int d = 0; d < Dd; ++d) { np += p[d]*p[d]; nd += dv[d]*dv[d]; }
        float pscale = 3.39411254969543f / (sqrtf(np) + 1e-12f);
        float dscale = 1.0f / (sqrtf(nd) + 1e-12f);
        float psq = 0.f, pdd = 0.f;
        for (int d = 0; d < Dd; ++d) {
            float ps = p[d]*pscale, du = dv[d]*dscale;
            g_pos[(size_t)i*Dd + d] = ps;
            g_dir[(size_t)i*Dd + d] = du;
            psq += ps*ps;  pdd += ps*du;
        }
        g_possq[i] = psq;  g_pdd[i] = pdd;
        float sc = expf(ls_in[i]);
        sc = fminf(fmaxf(sc, 0.3f), 1.2f);
        g_inv2s2[i] = 0.5f / (sc*sc);
    }
    __syncthreads();
    if (i < NH) {
        float m = -1e30f;
        for (int n = 0; n < NS; ++n) m = fmaxf(m, la_in[i*NS+n]);
        float s = 0.f, e[NS];
        for (int n = 0; n < NS; ++n) { e[n] = expf(la_in[i*NS+n]-m); s += e[n]; }
        for (int n = 0; n < NS; ++n) g_amp[i*NS+n] = e[n]/s;
    }
    if (i == 0) {
        g_ds = 1.0f / (1.0f + expf(-dstr[0]));
        float gsa = 1.0f / (1.0f + expf(-gstr[0]));
        g_blend = fminf(0.05f, gsa*0.1f);
    }
}

// ---------------- GSA linear-attention precompute (2-phase) ----------------
__global__ void gsa_kv_part()
{
    int ch = blockIdx.x, bh = blockIdx.y;
    int d = threadIdx.x;
    const f16* vb = g_Vth + (size_t)bh*Dd*Ss + (size_t)d*Ss;
    const float* ka = g_ka + (size_t)bh*Ss*NS;
    float acc[NS];
    #pragma unroll
    for (int n = 0; n < NS; ++n) acc[n] = 0.f;
    int s0 = ch*128;
    for (int s = s0; s < s0+128; ++s){
        float vv = __half2float(vb[s]);
        #pragma unroll
        for (int n = 0; n < NS; ++n) acc[n] += ka[s*NS+n]*vv;
    }
    #pragma unroll
    for (int n = 0; n < NS; ++n)
        g_kvp[(((size_t)ch*BH + bh)*NS + n)*Dd + d] = acc[n];
    if (d < NS){
        float kssum = 0.f;
        for (int s = s0; s < s0+128; ++s) kssum += ka[s*NS+d];
        g_ksp[(ch*BH + bh)*NS + d] = kssum;
    }
}

__global__ void gsa_red()
{
    int bh = blockIdx.x, d = threadIdx.x;
    #pragma unroll
    for (int n = 0; n < NS; ++n){
        float t = 0.f;
        #pragma unroll
        for (int ch = 0; ch < 8; ++ch)
            t += g_kvp[(((size_t)ch*BH + bh)*NS + n)*Dd + d];
        g_kvmat[((size_t)bh*NS + n)*Dd + d] = t;
    }
    if (d < NS){
        float t = 0.f;
        #pragma unroll
        for (int ch = 0; ch < 8; ++ch) t += g_ksp[(ch*BH + bh)*NS + d];
        g_ksum[bh*NS + d] = t;
    }
}

// ---------------- host: tensormap construction -----------------------------
typedef CUresult (*TMapEncode)(CUtensorMap*, CUtensorMapDataType, cuuint32_t, void*,
    const cuuint64_t*, const cuuint64_t*, const cuuint32_t*, const cuuint32_t*,
    CUtensorMapInterleave, CUtensorMapSwizzle, CUtensorMapL2promotion, CUtensorMapFloatOOBfill);

static void make_map(TMapEncode enc, CUtensorMap* m, void* base, uint64_t d0, uint64_t d1,
                     uint32_t b0, uint32_t b1){
    cuuint64_t dims[2]    = {d0, d1};
    cuuint64_t strides[1] = {d0 * 2};
    cuuint32_t box[2]     = {b0, b1};
    cuuint32_t es[2]      = {1, 1};
    enc(m, CU_TENSOR_MAP_DATA_TYPE_FLOAT16, 2, base, dims, strides, box, es,
        CU_TENSOR_MAP_INTERLEAVE_NONE, CU_TENSOR_MAP_SWIZZLE_128B,
        CU_TENSOR_MAP_L2_PROMOTION_L2_128B, CU_TENSOR_MAP_FLOAT_OOB_FILL_NONE);
}

// ---------------- launch ----------------------------------------------------
extern "C" void kernel_launch(void* const* d_in, const int* in_sizes, int n_in,
                              void* d_out, int out_size)
{
    const float* X   = (const float*)d_in[0];
    const float* Wq  = (const float*)d_in[1];
    const float* Wk  = (const float*)d_in[2];
    const float* Wv  = (const float*)d_in[3];
    const float* Wo  = (const float*)d_in[4];
    const float* pos = (const float*)d_in[5];
    const float* dir = (const float*)d_in[6];
    const float* ls  = (const float*)d_in[7];
    const float* la  = (const float*)d_in[8];
    const float* dstr= (const float*)d_in[9];
    const float* gstr= (const float*)d_in[10];
    float* out = (float*)d_out;

    void* fp = nullptr;
    cudaDriverEntryPointQueryResult qr;
#if CUDART_VERSION >= 12050
    cudaGetDriverEntryPointByVersion("cuTensorMapEncodeTiled", &fp, 12000, cudaEnableDefault, &qr);
#else
    cudaGetDriverEntryPoint("cuTensorMapEncodeTiled", &fp, cudaEnableDefault, &qr);
#endif
    TMapEncode enc = (TMapEncode)fp;

    void *pXf,*pWq,*pWk,*pWv,*pWo;
    void *pQf,*pKf,*pVh,*pCf;
    cudaGetSymbolAddress(&pXf, g_Xf);
    cudaGetSymbolAddress(&pWq, g_Wqt);
    cudaGetSymbolAddress(&pWk, g_Wkt);
    cudaGetSymbolAddress(&pWv, g_Wvt);
    cudaGetSymbolAddress(&pWo, g_Wot);
    cudaGetSymbolAddress(&pQf, g_Qf);
    cudaGetSymbolAddress(&pKf, g_Kf);
    cudaGetSymbolAddress(&pVh, g_Vth);
    cudaGetSymbolAddress(&pCf, g_Cf);

    CUtensorMap mXf,mWq,mWk,mWv,mWo;
    CUtensorMap mQf,mK64,mVh,mCf;
    make_map(enc,&mXf,pXf,HID,Mm,64,128);
    make_map(enc,&mWq,pWq,HID,HID,64,128);
    make_map(enc,&mWk,pWk,HID,HID,64,128);
    make_map(enc,&mWv,pWv,HID,HID,64,128);
    make_map(enc,&mWo,pWo,HID,HID,64,128);
    make_map(enc,&mQf,pQf,HID,Mm,64,128);
    make_map(enc,&mK64,pKf,HID,Mm,64,64);
    make_map(enc,&mVh,pVh,Ss,(uint64_t)BH*Dd,64,128);
    make_map(enc,&mCf,pCf,HID,Mm,64,128);

    cudaFuncSetAttribute(qkv_tc,   cudaFuncAttributeMaxDynamicSharedMemorySize, SMEM_SZ);
    cudaFuncSetAttribute(wo_tc,    cudaFuncAttributeMaxDynamicSharedMemorySize, SMEM_SZ);
    cudaFuncSetAttribute(flash_tc, cudaFuncAttributeMaxDynamicSharedMemorySize, SMEM_FL);

    prep_kernel<<<1, 128>>>(pos, dir, ls, la, dstr, gstr);
    tsplit_kernel<<<dim3(HID/32, HID/32, 5), dim3(32, 8)>>>(Wq, Wk, Wv, Wo, X);
    qkv_tc<<<dim3(HID/128, Mm/128, 3), 256, SMEM_SZ>>>(mXf,mWq,mWk,mWv);
    gsa_kv_part<<<dim3(8, BH), 128>>>();
    gsa_red<<<BH, 128>>>();
    flash_tc<<<dim3(Ss/128, BH), 256, SMEM_FL>>>(mQf,mK64,mVh);
    wo_tc<<<dim3(HID/128, Mm/128, 1), 256, SMEM_SZ>>>(mCf,mWo,out);
}

// round 15
// speedup vs baseline: 7.2246x; 1.0584x over previous
#include <cuda_runtime.h>
#include <cuda.h>
#include <cuda_fp16.h>
#include <math.h>
#include <stdint.h>

#define Bb 2
#define Ss 1024
#define HID 2048
#define NH 16
#define NS 8
#define Dd 128
#define Mm (Bb*Ss)      // 2048
#define BH (Bb*NH)      // 32
#define NCH 32          // gsa kv chunks

typedef __half f16;

// ---------------- scratch (device globals; no allocation allowed) ----------
__device__ float g_qa[(size_t)BH*Ss*NS];
__device__ float g_ka[(size_t)BH*Ss*NS];
__device__ float g_kvmat[(size_t)BH*NS*Dd];
__device__ float g_ksum[BH*NS];
__device__ float g_kvp[(size_t)NCH*BH*NS*Dd];
__device__ float g_ksp[NCH*BH*NS];
__device__ float g_pos[NH*NS*Dd];
__device__ float g_dir[NH*NS*Dd];
__device__ float g_possq[NH*NS];
__device__ float g_pdd[NH*NS];
__device__ float g_inv2s2[NH*NS];
__device__ float g_amp[NH*NS];
__device__ float g_ds;
__device__ float g_blend;

// fp16 operand arrays (all plain)
__device__ f16 g_Xf[(size_t)Mm*HID];
__device__ f16 g_Wqt[(size_t)HID*HID];
__device__ f16 g_Wkt[(size_t)HID*HID];
__device__ f16 g_Wvt[(size_t)HID*HID];
__device__ f16 g_Wot[(size_t)HID*HID];
__device__ f16 g_Qf[(size_t)Mm*HID];
__device__ f16 g_Kf[(size_t)Mm*HID];
__device__ f16 g_Vth[(size_t)BH*Dd*Ss];            // [bh][d][s]
__device__ f16 g_Cf[(size_t)Mm*HID];

__device__ __forceinline__ uint32_t packh2(float x, float y){
    __half2 t = __floats2half2_rn(x, y);
    return *(uint32_t*)&t;
}

// ================= low-level helpers =======================================
__device__ __forceinline__ uint32_t smem_u32(const void* p){
    uint32_t a;
    asm("{ .reg .u64 t; cvta.to.shared.u64 t, %1; cvt.u32.u64 %0, t; }" : "=r"(a) : "l"(p));
    return a;
}
__device__ __forceinline__ void mbar_init(uint32_t a, uint32_t cnt){
    asm volatile("mbarrier.init.shared.b64 [%0], %1;" :: "r"(a), "r"(cnt) : "memory");
}
__device__ __forceinline__ void mbar_inval(uint32_t a){
    asm volatile("mbarrier.inval.shared.b64 [%0];" :: "r"(a) : "memory");
}
__device__ __forceinline__ void mbar_expect(uint32_t a, uint32_t bytes){
    asm volatile("mbarrier.arrive.expect_tx.shared.b64 _, [%0], %1;" :: "r"(a), "r"(bytes) : "memory");
}
__device__ __forceinline__ void wait_parity(uint32_t mbar, uint32_t ph){
    uint32_t done;
    asm volatile(
        "{\n\t.reg .pred p;\n\t"
        "mbarrier.try_wait.parity.acquire.cta.shared::cta.b64 p, [%1], %2;\n\t"
        "selp.b32 %0, 1, 0, p;\n\t}"
        : "=r"(done) : "r"(mbar), "r"(ph) : "memory");
    if (!done) {
        asm volatile(
            "{\n\t.reg .pred P1;\n\t"
            "WL%=:\n\t"
            "mbarrier.try_wait.parity.acquire.cta.shared::cta.b64 P1, [%0], %1, 0x989680;\n\t"
            "@P1 bra.uni WD%=;\n\t"
            "bra.uni WL%=;\n\t"
            "WD%=:\n\t}"
            :: "r"(mbar), "r"(ph) : "memory");
    }
}
__device__ __forceinline__ void tma2d(uint32_t dst, const CUtensorMap* m, int x, int y, uint32_t mbar){
    asm volatile(
        "cp.async.bulk.tensor.2d.shared::cta.global.tile.mbarrier::complete_tx::bytes "
        "[%0], [%1, {%2, %3}], [%4];"
        :: "r"(dst), "l"(m), "r"(x), "r"(y), "r"(mbar) : "memory");
}
__device__ __forceinline__ void ldm4(uint32_t* r, uint32_t a){
    asm volatile("ldmatrix.sync.aligned.m8n8.x4.shared.b16 {%0,%1,%2,%3}, [%4];"
        : "=r"(r[0]),"=r"(r[1]),"=r"(r[2]),"=r"(r[3]) : "r"(a));
}
__device__ __forceinline__ void mma16816(float* c, const uint32_t* a, uint32_t b0, uint32_t b1){
    asm volatile("mma.sync.aligned.m16n8k16.row.col.f32.f16.f16.f32 "
        "{%0,%1,%2,%3}, {%4,%5,%6,%7}, {%8,%9}, {%0,%1,%2,%3};"
        : "+f"(c[0]),"+f"(c[1]),"+f"(c[2]),"+f"(c[3])
        : "r"(a[0]),"r"(a[1]),"r"(a[2]),"r"(a[3]), "r"(b0),"r"(b1));
}
__device__ __forceinline__ uint32_t swz(uint32_t x){ return x ^ ((x>>3)&0x70); }
__device__ __forceinline__ float wsum(float v){
    #pragma unroll
    for (int o = 16; o; o >>= 1) v += __shfl_xor_sync(0xffffffffu, v, o);
    return v;
}

#define TILE_B    16384
#define SMEM_SZ   99328                          // 3 x 32K stages (+1K); epilogue reuses as 68K stage
#define FSTAGE_B  32768                          // Kf(16K) Vh(16K)
#define SMEM_FL   (1024 + 32768 + 2*FSTAGE_B)    // Q(32K) + 2 stages = 97K -> 2 CTAs/SM

// ---------------- 128x128 CTA GEMM mainloop (256 threads, 8 warps) ---------
__device__ __forceinline__ void gemm_main(
    const CUtensorMap* mA, const CUtensorMap* mB,
    int ax0, int ay, int bx0, int by, int K, float* acc)
{
    extern __shared__ char smem[];
    uint32_t sb = smem_u32(smem);
    int tid = threadIdx.x, lane = tid & 31, wid = tid >> 5;
    int warp_m = (wid >> 2) * 64, warp_n = (wid & 3) * 32;

    if (tid == 0){ mbar_init(sb,1); mbar_init(sb+8,1); mbar_init(sb+16,1); }
    __syncthreads();

    #pragma unroll
    for (int i = 0; i < 64; ++i) acc[i] = 0.f;

    int NC = K / 64;

    auto issue = [&](int c){
        if (tid == 0){
            int st = c % 3;
            uint32_t mb = sb + 8*st;
            mbar_expect(mb, 2*TILE_B);
            uint32_t dst = sb + 1024 + st*2*TILE_B;
            tma2d(dst,          mA, ax0 + c*64, ay, mb);
            tma2d(dst + TILE_B, mB, bx0 + c*64, by, mb);
        }
    };
    issue(0);
    if (NC > 1) issue(1);
    if (NC > 2) issue(2);

    uint32_t a_row  = warp_m + (lane & 15);
    uint32_t a_colb = (lane >> 4) * 16;
    uint32_t b_row  = warp_n + (lane & 7) + ((lane >> 4) << 3);
    uint32_t b_colb = ((lane >> 3) & 1) * 16;

    for (int c = 0; c < NC; ++c){
        wait_parity(sb + 8*(c % 3), (c / 3) & 1);
        uint32_t st = sb + 1024 + (c % 3)*2*TILE_B;
        #pragma unroll
        for (int ks = 0; ks < 4; ++ks){
            uint32_t a_[16], bh[8];
            #pragma unroll
            for (int mt = 0; mt < 4; ++mt){
                uint32_t off = swz((a_row + mt*16)*128 + ks*32 + a_colb);
                ldm4(a_ + mt*4, st + off);
            }
            #pragma unroll
            for (int nt = 0; nt < 2; ++nt){
                uint32_t off = swz((b_row + nt*16)*128 + ks*32 + b_colb);
                ldm4(bh + nt*4, st + TILE_B + off);
            }
            #pragma unroll
            for (int mt = 0; mt < 4; ++mt)
                #pragma unroll
                for (int n8 = 0; n8 < 4; ++n8){
                    float* c4 = acc + (mt*4 + n8)*4;
                    int bi = (n8 >> 1)*4 + (n8 & 1)*2;
                    mma16816(c4, a_ + mt*4, bh[bi], bh[bi+1]);
                }
        }
        __syncthreads();
        if (c + 3 < NC) issue(c + 3);
    }
    if (tid == 0){ mbar_inval(sb); mbar_inval(sb+8); mbar_inval(sb+16); }
}

template<class F>
__device__ __forceinline__ void epi_loop(const float* acc, F f){
    int lane = threadIdx.x & 31, wid = threadIdx.x >> 5;
    int warp_m = (wid >> 2) * 64, warp_n = (wid & 3) * 32;
    int g = lane >> 2, tg = (lane & 3) * 2;
    #pragma unroll
    for (int mt = 0; mt < 4; ++mt)
        #pragma unroll
        for (int n8 = 0; n8 < 4; ++n8){
            const float* c4 = acc + (mt*4 + n8)*4;
            #pragma unroll
            for (int hh = 0; hh < 2; ++hh){
                int r  = warp_m + mt*16 + g + hh*8;
                int cc = warp_n + n8*8 + tg;
                f(r, cc, c4[hh*2], c4[hh*2+1]);
            }
        }
}

// ================= GEMM kernels ============================================
__global__ void __launch_bounds__(256, 2) qkv_tc(
    const __grid_constant__ CUtensorMap mXf,
    const __grid_constant__ CUtensorMap mWq,
    const __grid_constant__ CUtensorMap mWk,
    const __grid_constant__ CUtensorMap mWv)
{
    extern __shared__ char smem[];
    int z = blockIdx.z;
    int row0 = blockIdx.y*128, col0 = blockIdx.x*128;
    const CUtensorMap* pb = (z == 0) ? &mWq : (z == 1) ? &mWk : &mWv;
    float acc[64];
    gemm_main(&mXf, pb, 0, row0, 0, col0, HID, acc);

    int lane = threadIdx.x & 31, wid = threadIdx.x >> 5;

    if (z < 2){
        // write fp16 Q/K + stage fp32 tile for fused affinity
        float* Ts = (float*)(smem + 1024);   // [128][132]
        f16* dst16 = z ? g_Kf : g_Qf;
        epi_loop(acc, [&](int r, int cc, float v0, float v1){
            size_t idx = (size_t)(row0 + r)*HID + col0 + cc;
            *(uint32_t*)(dst16 + idx) = packh2(v0, v1);
            Ts[r*132 + cc]     = v0;
            Ts[r*132 + cc + 1] = v1;
        });
        __syncthreads();

        // fused affinity: 8 warps x 16 tokens, head h = col0/128
        int h = col0 >> 7;
        int bh = ((row0 >> 10) << 4) | h;
        float ds = g_ds;
        float* outp = (z ? g_ka : g_qa)
                    + (size_t)bh*Ss*NS + (size_t)(row0 & (Ss-1))*NS;
        for (int tt = 0; tt < 16; ++tt){
            int r = wid*16 + tt;
            const float* row = Ts + r*132;
            float tv0 = row[lane], tv1 = row[lane+32], tv2 = row[lane+64], tv3 = row[lane+96];
            float tsq = wsum(tv0*tv0 + tv1*tv1 + tv2*tv2 + tv3*tv3);
            #pragma unroll
            for (int n = 0; n < NS; ++n){
                int hn = h*NS + n;
                const float* pp = g_pos + hn*Dd;
                const float* dd = g_dir + hn*Dd;
                float tp = tv0*pp[lane] + tv1*pp[lane+32] + tv2*pp[lane+64] + tv3*pp[lane+96];
                float td = tv0*dd[lane] + tv1*dd[lane+32] + tv2*dd[lane+64] + tv3*dd[lane+96];
                tp = wsum(tp);  td = wsum(td);
                if (lane == n){
                    float dist2 = fmaxf(tsq - 2.0f*tp + g_possq[hn], 0.0f);
                    float proj  = td - g_pdd[hn];
                    float perp2 = fmaxf(dist2 - proj*proj, 0.0f);
                    float inv   = g_inv2s2[hn];
                    outp[(size_t)r*NS + n] = (1.0f-ds)*expf(-dist2*inv) + ds*expf(-perp2*inv);
                }
            }
        }
    } else {
        // stage transposed V tile in SMEM, then coalesced write to g_Vth
        f16* Ts = (f16*)(smem + 1024);      // [128 d][136 s-stride]
        epi_loop(acc, [&](int r, int cc, float v0, float v1){
            Ts[cc*136 + r]       = __float2half(v0);
            Ts[(cc+1)*136 + r]   = __float2half(v1);
        });
        __syncthreads();
        int b = row0 >> 10, s0 = row0 & (Ss-1);
        int h = col0 >> 7;
        size_t dbase = ((size_t)(b*NH + h))*Dd;
        for (int it = threadIdx.x; it < 128*16; it += 256){
            int d = it >> 4, seg = it & 15;
            uint4 val = *(const uint4*)(Ts + d*136 + seg*8);
            *(uint4*)(g_Vth + (dbase + d)*Ss + s0 + seg*8) = val;
        }
    }
}

__global__ void __launch_bounds__(256, 2) wo_tc(
    const __grid_constant__ CUtensorMap mCf,
    const __grid_constant__ CUtensorMap mWo,
    float* __restrict__ out)
{
    int row0 = blockIdx.y*128, col0 = blockIdx.x*128;
    float acc[64];
    gemm_main(&mCf, &mWo, 0, row0, 0, col0, HID, acc);
    epi_loop(acc, [&](int r, int cc, float v0, float v1){
        float2 fv; fv.x = v0; fv.y = v1;
        *(float2*)(out + (size_t)(row0 + r)*HID + col0 + cc) = fv;
    });
}

// ================= flash attention kernel ==================================
__global__ void __launch_bounds__(256, 2) flash_tc(
    const __grid_constant__ CUtensorMap mQf,
    const __grid_constant__ CUtensorMap mK64,
    const __grid_constant__ CUtensorMap mVh)
{
    extern __shared__ char smem[];
    uint32_t sb = smem_u32(smem);
    int tid = threadIdx.x, lane = tid & 31, wid = tid >> 5;
    int bh = blockIdx.y, b = bh >> 4, h = bh & 15;
    int row0 = blockIdx.x * 128;

    const uint32_t QF  = sb + 1024;          // two 16KB halves
    const uint32_t ST0 = QF + 32768;
    // stage: KF0(8K) KF1(8K) VH(16K) = 32KB

    if (tid == 0){ mbar_init(sb,1); mbar_init(sb+8,1); mbar_init(sb+16,1); }
    __syncthreads();

    if (tid == 0){
        mbar_expect(sb+16, 32768u);
        tma2d(QF,        &mQf, h*128,    b*Ss+row0, sb+16);
        tma2d(QF+16384,  &mQf, h*128+64, b*Ss+row0, sb+16);
    }
    auto issue = [&](int j){
        if (tid == 0){
            uint32_t mb = sb + 8*(j&1);
            mbar_expect(mb, (uint32_t)FSTAGE_B);
            uint32_t st = ST0 + (j&1)*FSTAGE_B;
            tma2d(st,         &mK64, h*128,    b*Ss+j*64, mb);
            tma2d(st+8192,    &mK64, h*128+64, b*Ss+j*64, mb);
            tma2d(st+16384,   &mVh,  j*64, bh*128, mb);
        }
    };
    issue(0); issue(1);

    float O[64];
    #pragma unroll
    for (int i = 0; i < 64; ++i) O[i] = 0.f;
    float m0 = -1e30f, m1 = -1e30f, l0 = 0.f, l1 = 0.f;
    const float qk = 0.08838834764831845f;

    uint32_t a_row = wid*16 + (lane & 15), a_colb = (lane >> 4)*16;
    uint32_t b_rw  = (lane & 7) + ((lane >> 4) << 3);
    uint32_t b_cb  = ((lane >> 3) & 1)*16;

    wait_parity(sb+16, 0);

    for (int j = 0; j < 16; ++j){
        wait_parity(sb + 8*(j&1), (j>>1)&1);
        uint32_t st = ST0 + (j&1)*FSTAGE_B;

        // ---- S = Q K^T
        float s[32];
        #pragma unroll
        for (int i = 0; i < 32; ++i) s[i] = 0.f;
        #pragma unroll
        for (int ks = 0; ks < 8; ++ks){
            uint32_t qf_[4], kh_[16];
            uint32_t offa = (ks>>2)*16384 + swz(a_row*128 + (ks&3)*32 + a_colb);
            ldm4(qf_, QF + offa);
            #pragma unroll
            for (int nt = 0; nt < 4; ++nt){
                uint32_t offb = (ks>>2)*8192 + swz((b_rw + nt*16)*128 + (ks&3)*32 + b_cb);
                ldm4(kh_ + nt*4, st + offb);
            }
            #pragma unroll
            for (int n8 = 0; n8 < 8; ++n8){
                int bi = (n8 >> 1)*4 + (n8 & 1)*2;
                mma16816(s + n8*4, qf_, kh_[bi], kh_[bi+1]);
            }
        }

        // ---- online softmax
        float tm0 = -1e30f, tm1 = -1e30f;
        #pragma unroll
        for (int t = 0; t < 8; ++t){
            s[t*4+0] *= qk; s[t*4+1] *= qk; s[t*4+2] *= qk; s[t*4+3] *= qk;
            tm0 = fmaxf(tm0, fmaxf(s[t*4+0], s[t*4+1]));
            tm1 = fmaxf(tm1, fmaxf(s[t*4+2], s[t*4+3]));
        }
        tm0 = fmaxf(tm0, __shfl_xor_sync(0xffffffffu, tm0, 1));
        tm0 = fmaxf(tm0, __shfl_xor_sync(0xffffffffu, tm0, 2));
        tm1 = fmaxf(tm1, __shfl_xor_sync(0xffffffffu, tm1, 1));
        tm1 = fmaxf(tm1, __shfl_xor_sync(0xffffffffu, tm1, 2));
        float nm0 = fmaxf(m0, tm0), nm1 = fmaxf(m1, tm1);
        float al0 = expf(m0 - nm0), al1 = expf(m1 - nm1);
        float ts0 = 0.f, ts1 = 0.f;
        #pragma unroll
        for (int t = 0; t < 8; ++t){
            s[t*4+0] = expf(s[t*4+0] - nm0); s[t*4+1] = expf(s[t*4+1] - nm0);
            s[t*4+2] = expf(s[t*4+2] - nm1); s[t*4+3] = expf(s[t*4+3] - nm1);
            ts0 += s[t*4+0] + s[t*4+1];
            ts1 += s[t*4+2] + s[t*4+3];
        }
        ts0 += __shfl_xor_sync(0xffffffffu, ts0, 1);
        ts0 += __shfl_xor_sync(0xffffffffu, ts0, 2);
        ts1 += __shfl_xor_sync(0xffffffffu, ts1, 1);
        ts1 += __shfl_xor_sync(0xffffffffu, ts1, 2);
        l0 = l0*al0 + ts0;  l1 = l1*al1 + ts1;
        m0 = nm0;  m1 = nm1;
        #pragma unroll
        for (int t = 0; t < 16; ++t){
            O[t*4+0] *= al0; O[t*4+1] *= al0; O[t*4+2] *= al1; O[t*4+3] *= al1;
        }

        // ---- pack P into A fragments
        uint32_t ph_[16];
        #pragma unroll
        for (int t = 0; t < 4; ++t){
            ph_[t*4+0] = packh2(s[(2*t)*4+0],   s[(2*t)*4+1]);
            ph_[t*4+1] = packh2(s[(2*t)*4+2],   s[(2*t)*4+3]);
            ph_[t*4+2] = packh2(s[(2*t+1)*4+0], s[(2*t+1)*4+1]);
            ph_[t*4+3] = packh2(s[(2*t+1)*4+2], s[(2*t+1)*4+3]);
        }

        // ---- O += P V
        #pragma unroll
        for (int ks = 0; ks < 4; ++ks){
            uint32_t vh_[32];
            #pragma unroll
            for (int nt = 0; nt < 8; ++nt){
                uint32_t offv = swz((b_rw + nt*16)*128 + ks*32 + b_cb);
                ldm4(vh_ + nt*4, st + 16384 + offv);
            }
            #pragma unroll
            for (int n8 = 0; n8 < 16; ++n8){
                int bi = (n8 >> 1)*4 + (n8 & 1)*2;
                mma16816(O + n8*4, ph_ + ks*4, vh_[bi], vh_[bi+1]);
            }
        }
        __syncthreads();
        if (j + 2 < 16) issue(j + 2);
    }

    // ---- epilogue: normalize, fuse GSA blend, write Cf
    float inv0 = 1.f / l0, inv1 = 1.f / l1;
    float blend = g_blend, ob = 1.f - blend;
    int g = lane >> 2, tg2 = (lane & 3)*2;
    int s0g = row0 + wid*16 + g, s1g = s0g + 8;

    float c0[8], c1[8];
    float den0 = 1e-8f, den1 = 1e-8f;
    #pragma unroll
    for (int n = 0; n < 8; ++n){
        float a = g_amp[h*8 + n], kss = g_ksum[bh*8 + n];
        c0[n] = g_qa[((size_t)bh*Ss + s0g)*8 + n] * a;  den0 += c0[n]*kss;
        c1[n] = g_qa[((size_t)bh*Ss + s1g)*8 + n] * a;  den1 += c1[n]*kss;
    }
    float id0 = blend/den0, id1 = blend/den1;

    size_t base0 = ((size_t)(b*Ss + s0g))*HID + h*128;
    size_t base1 = ((size_t)(b*Ss + s1g))*HID + h*128;
    #pragma unroll
    for (int n8 = 0; n8 < 16; ++n8){
        int d = n8*8 + tg2;
        float num00=0.f, num01=0.f, num10=0.f, num11=0.f;
        #pragma unroll
        for (int n = 0; n < 8; ++n){
            float2 kv = *(const float2*)(g_kvmat + ((size_t)bh*8 + n)*128 + d);
            num00 += c0[n]*kv.x;  num01 += c0[n]*kv.y;
            num10 += c1[n]*kv.x;  num11 += c1[n]*kv.y;
        }
        float v00 = ob*O[n8*4+0]*inv0 + id0*num00;
        float v01 = ob*O[n8*4+1]*inv0 + id0*num01;
        float v10 = ob*O[n8*4+2]*inv1 + id1*num10;
        float v11 = ob*O[n8*4+3]*inv1 + id1*num11;
        *(uint32_t*)(g_Cf + base0 + d) = packh2(v00, v01);
        *(uint32_t*)(g_Cf + base1 + d) = packh2(v10, v11);
    }
    __syncthreads();
    if (tid == 0){ mbar_inval(sb); mbar_inval(sb+8); mbar_inval(sb+16); }
}

// ================= conversion kernel (weights transpose + X round) =========
__global__ void tsplit_kernel(const float* __restrict__ Wq, const float* __restrict__ Wk,
                              const float* __restrict__ Wv, const float* __restrict__ Wo,
                              const float* __restrict__ X){
    __shared__ float t[32][33];
    int z = blockIdx.z;
    int n0 = blockIdx.x*32, k0 = blockIdx.y*32;
    int tx = threadIdx.x, ty = threadIdx.y;
    if (z == 4){
        #pragma unroll
        for (int j = 0; j < 4; ++j){
            size_t idx = (size_t)(k0 + ty + 8*j)*HID + n0 + tx;
            g_Xf[idx] = __float2half(X[idx]);
        }
        return;
    }
    const float* in = (z == 0) ? Wq : (z == 1) ? Wk : (z == 2) ? Wv : Wo;
    f16* oh = (z == 0) ? g_Wqt : (z == 1) ? g_Wkt : (z == 2) ? g_Wvt : g_Wot;
    #pragma unroll
    for (int j = 0; j < 4; ++j)
        t[ty + 8*j][tx] = in[(size_t)(k0 + ty + 8*j)*HID + n0 + tx];
    __syncthreads();
    #pragma unroll
    for (int j = 0; j < 4; ++j){
        float v = t[tx][ty + 8*j];
        oh[(size_t)(n0 + ty + 8*j)*HID + k0 + tx] = __float2half(v);
    }
}

// ---------------- prep ------------------------------------------------------
__global__ void prep_kernel(const float* __restrict__ pos_in,
                            const float* __restrict__ dir_in,
                            const float* __restrict__ ls_in,
                            const float* __restrict__ la_in,
                            const float* __restrict__ dstr,
                            const float* __restrict__ gstr)
{
    int i = threadIdx.x;
    if (i < NH*NS) {
        const float* p = pos_in + (size_t)i*Dd;
        const float* dv = dir_in + (size_t)i*Dd;
        float np = 0.f, nd = 0.f;
        for (int d = 0; d < Dd; ++d) { np += p[d]*p[d]; nd += dv[d]*dv[d]; }
        float pscale = 3.39411254969543f / (sqrtf(np) + 1e-12f);
        float dscale = 1.0f / (sqrtf(nd) + 1e-12f);
        float psq = 0.f, pdd = 0.f;
        for (int d = 0; d < Dd; ++d) {
            float ps = p[d]*pscale, du = dv[d]*dscale;
            g_pos[(size_t)i*Dd + d] = ps;
            g_dir[(size_t)i*Dd + d] = du;
            psq += ps*ps;  pdd += ps*du;
        }
        g_possq[i] = psq;  g_pdd[i] = pdd;
        float sc = expf(ls_in[i]);
        sc = fminf(fmaxf(sc, 0.3f), 1.2f);
        g_inv2s2[i] = 0.5f / (sc*sc);
    }
    __syncthreads();
    if (i < NH) {
        float m = -1e30f;
        for (int n = 0; n < NS; ++n) m = fmaxf(m, la_in[i*NS+n]);
        float s = 0.f, e[NS];
        for (int n = 0; n < NS; ++n) { e[n] = expf(la_in[i*NS+n]-m); s += e[n]; }
        for (int n = 0; n < NS; ++n) g_amp[i*NS+n] = e[n]/s;
    }
    if (i == 0) {
        g_ds = 1.0f / (1.0f + expf(-dstr[0]));
        float gsa = 1.0f / (1.0f + expf(-gstr[0]));
        g_blend = fminf(0.05f, gsa*0.1f);
    }
}

// ---------------- GSA linear-attention precompute (2-phase, 32 chunks) -----
__global__ void __launch_bounds__(128) gsa_kv_part()
{
    __shared__ float ska[32*NS];
    int ch = blockIdx.x, bh = blockIdx.y;
    int d = threadIdx.x;
    int s0 = ch*32;
    const float* ka = g_ka + ((size_t)bh*Ss + s0)*NS;
    // stage ka chunk (32 s x 8 n = 256 floats) into smem
    for (int i = d; i < 32*NS; i += 128) ska[i] = ka[i];
    __syncthreads();

    const f16* vb = g_Vth + (size_t)bh*Dd*Ss + (size_t)d*Ss + s0;
    // load 32 halves via 4 x uint4
    __half2 v2[16];
    #pragma unroll
    for (int q = 0; q < 4; ++q){
        uint4 raw = *(const uint4*)(vb + q*8);
        v2[q*4+0] = *(__half2*)&raw.x;  v2[q*4+1] = *(__half2*)&raw.y;
        v2[q*4+2] = *(__half2*)&raw.z;  v2[q*4+3] = *(__half2*)&raw.w;
    }
    float acc[NS];
    #pragma unroll
    for (int n = 0; n < NS; ++n) acc[n] = 0.f;
    #pragma unroll
    for (int sp = 0; sp < 16; ++sp){
        float va = __half2float(v2[sp].x);
        float vbv = __half2float(v2[sp].y);
        const float* k0 = ska + (2*sp)*NS;
        const float* k1 = ska + (2*sp+1)*NS;
        #pragma unroll
        for (int n = 0; n < NS; ++n) acc[n] += k0[n]*va + k1[n]*vbv;
    }
    #pragma unroll
    for (int n = 0; n < NS; ++n)
        g_kvp[(((size_t)ch*BH + bh)*NS + n)*Dd + d] = acc[n];
    if (d < NS){
        float kssum = 0.f;
        #pragma unroll
        for (int s = 0; s < 32; ++s) kssum += ska[s*NS + d];
        g_ksp[(ch*BH + bh)*NS + d] = kssum;
    }
}

__global__ void gsa_red()
{
    int bh = blockIdx.x, d = threadIdx.x;
    #pragma unroll
    for (int n = 0; n < NS; ++n){
        float t = 0.f;
        for (int ch = 0; ch < NCH; ++ch)
            t += g_kvp[(((size_t)ch*BH + bh)*NS + n)*Dd + d];
        g_kvmat[((size_t)bh*NS + n)*Dd + d] = t;
    }
    if (d < NS){
        float t = 0.f;
        for (int ch = 0; ch < NCH; ++ch) t += g_ksp[(ch*BH + bh)*NS + d];
        g_ksum[bh*NS + d] = t;
    }
}

// ---------------- host: tensormap construction -----------------------------
typedef CUresult (*TMapEncode)(CUtensorMap*, CUtensorMapDataType, cuuint32_t, void*,
    const cuuint64_t*, const cuuint64_t*, const cuuint32_t*, const cuuint32_t*,
    CUtensorMapInterleave, CUtensorMapSwizzle, CUtensorMapL2promotion, CUtensorMapFloatOOBfill);

static void make_map(TMapEncode enc, CUtensorMap* m, void* base, uint64_t d0, uint64_t d1,
                     uint32_t b0, uint32_t b1){
    cuuint64_t dims[2]    = {d0, d1};
    cuuint64_t strides[1] = {d0 * 2};
    cuuint32_t box[2]     = {b0, b1};
    cuuint32_t es[2]      = {1, 1};
    enc(m, CU_TENSOR_MAP_DATA_TYPE_FLOAT16, 2, base, dims, strides, box, es,
        CU_TENSOR_MAP_INTERLEAVE_NONE, CU_TENSOR_MAP_SWIZZLE_128B,
        CU_TENSOR_MAP_L2_PROMOTION_L2_128B, CU_TENSOR_MAP_FLOAT_OOB_FILL_NONE);
}

// ---------------- launch ----------------------------------------------------
extern "C" void kernel_launch(void* const* d_in, const int* in_sizes, int n_in,
                              void* d_out, int out_size)
{
    const float* X   = (const float*)d_in[0];
    const float* Wq  = (const float*)d_in[1];
    const float* Wk  = (const float*)d_in[2];
    const float* Wv  = (const float*)d_in[3];
    const float* Wo  = (const float*)d_in[4];
    const float* pos = (const float*)d_in[5];
    const float* dir = (const float*)d_in[6];
    const float* ls  = (const float*)d_in[7];
    const float* la  = (const float*)d_in[8];
    const float* dstr= (const float*)d_in[9];
    const float* gstr= (const float*)d_in[10];
    float* out = (float*)d_out;

    void* fp = nullptr;
    cudaDriverEntryPointQueryResult qr;
#if CUDART_VERSION >= 12050
    cudaGetDriverEntryPointByVersion("cuTensorMapEncodeTiled", &fp, 12000, cudaEnableDefault, &qr);
#else
    cudaGetDriverEntryPoint("cuTensorMapEncodeTiled", &fp, cudaEnableDefault, &qr);
#endif
    TMapEncode enc = (TMapEncode)fp;

    void *pXf,*pWq,*pWk,*pWv,*pWo;
    void *pQf,*pKf,*pVh,*pCf;
    cudaGetSymbolAddress(&pXf, g_Xf);
    cudaGetSymbolAddress(&pWq, g_Wqt);
    cudaGetSymbolAddress(&pWk, g_Wkt);
    cudaGetSymbolAddress(&pWv, g_Wvt);
    cudaGetSymbolAddress(&pWo, g_Wot);
    cudaGetSymbolAddress(&pQf, g_Qf);
    cudaGetSymbolAddress(&pKf, g_Kf);
    cudaGetSymbolAddress(&pVh, g_Vth);
    cudaGetSymbolAddress(&pCf, g_Cf);

    CUtensorMap mXf,mWq,mWk,mWv,mWo;
    CUtensorMap mQf,mK64,mVh,mCf;
    make_map(enc,&mXf,pXf,HID,Mm,64,128);
    make_map(enc,&mWq,pWq,HID,HID,64,128);
    make_map(enc,&mWk,pWk,HID,HID,64,128);
    make_map(enc,&mWv,pWv,HID,HID,64,128);
    make_map(enc,&mWo,pWo,HID,HID,64,128);
    make_map(enc,&mQf,pQf,HID,Mm,64,128);
    make_map(enc,&mK64,pKf,HID,Mm,64,64);
    make_map(enc,&mVh,pVh,Ss,(uint64_t)BH*Dd,64,128);
    make_map(enc,&mCf,pCf,HID,Mm,64,128);

    cudaFuncSetAttribute(qkv_tc,   cudaFuncAttributeMaxDynamicSharedMemorySize, SMEM_SZ);
    cudaFuncSetAttribute(wo_tc,    cudaFuncAttributeMaxDynamicSharedMemorySize, SMEM_SZ);
    cudaFuncSetAttribute(flash_tc, cudaFuncAttributeMaxDynamicSharedMemorySize, SMEM_FL);

    prep_kernel<<<1, 128>>>(pos, dir, ls, la, dstr, gstr);
    tsplit_kernel<<<dim3(HID/32, HID/32, 5), dim3(32, 8)>>>(Wq, Wk, Wv, Wo, X);
    qkv_tc<<<dim3(HID/128, Mm/128, 3), 256, SMEM_SZ>>>(mXf,mWq,mWk,mWv);
    gsa_kv_part<<<dim3(NCH, BH), 128>>>();
    gsa_red<<<BH, 128>>>();
    flash_tc<<<dim3(Ss/128, BH), 256, SMEM_FL>>>(mQf,mK64,mVh);
    wo_tc<<<dim3(HID/128, Mm/128, 1), 256, SMEM_SZ>>>(mCf,mWo,out);
}

// round 16
// speedup vs baseline: 7.3198x; 1.0132x over previous
#include <cuda_runtime.h>
#include <cuda.h>
#include <cuda_fp16.h>
#include <math.h>
#include <stdint.h>

#define Bb 2
#define Ss 1024
#define HID 2048
#define NH 16
#define NS 8
#define Dd 128
#define Mm (Bb*Ss)      // 2048
#define BH (Bb*NH)      // 32
#define NCH 32          // gsa kv chunks

typedef __half f16;

// ---------------- scratch (device globals; no allocation allowed) ----------
__device__ float g_qa[(size_t)BH*Ss*NS];
__device__ float g_ka[(size_t)BH*Ss*NS];
__device__ float g_kvmat[(size_t)BH*NS*Dd];
__device__ float g_ksum[BH*NS];
__device__ float g_kvp[(size_t)NCH*BH*NS*Dd];
__device__ float g_ksp[NCH*BH*NS];
__device__ float g_pos[NH*NS*Dd];
__device__ float g_dir[NH*NS*Dd];
__device__ float g_possq[NH*NS];
__device__ float g_pdd[NH*NS];
__device__ float g_inv2s2[NH*NS];
__device__ float g_amp[NH*NS];
__device__ float g_ds;
__device__ float g_blend;

// fp16 operand arrays (all plain)
__device__ f16 g_Xf[(size_t)Mm*HID];
__device__ f16 g_Wqt[(size_t)HID*HID];
__device__ f16 g_Wkt[(size_t)HID*HID];
__device__ f16 g_Wvt[(size_t)HID*HID];
__device__ f16 g_Wot[(size_t)HID*HID];
__device__ f16 g_Qf[(size_t)Mm*HID];
__device__ f16 g_Kf[(size_t)Mm*HID];
__device__ f16 g_Vth[(size_t)BH*Dd*Ss];            // [bh][d][s]
__device__ f16 g_Cf[(size_t)Mm*HID];

__device__ __forceinline__ uint32_t packh2(float x, float y){
    __half2 t = __floats2half2_rn(x, y);
    return *(uint32_t*)&t;
}

// ================= low-level helpers =======================================
__device__ __forceinline__ uint32_t smem_u32(const void* p){
    uint32_t a;
    asm("{ .reg .u64 t; cvta.to.shared.u64 t, %1; cvt.u32.u64 %0, t; }" : "=r"(a) : "l"(p));
    return a;
}
__device__ __forceinline__ void mbar_init(uint32_t a, uint32_t cnt){
    asm volatile("mbarrier.init.shared.b64 [%0], %1;" :: "r"(a), "r"(cnt) : "memory");
}
__device__ __forceinline__ void mbar_inval(uint32_t a){
    asm volatile("mbarrier.inval.shared.b64 [%0];" :: "r"(a) : "memory");
}
__device__ __forceinline__ void mbar_expect(uint32_t a, uint32_t bytes){
    asm volatile("mbarrier.arrive.expect_tx.shared.b64 _, [%0], %1;" :: "r"(a), "r"(bytes) : "memory");
}
__device__ __forceinline__ void wait_parity(uint32_t mbar, uint32_t ph){
    uint32_t done;
    asm volatile(
        "{\n\t.reg .pred p;\n\t"
        "mbarrier.try_wait.parity.acquire.cta.shared::cta.b64 p, [%1], %2;\n\t"
        "selp.b32 %0, 1, 0, p;\n\t}"
        : "=r"(done) : "r"(mbar), "r"(ph) : "memory");
    if (!done) {
        asm volatile(
            "{\n\t.reg .pred P1;\n\t"
            "WL%=:\n\t"
            "mbarrier.try_wait.parity.acquire.cta.shared::cta.b64 P1, [%0], %1, 0x989680;\n\t"
            "@P1 bra.uni WD%=;\n\t"
            "bra.uni WL%=;\n\t"
            "WD%=:\n\t}"
            :: "r"(mbar), "r"(ph) : "memory");
    }
}
__device__ __forceinline__ void tma2d(uint32_t dst, const CUtensorMap* m, int x, int y, uint32_t mbar){
    asm volatile(
        "cp.async.bulk.tensor.2d.shared::cta.global.tile.mbarrier::complete_tx::bytes "
        "[%0], [%1, {%2, %3}], [%4];"
        :: "r"(dst), "l"(m), "r"(x), "r"(y), "r"(mbar) : "memory");
}
__device__ __forceinline__ void ldm4(uint32_t* r, uint32_t a){
    asm volatile("ldmatrix.sync.aligned.m8n8.x4.shared.b16 {%0,%1,%2,%3}, [%4];"
        : "=r"(r[0]),"=r"(r[1]),"=r"(r[2]),"=r"(r[3]) : "r"(a));
}
__device__ __forceinline__ void mma16816(float* c, const uint32_t* a, uint32_t b0, uint32_t b1){
    asm volatile("mma.sync.aligned.m16n8k16.row.col.f32.f16.f16.f32 "
        "{%0,%1,%2,%3}, {%4,%5,%6,%7}, {%8,%9}, {%0,%1,%2,%3};"
        : "+f"(c[0]),"+f"(c[1]),"+f"(c[2]),"+f"(c[3])
        : "r"(a[0]),"r"(a[1]),"r"(a[2]),"r"(a[3]), "r"(b0),"r"(b1));
}
__device__ __forceinline__ uint32_t swz(uint32_t x){ return x ^ ((x>>3)&0x70); }
__device__ __forceinline__ float wsum(float v){
    #pragma unroll
    for (int o = 16; o; o >>= 1) v += __shfl_xor_sync(0xffffffffu, v, o);
    return v;
}

#define TILE_B    16384
#define SMEM_SZ   99328                          // 3 x 32K stages (+1K); epilogue reuses as 68K stage
#define FSTAGE_B  32768                          // Kf(16K) Vh(16K)
#define SMEM_FL   (1024 + 32768 + 2*FSTAGE_B)    // Q(32K) + 2 stages = 97K -> 2 CTAs/SM

// ---------------- 128x128 CTA GEMM mainloop (256 threads, 8 warps) ---------
__device__ __forceinline__ void gemm_main(
    const CUtensorMap* mA, const CUtensorMap* mB,
    int ax0, int ay, int bx0, int by, int K, float* acc)
{
    extern __shared__ char smem[];
    uint32_t sb = smem_u32(smem);
    int tid = threadIdx.x, lane = tid & 31, wid = tid >> 5;
    int warp_m = (wid >> 2) * 64, warp_n = (wid & 3) * 32;

    if (tid == 0){ mbar_init(sb,1); mbar_init(sb+8,1); mbar_init(sb+16,1); }
    __syncthreads();

    #pragma unroll
    for (int i = 0; i < 64; ++i) acc[i] = 0.f;

    int NC = K / 64;

    auto issue = [&](int c){
        if (tid == 0){
            int st = c % 3;
            uint32_t mb = sb + 8*st;
            mbar_expect(mb, 2*TILE_B);
            uint32_t dst = sb + 1024 + st*2*TILE_B;
            tma2d(dst,          mA, ax0 + c*64, ay, mb);
            tma2d(dst + TILE_B, mB, bx0 + c*64, by, mb);
        }
    };
    issue(0);
    if (NC > 1) issue(1);
    if (NC > 2) issue(2);

    uint32_t a_row  = warp_m + (lane & 15);
    uint32_t a_colb = (lane >> 4) * 16;
    uint32_t b_row  = warp_n + (lane & 7) + ((lane >> 4) << 3);
    uint32_t b_colb = ((lane >> 3) & 1) * 16;

    for (int c = 0; c < NC; ++c){
        wait_parity(sb + 8*(c % 3), (c / 3) & 1);
        uint32_t st = sb + 1024 + (c % 3)*2*TILE_B;
        #pragma unroll
        for (int ks = 0; ks < 4; ++ks){
            uint32_t a_[16], bh[8];
            #pragma unroll
            for (int mt = 0; mt < 4; ++mt){
                uint32_t off = swz((a_row + mt*16)*128 + ks*32 + a_colb);
                ldm4(a_ + mt*4, st + off);
            }
            #pragma unroll
            for (int nt = 0; nt < 2; ++nt){
                uint32_t off = swz((b_row + nt*16)*128 + ks*32 + b_colb);
                ldm4(bh + nt*4, st + TILE_B + off);
            }
            #pragma unroll
            for (int mt = 0; mt < 4; ++mt)
                #pragma unroll
                for (int n8 = 0; n8 < 4; ++n8){
                    float* c4 = acc + (mt*4 + n8)*4;
                    int bi = (n8 >> 1)*4 + (n8 & 1)*2;
                    mma16816(c4, a_ + mt*4, bh[bi], bh[bi+1]);
                }
        }
        __syncthreads();
        if (c + 3 < NC) issue(c + 3);
    }
    if (tid == 0){ mbar_inval(sb); mbar_inval(sb+8); mbar_inval(sb+16); }
}

template<class F>
__device__ __forceinline__ void epi_loop(const float* acc, F f){
    int lane = threadIdx.x & 31, wid = threadIdx.x >> 5;
    int warp_m = (wid >> 2) * 64, warp_n = (wid & 3) * 32;
    int g = lane >> 2, tg = (lane & 3) * 2;
    #pragma unroll
    for (int mt = 0; mt < 4; ++mt)
        #pragma unroll
        for (int n8 = 0; n8 < 4; ++n8){
            const float* c4 = acc + (mt*4 + n8)*4;
            #pragma unroll
            for (int hh = 0; hh < 2; ++hh){
                int r  = warp_m + mt*16 + g + hh*8;
                int cc = warp_n + n8*8 + tg;
                f(r, cc, c4[hh*2], c4[hh*2+1]);
            }
        }
}

// ================= GEMM kernels ============================================
__global__ void __launch_bounds__(256, 2) qkv_tc(
    const __grid_constant__ CUtensorMap mXf,
    const __grid_constant__ CUtensorMap mWq,
    const __grid_constant__ CUtensorMap mWk,
    const __grid_constant__ CUtensorMap mWv)
{
    extern __shared__ char smem[];
    int z = blockIdx.z;
    int row0 = blockIdx.y*128, col0 = blockIdx.x*128;
    const CUtensorMap* pb = (z == 0) ? &mWq : (z == 1) ? &mWk : &mWv;
    float acc[64];
    gemm_main(&mXf, pb, 0, row0, 0, col0, HID, acc);

    int lane = threadIdx.x & 31, wid = threadIdx.x >> 5;

    if (z < 2){
        // write fp16 Q/K + stage fp32 tile for fused affinity
        float* Ts = (float*)(smem + 1024);   // [128][132]
        f16* dst16 = z ? g_Kf : g_Qf;
        epi_loop(acc, [&](int r, int cc, float v0, float v1){
            size_t idx = (size_t)(row0 + r)*HID + col0 + cc;
            *(uint32_t*)(dst16 + idx) = packh2(v0, v1);
            Ts[r*132 + cc]     = v0;
            Ts[r*132 + cc + 1] = v1;
        });
        __syncthreads();

        // fused affinity: 8 warps x 16 tokens, head h = col0/128
        int h = col0 >> 7;
        int bh = ((row0 >> 10) << 4) | h;
        float ds = g_ds;
        float* outp = (z ? g_ka : g_qa)
                    + (size_t)bh*Ss*NS + (size_t)(row0 & (Ss-1))*NS;
        for (int tt = 0; tt < 16; ++tt){
            int r = wid*16 + tt;
            const float* row = Ts + r*132;
            float tv0 = row[lane], tv1 = row[lane+32], tv2 = row[lane+64], tv3 = row[lane+96];
            float tsq = wsum(tv0*tv0 + tv1*tv1 + tv2*tv2 + tv3*tv3);
            #pragma unroll
            for (int n = 0; n < NS; ++n){
                int hn = h*NS + n;
                const float* pp = g_pos + hn*Dd;
                const float* dd = g_dir + hn*Dd;
                float tp = tv0*pp[lane] + tv1*pp[lane+32] + tv2*pp[lane+64] + tv3*pp[lane+96];
                float td = tv0*dd[lane] + tv1*dd[lane+32] + tv2*dd[lane+64] + tv3*dd[lane+96];
                tp = wsum(tp);  td = wsum(td);
                if (lane == n){
                    float dist2 = fmaxf(tsq - 2.0f*tp + g_possq[hn], 0.0f);
                    float proj  = td - g_pdd[hn];
                    float perp2 = fmaxf(dist2 - proj*proj, 0.0f);
                    float inv   = g_inv2s2[hn];
                    outp[(size_t)r*NS + n] = (1.0f-ds)*expf(-dist2*inv) + ds*expf(-perp2*inv);
                }
            }
        }
    } else {
        // stage transposed V tile in SMEM, then coalesced write to g_Vth
        f16* Ts = (f16*)(smem + 1024);      // [128 d][136 s-stride]
        epi_loop(acc, [&](int r, int cc, float v0, float v1){
            Ts[cc*136 + r]       = __float2half(v0);
            Ts[(cc+1)*136 + r]   = __float2half(v1);
        });
        __syncthreads();
        int b = row0 >> 10, s0 = row0 & (Ss-1);
        int h = col0 >> 7;
        size_t dbase = ((size_t)(b*NH + h))*Dd;
        for (int it = threadIdx.x; it < 128*16; it += 256){
            int d = it >> 4, seg = it & 15;
            uint4 val = *(const uint4*)(Ts + d*136 + seg*8);
            *(uint4*)(g_Vth + (dbase + d)*Ss + s0 + seg*8) = val;
        }
    }
}

__global__ void __launch_bounds__(256, 2) wo_tc(
    const __grid_constant__ CUtensorMap mCf,
    const __grid_constant__ CUtensorMap mWo,
    float* __restrict__ out)
{
    int row0 = blockIdx.y*128, col0 = blockIdx.x*128;
    float acc[64];
    gemm_main(&mCf, &mWo, 0, row0, 0, col0, HID, acc);
    epi_loop(acc, [&](int r, int cc, float v0, float v1){
        float2 fv; fv.x = v0; fv.y = v1;
        *(float2*)(out + (size_t)(row0 + r)*HID + col0 + cc) = fv;
    });
}

// ================= flash attention kernel ==================================
// interleaved ldsm/mma to keep register pressure under the 128-reg cap
__global__ void __launch_bounds__(256, 2) flash_tc(
    const __grid_constant__ CUtensorMap mQf,
    const __grid_constant__ CUtensorMap mK64,
    const __grid_constant__ CUtensorMap mVh)
{
    extern __shared__ char smem[];
    uint32_t sb = smem_u32(smem);
    int tid = threadIdx.x, lane = tid & 31, wid = tid >> 5;
    int bh = blockIdx.y, b = bh >> 4, h = bh & 15;
    int row0 = blockIdx.x * 128;

    const uint32_t QF  = sb + 1024;          // two 16KB halves
    const uint32_t ST0 = QF + 32768;
    // stage: KF0(8K) KF1(8K) VH(16K) = 32KB

    if (tid == 0){ mbar_init(sb,1); mbar_init(sb+8,1); mbar_init(sb+16,1); }
    __syncthreads();

    if (tid == 0){
        mbar_expect(sb+16, 32768u);
        tma2d(QF,        &mQf, h*128,    b*Ss+row0, sb+16);
        tma2d(QF+16384,  &mQf, h*128+64, b*Ss+row0, sb+16);
    }
    auto issue = [&](int j){
        if (tid == 0){
            uint32_t mb = sb + 8*(j&1);
            mbar_expect(mb, (uint32_t)FSTAGE_B);
            uint32_t st = ST0 + (j&1)*FSTAGE_B;
            tma2d(st,         &mK64, h*128,    b*Ss+j*64, mb);
            tma2d(st+8192,    &mK64, h*128+64, b*Ss+j*64, mb);
            tma2d(st+16384,   &mVh,  j*64, bh*128, mb);
        }
    };
    issue(0); issue(1);

    float O[64];
    #pragma unroll
    for (int i = 0; i < 64; ++i) O[i] = 0.f;
    float m0 = -1e30f, m1 = -1e30f, l0 = 0.f, l1 = 0.f;
    const float qk = 0.08838834764831845f;

    uint32_t a_row = wid*16 + (lane & 15), a_colb = (lane >> 4)*16;
    uint32_t b_rw  = (lane & 7) + ((lane >> 4) << 3);
    uint32_t b_cb  = ((lane >> 3) & 1)*16;

    wait_parity(sb+16, 0);

    for (int j = 0; j < 16; ++j){
        wait_parity(sb + 8*(j&1), (j>>1)&1);
        uint32_t st = ST0 + (j&1)*FSTAGE_B;

        // ---- S = Q K^T (interleaved ld/mma, low reg pressure)
        float s[32];
        #pragma unroll
        for (int i = 0; i < 32; ++i) s[i] = 0.f;
        #pragma unroll
        for (int ks = 0; ks < 8; ++ks){
            uint32_t qf_[4];
            uint32_t offa = (ks>>2)*16384 + swz(a_row*128 + (ks&3)*32 + a_colb);
            ldm4(qf_, QF + offa);
            #pragma unroll
            for (int nt = 0; nt < 4; ++nt){
                uint32_t kh4[4];
                uint32_t offb = (ks>>2)*8192 + swz((b_rw + nt*16)*128 + (ks&3)*32 + b_cb);
                ldm4(kh4, st + offb);
                mma16816(s + (2*nt)*4,   qf_, kh4[0], kh4[1]);
                mma16816(s + (2*nt+1)*4, qf_, kh4[2], kh4[3]);
            }
        }

        // ---- online softmax
        float tm0 = -1e30f, tm1 = -1e30f;
        #pragma unroll
        for (int t = 0; t < 8; ++t){
            s[t*4+0] *= qk; s[t*4+1] *= qk; s[t*4+2] *= qk; s[t*4+3] *= qk;
            tm0 = fmaxf(tm0, fmaxf(s[t*4+0], s[t*4+1]));
            tm1 = fmaxf(tm1, fmaxf(s[t*4+2], s[t*4+3]));
        }
        tm0 = fmaxf(tm0, __shfl_xor_sync(0xffffffffu, tm0, 1));
        tm0 = fmaxf(tm0, __shfl_xor_sync(0xffffffffu, tm0, 2));
        tm1 = fmaxf(tm1, __shfl_xor_sync(0xffffffffu, tm1, 1));
        tm1 = fmaxf(tm1, __shfl_xor_sync(0xffffffffu, tm1, 2));
        float nm0 = fmaxf(m0, tm0), nm1 = fmaxf(m1, tm1);
        float al0 = expf(m0 - nm0), al1 = expf(m1 - nm1);
        float ts0 = 0.f, ts1 = 0.f;
        #pragma unroll
        for (int t = 0; t < 8; ++t){
            s[t*4+0] = expf(s[t*4+0] - nm0); s[t*4+1] = expf(s[t*4+1] - nm0);
            s[t*4+2] = expf(s[t*4+2] - nm1); s[t*4+3] = expf(s[t*4+3] - nm1);
            ts0 += s[t*4+0] + s[t*4+1];
            ts1 += s[t*4+2] + s[t*4+3];
        }
        ts0 += __shfl_xor_sync(0xffffffffu, ts0, 1);
        ts0 += __shfl_xor_sync(0xffffffffu, ts0, 2);
        ts1 += __shfl_xor_sync(0xffffffffu, ts1, 1);
        ts1 += __shfl_xor_sync(0xffffffffu, ts1, 2);
        l0 = l0*al0 + ts0;  l1 = l1*al1 + ts1;
        m0 = nm0;  m1 = nm1;
        #pragma unroll
        for (int t = 0; t < 16; ++t){
            O[t*4+0] *= al0; O[t*4+1] *= al0; O[t*4+2] *= al1; O[t*4+3] *= al1;
        }

        // ---- pack P into A fragments (s dead afterwards)
        uint32_t ph_[16];
        #pragma unroll
        for (int t = 0; t < 4; ++t){
            ph_[t*4+0] = packh2(s[(2*t)*4+0],   s[(2*t)*4+1]);
            ph_[t*4+1] = packh2(s[(2*t)*4+2],   s[(2*t)*4+3]);
            ph_[t*4+2] = packh2(s[(2*t+1)*4+0], s[(2*t+1)*4+1]);
            ph_[t*4+3] = packh2(s[(2*t+1)*4+2], s[(2*t+1)*4+3]);
        }

        // ---- O += P V (interleaved ld/mma)
        #pragma unroll
        for (int ks = 0; ks < 4; ++ks){
            #pragma unroll
            for (int nt = 0; nt < 8; ++nt){
                uint32_t vh4[4];
                uint32_t offv = swz((b_rw + nt*16)*128 + ks*32 + b_cb);
                ldm4(vh4, st + 16384 + offv);
                mma16816(O + (2*nt)*4,   ph_ + ks*4, vh4[0], vh4[1]);
                mma16816(O + (2*nt+1)*4, ph_ + ks*4, vh4[2], vh4[3]);
            }
        }
        __syncthreads();
        if (j + 2 < 16) issue(j + 2);
    }

    // ---- epilogue: normalize, fuse GSA blend, write Cf
    float inv0 = 1.f / l0, inv1 = 1.f / l1;
    float blend = g_blend, ob = 1.f - blend;
    int g = lane >> 2, tg2 = (lane & 3)*2;
    int s0g = row0 + wid*16 + g, s1g = s0g + 8;

    float c0[8], c1[8];
    float den0 = 1e-8f, den1 = 1e-8f;
    #pragma unroll
    for (int n = 0; n < 8; ++n){
        float a = g_amp[h*8 + n], kss = g_ksum[bh*8 + n];
        c0[n] = g_qa[((size_t)bh*Ss + s0g)*8 + n] * a;  den0 += c0[n]*kss;
        c1[n] = g_qa[((size_t)bh*Ss + s1g)*8 + n] * a;  den1 += c1[n]*kss;
    }
    float id0 = blend/den0, id1 = blend/den1;

    size_t base0 = ((size_t)(b*Ss + s0g))*HID + h*128;
    size_t base1 = ((size_t)(b*Ss + s1g))*HID + h*128;
    #pragma unroll
    for (int n8 = 0; n8 < 16; ++n8){
        int d = n8*8 + tg2;
        float num00=0.f, num01=0.f, num10=0.f, num11=0.f;
        #pragma unroll
        for (int n = 0; n < 8; ++n){
            float2 kv = *(const float2*)(g_kvmat + ((size_t)bh*8 + n)*128 + d);
            num00 += c0[n]*kv.x;  num01 += c0[n]*kv.y;
            num10 += c1[n]*kv.x;  num11 += c1[n]*kv.y;
        }
        float v00 = ob*O[n8*4+0]*inv0 + id0*num00;
        float v01 = ob*O[n8*4+1]*inv0 + id0*num01;
        float v10 = ob*O[n8*4+2]*inv1 + id1*num10;
        float v11 = ob*O[n8*4+3]*inv1 + id1*num11;
        *(uint32_t*)(g_Cf + base0 + d) = packh2(v00, v01);
        *(uint32_t*)(g_Cf + base1 + d) = packh2(v10, v11);
    }
    __syncthreads();
    if (tid == 0){ mbar_inval(sb); mbar_inval(sb+8); mbar_inval(sb+16); }
}

// ================= conversion kernel (weights + X + prep fused) ============
__global__ void tsplit_kernel(const float* __restrict__ Wq, const float* __restrict__ Wk,
                              const float* __restrict__ Wv, const float* __restrict__ Wo,
                              const float* __restrict__ X,
                              const float* __restrict__ pos_in,
                              const float* __restrict__ dir_in,
                              const float* __restrict__ ls_in,
                              const float* __restrict__ la_in,
                              const float* __restrict__ dstr,
                              const float* __restrict__ gstr){
    __shared__ float t[32][33];
    int z = blockIdx.z;
    int n0 = blockIdx.x*32, k0 = blockIdx.y*32;
    int tx = threadIdx.x, ty = threadIdx.y;
    if (z == 5){
        // prep slice: only block (0,0) works
        if (blockIdx.x || blockIdx.y) return;
        int i = ty*32 + tx;      // 0..255
        if (i < NH*NS) {
            const float* p = pos_in + (size_t)i*Dd;
            const float* dv = dir_in + (size_t)i*Dd;
            float np = 0.f, nd = 0.f;
            for (int d = 0; d < Dd; ++d) { np += p[d]*p[d]; nd += dv[d]*dv[d]; }
            float pscale = 3.39411254969543f / (sqrtf(np) + 1e-12f);
            float dscale = 1.0f / (sqrtf(nd) + 1e-12f);
            float psq = 0.f, pdd = 0.f;
            for (int d = 0; d < Dd; ++d) {
                float ps = p[d]*pscale, du = dv[d]*dscale;
                g_pos[(size_t)i*Dd + d] = ps;
                g_dir[(size_t)i*Dd + d] = du;
                psq += ps*ps;  pdd += ps*du;
            }
            g_possq[i] = psq;  g_pdd[i] = pdd;
            float sc = expf(ls_in[i]);
            sc = fminf(fmaxf(sc, 0.3f), 1.2f);
            g_inv2s2[i] = 0.5f / (sc*sc);
        }
        if (i < NH) {
            float m = -1e30f;
            for (int n = 0; n < NS; ++n) m = fmaxf(m, la_in[i*NS+n]);
            float s = 0.f, e[NS];
            for (int n = 0; n < NS; ++n) { e[n] = expf(la_in[i*NS+n]-m); s += e[n]; }
            for (int n = 0; n < NS; ++n) g_amp[i*NS+n] = e[n]/s;
        }
        if (i == 0) {
            g_ds = 1.0f / (1.0f + expf(-dstr[0]));
            float gsa = 1.0f / (1.0f + expf(-gstr[0]));
            g_blend = fminf(0.05f, gsa*0.1f);
        }
        return;
    }
    if (z == 4){
        #pragma unroll
        for (int j = 0; j < 4; ++j){
            size_t idx = (size_t)(k0 + ty + 8*j)*HID + n0 + tx;
            g_Xf[idx] = __float2half(X[idx]);
        }
        return;
    }
    const float* in = (z == 0) ? Wq : (z == 1) ? Wk : (z == 2) ? Wv : Wo;
    f16* oh = (z == 0) ? g_Wqt : (z == 1) ? g_Wkt : (z == 2) ? g_Wvt : g_Wot;
    #pragma unroll
    for (int j = 0; j < 4; ++j)
        t[ty + 8*j][tx] = in[(size_t)(k0 + ty + 8*j)*HID + n0 + tx];
    __syncthreads();
    #pragma unroll
    for (int j = 0; j < 4; ++j){
        float v = t[tx][ty + 8*j];
        oh[(size_t)(n0 + ty + 8*j)*HID + k0 + tx] = __float2half(v);
    }
}

// ---------------- GSA linear-attention precompute (2-phase, 32 chunks) -----
__global__ void __launch_bounds__(128) gsa_kv_part()
{
    __shared__ float ska[32*NS];
    int ch = blockIdx.x, bh = blockIdx.y;
    int d = threadIdx.x;
    int s0 = ch*32;
    const float* ka = g_ka + ((size_t)bh*Ss + s0)*NS;
    for (int i = d; i < 32*NS; i += 128) ska[i] = ka[i];
    __syncthreads();

    const f16* vb = g_Vth + (size_t)bh*Dd*Ss + (size_t)d*Ss + s0;
    __half2 v2[16];
    #pragma unroll
    for (int q = 0; q < 4; ++q){
        uint4 raw = *(const uint4*)(vb + q*8);
        v2[q*4+0] = *(__half2*)&raw.x;  v2[q*4+1] = *(__half2*)&raw.y;
        v2[q*4+2] = *(__half2*)&raw.z;  v2[q*4+3] = *(__half2*)&raw.w;
    }
    float acc[NS];
    #pragma unroll
    for (int n = 0; n < NS; ++n) acc[n] = 0.f;
    #pragma unroll
    for (int sp = 0; sp < 16; ++sp){
        float va = __half2float(v2[sp].x);
        float vbv = __half2float(v2[sp].y);
        const float* k0 = ska + (2*sp)*NS;
        const float* k1 = ska + (2*sp+1)*NS;
        #pragma unroll
        for (int n = 0; n < NS; ++n) acc[n] += k0[n]*va + k1[n]*vbv;
    }
    #pragma unroll
    for (int n = 0; n < NS; ++n)
        g_kvp[(((size_t)ch*BH + bh)*NS + n)*Dd + d] = acc[n];
    if (d < NS){
        float kssum = 0.f;
        #pragma unroll
        for (int s = 0; s < 32; ++s) kssum += ska[s*NS + d];
        g_ksp[(ch*BH + bh)*NS + d] = kssum;
    }
}

__global__ void gsa_red()
{
    int bh = blockIdx.x, d = threadIdx.x;
    #pragma unroll
    for (int n = 0; n < NS; ++n){
        float t = 0.f;
        for (int ch = 0; ch < NCH; ++ch)
            t += g_kvp[(((size_t)ch*BH + bh)*NS + n)*Dd + d];
        g_kvmat[((size_t)bh*NS + n)*Dd + d] = t;
    }
    if (d < NS){
        float t = 0.f;
        for (int ch = 0; ch < NCH; ++ch) t += g_ksp[(ch*BH + bh)*NS + d];
        g_ksum[bh*NS + d] = t;
    }
}

// ---------------- host: tensormap construction -----------------------------
typedef CUresult (*TMapEncode)(CUtensorMap*, CUtensorMapDataType, cuuint32_t, void*,
    const cuuint64_t*, const cuuint64_t*, const cuuint32_t*, const cuuint32_t*,
    CUtensorMapInterleave, CUtensorMapSwizzle, CUtensorMapL2promotion, CUtensorMapFloatOOBfill);

static void make_map(TMapEncode enc, CUtensorMap* m, void* base, uint64_t d0, uint64_t d1,
                     uint32_t b0, uint32_t b1){
    cuuint64_t dims[2]    = {d0, d1};
    cuuint64_t strides[1] = {d0 * 2};
    cuuint32_t box[2]     = {b0, b1};
    cuuint32_t es[2]      = {1, 1};
    enc(m, CU_TENSOR_MAP_DATA_TYPE_FLOAT16, 2, base, dims, strides, box, es,
        CU_TENSOR_MAP_INTERLEAVE_NONE, CU_TENSOR_MAP_SWIZZLE_128B,
        CU_TENSOR_MAP_L2_PROMOTION_L2_128B, CU_TENSOR_MAP_FLOAT_OOB_FILL_NONE);
}

// ---------------- launch ----------------------------------------------------
extern "C" void kernel_launch(void* const* d_in, const int* in_sizes, int n_in,
                              void* d_out, int out_size)
{
    const float* X   = (const float*)d_in[0];
    const float* Wq  = (const float*)d_in[1];
    const float* Wk  = (const float*)d_in[2];
    const float* Wv  = (const float*)d_in[3];
    const float* Wo  = (const float*)d_in[4];
    const float* pos = (const float*)d_in[5];
    const float* dir = (const float*)d_in[6];
    const float* ls  = (const float*)d_in[7];
    const float* la  = (const float*)d_in[8];
    const float* dstr= (const float*)d_in[9];
    const float* gstr= (const float*)d_in[10];
    float* out = (float*)d_out;

    void* fp = nullptr;
    cudaDriverEntryPointQueryResult qr;
#if CUDART_VERSION >= 12050
    cudaGetDriverEntryPointByVersion("cuTensorMapEncodeTiled", &fp, 12000, cudaEnableDefault, &qr);
#else
    cudaGetDriverEntryPoint("cuTensorMapEncodeTiled", &fp, cudaEnableDefault, &qr);
#endif
    TMapEncode enc = (TMapEncode)fp;

    void *pXf,*pWq,*pWk,*pWv,*pWo;
    void *pQf,*pKf,*pVh,*pCf;
    cudaGetSymbolAddress(&pXf, g_Xf);
    cudaGetSymbolAddress(&pWq, g_Wqt);
    cudaGetSymbolAddress(&pWk, g_Wkt);
    cudaGetSymbolAddress(&pWv, g_Wvt);
    cudaGetSymbolAddress(&pWo, g_Wot);
    cudaGetSymbolAddress(&pQf, g_Qf);
    cudaGetSymbolAddress(&pKf, g_Kf);
    cudaGetSymbolAddress(&pVh, g_Vth);
    cudaGetSymbolAddress(&pCf, g_Cf);

    CUtensorMap mXf,mWq,mWk,mWv,mWo;
    CUtensorMap mQf,mK64,mVh,mCf;
    make_map(enc,&mXf,pXf,HID,Mm,64,128);
    make_map(enc,&mWq,pWq,HID,HID,64,128);
    make_map(enc,&mWk,pWk,HID,HID,64,128);
    make_map(enc,&mWv,pWv,HID,HID,64,128);
    make_map(enc,&mWo,pWo,HID,HID,64,128);
    make_map(enc,&mQf,pQf,HID,Mm,64,128);
    make_map(enc,&mK64,pKf,HID,Mm,64,64);
    make_map(enc,&mVh,pVh,Ss,(uint64_t)BH*Dd,64,128);
    make_map(enc,&mCf,pCf,HID,Mm,64,128);

    cudaFuncSetAttribute(qkv_tc,   cudaFuncAttributeMaxDynamicSharedMemorySize, SMEM_SZ);
    cudaFuncSetAttribute(wo_tc,    cudaFuncAttributeMaxDynamicSharedMemorySize, SMEM_SZ);
    cudaFuncSetAttribute(flash_tc, cudaFuncAttributeMaxDynamicSharedMemorySize, SMEM_FL);

    tsplit_kernel<<<dim3(HID/32, HID/32, 6), dim3(32, 8)>>>(Wq, Wk, Wv, Wo, X,
                                                            pos, dir, ls, la, dstr, gstr);
    qkv_tc<<<dim3(HID/128, Mm/128, 3), 256, SMEM_SZ>>>(mXf,mWq,mWk,mWv);
    gsa_kv_part<<<dim3(NCH, BH), 128>>>();
    gsa_red<<<BH, 128>>>();
    flash_tc<<<dim3(Ss/128, BH), 256, SMEM_FL>>>(mQf,mK64,mVh);
    wo_tc<<<dim3(HID/128, Mm/128, 1), 256, SMEM_SZ>>>(mCf,mWo,out);
}

// round 17
// speedup vs baseline: 7.4201x; 1.0137x over previous
#include <cuda_runtime.h>
#include <cuda.h>
#include <cuda_fp16.h>
#include <math.h>
#include <stdint.h>

#define Bb 2
#define Ss 1024
#define HID 2048
#define NH 16
#define NS 8
#define Dd 128
#define Mm (Bb*Ss)      // 2048
#define BH (Bb*NH)      // 32
#define NCH 32          // gsa kv chunks

typedef __half f16;

// ---------------- scratch (device globals; no allocation allowed) ----------
__device__ float g_qa[(size_t)BH*Ss*NS];
__device__ float g_ka[(size_t)BH*Ss*NS];
__device__ float g_kvp[(size_t)NCH*BH*NS*Dd];
__device__ float g_ksp[NCH*BH*NS];
__device__ float g_pos[NH*NS*Dd];
__device__ float g_dir[NH*NS*Dd];
__device__ float g_possq[NH*NS];
__device__ float g_pdd[NH*NS];
__device__ float g_inv2s2[NH*NS];
__device__ float g_amp[NH*NS];
__device__ float g_ds;
__device__ float g_blend;

// fp16 operand arrays (all plain)
__device__ f16 g_Xf[(size_t)Mm*HID];
__device__ f16 g_Wqt[(size_t)HID*HID];
__device__ f16 g_Wkt[(size_t)HID*HID];
__device__ f16 g_Wvt[(size_t)HID*HID];
__device__ f16 g_Wot[(size_t)HID*HID];
__device__ f16 g_Qf[(size_t)Mm*HID];
__device__ f16 g_Kf[(size_t)Mm*HID];
__device__ f16 g_Vth[(size_t)BH*Dd*Ss];            // [bh][d][s]
__device__ f16 g_Cf[(size_t)Mm*HID];

__device__ __forceinline__ uint32_t packh2(float x, float y){
    __half2 t = __floats2half2_rn(x, y);
    return *(uint32_t*)&t;
}

// ================= low-level helpers =======================================
__device__ __forceinline__ uint32_t smem_u32(const void* p){
    uint32_t a;
    asm("{ .reg .u64 t; cvta.to.shared.u64 t, %1; cvt.u32.u64 %0, t; }" : "=r"(a) : "l"(p));
    return a;
}
__device__ __forceinline__ void mbar_init(uint32_t a, uint32_t cnt){
    asm volatile("mbarrier.init.shared.b64 [%0], %1;" :: "r"(a), "r"(cnt) : "memory");
}
__device__ __forceinline__ void mbar_inval(uint32_t a){
    asm volatile("mbarrier.inval.shared.b64 [%0];" :: "r"(a) : "memory");
}
__device__ __forceinline__ void mbar_expect(uint32_t a, uint32_t bytes){
    asm volatile("mbarrier.arrive.expect_tx.shared.b64 _, [%0], %1;" :: "r"(a), "r"(bytes) : "memory");
}
__device__ __forceinline__ void wait_parity(uint32_t mbar, uint32_t ph){
    uint32_t done;
    asm volatile(
        "{\n\t.reg .pred p;\n\t"
        "mbarrier.try_wait.parity.acquire.cta.shared::cta.b64 p, [%1], %2;\n\t"
        "selp.b32 %0, 1, 0, p;\n\t}"
        : "=r"(done) : "r"(mbar), "r"(ph) : "memory");
    if (!done) {
        asm volatile(
            "{\n\t.reg .pred P1;\n\t"
            "WL%=:\n\t"
            "mbarrier.try_wait.parity.acquire.cta.shared::cta.b64 P1, [%0], %1, 0x989680;\n\t"
            "@P1 bra.uni WD%=;\n\t"
            "bra.uni WL%=;\n\t"
            "WD%=:\n\t}"
            :: "r"(mbar), "r"(ph) : "memory");
    }
}
__device__ __forceinline__ void tma2d(uint32_t dst, const CUtensorMap* m, int x, int y, uint32_t mbar){
    asm volatile(
        "cp.async.bulk.tensor.2d.shared::cta.global.tile.mbarrier::complete_tx::bytes "
        "[%0], [%1, {%2, %3}], [%4];"
        :: "r"(dst), "l"(m), "r"(x), "r"(y), "r"(mbar) : "memory");
}
__device__ __forceinline__ void ldm4(uint32_t* r, uint32_t a){
    asm volatile("ldmatrix.sync.aligned.m8n8.x4.shared.b16 {%0,%1,%2,%3}, [%4];"
        : "=r"(r[0]),"=r"(r[1]),"=r"(r[2]),"=r"(r[3]) : "r"(a));
}
__device__ __forceinline__ void mma16816(float* c, const uint32_t* a, uint32_t b0, uint32_t b1){
    asm volatile("mma.sync.aligned.m16n8k16.row.col.f32.f16.f16.f32 "
        "{%0,%1,%2,%3}, {%4,%5,%6,%7}, {%8,%9}, {%0,%1,%2,%3};"
        : "+f"(c[0]),"+f"(c[1]),"+f"(c[2]),"+f"(c[3])
        : "r"(a[0]),"r"(a[1]),"r"(a[2]),"r"(a[3]), "r"(b0),"r"(b1));
}
__device__ __forceinline__ uint32_t swz(uint32_t x){ return x ^ ((x>>3)&0x70); }
__device__ __forceinline__ float wsum(float v){
    #pragma unroll
    for (int o = 16; o; o >>= 1) v += __shfl_xor_sync(0xffffffffu, v, o);
    return v;
}

#define TILE_B    16384
#define SMEM_SZ   99328                          // 3 x 32K stages (+1K); epilogue reuses as 68K stage
#define FSTAGE_B  32768                          // Kf(16K) Vh(16K)
// flash: mbar(1K) + Q(32K) + 2 stages(64K) + kv smem (8*128*4 + 32 = 4128)
#define SMEM_FL   (1024 + 32768 + 2*FSTAGE_B + 4352)

// ---------------- 128x128 CTA GEMM mainloop (256 threads, 8 warps) ---------
__device__ __forceinline__ void gemm_main(
    const CUtensorMap* mA, const CUtensorMap* mB,
    int ax0, int ay, int bx0, int by, int K, float* acc)
{
    extern __shared__ char smem[];
    uint32_t sb = smem_u32(smem);
    int tid = threadIdx.x, lane = tid & 31, wid = tid >> 5;
    int warp_m = (wid >> 2) * 64, warp_n = (wid & 3) * 32;

    if (tid == 0){ mbar_init(sb,1); mbar_init(sb+8,1); mbar_init(sb+16,1); }
    __syncthreads();

    #pragma unroll
    for (int i = 0; i < 64; ++i) acc[i] = 0.f;

    int NC = K / 64;

    auto issue = [&](int c){
        if (tid == 0){
            int st = c % 3;
            uint32_t mb = sb + 8*st;
            mbar_expect(mb, 2*TILE_B);
            uint32_t dst = sb + 1024 + st*2*TILE_B;
            tma2d(dst,          mA, ax0 + c*64, ay, mb);
            tma2d(dst + TILE_B, mB, bx0 + c*64, by, mb);
        }
    };
    issue(0);
    if (NC > 1) issue(1);
    if (NC > 2) issue(2);

    uint32_t a_row  = warp_m + (lane & 15);
    uint32_t a_colb = (lane >> 4) * 16;
    uint32_t b_row  = warp_n + (lane & 7) + ((lane >> 4) << 3);
    uint32_t b_colb = ((lane >> 3) & 1) * 16;

    for (int c = 0; c < NC; ++c){
        wait_parity(sb + 8*(c % 3), (c / 3) & 1);
        uint32_t st = sb + 1024 + (c % 3)*2*TILE_B;
        #pragma unroll
        for (int ks = 0; ks < 4; ++ks){
            uint32_t a_[16], bh[8];
            #pragma unroll
            for (int mt = 0; mt < 4; ++mt){
                uint32_t off = swz((a_row + mt*16)*128 + ks*32 + a_colb);
                ldm4(a_ + mt*4, st + off);
            }
            #pragma unroll
            for (int nt = 0; nt < 2; ++nt){
                uint32_t off = swz((b_row + nt*16)*128 + ks*32 + b_colb);
                ldm4(bh + nt*4, st + TILE_B + off);
            }
            #pragma unroll
            for (int mt = 0; mt < 4; ++mt)
                #pragma unroll
                for (int n8 = 0; n8 < 4; ++n8){
                    float* c4 = acc + (mt*4 + n8)*4;
                    int bi = (n8 >> 1)*4 + (n8 & 1)*2;
                    mma16816(c4, a_ + mt*4, bh[bi], bh[bi+1]);
                }
        }
        __syncthreads();
        if (c + 3 < NC) issue(c + 3);
    }
    if (tid == 0){ mbar_inval(sb); mbar_inval(sb+8); mbar_inval(sb+16); }
}

template<class F>
__device__ __forceinline__ void epi_loop(const float* acc, F f){
    int lane = threadIdx.x & 31, wid = threadIdx.x >> 5;
    int warp_m = (wid >> 2) * 64, warp_n = (wid & 3) * 32;
    int g = lane >> 2, tg = (lane & 3) * 2;
    #pragma unroll
    for (int mt = 0; mt < 4; ++mt)
        #pragma unroll
        for (int n8 = 0; n8 < 4; ++n8){
            const float* c4 = acc + (mt*4 + n8)*4;
            #pragma unroll
            for (int hh = 0; hh < 2; ++hh){
                int r  = warp_m + mt*16 + g + hh*8;
                int cc = warp_n + n8*8 + tg;
                f(r, cc, c4[hh*2], c4[hh*2+1]);
            }
        }
}

// ================= GEMM kernels ============================================
__global__ void __launch_bounds__(256, 2) qkv_tc(
    const __grid_constant__ CUtensorMap mXf,
    const __grid_constant__ CUtensorMap mWq,
    const __grid_constant__ CUtensorMap mWk,
    const __grid_constant__ CUtensorMap mWv)
{
    extern __shared__ char smem[];
    int z = blockIdx.z;
    int row0 = blockIdx.y*128, col0 = blockIdx.x*128;
    const CUtensorMap* pb = (z == 0) ? &mWq : (z == 1) ? &mWk : &mWv;
    float acc[64];
    gemm_main(&mXf, pb, 0, row0, 0, col0, HID, acc);

    int lane = threadIdx.x & 31, wid = threadIdx.x >> 5;

    if (z < 2){
        // write fp16 Q/K + stage fp32 tile for fused affinity
        float* Ts = (float*)(smem + 1024);   // [128][132]
        f16* dst16 = z ? g_Kf : g_Qf;
        epi_loop(acc, [&](int r, int cc, float v0, float v1){
            size_t idx = (size_t)(row0 + r)*HID + col0 + cc;
            *(uint32_t*)(dst16 + idx) = packh2(v0, v1);
            Ts[r*132 + cc]     = v0;
            Ts[r*132 + cc + 1] = v1;
        });
        __syncthreads();

        // fused affinity: 8 warps x 16 tokens, head h = col0/128
        int h = col0 >> 7;
        int bh = ((row0 >> 10) << 4) | h;
        float ds = g_ds;
        float* outp = (z ? g_ka : g_qa)
                    + (size_t)bh*Ss*NS + (size_t)(row0 & (Ss-1))*NS;
        for (int tt = 0; tt < 16; ++tt){
            int r = wid*16 + tt;
            const float* row = Ts + r*132;
            float tv0 = row[lane], tv1 = row[lane+32], tv2 = row[lane+64], tv3 = row[lane+96];
            float tsq = wsum(tv0*tv0 + tv1*tv1 + tv2*tv2 + tv3*tv3);
            #pragma unroll
            for (int n = 0; n < NS; ++n){
                int hn = h*NS + n;
                const float* pp = g_pos + hn*Dd;
                const float* dd = g_dir + hn*Dd;
                float tp = tv0*pp[lane] + tv1*pp[lane+32] + tv2*pp[lane+64] + tv3*pp[lane+96];
                float td = tv0*dd[lane] + tv1*dd[lane+32] + tv2*dd[lane+64] + tv3*dd[lane+96];
                tp = wsum(tp);  td = wsum(td);
                if (lane == n){
                    float dist2 = fmaxf(tsq - 2.0f*tp + g_possq[hn], 0.0f);
                    float proj  = td - g_pdd[hn];
                    float perp2 = fmaxf(dist2 - proj*proj, 0.0f);
                    float inv   = g_inv2s2[hn];
                    outp[(size_t)r*NS + n] = (1.0f-ds)*expf(-dist2*inv) + ds*expf(-perp2*inv);
                }
            }
        }
    } else {
        // stage transposed V tile in SMEM, then coalesced write to g_Vth
        f16* Ts = (f16*)(smem + 1024);      // [128 d][136 s-stride]
        epi_loop(acc, [&](int r, int cc, float v0, float v1){
            Ts[cc*136 + r]       = __float2half(v0);
            Ts[(cc+1)*136 + r]   = __float2half(v1);
        });
        __syncthreads();
        int b = row0 >> 10, s0 = row0 & (Ss-1);
        int h = col0 >> 7;
        size_t dbase = ((size_t)(b*NH + h))*Dd;
        for (int it = threadIdx.x; it < 128*16; it += 256){
            int d = it >> 4, seg = it & 15;
            uint4 val = *(const uint4*)(Ts + d*136 + seg*8);
            *(uint4*)(g_Vth + (dbase + d)*Ss + s0 + seg*8) = val;
        }
    }
}

__global__ void __launch_bounds__(256, 2) wo_tc(
    const __grid_constant__ CUtensorMap mCf,
    const __grid_constant__ CUtensorMap mWo,
    float* __restrict__ out)
{
    int row0 = blockIdx.y*128, col0 = blockIdx.x*128;
    float acc[64];
    gemm_main(&mCf, &mWo, 0, row0, 0, col0, HID, acc);
    epi_loop(acc, [&](int r, int cc, float v0, float v1){
        float2 fv; fv.x = v0; fv.y = v1;
        *(float2*)(out + (size_t)(row0 + r)*HID + col0 + cc) = fv;
    });
}

// ================= flash attention kernel ==================================
// interleaved ldsm/mma; kvmat/ksum reduction fused into prologue (SMEM)
__global__ void __launch_bounds__(256, 2) flash_tc(
    const __grid_constant__ CUtensorMap mQf,
    const __grid_constant__ CUtensorMap mK64,
    const __grid_constant__ CUtensorMap mVh)
{
    extern __shared__ char smem[];
    uint32_t sb = smem_u32(smem);
    int tid = threadIdx.x, lane = tid & 31, wid = tid >> 5;
    int bh = blockIdx.y, b = bh >> 4, h = bh & 15;
    int row0 = blockIdx.x * 128;

    const uint32_t QF  = sb + 1024;          // two 16KB halves
    const uint32_t ST0 = QF + 32768;
    float* skv = (float*)(smem + 1024 + 32768 + 2*FSTAGE_B);  // [8][128]
    float* sks = skv + NS*Dd;                                  // [8]

    if (tid == 0){ mbar_init(sb,1); mbar_init(sb+8,1); mbar_init(sb+16,1); }
    __syncthreads();

    if (tid == 0){
        mbar_expect(sb+16, 32768u);
        tma2d(QF,        &mQf, h*128,    b*Ss+row0, sb+16);
        tma2d(QF+16384,  &mQf, h*128+64, b*Ss+row0, sb+16);
    }
    auto issue = [&](int j){
        if (tid == 0){
            uint32_t mb = sb + 8*(j&1);
            mbar_expect(mb, (uint32_t)FSTAGE_B);
            uint32_t st = ST0 + (j&1)*FSTAGE_B;
            tma2d(st,         &mK64, h*128,    b*Ss+j*64, mb);
            tma2d(st+8192,    &mK64, h*128+64, b*Ss+j*64, mb);
            tma2d(st+16384,   &mVh,  j*64, bh*128, mb);
        }
    };
    issue(0); issue(1);

    // ---- fused GSA reduction (overlaps with TMA latency) ----
    // kvmat[n][d] = sum_ch kvp[ch][bh][n][d];  ksum[n] = sum_ch ksp[ch][bh][n]
    for (int i = tid; i < NS*Dd; i += 256){
        float t = 0.f;
        #pragma unroll 8
        for (int ch = 0; ch < NCH; ++ch)
            t += g_kvp[(((size_t)ch*BH + bh)*NS)*Dd + i];
        skv[i] = t;
    }
    if (tid < NS){
        float t = 0.f;
        #pragma unroll
        for (int ch = 0; ch < NCH; ++ch) t += g_ksp[(ch*BH + bh)*NS + tid];
        sks[tid] = t;
    }

    float O[64];
    #pragma unroll
    for (int i = 0; i < 64; ++i) O[i] = 0.f;
    float m0 = -1e30f, m1 = -1e30f, l0 = 0.f, l1 = 0.f;
    const float qk = 0.08838834764831845f;

    uint32_t a_row = wid*16 + (lane & 15), a_colb = (lane >> 4)*16;
    uint32_t b_rw  = (lane & 7) + ((lane >> 4) << 3);
    uint32_t b_cb  = ((lane >> 3) & 1)*16;

    wait_parity(sb+16, 0);

    for (int j = 0; j < 16; ++j){
        wait_parity(sb + 8*(j&1), (j>>1)&1);
        uint32_t st = ST0 + (j&1)*FSTAGE_B;

        // ---- S = Q K^T (interleaved ld/mma)
        float s[32];
        #pragma unroll
        for (int i = 0; i < 32; ++i) s[i] = 0.f;
        #pragma unroll
        for (int ks = 0; ks < 8; ++ks){
            uint32_t qf_[4];
            uint32_t offa = (ks>>2)*16384 + swz(a_row*128 + (ks&3)*32 + a_colb);
            ldm4(qf_, QF + offa);
            #pragma unroll
            for (int nt = 0; nt < 4; ++nt){
                uint32_t kh4[4];
                uint32_t offb = (ks>>2)*8192 + swz((b_rw + nt*16)*128 + (ks&3)*32 + b_cb);
                ldm4(kh4, st + offb);
                mma16816(s + (2*nt)*4,   qf_, kh4[0], kh4[1]);
                mma16816(s + (2*nt+1)*4, qf_, kh4[2], kh4[3]);
            }
        }

        // ---- online softmax
        float tm0 = -1e30f, tm1 = -1e30f;
        #pragma unroll
        for (int t = 0; t < 8; ++t){
            s[t*4+0] *= qk; s[t*4+1] *= qk; s[t*4+2] *= qk; s[t*4+3] *= qk;
            tm0 = fmaxf(tm0, fmaxf(s[t*4+0], s[t*4+1]));
            tm1 = fmaxf(tm1, fmaxf(s[t*4+2], s[t*4+3]));
        }
        tm0 = fmaxf(tm0, __shfl_xor_sync(0xffffffffu, tm0, 1));
        tm0 = fmaxf(tm0, __shfl_xor_sync(0xffffffffu, tm0, 2));
        tm1 = fmaxf(tm1, __shfl_xor_sync(0xffffffffu, tm1, 1));
        tm1 = fmaxf(tm1, __shfl_xor_sync(0xffffffffu, tm1, 2));
        float nm0 = fmaxf(m0, tm0), nm1 = fmaxf(m1, tm1);
        float al0 = expf(m0 - nm0), al1 = expf(m1 - nm1);
        float ts0 = 0.f, ts1 = 0.f;
        #pragma unroll
        for (int t = 0; t < 8; ++t){
            s[t*4+0] = expf(s[t*4+0] - nm0); s[t*4+1] = expf(s[t*4+1] - nm0);
            s[t*4+2] = expf(s[t*4+2] - nm1); s[t*4+3] = expf(s[t*4+3] - nm1);
            ts0 += s[t*4+0] + s[t*4+1];
            ts1 += s[t*4+2] + s[t*4+3];
        }
        ts0 += __shfl_xor_sync(0xffffffffu, ts0, 1);
        ts0 += __shfl_xor_sync(0xffffffffu, ts0, 2);
        ts1 += __shfl_xor_sync(0xffffffffu, ts1, 1);
        ts1 += __shfl_xor_sync(0xffffffffu, ts1, 2);
        l0 = l0*al0 + ts0;  l1 = l1*al1 + ts1;
        m0 = nm0;  m1 = nm1;
        #pragma unroll
        for (int t = 0; t < 16; ++t){
            O[t*4+0] *= al0; O[t*4+1] *= al0; O[t*4+2] *= al1; O[t*4+3] *= al1;
        }

        // ---- pack P into A fragments
        uint32_t ph_[16];
        #pragma unroll
        for (int t = 0; t < 4; ++t){
            ph_[t*4+0] = packh2(s[(2*t)*4+0],   s[(2*t)*4+1]);
            ph_[t*4+1] = packh2(s[(2*t)*4+2],   s[(2*t)*4+3]);
            ph_[t*4+2] = packh2(s[(2*t+1)*4+0], s[(2*t+1)*4+1]);
            ph_[t*4+3] = packh2(s[(2*t+1)*4+2], s[(2*t+1)*4+3]);
        }

        // ---- O += P V (interleaved ld/mma)
        #pragma unroll
        for (int ks = 0; ks < 4; ++ks){
            #pragma unroll
            for (int nt = 0; nt < 8; ++nt){
                uint32_t vh4[4];
                uint32_t offv = swz((b_rw + nt*16)*128 + ks*32 + b_cb);
                ldm4(vh4, st + 16384 + offv);
                mma16816(O + (2*nt)*4,   ph_ + ks*4, vh4[0], vh4[1]);
                mma16816(O + (2*nt+1)*4, ph_ + ks*4, vh4[2], vh4[3]);
            }
        }
        __syncthreads();
        if (j + 2 < 16) issue(j + 2);
    }

    // ---- epilogue: normalize, fuse GSA blend (kv from SMEM), write Cf
    float inv0 = 1.f / l0, inv1 = 1.f / l1;
    float blend = g_blend, ob = 1.f - blend;
    int g = lane >> 2, tg2 = (lane & 3)*2;
    int s0g = row0 + wid*16 + g, s1g = s0g + 8;

    float c0[8], c1[8];
    float den0 = 1e-8f, den1 = 1e-8f;
    #pragma unroll
    for (int n = 0; n < 8; ++n){
        float a = g_amp[h*8 + n], kss = sks[n];
        c0[n] = g_qa[((size_t)bh*Ss + s0g)*8 + n] * a;  den0 += c0[n]*kss;
        c1[n] = g_qa[((size_t)bh*Ss + s1g)*8 + n] * a;  den1 += c1[n]*kss;
    }
    float id0 = blend/den0, id1 = blend/den1;

    size_t base0 = ((size_t)(b*Ss + s0g))*HID + h*128;
    size_t base1 = ((size_t)(b*Ss + s1g))*HID + h*128;
    #pragma unroll
    for (int n8 = 0; n8 < 16; ++n8){
        int d = n8*8 + tg2;
        float num00=0.f, num01=0.f, num10=0.f, num11=0.f;
        #pragma unroll
        for (int n = 0; n < 8; ++n){
            float kvx = skv[n*Dd + d], kvy = skv[n*Dd + d + 1];
            num00 += c0[n]*kvx;  num01 += c0[n]*kvy;
            num10 += c1[n]*kvx;  num11 += c1[n]*kvy;
        }
        float v00 = ob*O[n8*4+0]*inv0 + id0*num00;
        float v01 = ob*O[n8*4+1]*inv0 + id0*num01;
        float v10 = ob*O[n8*4+2]*inv1 + id1*num10;
        float v11 = ob*O[n8*4+3]*inv1 + id1*num11;
        *(uint32_t*)(g_Cf + base0 + d) = packh2(v00, v01);
        *(uint32_t*)(g_Cf + base1 + d) = packh2(v10, v11);
    }
    __syncthreads();
    if (tid == 0){ mbar_inval(sb); mbar_inval(sb+8); mbar_inval(sb+16); }
}

// ================= conversion kernel (weights + X + prep fused) ============
__global__ void tsplit_kernel(const float* __restrict__ Wq, const float* __restrict__ Wk,
                              const float* __restrict__ Wv, const float* __restrict__ Wo,
                              const float* __restrict__ X,
                              const float* __restrict__ pos_in,
                              const float* __restrict__ dir_in,
                              const float* __restrict__ ls_in,
                              const float* __restrict__ la_in,
                              const float* __restrict__ dstr,
                              const float* __restrict__ gstr){
    __shared__ float t[32][33];
    int z = blockIdx.z;
    int n0 = blockIdx.x*32, k0 = blockIdx.y*32;
    int tx = threadIdx.x, ty = threadIdx.y;
    if (z == 5){
        if (blockIdx.x || blockIdx.y) return;
        int i = ty*32 + tx;      // 0..255
        if (i < NH*NS) {
            const float* p = pos_in + (size_t)i*Dd;
            const float* dv = dir_in + (size_t)i*Dd;
            float np = 0.f, nd = 0.f;
            for (int d = 0; d < Dd; ++d) { np += p[d]*p[d]; nd += dv[d]*dv[d]; }
            float pscale = 3.39411254969543f / (sqrtf(np) + 1e-12f);
            float dscale = 1.0f / (sqrtf(nd) + 1e-12f);
            float psq = 0.f, pdd = 0.f;
            for (int d = 0; d < Dd; ++d) {
                float ps = p[d]*pscale, du = dv[d]*dscale;
                g_pos[(size_t)i*Dd + d] = ps;
                g_dir[(size_t)i*Dd + d] = du;
                psq += ps*ps;  pdd += ps*du;
            }
            g_possq[i] = psq;  g_pdd[i] = pdd;
            float sc = expf(ls_in[i]);
            sc = fminf(fmaxf(sc, 0.3f), 1.2f);
            g_inv2s2[i] = 0.5f / (sc*sc);
        }
        if (i < NH) {
            float m = -1e30f;
            for (int n = 0; n < NS; ++n) m = fmaxf(m, la_in[i*NS+n]);
            float s = 0.f, e[NS];
            for (int n = 0; n < NS; ++n) { e[n] = expf(la_in[i*NS+n]-m); s += e[n]; }
            for (int n = 0; n < NS; ++n) g_amp[i*NS+n] = e[n]/s;
        }
        if (i == 0) {
            g_ds = 1.0f / (1.0f + expf(-dstr[0]));
            float gsa = 1.0f / (1.0f + expf(-gstr[0]));
            g_blend = fminf(0.05f, gsa*0.1f);
        }
        return;
    }
    if (z == 4){
        #pragma unroll
        for (int j = 0; j < 4; ++j){
            size_t idx = (size_t)(k0 + ty + 8*j)*HID + n0 + tx;
            g_Xf[idx] = __float2half(X[idx]);
        }
        return;
    }
    const float* in = (z == 0) ? Wq : (z == 1) ? Wk : (z == 2) ? Wv : Wo;
    f16* oh = (z == 0) ? g_Wqt : (z == 1) ? g_Wkt : (z == 2) ? g_Wvt : g_Wot;
    #pragma unroll
    for (int j = 0; j < 4; ++j)
        t[ty + 8*j][tx] = in[(size_t)(k0 + ty + 8*j)*HID + n0 + tx];
    __syncthreads();
    #pragma unroll
    for (int j = 0; j < 4; ++j){
        float v = t[tx][ty + 8*j];
        oh[(size_t)(n0 + ty + 8*j)*HID + k0 + tx] = __float2half(v);
    }
}

// ---------------- GSA linear-attention precompute (chunked partials) -------
__global__ void __launch_bounds__(128) gsa_kv_part()
{
    __shared__ float ska[32*NS];
    int ch = blockIdx.x, bh = blockIdx.y;
    int d = threadIdx.x;
    int s0 = ch*32;
    const float* ka = g_ka + ((size_t)bh*Ss + s0)*NS;
    for (int i = d; i < 32*NS; i += 128) ska[i] = ka[i];
    __syncthreads();

    const f16* vb = g_Vth + (size_t)bh*Dd*Ss + (size_t)d*Ss + s0;
    __half2 v2[16];
    #pragma unroll
    for (int q = 0; q < 4; ++q){
        uint4 raw = *(const uint4*)(vb + q*8);
        v2[q*4+0] = *(__half2*)&raw.x;  v2[q*4+1] = *(__half2*)&raw.y;
        v2[q*4+2] = *(__half2*)&raw.z;  v2[q*4+3] = *(__half2*)&raw.w;
    }
    float acc[NS];
    #pragma unroll
    for (int n = 0; n < NS; ++n) acc[n] = 0.f;
    #pragma unroll
    for (int sp = 0; sp < 16; ++sp){
        float va = __half2float(v2[sp].x);
        float vbv = __half2float(v2[sp].y);
        const float* k0 = ska + (2*sp)*NS;
        const float* k1 = ska + (2*sp+1)*NS;
        #pragma unroll
        for (int n = 0; n < NS; ++n) acc[n] += k0[n]*va + k1[n]*vbv;
    }
    #pragma unroll
    for (int n = 0; n < NS; ++n)
        g_kvp[(((size_t)ch*BH + bh)*NS + n)*Dd + d] = acc[n];
    if (d < NS){
        float kssum = 0.f;
        #pragma unroll
        for (int s = 0; s < 32; ++s) kssum += ska[s*NS + d];
        g_ksp[(ch*BH + bh)*NS + d] = kssum;
    }
}

// ---------------- host: tensormap construction -----------------------------
typedef CUresult (*TMapEncode)(CUtensorMap*, CUtensorMapDataType, cuuint32_t, void*,
    const cuuint64_t*, const cuuint64_t*, const cuuint32_t*, const cuuint32_t*,
    CUtensorMapInterleave, CUtensorMapSwizzle, CUtensorMapL2promotion, CUtensorMapFloatOOBfill);

static void make_map(TMapEncode enc, CUtensorMap* m, void* base, uint64_t d0, uint64_t d1,
                     uint32_t b0, uint32_t b1){
    cuuint64_t dims[2]    = {d0, d1};
    cuuint64_t strides[1] = {d0 * 2};
    cuuint32_t box[2]     = {b0, b1};
    cuuint32_t es[2]      = {1, 1};
    enc(m, CU_TENSOR_MAP_DATA_TYPE_FLOAT16, 2, base, dims, strides, box, es,
        CU_TENSOR_MAP_INTERLEAVE_NONE, CU_TENSOR_MAP_SWIZZLE_128B,
        CU_TENSOR_MAP_L2_PROMOTION_L2_128B, CU_TENSOR_MAP_FLOAT_OOB_FILL_NONE);
}

// ---------------- launch ----------------------------------------------------
extern "C" void kernel_launch(void* const* d_in, const int* in_sizes, int n_in,
                              void* d_out, int out_size)
{
    const float* X   = (const float*)d_in[0];
    const float* Wq  = (const float*)d_in[1];
    const float* Wk  = (const float*)d_in[2];
    const float* Wv  = (const float*)d_in[3];
    const float* Wo  = (const float*)d_in[4];
    const float* pos = (const float*)d_in[5];
    const float* dir = (const float*)d_in[6];
    const float* ls  = (const float*)d_in[7];
    const float* la  = (const float*)d_in[8];
    const float* dstr= (const float*)d_in[9];
    const float* gstr= (const float*)d_in[10];
    float* out = (float*)d_out;

    void* fp = nullptr;
    cudaDriverEntryPointQueryResult qr;
#if CUDART_VERSION >= 12050
    cudaGetDriverEntryPointByVersion("cuTensorMapEncodeTiled", &fp, 12000, cudaEnableDefault, &qr);
#else
    cudaGetDriverEntryPoint("cuTensorMapEncodeTiled", &fp, cudaEnableDefault, &qr);
#endif
    TMapEncode enc = (TMapEncode)fp;

    void *pXf,*pWq,*pWk,*pWv,*pWo;
    void *pQf,*pKf,*pVh,*pCf;
    cudaGetSymbolAddress(&pXf, g_Xf);
    cudaGetSymbolAddress(&pWq, g_Wqt);
    cudaGetSymbolAddress(&pWk, g_Wkt);
    cudaGetSymbolAddress(&pWv, g_Wvt);
    cudaGetSymbolAddress(&pWo, g_Wot);
    cudaGetSymbolAddress(&pQf, g_Qf);
    cudaGetSymbolAddress(&pKf, g_Kf);
    cudaGetSymbolAddress(&pVh, g_Vth);
    cudaGetSymbolAddress(&pCf, g_Cf);

    CUtensorMap mXf,mWq,mWk,mWv,mWo;
    CUtensorMap mQf,mK64,mVh,mCf;
    make_map(enc,&mXf,pXf,HID,Mm,64,128);
    make_map(enc,&mWq,pWq,HID,HID,64,128);
    make_map(enc,&mWk,pWk,HID,HID,64,128);
    make_map(enc,&mWv,pWv,HID,HID,64,128);
    make_map(enc,&mWo,pWo,HID,HID,64,128);
    make_map(enc,&mQf,pQf,HID,Mm,64,128);
    make_map(enc,&mK64,pKf,HID,Mm,64,64);
    make_map(enc,&mVh,pVh,Ss,(uint64_t)BH*Dd,64,128);
    make_map(enc,&mCf,pCf,HID,Mm,64,128);

    cudaFuncSetAttribute(qkv_tc,   cudaFuncAttributeMaxDynamicSharedMemorySize, SMEM_SZ);
    cudaFuncSetAttribute(wo_tc,    cudaFuncAttributeMaxDynamicSharedMemorySize, SMEM_SZ);
    cudaFuncSetAttribute(flash_tc, cudaFuncAttributeMaxDynamicSharedMemorySize, SMEM_FL);

    tsplit_kernel<<<dim3(HID/32, HID/32, 6), dim3(32, 8)>>>(Wq, Wk, Wv, Wo, X,
                                                            pos, dir, ls, la, dstr, gstr);
    qkv_tc<<<dim3(HID/128, Mm/128, 3), 256, SMEM_SZ>>>(mXf,mWq,mWk,mWv);
    gsa_kv_part<<<dim3(NCH, BH), 128>>>();
    flash_tc<<<dim3(Ss/128, BH), 256, SMEM_FL>>>(mQf,mK64,mVh);
    wo_tc<<<dim3(HID/128, Mm/128, 1), 256, SMEM_SZ>>>(mCf,mWo,out);
}